// round 1
// baseline (speedup 1.0000x reference)
#include <cuda_runtime.h>
#include <cuda_bf16.h>

// Problem constants
#define BB 2
#define LL 2048
#define DM 1024
#define NH 16
#define FD 16
#define HD 64
#define DF 273          // 1 + 16 + 256
#define CHUNK 64
#define NC 32           // LL / CHUNK
#define NBH 32          // BB * NH
#define INV_RRD 0.5f
#define INV_Q2 0.17677669529663687f   // 1/(4*sqrt(2))
#define EPS 1e-12f

// Scratch (device globals; no allocation)
__device__ float g_q[4096 * 256];
__device__ float g_k[4096 * 256];
__device__ float g_v[4096 * 1024];
__device__ float g_y[4096 * 1024];
__device__ float g_S[NBH * NC * DF * 64];   // 17,891,328 floats
__device__ float g_ss[NBH * NC * DF];       // 279,552 floats

// ---------------------------------------------------------------------------
// Classic 128x128x8 SGEMM, 256 threads, 8x8 microtile. Handles two (B,C)
// pairs in one launch (for fusing the q and k projections).
// A: (M x K) row-major, B: (K x N) row-major, C: (M x N) row-major.
// ---------------------------------------------------------------------------
__global__ void sgemm_dual(const float* __restrict__ A,
                           const float* __restrict__ B1, float* __restrict__ C1,
                           const float* __restrict__ B2, float* __restrict__ C2,
                           int N, int K, int nsplit) {
    __shared__ float As[8][128];
    __shared__ float Bs[8][128];
    int t = threadIdx.x;
    int bn = blockIdx.x, bm = blockIdx.y;
    const float* Bsel = B1;
    float* Csel = C1;
    if (bn >= nsplit) { Bsel = B2; Csel = C2; bn -= nsplit; }

    const float* Ab = A + (long)bm * 128 * K;
    const float* Bb = Bsel + bn * 128;

    float accum[8][8];
#pragma unroll
    for (int i = 0; i < 8; i++)
#pragma unroll
        for (int j = 0; j < 8; j++) accum[i][j] = 0.f;

    int arow = t >> 1, acol = (t & 1) * 4;
    int brow = t >> 5, bcol = (t & 31) * 4;
    int tx = t & 15, ty = t >> 4;

    for (int k0 = 0; k0 < K; k0 += 8) {
        float4 a  = *(const float4*)&Ab[(long)arow * K + k0 + acol];
        float4 bv = *(const float4*)&Bb[(long)(k0 + brow) * N + bcol];
        As[acol + 0][arow] = a.x;
        As[acol + 1][arow] = a.y;
        As[acol + 2][arow] = a.z;
        As[acol + 3][arow] = a.w;
        *(float4*)&Bs[brow][bcol] = bv;
        __syncthreads();
#pragma unroll
        for (int kk = 0; kk < 8; kk++) {
            float av[8], bw[8];
            *(float4*)(av)     = *(const float4*)&As[kk][ty * 8];
            *(float4*)(av + 4) = *(const float4*)&As[kk][ty * 8 + 4];
            *(float4*)(bw)     = *(const float4*)&Bs[kk][tx * 8];
            *(float4*)(bw + 4) = *(const float4*)&Bs[kk][tx * 8 + 4];
#pragma unroll
            for (int i = 0; i < 8; i++)
#pragma unroll
                for (int j = 0; j < 8; j++)
                    accum[i][j] += av[i] * bw[j];
        }
        __syncthreads();
    }
#pragma unroll
    for (int i = 0; i < 8; i++) {
        long row = (long)bm * 128 + ty * 8 + i;
        float* Cp = Csel + row * N + bn * 128 + tx * 8;
        *(float4*)Cp       = make_float4(accum[i][0], accum[i][1], accum[i][2], accum[i][3]);
        *(float4*)(Cp + 4) = make_float4(accum[i][4], accum[i][5], accum[i][6], accum[i][7]);
    }
}

// ---------------------------------------------------------------------------
// Per-chunk local state: S_local[d][e] = sum_m phi(k[m])[d] * v[m][e]
// and ssum_local[d] = sum_m phi(k[m])[d]. One block per (b,h,chunk).
// ---------------------------------------------------------------------------
__global__ void chunk_state_kernel() {
    extern __shared__ float sm[];
    float* k_s  = sm;              // 64*16  = 1024
    float* v_s  = k_s + 1024;      // 64*64  = 4096
    float* kf_s = v_s + 4096;      // 64*336 = 21504 (padded feature dim)

    int blk = blockIdx.x;
    int c = blk & (NC - 1);
    int bh = blk >> 5;
    int b = bh >> 4, h = bh & 15;
    int t = threadIdx.x;
    long tok0 = (long)b * LL + (long)c * CHUNK;

    for (int i = t; i < 64 * 16; i += 256) {
        int n = i >> 4, f = i & 15;
        k_s[i] = g_k[(tok0 + n) * 256 + h * 16 + f];
    }
    for (int i = t; i < 64 * 64; i += 256) {
        int n = i >> 6, e = i & 63;
        v_s[i] = g_v[(tok0 + n) * 1024 + h * 64 + e];
    }
    __syncthreads();

    for (int i = t; i < 64 * 336; i += 256) {
        int n = i / 336, d = i % 336;
        float val = 0.f;
        if (d == 0) val = 1.f;
        else if (d <= 16) val = k_s[n * 16 + d - 1] * INV_RRD;
        else if (d < DF) {
            int dd = d - 17;
            val = k_s[n * 16 + (dd >> 4)] * k_s[n * 16 + (dd & 15)] * INV_Q2;
        }
        kf_s[i] = val;
    }
    __syncthreads();

    int e = t & 63, g = t >> 6;
    long outbase = (long)blk * DF * 64;
    for (int d0 = g * 16; d0 < DF; d0 += 64) {
        float acc[16];
#pragma unroll
        for (int dd = 0; dd < 16; dd++) acc[dd] = 0.f;
        for (int m = 0; m < 64; m++) {
            float vv = v_s[m * 64 + e];
#pragma unroll
            for (int dd = 0; dd < 16; dd++)
                acc[dd] += kf_s[m * 336 + d0 + dd] * vv;
        }
#pragma unroll
        for (int dd = 0; dd < 16; dd++) {
            int d = d0 + dd;
            if (d < DF) g_S[outbase + (long)d * 64 + e] = acc[dd];
        }
    }

    if (t < 128) {
        for (int d = t; d < DF; d += 128) {
            float s = 0.f;
            for (int m = 0; m < 64; m++) s += kf_s[m * 336 + d];
            g_ss[(long)blk * DF + d] = s;
        }
    }
}

// ---------------------------------------------------------------------------
// In-place exclusive prefix scan over the NC chunk states per (b,h).
// ---------------------------------------------------------------------------
__global__ void scan_S_kernel() {
    long idx = (long)blockIdx.x * 256 + threadIdx.x;
    if (idx >= (long)NBH * DF * 64) return;
    long bh = idx / (DF * 64);
    long de = idx % (DF * 64);
    long base = bh * NC * DF * 64 + de;
    float acc = 0.f;
#pragma unroll
    for (int c = 0; c < NC; c++) {
        long p = base + (long)c * DF * 64;
        float tmp = g_S[p];
        g_S[p] = acc;
        acc += tmp;
    }
}

__global__ void scan_ss_kernel() {
    long idx = (long)blockIdx.x * 256 + threadIdx.x;
    if (idx >= (long)NBH * DF) return;
    long bh = idx / DF;
    long d = idx % DF;
    long base = bh * NC * DF + d;
    float acc = 0.f;
#pragma unroll
    for (int c = 0; c < NC; c++) {
        long p = base + (long)c * DF;
        float tmp = g_ss[p];
        g_ss[p] = acc;
        acc += tmp;
    }
}

// ---------------------------------------------------------------------------
// Output: per (b,h,chunk) block — intra-chunk causal attention (scalar
// polynomial score) + inter-chunk phi(q)@S_prefix, normalized.
// ---------------------------------------------------------------------------
__global__ void output_kernel() {
    extern __shared__ float sm[];
    float* q_s  = sm;                // 1024
    float* k_s  = q_s + 1024;        // 1024
    float* v_s  = k_s + 1024;        // 4096
    float* A_s  = v_s + 4096;        // 4096
    float* qf_s = A_s + 4096;        // 64*274 = 17536
    float* S_s  = qf_s + 17536;      // 274*64 = 17536
    float* sp_s = S_s + 17536;       // 274
    float* z_s  = sp_s + 274;        // 64

    int blk = blockIdx.x;
    int c = blk & (NC - 1);
    int bh = blk >> 5;
    int b = bh >> 4, h = bh & 15;
    int t = threadIdx.x;
    long tok0 = (long)b * LL + (long)c * CHUNK;

    for (int i = t; i < 64 * 16; i += 256) {
        int n = i >> 4, f = i & 15;
        long off = (tok0 + n) * 256 + h * 16 + f;
        q_s[i] = g_q[off];
        k_s[i] = g_k[off];
    }
    for (int i = t; i < 64 * 64; i += 256) {
        int n = i >> 6, e = i & 63;
        v_s[i] = g_v[(tok0 + n) * 1024 + h * 64 + e];
    }
    long Sbase = (long)blk * DF * 64;
    for (int i = t; i < DF * 64; i += 256) S_s[i] = g_S[Sbase + i];
    if (t < 64) S_s[273 * 64 + t] = 0.f;           // pad row d=273
    for (int i = t; i < 274; i += 256) sp_s[i] = (i < DF) ? g_ss[(long)blk * DF + i] : 0.f;
    __syncthreads();

    // phi(q) into smem (padded to 274)
    for (int i = t; i < 64 * 274; i += 256) {
        int n = i / 274, d = i % 274;
        float val = 0.f;
        if (d == 0) val = 1.f;
        else if (d <= 16) val = q_s[n * 16 + d - 1] * INV_RRD;
        else if (d < DF) {
            int dd = d - 17;
            val = q_s[n * 16 + (dd >> 4)] * q_s[n * 16 + (dd & 15)] * INV_Q2;
        }
        qf_s[i] = val;
    }

    // causal score matrix A[n][m] = 1 + s/4 + s^2/32, s = q[n].k[m]; 0 above diag
    for (int i = t; i < 64 * 64; i += 256) {
        int n = i >> 6, m = i & 63;
        float a = 0.f;
        if (m <= n) {
            float s = 0.f;
#pragma unroll
            for (int f = 0; f < 16; f++) s += q_s[n * 16 + f] * k_s[m * 16 + f];
            a = 1.f + 0.25f * s + s * s * 0.03125f;
        }
        A_s[i] = a;
    }
    __syncthreads();

    // denominators
    if (t < 64) {
        int n = t;
        float dsum = 0.f;
        for (int d = 0; d < DF; d++) dsum += qf_s[n * 274 + d] * sp_s[d];
        for (int m = 0; m <= n; m++) dsum += A_s[n * 64 + m];
        z_s[n] = 1.f / (dsum + EPS);
    }
    __syncthreads();

    // main: each thread -> one e column, 16 n rows
    int e = t & 63, g = t >> 6, nb = g * 16;
    float acc[16];
#pragma unroll
    for (int i = 0; i < 16; i++) acc[i] = 0.f;

    for (int d = 0; d < 274; d += 2) {
        float s0 = S_s[d * 64 + e];
        float s1 = S_s[(d + 1) * 64 + e];
#pragma unroll
        for (int nn = 0; nn < 16; nn++) {
            float2 qv = *(const float2*)&qf_s[(nb + nn) * 274 + d];
            acc[nn] += qv.x * s0 + qv.y * s1;
        }
    }
    for (int m = 0; m < 64; m += 2) {
        float v0 = v_s[m * 64 + e];
        float v1 = v_s[(m + 1) * 64 + e];
#pragma unroll
        for (int nn = 0; nn < 16; nn++) {
            float2 av = *(const float2*)&A_s[(nb + nn) * 64 + m];
            acc[nn] += av.x * v0 + av.y * v1;
        }
    }
#pragma unroll
    for (int nn = 0; nn < 16; nn++) {
        int n = nb + nn;
        g_y[(tok0 + n) * 1024 + h * 64 + e] = acc[nn] * z_s[n];
    }
}

// ---------------------------------------------------------------------------
extern "C" void kernel_launch(void* const* d_in, const int* in_sizes, int n_in,
                              void* d_out, int out_size) {
    const float* x  = (const float*)d_in[0];
    const float* Wq = (const float*)d_in[1];
    const float* Wk = (const float*)d_in[2];
    const float* Wv = (const float*)d_in[3];
    const float* Wo = (const float*)d_in[4];
    float* out = (float*)d_out;

    void *pq, *pk, *pv, *py;
    cudaGetSymbolAddress(&pq, g_q);
    cudaGetSymbolAddress(&pk, g_k);
    cudaGetSymbolAddress(&pv, g_v);
    cudaGetSymbolAddress(&py, g_y);

    const int SM2_BYTES = (1024 + 4096 + 64 * 336) * 4;          // 106,496
    const int SM4_BYTES = (1024 + 1024 + 4096 + 4096 + 17536 + 17536 + 274 + 64) * 4; // 182,600
    cudaFuncSetAttribute(chunk_state_kernel, cudaFuncAttributeMaxDynamicSharedMemorySize, SM2_BYTES);
    cudaFuncSetAttribute(output_kernel, cudaFuncAttributeMaxDynamicSharedMemorySize, SM4_BYTES);

    // q,k projections fused into one launch (N=256 each)
    sgemm_dual<<<dim3(4, 32), 256>>>(x, Wq, (float*)pq, Wk, (float*)pk, 256, 1024, 2);
    // v projection (N=1024)
    sgemm_dual<<<dim3(8, 32), 256>>>(x, Wv, (float*)pv, Wv, (float*)pv, 1024, 1024, 8);
    // per-chunk local states
    chunk_state_kernel<<<NBH * NC, 256, SM2_BYTES>>>();
    // exclusive prefix scans over chunks
    scan_S_kernel<<<(NBH * DF * 64 + 255) / 256, 256>>>();
    scan_ss_kernel<<<(NBH * DF + 255) / 256, 256>>>();
    // attention output (normalized), into g_y
    output_kernel<<<NBH * NC, 256, SM4_BYTES>>>();
    // final projection y @ Wo -> out
    sgemm_dual<<<dim3(8, 32), 256>>>((const float*)py, Wo, out, Wo, out, 1024, 1024, 8);
}

// round 3
// speedup vs baseline: 1.4308x; 1.4308x over previous
#include <cuda_runtime.h>
#include <cuda_bf16.h>
#include <cstdint>

// Problem constants
#define BB 2
#define LL 2048
#define DM 1024
#define NH 16
#define FD 16
#define HD 64
#define DF 273          // 1 + 16 + 256
#define CHUNK 64
#define NC 32           // LL / CHUNK
#define NBH 32          // BB * NH
#define INV_RRD 0.5f
#define INV_Q2 0.17677669529663687f   // 1/(4*sqrt(2))
#define EPS 1e-12f

#define KTOT 3072       // 3-way split-K: [x_hi | x_lo | x_hi] vs [W_hi ; W_hi ; W_lo]
#define KT 64           // K per smem tile
#define NKT 48          // KTOT / KT

// ---------------------------------------------------------------------------
// Scratch (device globals; no allocation)
// ---------------------------------------------------------------------------
__device__ __nv_bfloat16 g_x2[4096 * KTOT];     // x: [hi | lo | hi]
__device__ __nv_bfloat16 g_wqk[512 * KTOT];     // [Wq|Wk]^T: [hi | hi | lo]
__device__ __nv_bfloat16 g_wv[1024 * KTOT];     // Wv^T
__device__ __nv_bfloat16 g_wo[1024 * KTOT];     // Wo^T
__device__ float g_qk[4096 * 512];              // q (cols 0..255) | k (256..511)
__device__ float g_v[4096 * 1024];
__device__ __nv_bfloat16 g_y2[4096 * KTOT];     // y: [hi | lo | hi]
__device__ float g_S[NBH * NC * DF * 64];
__device__ float g_ss[NBH * NC * DF];

// ---------------------------------------------------------------------------
// PTX helpers (baseline sm_80-compatible only: ldmatrix, mma.sync, cp.async)
// ---------------------------------------------------------------------------
__device__ __forceinline__ uint32_t smem_u32(const void* p) {
    uint32_t a;
    asm("{ .reg .u64 t; cvta.to.shared.u64 t, %1; cvt.u32.u64 %0, t; }" : "=r"(a) : "l"(p));
    return a;
}
__device__ __forceinline__ void ldsm_x4(uint32_t* r, uint32_t addr) {
    asm volatile("ldmatrix.sync.aligned.m8n8.x4.shared.b16 {%0,%1,%2,%3}, [%4];"
        : "=r"(r[0]), "=r"(r[1]), "=r"(r[2]), "=r"(r[3]) : "r"(addr));
}
__device__ __forceinline__ void ldsm_x2(uint32_t* r, uint32_t addr) {
    asm volatile("ldmatrix.sync.aligned.m8n8.x2.shared.b16 {%0,%1}, [%2];"
        : "=r"(r[0]), "=r"(r[1]) : "r"(addr));
}
__device__ __forceinline__ void mma16816(float* d, const uint32_t* a, const uint32_t* b) {
    asm volatile("mma.sync.aligned.m16n8k16.row.col.f32.bf16.bf16.f32 "
        "{%0,%1,%2,%3}, {%4,%5,%6,%7}, {%8,%9}, {%0,%1,%2,%3};"
        : "+f"(d[0]), "+f"(d[1]), "+f"(d[2]), "+f"(d[3])
        : "r"(a[0]), "r"(a[1]), "r"(a[2]), "r"(a[3]), "r"(b[0]), "r"(b[1]));
}
#define CP_ASYNC16(dst, src) \
    asm volatile("cp.async.cg.shared.global [%0], [%1], 16;" :: "r"(dst), "l"(src))
#define CP_COMMIT() asm volatile("cp.async.commit_group;" ::: "memory")
#define CP_WAIT(n)  asm volatile("cp.async.wait_group %0;" :: "n"(n) : "memory")

// ---------------------------------------------------------------------------
// Converters: fp32 -> 3-block hi/lo bf16 split (K-concat layout)
// ---------------------------------------------------------------------------
__global__ void conv_x_kernel(const float* __restrict__ x) {
    int idx = blockIdx.x * 256 + threadIdx.x;          // 4096*1024 elements
    int m = idx >> 10, k = idx & 1023;
    float v = x[idx];
    __nv_bfloat16 hi = __float2bfloat16(v);
    __nv_bfloat16 lo = __float2bfloat16(v - __bfloat162float(hi));
    size_t base = (size_t)m * KTOT + k;
    g_x2[base] = hi;
    g_x2[base + 1024] = lo;
    g_x2[base + 2048] = hi;
}

// Transposed split: W (1024 x Ncols) -> Bt rows: [W_hi | W_hi | W_lo]
__global__ void wsplit_kernel(const float* __restrict__ W, int Ncols,
                              __nv_bfloat16* __restrict__ Bt, int rowoff) {
    __shared__ float tile[32][33];
    int n0 = blockIdx.x * 32, k0 = blockIdx.y * 32;
    int tx = threadIdx.x, ty = threadIdx.y;            // 32 x 8
    for (int i = ty; i < 32; i += 8)
        tile[i][tx] = W[(size_t)(k0 + i) * Ncols + n0 + tx];
    __syncthreads();
    for (int i = ty; i < 32; i += 8) {
        int n = n0 + i, k = k0 + tx;
        float v = tile[tx][i];
        __nv_bfloat16 hi = __float2bfloat16(v);
        __nv_bfloat16 lo = __float2bfloat16(v - __bfloat162float(hi));
        size_t base = (size_t)(rowoff + n) * KTOT + k;
        Bt[base] = hi;
        Bt[base + 1024] = hi;
        Bt[base + 2048] = lo;
    }
}

// ---------------------------------------------------------------------------
// bf16 mma.sync GEMM: C (4096 x N, fp32) = A2 (4096 x KTOT) @ Bt (N x KTOT)^T
// 128x128 CTA tile, 8 warps (64x32 each), K-tile 64, cp.async double buffer.
// ---------------------------------------------------------------------------
#define SMA(b) ((b) * 32768)
#define SMB(b) ((b) * 32768 + 16384)
#define GEMM_SMEM 65536

__device__ __forceinline__ void gemm_load_tile(const __nv_bfloat16* A, const __nv_bfloat16* B,
                                               char* sm, int m0, int n0, int kb, int buf, int t) {
#pragma unroll
    for (int i = 0; i < 8; i++) {
        int idx = t + i * 256;            // 0..2047
        int row = (idx & 1023) >> 3, c = idx & 7;
        uint32_t dst;
        const __nv_bfloat16* src;
        if (idx < 1024) {
            src = A + (size_t)(m0 + row) * KTOT + kb * KT + c * 8;
            dst = smem_u32(sm + SMA(buf) + row * 128 + ((c ^ (row & 7)) << 4));
        } else {
            src = B + (size_t)(n0 + row) * KTOT + kb * KT + c * 8;
            dst = smem_u32(sm + SMB(buf) + row * 128 + ((c ^ (row & 7)) << 4));
        }
        CP_ASYNC16(dst, src);
    }
}

__global__ void __launch_bounds__(256, 1)
gemm_mma(const __nv_bfloat16* __restrict__ A, const __nv_bfloat16* __restrict__ B,
         float* __restrict__ C, int N) {
    extern __shared__ char sm[];
    int t = threadIdx.x;
    int m0 = blockIdx.y * 128, n0 = blockIdx.x * 128;
    int w = t >> 5, l = t & 31;
    int wm = (w >> 2) * 64, wn = (w & 3) * 32;

    float acc[4][4][4];
#pragma unroll
    for (int i = 0; i < 4; i++)
#pragma unroll
        for (int j = 0; j < 4; j++)
#pragma unroll
            for (int r = 0; r < 4; r++) acc[i][j][r] = 0.f;

    // A-fragment row / B-fragment row per lane (fixed across k)
    int ar = wm + (l & 15);               // + mi*16
    int ac = (l >> 4);                    // k half (0/1)
    int br = wn + (l & 7);                // + ni*8
    int bc = (l >> 3) & 1;

    gemm_load_tile(A, B, sm, m0, n0, 0, 0, t);
    CP_COMMIT();

    for (int kt = 0; kt < NKT; kt++) {
        int b = kt & 1;
        if (kt + 1 < NKT) {
            gemm_load_tile(A, B, sm, m0, n0, kt + 1, b ^ 1, t);
            CP_COMMIT();
            CP_WAIT(1);
        } else {
            CP_WAIT(0);
        }
        __syncthreads();

        uint32_t Ab = smem_u32(sm + SMA(b));
        uint32_t Bb = smem_u32(sm + SMB(b));
#pragma unroll
        for (int ks = 0; ks < 4; ks++) {
            uint32_t afr[4][4], bfr[4][2];
#pragma unroll
            for (int mi = 0; mi < 4; mi++) {
                int row = ar + mi * 16;
                int ch = ks * 2 + ac;
                ldsm_x4(afr[mi], Ab + row * 128 + ((ch ^ (row & 7)) << 4));
            }
#pragma unroll
            for (int ni = 0; ni < 4; ni++) {
                int row = br + ni * 8;
                int ch = ks * 2 + bc;
                ldsm_x2(bfr[ni], Bb + row * 128 + ((ch ^ (row & 7)) << 4));
            }
#pragma unroll
            for (int mi = 0; mi < 4; mi++)
#pragma unroll
                for (int ni = 0; ni < 4; ni++)
                    mma16816(acc[mi][ni], afr[mi], bfr[ni]);
        }
        __syncthreads();
    }

    // epilogue
    int r0 = l >> 2, c0 = (l & 3) * 2;
#pragma unroll
    for (int mi = 0; mi < 4; mi++) {
#pragma unroll
        for (int ni = 0; ni < 4; ni++) {
            int row = m0 + wm + mi * 16 + r0;
            int col = n0 + wn + ni * 8 + c0;
            *(float2*)(C + (size_t)row * N + col) = make_float2(acc[mi][ni][0], acc[mi][ni][1]);
            *(float2*)(C + (size_t)(row + 8) * N + col) = make_float2(acc[mi][ni][2], acc[mi][ni][3]);
        }
    }
}

// ---------------------------------------------------------------------------
// Per-chunk local state: S_local[d][e] = sum_m phi(k[m])[d] * v[m][e]
// ---------------------------------------------------------------------------
__global__ void chunk_state_kernel() {
    extern __shared__ float smf[];
    float* k_s  = smf;             // 64*16
    float* v_s  = k_s + 1024;      // 64*64
    float* kf_s = v_s + 4096;      // 64*336

    int blk = blockIdx.x;
    int c = blk & (NC - 1);
    int bh = blk >> 5;
    int b = bh >> 4, h = bh & 15;
    int t = threadIdx.x;
    long tok0 = (long)b * LL + (long)c * CHUNK;

    for (int i = t; i < 64 * 16; i += 256) {
        int n = i >> 4, f = i & 15;
        k_s[i] = g_qk[(tok0 + n) * 512 + 256 + h * 16 + f];
    }
    for (int i = t; i < 64 * 64; i += 256) {
        int n = i >> 6, e = i & 63;
        v_s[i] = g_v[(tok0 + n) * 1024 + h * 64 + e];
    }
    __syncthreads();

    for (int i = t; i < 64 * 336; i += 256) {
        int n = i / 336, d = i % 336;
        float val = 0.f;
        if (d == 0) val = 1.f;
        else if (d <= 16) val = k_s[n * 16 + d - 1] * INV_RRD;
        else if (d < DF) {
            int dd = d - 17;
            val = k_s[n * 16 + (dd >> 4)] * k_s[n * 16 + (dd & 15)] * INV_Q2;
        }
        kf_s[i] = val;
    }
    __syncthreads();

    int e = t & 63, g = t >> 6;
    long outbase = (long)blk * DF * 64;
    for (int d0 = g * 16; d0 < DF; d0 += 64) {
        float acc[16];
#pragma unroll
        for (int dd = 0; dd < 16; dd++) acc[dd] = 0.f;
        for (int m = 0; m < 64; m++) {
            float vv = v_s[m * 64 + e];
#pragma unroll
            for (int dd = 0; dd < 16; dd++)
                acc[dd] += kf_s[m * 336 + d0 + dd] * vv;
        }
#pragma unroll
        for (int dd = 0; dd < 16; dd++) {
            int d = d0 + dd;
            if (d < DF) g_S[outbase + (long)d * 64 + e] = acc[dd];
        }
    }

    if (t < 128) {
        for (int d = t; d < DF; d += 128) {
            float s = 0.f;
            for (int m = 0; m < 64; m++) s += kf_s[m * 336 + d];
            g_ss[(long)blk * DF + d] = s;
        }
    }
}

// ---------------------------------------------------------------------------
// In-place exclusive prefix scans over chunk index
// ---------------------------------------------------------------------------
__global__ void scan_S_kernel() {
    long idx = (long)blockIdx.x * 256 + threadIdx.x;
    if (idx >= (long)NBH * DF * 64) return;
    long bh = idx / (DF * 64);
    long de = idx % (DF * 64);
    long base = bh * NC * DF * 64 + de;
    float acc = 0.f;
#pragma unroll
    for (int c = 0; c < NC; c++) {
        long p = base + (long)c * DF * 64;
        float tmp = g_S[p];
        g_S[p] = acc;
        acc += tmp;
    }
}

__global__ void scan_ss_kernel() {
    long idx = (long)blockIdx.x * 256 + threadIdx.x;
    if (idx >= (long)NBH * DF) return;
    long bh = idx / DF;
    long d = idx % DF;
    long base = bh * NC * DF + d;
    float acc = 0.f;
#pragma unroll
    for (int c = 0; c < NC; c++) {
        long p = base + (long)c * DF;
        float tmp = g_ss[p];
        g_ss[p] = acc;
        acc += tmp;
    }
}

// ---------------------------------------------------------------------------
// Output kernel: intra-chunk causal polynomial attention + phi(q) @ S_prefix.
// Writes y as 3-block hi/lo bf16 split (ready for final GEMM).
// ---------------------------------------------------------------------------
__global__ void output_kernel() {
    extern __shared__ float smf[];
    float* q_s  = smf;               // 1024
    float* k_s  = q_s + 1024;        // 1024
    float* v_s  = k_s + 1024;        // 4096
    float* A_s  = v_s + 4096;        // 4096
    float* qf_s = A_s + 4096;        // 64*274
    float* S_s  = qf_s + 17536;      // 274*64
    float* sp_s = S_s + 17536;       // 274
    float* z_s  = sp_s + 274;        // 64

    int blk = blockIdx.x;
    int c = blk & (NC - 1);
    int bh = blk >> 5;
    int b = bh >> 4, h = bh & 15;
    int t = threadIdx.x;
    long tok0 = (long)b * LL + (long)c * CHUNK;

    for (int i = t; i < 64 * 16; i += 256) {
        int n = i >> 4, f = i & 15;
        long off = (tok0 + n) * 512 + h * 16 + f;
        q_s[i] = g_qk[off];
        k_s[i] = g_qk[off + 256];
    }
    for (int i = t; i < 64 * 64; i += 256) {
        int n = i >> 6, e = i & 63;
        v_s[i] = g_v[(tok0 + n) * 1024 + h * 64 + e];
    }
    long Sbase = (long)blk * DF * 64;
    for (int i = t; i < DF * 64; i += 256) S_s[i] = g_S[Sbase + i];
    if (t < 64) S_s[273 * 64 + t] = 0.f;
    for (int i = t; i < 274; i += 256) sp_s[i] = (i < DF) ? g_ss[(long)blk * DF + i] : 0.f;
    __syncthreads();

    for (int i = t; i < 64 * 274; i += 256) {
        int n = i / 274, d = i % 274;
        float val = 0.f;
        if (d == 0) val = 1.f;
        else if (d <= 16) val = q_s[n * 16 + d - 1] * INV_RRD;
        else if (d < DF) {
            int dd = d - 17;
            val = q_s[n * 16 + (dd >> 4)] * q_s[n * 16 + (dd & 15)] * INV_Q2;
        }
        qf_s[i] = val;
    }

    for (int i = t; i < 64 * 64; i += 256) {
        int n = i >> 6, m = i & 63;
        float a = 0.f;
        if (m <= n) {
            float s = 0.f;
#pragma unroll
            for (int f = 0; f < 16; f++) s += q_s[n * 16 + f] * k_s[m * 16 + f];
            a = 1.f + 0.25f * s + s * s * 0.03125f;
        }
        A_s[i] = a;
    }
    __syncthreads();

    if (t < 64) {
        int n = t;
        float dsum = 0.f;
        for (int d = 0; d < DF; d++) dsum += qf_s[n * 274 + d] * sp_s[d];
        for (int m = 0; m <= n; m++) dsum += A_s[n * 64 + m];
        z_s[n] = 1.f / (dsum + EPS);
    }
    __syncthreads();

    int e = t & 63, g = t >> 6, nb = g * 16;
    float acc[16];
#pragma unroll
    for (int i = 0; i < 16; i++) acc[i] = 0.f;

    for (int d = 0; d < 274; d += 2) {
        float s0 = S_s[d * 64 + e];
        float s1 = S_s[(d + 1) * 64 + e];
#pragma unroll
        for (int nn = 0; nn < 16; nn++) {
            float2 qv = *(const float2*)&qf_s[(nb + nn) * 274 + d];
            acc[nn] += qv.x * s0 + qv.y * s1;
        }
    }
    for (int m = 0; m < 64; m += 2) {
        float v0 = v_s[m * 64 + e];
        float v1 = v_s[(m + 1) * 64 + e];
#pragma unroll
        for (int nn = 0; nn < 16; nn++) {
            float2 av = *(const float2*)&A_s[(nb + nn) * 64 + m];
            acc[nn] += av.x * v0 + av.y * v1;
        }
    }
#pragma unroll
    for (int nn = 0; nn < 16; nn++) {
        int n = nb + nn;
        float val = acc[nn] * z_s[n];
        __nv_bfloat16 hi = __float2bfloat16(val);
        __nv_bfloat16 lo = __float2bfloat16(val - __bfloat162float(hi));
        size_t base = (size_t)(tok0 + n) * KTOT + h * 64 + e;
        g_y2[base] = hi;
        g_y2[base + 1024] = lo;
        g_y2[base + 2048] = hi;
    }
}

// ---------------------------------------------------------------------------
extern "C" void kernel_launch(void* const* d_in, const int* in_sizes, int n_in,
                              void* d_out, int out_size) {
    const float* x  = (const float*)d_in[0];
    const float* Wq = (const float*)d_in[1];
    const float* Wk = (const float*)d_in[2];
    const float* Wv = (const float*)d_in[3];
    const float* Wo = (const float*)d_in[4];
    float* out = (float*)d_out;

    void *px2, *pwqk, *pwv, *pwo, *pqk, *pv, *py2;
    cudaGetSymbolAddress(&px2, g_x2);
    cudaGetSymbolAddress(&pwqk, g_wqk);
    cudaGetSymbolAddress(&pwv, g_wv);
    cudaGetSymbolAddress(&pwo, g_wo);
    cudaGetSymbolAddress(&pqk, g_qk);
    cudaGetSymbolAddress(&pv, g_v);
    cudaGetSymbolAddress(&py2, g_y2);

    const int SM2_BYTES = (1024 + 4096 + 64 * 336) * 4;
    const int SM4_BYTES = (1024 + 1024 + 4096 + 4096 + 17536 + 17536 + 274 + 64) * 4;
    cudaFuncSetAttribute(chunk_state_kernel, cudaFuncAttributeMaxDynamicSharedMemorySize, SM2_BYTES);
    cudaFuncSetAttribute(output_kernel, cudaFuncAttributeMaxDynamicSharedMemorySize, SM4_BYTES);
    cudaFuncSetAttribute(gemm_mma, cudaFuncAttributeMaxDynamicSharedMemorySize, GEMM_SMEM);

    // split/convert inputs
    conv_x_kernel<<<16384, 256>>>(x);
    wsplit_kernel<<<dim3(8, 32), dim3(32, 8)>>>(Wq, 256, (__nv_bfloat16*)pwqk, 0);
    wsplit_kernel<<<dim3(8, 32), dim3(32, 8)>>>(Wk, 256, (__nv_bfloat16*)pwqk, 256);
    wsplit_kernel<<<dim3(32, 32), dim3(32, 8)>>>(Wv, 1024, (__nv_bfloat16*)pwv, 0);
    wsplit_kernel<<<dim3(32, 32), dim3(32, 8)>>>(Wo, 1024, (__nv_bfloat16*)pwo, 0);

    // projections on tensor cores (3-way split-K bf16 mma.sync, fp32 accumulate)
    gemm_mma<<<dim3(4, 32), 256, GEMM_SMEM>>>((const __nv_bfloat16*)px2, (const __nv_bfloat16*)pwqk,
                                              (float*)pqk, 512);
    gemm_mma<<<dim3(8, 32), 256, GEMM_SMEM>>>((const __nv_bfloat16*)px2, (const __nv_bfloat16*)pwv,
                                              (float*)pv, 1024);

    // chunked linear attention
    chunk_state_kernel<<<NBH * NC, 256, SM2_BYTES>>>();
    scan_S_kernel<<<(NBH * DF * 64 + 255) / 256, 256>>>();
    scan_ss_kernel<<<(NBH * DF + 255) / 256, 256>>>();
    output_kernel<<<NBH * NC, 256, SM4_BYTES>>>();

    // final projection
    gemm_mma<<<dim3(8, 32), 256, GEMM_SMEM>>>((const __nv_bfloat16*)py2, (const __nv_bfloat16*)pwo,
                                              out, 1024);
}

// round 4
// speedup vs baseline: 2.4201x; 1.6914x over previous
#include <cuda_runtime.h>
#include <cuda_bf16.h>
#include <cuda_fp16.h>
#include <cstdint>

// Problem constants
#define BB 2
#define LL 2048
#define DM 1024
#define NH 16
#define FD 16
#define HD 64
#define DF 273          // 1 + 16 + 256
#define CHUNK 64
#define NC 32           // LL / CHUNK
#define NBH 32          // BB * NH
#define INV_RRD 0.5f
#define INV_Q2 0.17677669529663687f   // 1/(4*sqrt(2))
#define EPS 1e-12f

#define KQK 3072        // bf16 3-term split for q/k projection
#define KVO 2048        // fp16 2-term split for v/o projections

// ---------------------------------------------------------------------------
// Scratch (device globals; no allocation)
// ---------------------------------------------------------------------------
__device__ __nv_bfloat16 g_x2[4096 * KQK];      // x: [hi | lo | hi] bf16
__device__ __half        g_xh[4096 * KVO];      // x: [hi | lo] fp16
__device__ __nv_bfloat16 g_wqk[512 * KQK];      // [Wq|Wk]^T: [hi | hi | lo] bf16
__device__ __half        g_wvh[1024 * KVO];     // Wv^T: [hi | hi] fp16
__device__ __half        g_woh[1024 * KVO];     // Wo^T: [hi | hi] fp16
__device__ float g_qk[4096 * 512];              // q (cols 0..255) | k (256..511)
__device__ float g_v[4096 * 1024];
__device__ __half g_yh[4096 * KVO];             // y: [hi | lo] fp16
__device__ float g_S[NBH * NC * DF * 64];
__device__ float g_ss[NBH * NC * DF];

// ---------------------------------------------------------------------------
// PTX helpers (baseline sm_80-compatible: ldmatrix, mma.sync, cp.async)
// ---------------------------------------------------------------------------
__device__ __forceinline__ uint32_t smem_u32(const void* p) {
    uint32_t a;
    asm("{ .reg .u64 t; cvta.to.shared.u64 t, %1; cvt.u32.u64 %0, t; }" : "=r"(a) : "l"(p));
    return a;
}
__device__ __forceinline__ void ldsm_x4(uint32_t* r, uint32_t addr) {
    asm volatile("ldmatrix.sync.aligned.m8n8.x4.shared.b16 {%0,%1,%2,%3}, [%4];"
        : "=r"(r[0]), "=r"(r[1]), "=r"(r[2]), "=r"(r[3]) : "r"(addr));
}
__device__ __forceinline__ void ldsm_x2(uint32_t* r, uint32_t addr) {
    asm volatile("ldmatrix.sync.aligned.m8n8.x2.shared.b16 {%0,%1}, [%2];"
        : "=r"(r[0]), "=r"(r[1]) : "r"(addr));
}
template<bool F16>
__device__ __forceinline__ void mma_any(float* d, const uint32_t* a, const uint32_t* b) {
    if constexpr (F16) {
        asm volatile("mma.sync.aligned.m16n8k16.row.col.f32.f16.f16.f32 "
            "{%0,%1,%2,%3}, {%4,%5,%6,%7}, {%8,%9}, {%0,%1,%2,%3};"
            : "+f"(d[0]), "+f"(d[1]), "+f"(d[2]), "+f"(d[3])
            : "r"(a[0]), "r"(a[1]), "r"(a[2]), "r"(a[3]), "r"(b[0]), "r"(b[1]));
    } else {
        asm volatile("mma.sync.aligned.m16n8k16.row.col.f32.bf16.bf16.f32 "
            "{%0,%1,%2,%3}, {%4,%5,%6,%7}, {%8,%9}, {%0,%1,%2,%3};"
            : "+f"(d[0]), "+f"(d[1]), "+f"(d[2]), "+f"(d[3])
            : "r"(a[0]), "r"(a[1]), "r"(a[2]), "r"(a[3]), "r"(b[0]), "r"(b[1]));
    }
}
#define CP_ASYNC16(dst, src) \
    asm volatile("cp.async.cg.shared.global [%0], [%1], 16;" :: "r"(dst), "l"(src))
#define CP_COMMIT() asm volatile("cp.async.commit_group;" ::: "memory")
#define CP_WAIT(n)  asm volatile("cp.async.wait_group %0;" :: "n"(n) : "memory")

// ---------------------------------------------------------------------------
// Converters
// ---------------------------------------------------------------------------
__global__ void conv_x_kernel(const float* __restrict__ x) {
    int idx = blockIdx.x * 256 + threadIdx.x;          // 4096*1024 elements
    int m = idx >> 10, k = idx & 1023;
    float v = x[idx];
    __nv_bfloat16 bh = __float2bfloat16(v);
    __nv_bfloat16 bl = __float2bfloat16(v - __bfloat162float(bh));
    size_t b2 = (size_t)m * KQK + k;
    g_x2[b2] = bh;
    g_x2[b2 + 1024] = bl;
    g_x2[b2 + 2048] = bh;
    __half fh = __float2half_rn(v);
    __half fl = __float2half_rn(v - __half2float(fh));
    size_t bh2 = (size_t)m * KVO + k;
    g_xh[bh2] = fh;
    g_xh[bh2 + 1024] = fl;
}

// Transposed bf16 3-term split: W (1024 x Ncols) -> rows [W_hi | W_hi | W_lo]
__global__ void wsplit_bf16(const float* __restrict__ W, int Ncols,
                            __nv_bfloat16* __restrict__ Bt, int rowoff) {
    __shared__ float tile[32][33];
    int n0 = blockIdx.x * 32, k0 = blockIdx.y * 32;
    int tx = threadIdx.x, ty = threadIdx.y;            // 32 x 8
    for (int i = ty; i < 32; i += 8)
        tile[i][tx] = W[(size_t)(k0 + i) * Ncols + n0 + tx];
    __syncthreads();
    for (int i = ty; i < 32; i += 8) {
        int n = n0 + i, k = k0 + tx;
        float v = tile[tx][i];
        __nv_bfloat16 hi = __float2bfloat16(v);
        __nv_bfloat16 lo = __float2bfloat16(v - __bfloat162float(hi));
        size_t base = (size_t)(rowoff + n) * KQK + k;
        Bt[base] = hi;
        Bt[base + 1024] = hi;
        Bt[base + 2048] = lo;
    }
}

// Transposed fp16 2-term: W (1024 x Ncols) -> rows [W_hi | W_hi]
__global__ void wsplit_f16(const float* __restrict__ W, int Ncols,
                           __half* __restrict__ Bt) {
    __shared__ float tile[32][33];
    int n0 = blockIdx.x * 32, k0 = blockIdx.y * 32;
    int tx = threadIdx.x, ty = threadIdx.y;
    for (int i = ty; i < 32; i += 8)
        tile[i][tx] = W[(size_t)(k0 + i) * Ncols + n0 + tx];
    __syncthreads();
    for (int i = ty; i < 32; i += 8) {
        int n = n0 + i, k = k0 + tx;
        __half hi = __float2half_rn(tile[tx][i]);
        size_t base = (size_t)n * KVO + k;
        Bt[base] = hi;
        Bt[base + 1024] = hi;
    }
}

// ---------------------------------------------------------------------------
// mma.sync GEMM: C (4096 x N, fp32) = A (4096 x K) @ Bt (N x K)^T
// 128x128 CTA tile, 8 warps (64x32 each), K-tile 64, cp.async double buffer,
// 2 CTAs/SM.
// ---------------------------------------------------------------------------
#define SMA(b) ((b) * 32768)
#define SMB(b) ((b) * 32768 + 16384)
#define GEMM_SMEM 65536

__device__ __forceinline__ void gemm_load_tile(const uint16_t* A, const uint16_t* B,
                                               char* sm, int m0, int n0, int kb, int buf,
                                               int t, int K) {
#pragma unroll
    for (int i = 0; i < 8; i++) {
        int idx = t + i * 256;            // 0..2047
        int row = (idx & 1023) >> 3, c = idx & 7;
        uint32_t dst;
        const uint16_t* src;
        if (idx < 1024) {
            src = A + (size_t)(m0 + row) * K + kb * 64 + c * 8;
            dst = smem_u32(sm + SMA(buf) + row * 128 + ((c ^ (row & 7)) << 4));
        } else {
            src = B + (size_t)(n0 + row) * K + kb * 64 + c * 8;
            dst = smem_u32(sm + SMB(buf) + row * 128 + ((c ^ (row & 7)) << 4));
        }
        CP_ASYNC16(dst, src);
    }
}

template<bool F16>
__global__ void __launch_bounds__(256, 2)
gemm_mma(const uint16_t* __restrict__ A, const uint16_t* __restrict__ B,
         float* __restrict__ C, int N, int K, int nkt) {
    extern __shared__ char sm[];
    int t = threadIdx.x;
    int m0 = blockIdx.y * 128, n0 = blockIdx.x * 128;
    int w = t >> 5, l = t & 31;
    int wm = (w >> 2) * 64, wn = (w & 3) * 32;

    float acc[4][4][4];
#pragma unroll
    for (int i = 0; i < 4; i++)
#pragma unroll
        for (int j = 0; j < 4; j++)
#pragma unroll
            for (int r = 0; r < 4; r++) acc[i][j][r] = 0.f;

    int ar = wm + (l & 15);
    int ac = (l >> 4);
    int br = wn + (l & 7);
    int bc = (l >> 3) & 1;

    gemm_load_tile(A, B, sm, m0, n0, 0, 0, t, K);
    CP_COMMIT();

    for (int kt = 0; kt < nkt; kt++) {
        int b = kt & 1;
        if (kt + 1 < nkt) {
            gemm_load_tile(A, B, sm, m0, n0, kt + 1, b ^ 1, t, K);
            CP_COMMIT();
            CP_WAIT(1);
        } else {
            CP_WAIT(0);
        }
        __syncthreads();

        uint32_t Ab = smem_u32(sm + SMA(b));
        uint32_t Bb = smem_u32(sm + SMB(b));
#pragma unroll
        for (int ks = 0; ks < 4; ks++) {
            uint32_t afr[4][4], bfr[4][2];
#pragma unroll
            for (int mi = 0; mi < 4; mi++) {
                int row = ar + mi * 16;
                int ch = ks * 2 + ac;
                ldsm_x4(afr[mi], Ab + row * 128 + ((ch ^ (row & 7)) << 4));
            }
#pragma unroll
            for (int ni = 0; ni < 4; ni++) {
                int row = br + ni * 8;
                int ch = ks * 2 + bc;
                ldsm_x2(bfr[ni], Bb + row * 128 + ((ch ^ (row & 7)) << 4));
            }
#pragma unroll
            for (int mi = 0; mi < 4; mi++)
#pragma unroll
                for (int ni = 0; ni < 4; ni++)
                    mma_any<F16>(acc[mi][ni], afr[mi], bfr[ni]);
        }
        __syncthreads();
    }

    int r0 = l >> 2, c0 = (l & 3) * 2;
#pragma unroll
    for (int mi = 0; mi < 4; mi++) {
#pragma unroll
        for (int ni = 0; ni < 4; ni++) {
            int row = m0 + wm + mi * 16 + r0;
            int col = n0 + wn + ni * 8 + c0;
            *(float2*)(C + (size_t)row * N + col) = make_float2(acc[mi][ni][0], acc[mi][ni][1]);
            *(float2*)(C + (size_t)(row + 8) * N + col) = make_float2(acc[mi][ni][2], acc[mi][ni][3]);
        }
    }
}

// ---------------------------------------------------------------------------
// Per-chunk local state: S_local[d][e] = sum_m phi(k[m])[d] * v[m][e]
// ---------------------------------------------------------------------------
__global__ void __launch_bounds__(256, 2) chunk_state_kernel() {
    extern __shared__ float smf[];
    float* k_s  = smf;             // 64*16
    float* v_s  = k_s + 1024;      // 64*64
    float* kf_s = v_s + 4096;      // 64*336

    int blk = blockIdx.x;
    int c = blk & (NC - 1);
    int bh = blk >> 5;
    int b = bh >> 4, h = bh & 15;
    int t = threadIdx.x;
    long tok0 = (long)b * LL + (long)c * CHUNK;

    for (int i = t; i < 64 * 16; i += 256) {
        int n = i >> 4, f = i & 15;
        k_s[i] = g_qk[(tok0 + n) * 512 + 256 + h * 16 + f];
    }
    for (int i = t; i < 64 * 64; i += 256) {
        int n = i >> 6, e = i & 63;
        v_s[i] = g_v[(tok0 + n) * 1024 + h * 64 + e];
    }
    __syncthreads();

    for (int i = t; i < 64 * 336; i += 256) {
        int n = i / 336, d = i % 336;
        float val = 0.f;
        if (d == 0) val = 1.f;
        else if (d <= 16) val = k_s[n * 16 + d - 1] * INV_RRD;
        else if (d < DF) {
            int dd = d - 17;
            val = k_s[n * 16 + (dd >> 4)] * k_s[n * 16 + (dd & 15)] * INV_Q2;
        }
        kf_s[i] = val;
    }
    __syncthreads();

    int e = t & 63, g = t >> 6;
    long outbase = (long)blk * DF * 64;
    for (int d0 = g * 16; d0 < DF; d0 += 64) {
        float acc[16];
#pragma unroll
        for (int dd = 0; dd < 16; dd++) acc[dd] = 0.f;
#pragma unroll 4
        for (int m = 0; m < 64; m++) {
            const float* kr = &kf_s[m * 336 + d0];
            float4 a0 = *(const float4*)(kr);
            float4 a1 = *(const float4*)(kr + 4);
            float4 a2 = *(const float4*)(kr + 8);
            float4 a3 = *(const float4*)(kr + 12);
            float vv = v_s[m * 64 + e];
            acc[0]  += a0.x * vv; acc[1]  += a0.y * vv; acc[2]  += a0.z * vv; acc[3]  += a0.w * vv;
            acc[4]  += a1.x * vv; acc[5]  += a1.y * vv; acc[6]  += a1.z * vv; acc[7]  += a1.w * vv;
            acc[8]  += a2.x * vv; acc[9]  += a2.y * vv; acc[10] += a2.z * vv; acc[11] += a2.w * vv;
            acc[12] += a3.x * vv; acc[13] += a3.y * vv; acc[14] += a3.z * vv; acc[15] += a3.w * vv;
        }
#pragma unroll
        for (int dd = 0; dd < 16; dd++) {
            int d = d0 + dd;
            if (d < DF) g_S[outbase + (long)d * 64 + e] = acc[dd];
        }
    }

    for (int d = t; d < DF; d += 256) {
        float s = 0.f;
        for (int m = 0; m < 64; m++) s += kf_s[m * 336 + d];
        g_ss[(long)blk * DF + d] = s;
    }
}

// ---------------------------------------------------------------------------
// In-place exclusive prefix scans over chunk index
// ---------------------------------------------------------------------------
__global__ void scan_S_kernel() {
    long idx = (long)blockIdx.x * 256 + threadIdx.x;
    if (idx >= (long)NBH * DF * 64) return;
    long bh = idx / (DF * 64);
    long de = idx % (DF * 64);
    long base = bh * NC * DF * 64 + de;
    float acc = 0.f;
#pragma unroll
    for (int c = 0; c < NC; c++) {
        long p = base + (long)c * DF * 64;
        float tmp = g_S[p];
        g_S[p] = acc;
        acc += tmp;
    }
}

__global__ void scan_ss_kernel() {
    long idx = (long)blockIdx.x * 256 + threadIdx.x;
    if (idx >= (long)NBH * DF) return;
    long bh = idx / DF;
    long d = idx % DF;
    long base = bh * NC * DF + d;
    float acc = 0.f;
#pragma unroll
    for (int c = 0; c < NC; c++) {
        long p = base + (long)c * DF;
        float tmp = g_ss[p];
        g_ss[p] = acc;
        acc += tmp;
    }
}

// ---------------------------------------------------------------------------
// Output kernel (512 threads): intra-chunk causal polynomial attention +
// phi(q) @ S_prefix, normalized; writes y as fp16 hi/lo 2-block split.
// ---------------------------------------------------------------------------
#define QFP 276     // padded feature stride (multiple of 4)
__global__ void __launch_bounds__(512, 1) output_kernel() {
    extern __shared__ float smf[];
    float* q_s  = smf;                 // 1024
    float* k_s  = q_s + 1024;          // 1024
    float* v_s  = k_s + 1024;          // 4096
    float* A_s  = v_s + 4096;          // 4096
    float* qf_s = A_s + 4096;          // 64*276 = 17664
    float* S_s  = qf_s + 64 * QFP;     // 276*64 = 17664
    float* sp_s = S_s + 64 * QFP;      // 276
    float* z_s  = sp_s + QFP;          // 64

    int blk = blockIdx.x;
    int c = blk & (NC - 1);
    int bh = blk >> 5;
    int b = bh >> 4, h = bh & 15;
    int t = threadIdx.x;
    long tok0 = (long)b * LL + (long)c * CHUNK;

    for (int i = t; i < 64 * 16; i += 512) {
        int n = i >> 4, f = i & 15;
        long off = (tok0 + n) * 512 + h * 16 + f;
        q_s[i] = g_qk[off];
        k_s[i] = g_qk[off + 256];
    }
    for (int i = t; i < 64 * 64; i += 512) {
        int n = i >> 6, e = i & 63;
        v_s[i] = g_v[(tok0 + n) * 1024 + h * 64 + e];
    }
    long Sbase = (long)blk * DF * 64;
    for (int i = t; i < DF * 64; i += 512) S_s[i] = g_S[Sbase + i];
    for (int i = DF * 64 + t; i < QFP * 64; i += 512) S_s[i] = 0.f;   // pad rows
    for (int i = t; i < QFP; i += 512) sp_s[i] = (i < DF) ? g_ss[(long)blk * DF + i] : 0.f;
    __syncthreads();

    // phi(q) into smem (padded stride QFP)
    for (int i = t; i < 64 * QFP; i += 512) {
        int n = i / QFP, d = i % QFP;
        float val = 0.f;
        if (d == 0) val = 1.f;
        else if (d <= 16) val = q_s[n * 16 + d - 1] * INV_RRD;
        else if (d < DF) {
            int dd = d - 17;
            val = q_s[n * 16 + (dd >> 4)] * q_s[n * 16 + (dd & 15)] * INV_Q2;
        }
        qf_s[i] = val;
    }

    // causal score matrix
    for (int i = t; i < 64 * 64; i += 512) {
        int n = i >> 6, m = i & 63;
        float a = 0.f;
        if (m <= n) {
            float s = 0.f;
#pragma unroll
            for (int f = 0; f < 16; f++) s += q_s[n * 16 + f] * k_s[m * 16 + f];
            a = 1.f + 0.25f * s + s * s * 0.03125f;
        }
        A_s[i] = a;
    }
    __syncthreads();

    // denominators: 8 lanes per n, shfl-reduced
    {
        int n = t >> 3, l8 = t & 7;
        float dsum = 0.f;
        for (int d = l8 * 4; d < QFP; d += 32) {
            float4 q4 = *(const float4*)&qf_s[n * QFP + d];
            float4 p4 = *(const float4*)&sp_s[d];
            dsum += q4.x * p4.x + q4.y * p4.y + q4.z * p4.z + q4.w * p4.w;
        }
        for (int m = l8 * 4; m < 64; m += 32) {
            float4 a4 = *(const float4*)&A_s[n * 64 + m];
            dsum += a4.x + a4.y + a4.z + a4.w;
        }
        dsum += __shfl_xor_sync(0xffffffffu, dsum, 4);
        dsum += __shfl_xor_sync(0xffffffffu, dsum, 2);
        dsum += __shfl_xor_sync(0xffffffffu, dsum, 1);
        if (l8 == 0) z_s[n] = 1.f / (dsum + EPS);
    }
    __syncthreads();

    // main: each thread -> one e column, 8 n rows
    int e = t & 63, g = t >> 6, nb = g * 8;
    float acc[8];
#pragma unroll
    for (int i = 0; i < 8; i++) acc[i] = 0.f;

    for (int d = 0; d < QFP; d += 4) {
        float s0 = S_s[(d + 0) * 64 + e];
        float s1 = S_s[(d + 1) * 64 + e];
        float s2 = S_s[(d + 2) * 64 + e];
        float s3 = S_s[(d + 3) * 64 + e];
#pragma unroll
        for (int nn = 0; nn < 8; nn++) {
            float4 q4 = *(const float4*)&qf_s[(nb + nn) * QFP + d];
            acc[nn] += q4.x * s0 + q4.y * s1 + q4.z * s2 + q4.w * s3;
        }
    }
    for (int m = 0; m < 64; m += 4) {
        float v0 = v_s[(m + 0) * 64 + e];
        float v1 = v_s[(m + 1) * 64 + e];
        float v2 = v_s[(m + 2) * 64 + e];
        float v3 = v_s[(m + 3) * 64 + e];
#pragma unroll
        for (int nn = 0; nn < 8; nn++) {
            float4 a4 = *(const float4*)&A_s[(nb + nn) * 64 + m];
            acc[nn] += a4.x * v0 + a4.y * v1 + a4.z * v2 + a4.w * v3;
        }
    }
#pragma unroll
    for (int nn = 0; nn < 8; nn++) {
        int n = nb + nn;
        float val = acc[nn] * z_s[n];
        __half hi = __float2half_rn(val);
        __half lo = __float2half_rn(val - __half2float(hi));
        size_t base = (size_t)(tok0 + n) * KVO + h * 64 + e;
        g_yh[base] = hi;
        g_yh[base + 1024] = lo;
    }
}

// ---------------------------------------------------------------------------
extern "C" void kernel_launch(void* const* d_in, const int* in_sizes, int n_in,
                              void* d_out, int out_size) {
    const float* x  = (const float*)d_in[0];
    const float* Wq = (const float*)d_in[1];
    const float* Wk = (const float*)d_in[2];
    const float* Wv = (const float*)d_in[3];
    const float* Wo = (const float*)d_in[4];
    float* out = (float*)d_out;

    void *px2, *pxh, *pwqk, *pwvh, *pwoh, *pqk, *pv, *pyh;
    cudaGetSymbolAddress(&px2, g_x2);
    cudaGetSymbolAddress(&pxh, g_xh);
    cudaGetSymbolAddress(&pwqk, g_wqk);
    cudaGetSymbolAddress(&pwvh, g_wvh);
    cudaGetSymbolAddress(&pwoh, g_woh);
    cudaGetSymbolAddress(&pqk, g_qk);
    cudaGetSymbolAddress(&pv, g_v);
    cudaGetSymbolAddress(&pyh, g_yh);

    const int SM2_BYTES = (1024 + 4096 + 64 * 336) * 4;
    const int SM4_BYTES = (1024 + 1024 + 4096 + 4096 + 64 * QFP + 64 * QFP + QFP + 64) * 4;
    cudaFuncSetAttribute(chunk_state_kernel, cudaFuncAttributeMaxDynamicSharedMemorySize, SM2_BYTES);
    cudaFuncSetAttribute(output_kernel, cudaFuncAttributeMaxDynamicSharedMemorySize, SM4_BYTES);
    cudaFuncSetAttribute(gemm_mma<false>, cudaFuncAttributeMaxDynamicSharedMemorySize, GEMM_SMEM);
    cudaFuncSetAttribute(gemm_mma<true>, cudaFuncAttributeMaxDynamicSharedMemorySize, GEMM_SMEM);

    // split/convert inputs
    conv_x_kernel<<<16384, 256>>>(x);
    wsplit_bf16<<<dim3(8, 32), dim3(32, 8)>>>(Wq, 256, (__nv_bfloat16*)pwqk, 0);
    wsplit_bf16<<<dim3(8, 32), dim3(32, 8)>>>(Wk, 256, (__nv_bfloat16*)pwqk, 256);
    wsplit_f16<<<dim3(32, 32), dim3(32, 8)>>>(Wv, 1024, (__half*)pwvh);
    wsplit_f16<<<dim3(32, 32), dim3(32, 8)>>>(Wo, 1024, (__half*)pwoh);

    // projections on tensor cores
    gemm_mma<false><<<dim3(4, 32), 256, GEMM_SMEM>>>((const uint16_t*)px2, (const uint16_t*)pwqk,
                                                     (float*)pqk, 512, KQK, KQK / 64);
    gemm_mma<true><<<dim3(8, 32), 256, GEMM_SMEM>>>((const uint16_t*)pxh, (const uint16_t*)pwvh,
                                                    (float*)pv, 1024, KVO, KVO / 64);

    // chunked linear attention
    chunk_state_kernel<<<NBH * NC, 256, SM2_BYTES>>>();
    scan_S_kernel<<<(NBH * DF * 64 + 255) / 256, 256>>>();
    scan_ss_kernel<<<(NBH * DF + 255) / 256, 256>>>();
    output_kernel<<<NBH * NC, 512, SM4_BYTES>>>();

    // final projection
    gemm_mma<true><<<dim3(8, 32), 256, GEMM_SMEM>>>((const uint16_t*)pyh, (const uint16_t*)pwoh,
                                                    out, 1024, KVO, KVO / 64);
}

// round 5
// speedup vs baseline: 2.6315x; 1.0874x over previous
#include <cuda_runtime.h>
#include <cuda_bf16.h>
#include <cuda_fp16.h>
#include <cstdint>

// Problem constants
#define BB 2
#define LL 2048
#define DM 1024
#define NH 16
#define FD 16
#define HD 64
#define DF 273          // 1 + 16 + 256
#define CHUNK 64
#define NC 32           // LL / CHUNK
#define NBH 32          // BB * NH
#define INV_RRD 0.5f
#define INV_Q2 0.17677669529663687f   // 1/(4*sqrt(2))
#define EPS 1e-12f

#define KQK 3072        // bf16 3-term split for q/k projection
#define KVO 2048        // fp16 2-term split for v/o projections
#define QFP 276         // padded feature stride (mult of 4; /4 odd -> conflict-free)
#define VTP 68          // v transposed stride

// ---------------------------------------------------------------------------
// Scratch (device globals; no allocation)
// ---------------------------------------------------------------------------
__device__ __nv_bfloat16 g_x2[4096 * KQK];      // x: [hi | lo | hi] bf16
__device__ __half        g_xh[4096 * KVO];      // x: [hi | lo] fp16
__device__ __nv_bfloat16 g_wqk[512 * KQK];      // [Wq|Wk]^T: [hi | hi | lo] bf16
__device__ __half        g_wvh[1024 * KVO];     // Wv^T: [hi | hi] fp16
__device__ __half        g_woh[1024 * KVO];     // Wo^T: [hi | hi] fp16
__device__ float g_qk[4096 * 512];              // q (cols 0..255) | k (256..511)
__device__ float g_v[4096 * 1024];
__device__ __half g_yh[4096 * KVO];             // y: [hi | lo] fp16
__device__ __half g_Sh[(size_t)NBH * NC * DF * 64];   // chunk states (fp16)
__device__ float g_ss[NBH * NC * DF];

// ---------------------------------------------------------------------------
// PTX helpers (baseline sm_80-compatible: ldmatrix, mma.sync, cp.async)
// ---------------------------------------------------------------------------
__device__ __forceinline__ uint32_t smem_u32(const void* p) {
    uint32_t a;
    asm("{ .reg .u64 t; cvta.to.shared.u64 t, %1; cvt.u32.u64 %0, t; }" : "=r"(a) : "l"(p));
    return a;
}
__device__ __forceinline__ void ldsm_x4(uint32_t* r, uint32_t addr) {
    asm volatile("ldmatrix.sync.aligned.m8n8.x4.shared.b16 {%0,%1,%2,%3}, [%4];"
        : "=r"(r[0]), "=r"(r[1]), "=r"(r[2]), "=r"(r[3]) : "r"(addr));
}
template<bool F16>
__device__ __forceinline__ void mma_any(float* d, const uint32_t* a, const uint32_t* b) {
    if constexpr (F16) {
        asm volatile("mma.sync.aligned.m16n8k16.row.col.f32.f16.f16.f32 "
            "{%0,%1,%2,%3}, {%4,%5,%6,%7}, {%8,%9}, {%0,%1,%2,%3};"
            : "+f"(d[0]), "+f"(d[1]), "+f"(d[2]), "+f"(d[3])
            : "r"(a[0]), "r"(a[1]), "r"(a[2]), "r"(a[3]), "r"(b[0]), "r"(b[1]));
    } else {
        asm volatile("mma.sync.aligned.m16n8k16.row.col.f32.bf16.bf16.f32 "
            "{%0,%1,%2,%3}, {%4,%5,%6,%7}, {%8,%9}, {%0,%1,%2,%3};"
            : "+f"(d[0]), "+f"(d[1]), "+f"(d[2]), "+f"(d[3])
            : "r"(a[0]), "r"(a[1]), "r"(a[2]), "r"(a[3]), "r"(b[0]), "r"(b[1]));
    }
}
#define CP_ASYNC16(dst, src) \
    asm volatile("cp.async.cg.shared.global [%0], [%1], 16;" :: "r"(dst), "l"(src))
#define CP_COMMIT() asm volatile("cp.async.commit_group;" ::: "memory")
#define CP_WAIT(n)  asm volatile("cp.async.wait_group %0;" :: "n"(n) : "memory")

// ---------------------------------------------------------------------------
// Converters
// ---------------------------------------------------------------------------
__global__ void conv_x_kernel(const float* __restrict__ x) {
    int idx = blockIdx.x * 256 + threadIdx.x;          // 4096*1024 elements
    int m = idx >> 10, k = idx & 1023;
    float v = x[idx];
    __nv_bfloat16 bh = __float2bfloat16(v);
    __nv_bfloat16 bl = __float2bfloat16(v - __bfloat162float(bh));
    size_t b2 = (size_t)m * KQK + k;
    g_x2[b2] = bh;
    g_x2[b2 + 1024] = bl;
    g_x2[b2 + 2048] = bh;
    __half fh = __float2half_rn(v);
    __half fl = __float2half_rn(v - __half2float(fh));
    size_t bh2 = (size_t)m * KVO + k;
    g_xh[bh2] = fh;
    g_xh[bh2 + 1024] = fl;
}

// Transposed bf16 3-term split: W (1024 x Ncols) -> rows [W_hi | W_hi | W_lo]
__global__ void wsplit_bf16(const float* __restrict__ W, int Ncols,
                            __nv_bfloat16* __restrict__ Bt, int rowoff) {
    __shared__ float tile[32][33];
    int n0 = blockIdx.x * 32, k0 = blockIdx.y * 32;
    int tx = threadIdx.x, ty = threadIdx.y;            // 32 x 8
    for (int i = ty; i < 32; i += 8)
        tile[i][tx] = W[(size_t)(k0 + i) * Ncols + n0 + tx];
    __syncthreads();
    for (int i = ty; i < 32; i += 8) {
        int n = n0 + i, k = k0 + tx;
        float v = tile[tx][i];
        __nv_bfloat16 hi = __float2bfloat16(v);
        __nv_bfloat16 lo = __float2bfloat16(v - __bfloat162float(hi));
        size_t base = (size_t)(rowoff + n) * KQK + k;
        Bt[base] = hi;
        Bt[base + 1024] = hi;
        Bt[base + 2048] = lo;
    }
}

// Transposed fp16 2-term: W (1024 x Ncols) -> rows [W_hi | W_hi]
__global__ void wsplit_f16(const float* __restrict__ W, int Ncols,
                           __half* __restrict__ Bt) {
    __shared__ float tile[32][33];
    int n0 = blockIdx.x * 32, k0 = blockIdx.y * 32;
    int tx = threadIdx.x, ty = threadIdx.y;
    for (int i = ty; i < 32; i += 8)
        tile[i][tx] = W[(size_t)(k0 + i) * Ncols + n0 + tx];
    __syncthreads();
    for (int i = ty; i < 32; i += 8) {
        int n = n0 + i, k = k0 + tx;
        __half hi = __float2half_rn(tile[tx][i]);
        size_t base = (size_t)n * KVO + k;
        Bt[base] = hi;
        Bt[base + 1024] = hi;
    }
}

// ---------------------------------------------------------------------------
// mma.sync GEMM: C (4096 x N, fp32) = A (4096 x K) @ Bt (N x K)^T
// 128x128 CTA tile, 8 warps (64x32 each), K-tile 64, 3-stage cp.async
// pipeline, paired-B ldmatrix, 2 CTAs/SM.
// ---------------------------------------------------------------------------
#define SMA(b) ((b) * 32768)
#define SMB(b) ((b) * 32768 + 16384)
#define GEMM_SMEM 98304

__device__ __forceinline__ void gemm_load_tile(const uint16_t* A, const uint16_t* B,
                                               char* sm, int m0, int n0, int kb, int buf,
                                               int t, int K) {
#pragma unroll
    for (int i = 0; i < 8; i++) {
        int idx = t + i * 256;            // 0..2047
        int row = (idx & 1023) >> 3, c = idx & 7;
        uint32_t dst;
        const uint16_t* src;
        if (idx < 1024) {
            src = A + (size_t)(m0 + row) * K + kb * 64 + c * 8;
            dst = smem_u32(sm + SMA(buf) + row * 128 + ((c ^ (row & 7)) << 4));
        } else {
            src = B + (size_t)(n0 + row) * K + kb * 64 + c * 8;
            dst = smem_u32(sm + SMB(buf) + row * 128 + ((c ^ (row & 7)) << 4));
        }
        CP_ASYNC16(dst, src);
    }
}

template<bool F16>
__global__ void __launch_bounds__(256, 2)
gemm_mma(const uint16_t* __restrict__ A, const uint16_t* __restrict__ B,
         float* __restrict__ C, int N, int K, int nkt) {
    extern __shared__ char sm[];
    int t = threadIdx.x;
    int m0 = blockIdx.y * 128, n0 = blockIdx.x * 128;
    int w = t >> 5, l = t & 31;
    int wm = (w >> 2) * 64, wn = (w & 3) * 32;

    float acc[4][4][4];
#pragma unroll
    for (int i = 0; i < 4; i++)
#pragma unroll
        for (int j = 0; j < 4; j++)
#pragma unroll
            for (int r = 0; r < 4; r++) acc[i][j][r] = 0.f;

    int ar = wm + (l & 15);
    int ac = (l >> 4);
    int brow = wn + (l & 7) + ((l >> 4) << 3);   // base row for paired-B ldsm
    int bkh = (l >> 3) & 1;

    gemm_load_tile(A, B, sm, m0, n0, 0, 0, t, K);
    CP_COMMIT();
    gemm_load_tile(A, B, sm, m0, n0, 1, 1, t, K);
    CP_COMMIT();

    int buf = 0;
    for (int kt = 0; kt < nkt; kt++) {
        if (kt + 2 < nkt) {
            int lb = buf + 2; if (lb >= 3) lb -= 3;
            gemm_load_tile(A, B, sm, m0, n0, kt + 2, lb, t, K);
        }
        CP_COMMIT();
        CP_WAIT(2);
        __syncthreads();

        uint32_t Ab = smem_u32(sm + SMA(buf));
        uint32_t Bb = smem_u32(sm + SMB(buf));
#pragma unroll
        for (int ks = 0; ks < 4; ks++) {
            uint32_t afr[4][4], bfr[4][2];
#pragma unroll
            for (int mi = 0; mi < 4; mi++) {
                int row = ar + mi * 16;
                int ch = ks * 2 + ac;
                ldsm_x4(afr[mi], Ab + row * 128 + ((ch ^ (row & 7)) << 4));
            }
#pragma unroll
            for (int p = 0; p < 2; p++) {
                uint32_t bp[4];
                int row = brow + p * 16;
                int ch = ks * 2 + bkh;
                ldsm_x4(bp, Bb + row * 128 + ((ch ^ (row & 7)) << 4));
                bfr[2 * p][0] = bp[0]; bfr[2 * p][1] = bp[1];
                bfr[2 * p + 1][0] = bp[2]; bfr[2 * p + 1][1] = bp[3];
            }
#pragma unroll
            for (int mi = 0; mi < 4; mi++)
#pragma unroll
                for (int ni = 0; ni < 4; ni++)
                    mma_any<F16>(acc[mi][ni], afr[mi], bfr[ni]);
        }
        __syncthreads();
        if (++buf == 3) buf = 0;
    }

    int r0 = l >> 2, c0 = (l & 3) * 2;
#pragma unroll
    for (int mi = 0; mi < 4; mi++) {
#pragma unroll
        for (int ni = 0; ni < 4; ni++) {
            int row = m0 + wm + mi * 16 + r0;
            int col = n0 + wn + ni * 8 + c0;
            *(float2*)(C + (size_t)row * N + col) = make_float2(acc[mi][ni][0], acc[mi][ni][1]);
            *(float2*)(C + (size_t)(row + 8) * N + col) = make_float2(acc[mi][ni][2], acc[mi][ni][3]);
        }
    }
}

// ---------------------------------------------------------------------------
// Per-chunk local state: S_local[d][e] = sum_m phi(k[m])[d] * v[m][e]  (fp16 out)
// ---------------------------------------------------------------------------
__global__ void __launch_bounds__(256, 2) chunk_state_kernel() {
    extern __shared__ float smf[];
    float* k_s  = smf;             // 64*16
    float* v_s  = k_s + 1024;      // 64*64
    float* kf_s = v_s + 4096;      // 64*336

    int blk = blockIdx.x;
    int c = blk & (NC - 1);
    int bh = blk >> 5;
    int b = bh >> 4, h = bh & 15;
    int t = threadIdx.x;
    long tok0 = (long)b * LL + (long)c * CHUNK;

    for (int i = t; i < 64 * 16; i += 256) {
        int n = i >> 4, f = i & 15;
        k_s[i] = g_qk[(tok0 + n) * 512 + 256 + h * 16 + f];
    }
    for (int i = t; i < 64 * 64; i += 256) {
        int n = i >> 6, e = i & 63;
        v_s[i] = g_v[(tok0 + n) * 1024 + h * 64 + e];
    }
    __syncthreads();

    for (int i = t; i < 64 * 336; i += 256) {
        int n = i / 336, d = i % 336;
        float val = 0.f;
        if (d == 0) val = 1.f;
        else if (d <= 16) val = k_s[n * 16 + d - 1] * INV_RRD;
        else if (d < DF) {
            int dd = d - 17;
            val = k_s[n * 16 + (dd >> 4)] * k_s[n * 16 + (dd & 15)] * INV_Q2;
        }
        kf_s[i] = val;
    }
    __syncthreads();

    int e = t & 63, g = t >> 6;
    size_t outbase = (size_t)blk * DF * 64;
    for (int d0 = g * 16; d0 < DF; d0 += 64) {
        float acc[16];
#pragma unroll
        for (int dd = 0; dd < 16; dd++) acc[dd] = 0.f;
#pragma unroll 4
        for (int m = 0; m < 64; m++) {
            const float* kr = &kf_s[m * 336 + d0];
            float4 a0 = *(const float4*)(kr);
            float4 a1 = *(const float4*)(kr + 4);
            float4 a2 = *(const float4*)(kr + 8);
            float4 a3 = *(const float4*)(kr + 12);
            float vv = v_s[m * 64 + e];
            acc[0]  += a0.x * vv; acc[1]  += a0.y * vv; acc[2]  += a0.z * vv; acc[3]  += a0.w * vv;
            acc[4]  += a1.x * vv; acc[5]  += a1.y * vv; acc[6]  += a1.z * vv; acc[7]  += a1.w * vv;
            acc[8]  += a2.x * vv; acc[9]  += a2.y * vv; acc[10] += a2.z * vv; acc[11] += a2.w * vv;
            acc[12] += a3.x * vv; acc[13] += a3.y * vv; acc[14] += a3.z * vv; acc[15] += a3.w * vv;
        }
#pragma unroll
        for (int dd = 0; dd < 16; dd++) {
            int d = d0 + dd;
            if (d < DF) g_Sh[outbase + (size_t)d * 64 + e] = __float2half(acc[dd]);
        }
    }

    for (int d = t; d < DF; d += 256) {
        float s = 0.f;
        for (int m = 0; m < 64; m++) s += kf_s[m * 336 + d];
        g_ss[(long)blk * DF + d] = s;
    }
}

// ---------------------------------------------------------------------------
// In-place exclusive prefix scans over chunk index
// ---------------------------------------------------------------------------
__global__ void scan_S_kernel() {      // over half2 pairs
    long idx = (long)blockIdx.x * 256 + threadIdx.x;
    if (idx >= (long)NBH * DF * 32) return;
    long bh = idx / (DF * 32);
    long de = idx % (DF * 32);
    __half2* Sp = (__half2*)g_Sh;
    size_t base = (size_t)bh * NC * DF * 32 + de;
    float2 acc = make_float2(0.f, 0.f);
#pragma unroll
    for (int c = 0; c < NC; c++) {
        size_t p = base + (size_t)c * DF * 32;
        float2 tmp = __half22float2(Sp[p]);
        Sp[p] = __floats2half2_rn(acc.x, acc.y);
        acc.x += tmp.x; acc.y += tmp.y;
    }
}

__global__ void scan_ss_kernel() {
    long idx = (long)blockIdx.x * 256 + threadIdx.x;
    if (idx >= (long)NBH * DF) return;
    long bh = idx / DF;
    long d = idx % DF;
    long base = bh * NC * DF + d;
    float acc = 0.f;
#pragma unroll
    for (int c = 0; c < NC; c++) {
        long p = base + (long)c * DF;
        float tmp = g_ss[p];
        g_ss[p] = acc;
        acc += tmp;
    }
}

// ---------------------------------------------------------------------------
// Output kernel (512 threads): intra-chunk causal polynomial attention +
// phi(q) @ S_prefix, normalized; e-major transposed S/v in smem for
// conflict-free float4 + warp-broadcast qf/A reads.
// ---------------------------------------------------------------------------
__global__ void __launch_bounds__(512, 1) output_kernel() {
    extern __shared__ float smf[];
    float* q_s  = smf;                 // 1024
    float* k_s  = q_s + 1024;          // 1024
    float* A_s  = k_s + 1024;          // 4096
    float* qf_s = A_s + 4096;          // 64*276
    float* S_T  = qf_s + 64 * QFP;     // 64*276 (e-major: [e][d])
    float* v_T  = S_T + 64 * QFP;      // 64*68  (e-major: [e][m])
    float* sp_s = v_T + 64 * VTP;      // 276
    float* z_s  = sp_s + QFP;          // 64

    int blk = blockIdx.x;
    int c = blk & (NC - 1);
    int bh = blk >> 5;
    int b = bh >> 4, h = bh & 15;
    int t = threadIdx.x;
    long tok0 = (long)b * LL + (long)c * CHUNK;

    for (int i = t; i < 64 * 16; i += 512) {
        int n = i >> 4, f = i & 15;
        long off = (tok0 + n) * 512 + h * 16 + f;
        q_s[i] = g_qk[off];
        k_s[i] = g_qk[off + 256];
    }
    for (int i = t; i < 64 * 64; i += 512) {
        int n = i >> 6, e = i & 63;
        v_T[e * VTP + n] = g_v[(tok0 + n) * 1024 + h * 64 + e];
    }
    size_t Sbase = (size_t)blk * DF * 64;
    for (int i = t; i < DF * 64; i += 512) {
        int d = i >> 6, e = i & 63;
        S_T[e * QFP + d] = __half2float(g_Sh[Sbase + i]);
    }
    if (t < 192) {                      // pad d = 273..275
        int e = t / 3, d = DF + t % 3;
        S_T[e * QFP + d] = 0.f;
    }
    for (int i = t; i < QFP; i += 512) sp_s[i] = (i < DF) ? g_ss[(long)blk * DF + i] : 0.f;
    __syncthreads();

    // phi(q) into smem (padded stride QFP)
    for (int i = t; i < 64 * QFP; i += 512) {
        int n = i / QFP, d = i % QFP;
        float val = 0.f;
        if (d == 0) val = 1.f;
        else if (d <= 16) val = q_s[n * 16 + d - 1] * INV_RRD;
        else if (d < DF) {
            int dd = d - 17;
            val = q_s[n * 16 + (dd >> 4)] * q_s[n * 16 + (dd & 15)] * INV_Q2;
        }
        qf_s[i] = val;
    }

    // causal score matrix
    for (int i = t; i < 64 * 64; i += 512) {
        int n = i >> 6, m = i & 63;
        float a = 0.f;
        if (m <= n) {
            float s = 0.f;
#pragma unroll
            for (int f = 0; f < 16; f++) s += q_s[n * 16 + f] * k_s[m * 16 + f];
            a = 1.f + 0.25f * s + s * s * 0.03125f;
        }
        A_s[i] = a;
    }
    __syncthreads();

    // denominators: 8 lanes per n, shfl-reduced
    {
        int n = t >> 3, l8 = t & 7;
        float dsum = 0.f;
        for (int d = l8 * 4; d < QFP; d += 32) {
            float4 q4 = *(const float4*)&qf_s[n * QFP + d];
            float4 p4 = *(const float4*)&sp_s[d];
            dsum += q4.x * p4.x + q4.y * p4.y + q4.z * p4.z + q4.w * p4.w;
        }
        for (int m = l8 * 4; m < 64; m += 32) {
            float4 a4 = *(const float4*)&A_s[n * 64 + m];
            dsum += a4.x + a4.y + a4.z + a4.w;
        }
        dsum += __shfl_xor_sync(0xffffffffu, dsum, 4);
        dsum += __shfl_xor_sync(0xffffffffu, dsum, 2);
        dsum += __shfl_xor_sync(0xffffffffu, dsum, 1);
        if (l8 == 0) z_s[n] = 1.f / (dsum + EPS);
    }
    __syncthreads();

    // main: thread = (warp -> 4 n rows, lane -> e and e+32)
    int lane = t & 31, wid = t >> 5;
    int n0 = wid * 4;
    int e0 = lane, e1 = lane + 32;
    float acc[4][2];
#pragma unroll
    for (int i = 0; i < 4; i++) { acc[i][0] = 0.f; acc[i][1] = 0.f; }

    const float* S0 = &S_T[e0 * QFP];
    const float* S1 = &S_T[e1 * QFP];
    for (int d = 0; d < QFP; d += 4) {
        float4 s0 = *(const float4*)(S0 + d);
        float4 s1 = *(const float4*)(S1 + d);
#pragma unroll
        for (int nn = 0; nn < 4; nn++) {
            float4 q4 = *(const float4*)&qf_s[(n0 + nn) * QFP + d];   // broadcast
            acc[nn][0] += q4.x * s0.x + q4.y * s0.y + q4.z * s0.z + q4.w * s0.w;
            acc[nn][1] += q4.x * s1.x + q4.y * s1.y + q4.z * s1.z + q4.w * s1.w;
        }
    }
    const float* V0 = &v_T[e0 * VTP];
    const float* V1 = &v_T[e1 * VTP];
    for (int m = 0; m < 64; m += 4) {
        float4 v0 = *(const float4*)(V0 + m);
        float4 v1 = *(const float4*)(V1 + m);
#pragma unroll
        for (int nn = 0; nn < 4; nn++) {
            float4 a4 = *(const float4*)&A_s[(n0 + nn) * 64 + m];     // broadcast
            acc[nn][0] += a4.x * v0.x + a4.y * v0.y + a4.z * v0.z + a4.w * v0.w;
            acc[nn][1] += a4.x * v1.x + a4.y * v1.y + a4.z * v1.z + a4.w * v1.w;
        }
    }
#pragma unroll
    for (int nn = 0; nn < 4; nn++) {
        int n = n0 + nn;
        float z = z_s[n];
        size_t base = (size_t)(tok0 + n) * KVO + h * 64;
#pragma unroll
        for (int ee = 0; ee < 2; ee++) {
            int e = ee ? e1 : e0;
            float val = acc[nn][ee] * z;
            __half hi = __float2half_rn(val);
            __half lo = __float2half_rn(val - __half2float(hi));
            g_yh[base + e] = hi;
            g_yh[base + e + 1024] = lo;
        }
    }
}

// ---------------------------------------------------------------------------
extern "C" void kernel_launch(void* const* d_in, const int* in_sizes, int n_in,
                              void* d_out, int out_size) {
    const float* x  = (const float*)d_in[0];
    const float* Wq = (const float*)d_in[1];
    const float* Wk = (const float*)d_in[2];
    const float* Wv = (const float*)d_in[3];
    const float* Wo = (const float*)d_in[4];
    float* out = (float*)d_out;

    void *px2, *pxh, *pwqk, *pwvh, *pwoh, *pqk, *pv, *pyh;
    cudaGetSymbolAddress(&px2, g_x2);
    cudaGetSymbolAddress(&pxh, g_xh);
    cudaGetSymbolAddress(&pwqk, g_wqk);
    cudaGetSymbolAddress(&pwvh, g_wvh);
    cudaGetSymbolAddress(&pwoh, g_woh);
    cudaGetSymbolAddress(&pqk, g_qk);
    cudaGetSymbolAddress(&pv, g_v);
    cudaGetSymbolAddress(&pyh, g_yh);

    const int SM2_BYTES = (1024 + 4096 + 64 * 336) * 4;
    const int SM4_BYTES = (1024 + 1024 + 4096 + 64 * QFP + 64 * QFP + 64 * VTP + QFP + 64) * 4;
    cudaFuncSetAttribute(chunk_state_kernel, cudaFuncAttributeMaxDynamicSharedMemorySize, SM2_BYTES);
    cudaFuncSetAttribute(output_kernel, cudaFuncAttributeMaxDynamicSharedMemorySize, SM4_BYTES);
    cudaFuncSetAttribute(gemm_mma<false>, cudaFuncAttributeMaxDynamicSharedMemorySize, GEMM_SMEM);
    cudaFuncSetAttribute(gemm_mma<true>, cudaFuncAttributeMaxDynamicSharedMemorySize, GEMM_SMEM);

    // split/convert inputs
    conv_x_kernel<<<16384, 256>>>(x);
    wsplit_bf16<<<dim3(8, 32), dim3(32, 8)>>>(Wq, 256, (__nv_bfloat16*)pwqk, 0);
    wsplit_bf16<<<dim3(8, 32), dim3(32, 8)>>>(Wk, 256, (__nv_bfloat16*)pwqk, 256);
    wsplit_f16<<<dim3(32, 32), dim3(32, 8)>>>(Wv, 1024, (__half*)pwvh);
    wsplit_f16<<<dim3(32, 32), dim3(32, 8)>>>(Wo, 1024, (__half*)pwoh);

    // projections on tensor cores
    gemm_mma<false><<<dim3(4, 32), 256, GEMM_SMEM>>>((const uint16_t*)px2, (const uint16_t*)pwqk,
                                                     (float*)pqk, 512, KQK, KQK / 64);
    gemm_mma<true><<<dim3(8, 32), 256, GEMM_SMEM>>>((const uint16_t*)pxh, (const uint16_t*)pwvh,
                                                    (float*)pv, 1024, KVO, KVO / 64);

    // chunked linear attention
    chunk_state_kernel<<<NBH * NC, 256, SM2_BYTES>>>();
    scan_S_kernel<<<(NBH * DF * 32 + 255) / 256, 256>>>();
    scan_ss_kernel<<<(NBH * DF + 255) / 256, 256>>>();
    output_kernel<<<NBH * NC, 512, SM4_BYTES>>>();

    // final projection
    gemm_mma<true><<<dim3(8, 32), 256, GEMM_SMEM>>>((const uint16_t*)pyh, (const uint16_t*)pwoh,
                                                    out, 1024, KVO, KVO / 64);
}

// round 6
// speedup vs baseline: 2.7573x; 1.0478x over previous
#include <cuda_runtime.h>
#include <cuda_bf16.h>
#include <cuda_fp16.h>
#include <cstdint>

// Problem constants
#define BB 2
#define LL 2048
#define DM 1024
#define NH 16
#define FD 16
#define HD 64
#define DF 273          // 1 + 16 + 256
#define DFP 288         // DF padded to 18 n8-tiles for mma
#define CHUNK 64
#define NC 32           // LL / CHUNK
#define NBH 32          // BB * NH
#define INV_RRD 0.5f
#define INV_Q2 0.17677669529663687f   // 1/(4*sqrt(2))
#define EPS 1e-12f

#define KQK 3072        // bf16 3-term split for q/k projection
#define KVO 2048        // fp16 2-term split for v/o projections
#define QFP 276         // padded feature stride in output kernel
#define VTP 68          // v transposed stride

// ---------------------------------------------------------------------------
// Scratch (device globals; no allocation)
// ---------------------------------------------------------------------------
__device__ __nv_bfloat16 g_x2[4096 * KQK];      // x: [hi | lo | hi] bf16
__device__ __half        g_xh[4096 * KVO];      // x: [hi | lo] fp16
__device__ __nv_bfloat16 g_wqk[512 * KQK];      // [Wq|Wk]^T: [hi | hi | lo] bf16
__device__ __half        g_wvh[1024 * KVO];     // Wv^T: [hi | hi] fp16
__device__ __half        g_woh[1024 * KVO];     // Wo^T: [hi | hi] fp16
__device__ float g_qk[4096 * 512];              // q (cols 0..255) | k (256..511)
__device__ float g_v[4096 * 1024];
__device__ __half g_yh[4096 * KVO];             // y: [hi | lo] fp16
__device__ __half g_Sh[(size_t)NBH * NC * 64 * DFP];  // chunk states, e-major S^T (fp16)
__device__ float g_ss[NBH * NC * DF];

// ---------------------------------------------------------------------------
// PTX helpers (baseline sm_80-compatible: ldmatrix, mma.sync, cp.async)
// ---------------------------------------------------------------------------
__device__ __forceinline__ uint32_t smem_u32(const void* p) {
    uint32_t a;
    asm("{ .reg .u64 t; cvta.to.shared.u64 t, %1; cvt.u32.u64 %0, t; }" : "=r"(a) : "l"(p));
    return a;
}
__device__ __forceinline__ void ldsm_x4(uint32_t* r, uint32_t addr) {
    asm volatile("ldmatrix.sync.aligned.m8n8.x4.shared.b16 {%0,%1,%2,%3}, [%4];"
        : "=r"(r[0]), "=r"(r[1]), "=r"(r[2]), "=r"(r[3]) : "r"(addr));
}
template<bool F16>
__device__ __forceinline__ void mma_any(float* d, const uint32_t* a, const uint32_t* b) {
    if constexpr (F16) {
        asm volatile("mma.sync.aligned.m16n8k16.row.col.f32.f16.f16.f32 "
            "{%0,%1,%2,%3}, {%4,%5,%6,%7}, {%8,%9}, {%0,%1,%2,%3};"
            : "+f"(d[0]), "+f"(d[1]), "+f"(d[2]), "+f"(d[3])
            : "r"(a[0]), "r"(a[1]), "r"(a[2]), "r"(a[3]), "r"(b[0]), "r"(b[1]));
    } else {
        asm volatile("mma.sync.aligned.m16n8k16.row.col.f32.bf16.bf16.f32 "
            "{%0,%1,%2,%3}, {%4,%5,%6,%7}, {%8,%9}, {%0,%1,%2,%3};"
            : "+f"(d[0]), "+f"(d[1]), "+f"(d[2]), "+f"(d[3])
            : "r"(a[0]), "r"(a[1]), "r"(a[2]), "r"(a[3]), "r"(b[0]), "r"(b[1]));
    }
}
#define CP_ASYNC16(dst, src) \
    asm volatile("cp.async.cg.shared.global [%0], [%1], 16;" :: "r"(dst), "l"(src))
#define CP_COMMIT() asm volatile("cp.async.commit_group;" ::: "memory")
#define CP_WAIT(n)  asm volatile("cp.async.wait_group %0;" :: "n"(n) : "memory")

// ---------------------------------------------------------------------------
// Converters
// ---------------------------------------------------------------------------
__global__ void conv_x_kernel(const float* __restrict__ x) {
    int idx = blockIdx.x * 256 + threadIdx.x;          // 4096*1024 elements
    int m = idx >> 10, k = idx & 1023;
    float v = x[idx];
    __nv_bfloat16 bh = __float2bfloat16(v);
    __nv_bfloat16 bl = __float2bfloat16(v - __bfloat162float(bh));
    size_t b2 = (size_t)m * KQK + k;
    g_x2[b2] = bh;
    g_x2[b2 + 1024] = bl;
    g_x2[b2 + 2048] = bh;
    __half fh = __float2half_rn(v);
    __half fl = __float2half_rn(v - __half2float(fh));
    size_t bh2 = (size_t)m * KVO + k;
    g_xh[bh2] = fh;
    g_xh[bh2 + 1024] = fl;
}

// All weight splits fused: blocks 0..7 Wq, 8..15 Wk (bf16 3-term),
// 16..47 Wv, 48..79 Wo (fp16 2-term).
__global__ void wsplit_all(const float* __restrict__ Wq, const float* __restrict__ Wk,
                           const float* __restrict__ Wv, const float* __restrict__ Wo) {
    __shared__ float tile[32][33];
    int bx = blockIdx.x, k0 = blockIdx.y * 32;
    const float* W;
    int Ncols, n0, mode, rowoff = 0;
    if (bx < 8)       { W = Wq; Ncols = 256;  n0 = bx * 32;        mode = 0; rowoff = 0;   }
    else if (bx < 16) { W = Wk; Ncols = 256;  n0 = (bx - 8) * 32;  mode = 0; rowoff = 256; }
    else if (bx < 48) { W = Wv; Ncols = 1024; n0 = (bx - 16) * 32; mode = 1; }
    else              { W = Wo; Ncols = 1024; n0 = (bx - 48) * 32; mode = 2; }
    int tx = threadIdx.x, ty = threadIdx.y;            // 32 x 8
    for (int i = ty; i < 32; i += 8)
        tile[i][tx] = W[(size_t)(k0 + i) * Ncols + n0 + tx];
    __syncthreads();
    for (int i = ty; i < 32; i += 8) {
        int n = n0 + i, k = k0 + tx;
        float v = tile[tx][i];
        if (mode == 0) {
            __nv_bfloat16 hi = __float2bfloat16(v);
            __nv_bfloat16 lo = __float2bfloat16(v - __bfloat162float(hi));
            size_t base = (size_t)(rowoff + n) * KQK + k;
            g_wqk[base] = hi;
            g_wqk[base + 1024] = hi;
            g_wqk[base + 2048] = lo;
        } else {
            __half hi = __float2half_rn(v);
            __half* dst = (mode == 1) ? g_wvh : g_woh;
            size_t base = (size_t)n * KVO + k;
            dst[base] = hi;
            dst[base + 1024] = hi;
        }
    }
}

// ---------------------------------------------------------------------------
// mma.sync GEMM: C (4096 x N, fp32) = A (4096 x K) @ Bt (N x K)^T
// 128x128 CTA tile, 8 warps (64x32 each), K-tile 64, 3-stage cp.async
// pipeline, paired-B ldmatrix, 2 CTAs/SM.
// ---------------------------------------------------------------------------
#define SMA(b) ((b) * 32768)
#define SMB(b) ((b) * 32768 + 16384)
#define GEMM_SMEM 98304

__device__ __forceinline__ void gemm_load_tile(const uint16_t* A, const uint16_t* B,
                                               char* sm, int m0, int n0, int kb, int buf,
                                               int t, int K) {
#pragma unroll
    for (int i = 0; i < 8; i++) {
        int idx = t + i * 256;            // 0..2047
        int row = (idx & 1023) >> 3, c = idx & 7;
        uint32_t dst;
        const uint16_t* src;
        if (idx < 1024) {
            src = A + (size_t)(m0 + row) * K + kb * 64 + c * 8;
            dst = smem_u32(sm + SMA(buf) + row * 128 + ((c ^ (row & 7)) << 4));
        } else {
            src = B + (size_t)(n0 + row) * K + kb * 64 + c * 8;
            dst = smem_u32(sm + SMB(buf) + row * 128 + ((c ^ (row & 7)) << 4));
        }
        CP_ASYNC16(dst, src);
    }
}

template<bool F16>
__global__ void __launch_bounds__(256, 2)
gemm_mma(const uint16_t* __restrict__ A, const uint16_t* __restrict__ B,
         float* __restrict__ C, int N, int K, int nkt) {
    extern __shared__ char sm[];
    int t = threadIdx.x;
    int m0 = blockIdx.y * 128, n0 = blockIdx.x * 128;
    int w = t >> 5, l = t & 31;
    int wm = (w >> 2) * 64, wn = (w & 3) * 32;

    float acc[4][4][4];
#pragma unroll
    for (int i = 0; i < 4; i++)
#pragma unroll
        for (int j = 0; j < 4; j++)
#pragma unroll
            for (int r = 0; r < 4; r++) acc[i][j][r] = 0.f;

    int ar = wm + (l & 15);
    int ac = (l >> 4);
    int brow = wn + (l & 7) + ((l >> 4) << 3);   // base row for paired-B ldsm
    int bkh = (l >> 3) & 1;

    gemm_load_tile(A, B, sm, m0, n0, 0, 0, t, K);
    CP_COMMIT();
    gemm_load_tile(A, B, sm, m0, n0, 1, 1, t, K);
    CP_COMMIT();

    int buf = 0;
    for (int kt = 0; kt < nkt; kt++) {
        if (kt + 2 < nkt) {
            int lb = buf + 2; if (lb >= 3) lb -= 3;
            gemm_load_tile(A, B, sm, m0, n0, kt + 2, lb, t, K);
        }
        CP_COMMIT();
        CP_WAIT(2);
        __syncthreads();

        uint32_t Ab = smem_u32(sm + SMA(buf));
        uint32_t Bb = smem_u32(sm + SMB(buf));
#pragma unroll
        for (int ks = 0; ks < 4; ks++) {
            uint32_t afr[4][4], bfr[4][2];
#pragma unroll
            for (int mi = 0; mi < 4; mi++) {
                int row = ar + mi * 16;
                int ch = ks * 2 + ac;
                ldsm_x4(afr[mi], Ab + row * 128 + ((ch ^ (row & 7)) << 4));
            }
#pragma unroll
            for (int p = 0; p < 2; p++) {
                uint32_t bp[4];
                int row = brow + p * 16;
                int ch = ks * 2 + bkh;
                ldsm_x4(bp, Bb + row * 128 + ((ch ^ (row & 7)) << 4));
                bfr[2 * p][0] = bp[0]; bfr[2 * p][1] = bp[1];
                bfr[2 * p + 1][0] = bp[2]; bfr[2 * p + 1][1] = bp[3];
            }
#pragma unroll
            for (int mi = 0; mi < 4; mi++)
#pragma unroll
                for (int ni = 0; ni < 4; ni++)
                    mma_any<F16>(acc[mi][ni], afr[mi], bfr[ni]);
        }
        __syncthreads();
        if (++buf == 3) buf = 0;
    }

    int r0 = l >> 2, c0 = (l & 3) * 2;
#pragma unroll
    for (int mi = 0; mi < 4; mi++) {
#pragma unroll
        for (int ni = 0; ni < 4; ni++) {
            int row = m0 + wm + mi * 16 + r0;
            int col = n0 + wn + ni * 8 + c0;
            *(float2*)(C + (size_t)row * N + col) = make_float2(acc[mi][ni][0], acc[mi][ni][1]);
            *(float2*)(C + (size_t)(row + 8) * N + col) = make_float2(acc[mi][ni][2], acc[mi][ni][3]);
        }
    }
}

// ---------------------------------------------------------------------------
// Per-chunk local state via mma.sync:
// S^T[e][d] = sum_m v[m][e] * phi(k[m])[d]  -> A = v^T (64 x 64), B = kf^T (DFP x 64)
// Output stored e-major in g_Sh (fp16). ssum via smem reduction of kf^T.
// ---------------------------------------------------------------------------
#define CS_KFT 0                       // kf^T fp16: 288 rows x 128B = 36864
#define CS_VT  36864                   // v^T  fp16: 64 rows x 128B  = 8192
#define CS_KS  45056                   // k fp32: 64 x 16 = 4096
#define CS_SMEM 49152

__global__ void __launch_bounds__(256, 2) chunk_state_mma() {
    extern __shared__ char smc[];
    float* k_s = (float*)(smc + CS_KS);

    int blk = blockIdx.x;
    int c = blk & (NC - 1);
    int bh = blk >> 5;
    int b = bh >> 4, h = bh & 15;
    int t = threadIdx.x;
    long tok0 = (long)b * LL + (long)c * CHUNK;

    for (int i = t; i < 64 * 16; i += 256) {
        int n = i >> 4, f = i & 15;
        k_s[i] = g_qk[(tok0 + n) * 512 + 256 + h * 16 + f];
    }
    // v^T fp16 (e rows, m cols), GEMM swizzle
    for (int i = t; i < 64 * 64; i += 256) {
        int m = i >> 6, e = i & 63;
        float vv = g_v[(tok0 + m) * 1024 + h * 64 + e];
        int off = e * 128 + ((((m >> 3) ^ (e & 7))) << 4) + (m & 7) * 2;
        *(__half*)(smc + CS_VT + off) = __float2half(vv);
    }
    __syncthreads();

    // kf^T fp16 (d rows, m cols), rows >= DF zeroed
    for (int i = t; i < DFP * 64; i += 256) {
        int d = i >> 6, m = i & 63;
        float val = 0.f;
        if (d == 0) val = 1.f;
        else if (d <= 16) val = k_s[m * 16 + d - 1] * INV_RRD;
        else if (d < DF) {
            int dd = d - 17;
            val = k_s[m * 16 + (dd >> 4)] * k_s[m * 16 + (dd & 15)] * INV_Q2;
        }
        int off = d * 128 + ((((m >> 3) ^ (d & 7))) << 4) + (m & 7) * 2;
        *(__half*)(smc + CS_KFT + off) = __float2half(val);
    }
    __syncthreads();

    // mma: warp w -> e-tile (w>>1), d-tiles (w&1)*18 .. +17
    int w = t >> 5, l = t & 31;
    float acc[18][4];
#pragma unroll
    for (int j = 0; j < 18; j++)
#pragma unroll
        for (int r = 0; r < 4; r++) acc[j][r] = 0.f;

    uint32_t Ab = smem_u32(smc + CS_VT);
    uint32_t Bb = smem_u32(smc + CS_KFT);
    int ar = (w >> 1) * 16 + (l & 15);
    int ac = l >> 4;
    int brow_base = (l & 7) + ((l >> 4) << 3);
    int bkh = (l >> 3) & 1;
    int ntile0 = (w & 1) * 18;

#pragma unroll
    for (int ks = 0; ks < 4; ks++) {
        uint32_t afr[4];
        int ch = ks * 2 + ac;
        ldsm_x4(afr, Ab + ar * 128 + ((ch ^ (ar & 7)) << 4));
        int chb = ks * 2 + bkh;
#pragma unroll
        for (int jp = 0; jp < 9; jp++) {
            uint32_t bp[4];
            int row = (ntile0 + jp * 2) * 8 + brow_base;
            ldsm_x4(bp, Bb + row * 128 + ((chb ^ (row & 7)) << 4));
            mma_any<true>(acc[jp * 2],     afr, bp);
            mma_any<true>(acc[jp * 2 + 1], afr, bp + 2);
        }
    }

    // store S^T e-major fp16
    int r0 = l >> 2, c0 = (l & 3) * 2;
    size_t Sbase = (size_t)blk * 64 * DFP;
    int e_lo = (w >> 1) * 16 + r0;
#pragma unroll
    for (int j = 0; j < 18; j++) {
        int d = (ntile0 + j) * 8 + c0;
        *(__half2*)&g_Sh[Sbase + (size_t)e_lo * DFP + d] =
            __floats2half2_rn(acc[j][0], acc[j][1]);
        *(__half2*)&g_Sh[Sbase + (size_t)(e_lo + 8) * DFP + d] =
            __floats2half2_rn(acc[j][2], acc[j][3]);
    }

    // ssum[d] = sum_m kf[m][d] from kf^T smem
    for (int d = t; d < DF; d += 256) {
        float s = 0.f;
#pragma unroll
        for (int c8 = 0; c8 < 8; c8++) {
            int off = d * 128 + (((c8 ^ (d & 7))) << 4);
            uint4 u = *(const uint4*)(smc + CS_KFT + off);
            const __half2* hp = (const __half2*)&u;
#pragma unroll
            for (int q = 0; q < 4; q++) {
                float2 f2 = __half22float2(hp[q]);
                s += f2.x + f2.y;
            }
        }
        g_ss[(long)blk * DF + d] = s;
    }
}

// ---------------------------------------------------------------------------
// In-place exclusive prefix scans over chunk index
// ---------------------------------------------------------------------------
__global__ void scan_S_kernel() {      // over half2 pairs, e-major layout
    long idx = (long)blockIdx.x * 256 + threadIdx.x;
    const long PER_BH = 64 * DFP / 2;  // 9216 half2 per chunk
    if (idx >= (long)NBH * PER_BH) return;
    long bh = idx / PER_BH;
    long de = idx % PER_BH;
    __half2* Sp = (__half2*)g_Sh;
    size_t base = (size_t)bh * NC * PER_BH + de;
    float2 acc = make_float2(0.f, 0.f);
#pragma unroll
    for (int c = 0; c < NC; c++) {
        size_t p = base + (size_t)c * PER_BH;
        float2 tmp = __half22float2(Sp[p]);
        Sp[p] = __floats2half2_rn(acc.x, acc.y);
        acc.x += tmp.x; acc.y += tmp.y;
    }
}

__global__ void scan_ss_kernel() {
    long idx = (long)blockIdx.x * 256 + threadIdx.x;
    if (idx >= (long)NBH * DF) return;
    long bh = idx / DF;
    long d = idx % DF;
    long base = bh * NC * DF + d;
    float acc = 0.f;
#pragma unroll
    for (int c = 0; c < NC; c++) {
        long p = base + (long)c * DF;
        float tmp = g_ss[p];
        g_ss[p] = acc;
        acc += tmp;
    }
}

// ---------------------------------------------------------------------------
// Output kernel (512 threads): intra-chunk causal polynomial attention +
// phi(q) @ S_prefix, normalized; e-major S in smem (direct load now).
// ---------------------------------------------------------------------------
__global__ void __launch_bounds__(512, 1) output_kernel() {
    extern __shared__ float smf[];
    float* q_s  = smf;                 // 1024
    float* k_s  = q_s + 1024;          // 1024
    float* A_s  = k_s + 1024;          // 4096
    float* qf_s = A_s + 4096;          // 64*276
    float* S_T  = qf_s + 64 * QFP;     // 64*276 (e-major: [e][d])
    float* v_T  = S_T + 64 * QFP;      // 64*68  (e-major: [e][m])
    float* sp_s = v_T + 64 * VTP;      // 276
    float* z_s  = sp_s + QFP;          // 64

    int blk = blockIdx.x;
    int c = blk & (NC - 1);
    int bh = blk >> 5;
    int b = bh >> 4, h = bh & 15;
    int t = threadIdx.x;
    long tok0 = (long)b * LL + (long)c * CHUNK;

    for (int i = t; i < 64 * 16; i += 512) {
        int n = i >> 4, f = i & 15;
        long off = (tok0 + n) * 512 + h * 16 + f;
        q_s[i] = g_qk[off];
        k_s[i] = g_qk[off + 256];
    }
    for (int i = t; i < 64 * 64; i += 512) {
        int n = i >> 6, e = i & 63;
        v_T[e * VTP + n] = g_v[(tok0 + n) * 1024 + h * 64 + e];
    }
    // S^T e-major: straight load
    {
        int e8 = t >> 3, l8 = t & 7;
        size_t Sb = (size_t)blk * 64 * DFP + (size_t)e8 * DFP;
        for (int d = l8; d < DF; d += 8)
            S_T[e8 * QFP + d] = __half2float(g_Sh[Sb + d]);
        if (l8 < 3) S_T[e8 * QFP + DF + l8] = 0.f;
    }
    for (int i = t; i < QFP; i += 512) sp_s[i] = (i < DF) ? g_ss[(long)blk * DF + i] : 0.f;
    __syncthreads();

    // phi(q) into smem (padded stride QFP)
    for (int i = t; i < 64 * QFP; i += 512) {
        int n = i / QFP, d = i % QFP;
        float val = 0.f;
        if (d == 0) val = 1.f;
        else if (d <= 16) val = q_s[n * 16 + d - 1] * INV_RRD;
        else if (d < DF) {
            int dd = d - 17;
            val = q_s[n * 16 + (dd >> 4)] * q_s[n * 16 + (dd & 15)] * INV_Q2;
        }
        qf_s[i] = val;
    }

    // causal score matrix
    for (int i = t; i < 64 * 64; i += 512) {
        int n = i >> 6, m = i & 63;
        float a = 0.f;
        if (m <= n) {
            float s = 0.f;
#pragma unroll
            for (int f = 0; f < 16; f++) s += q_s[n * 16 + f] * k_s[m * 16 + f];
            a = 1.f + 0.25f * s + s * s * 0.03125f;
        }
        A_s[i] = a;
    }
    __syncthreads();

    // denominators: 8 lanes per n, shfl-reduced
    {
        int n = t >> 3, l8 = t & 7;
        float dsum = 0.f;
        for (int d = l8 * 4; d < QFP; d += 32) {
            float4 q4 = *(const float4*)&qf_s[n * QFP + d];
            float4 p4 = *(const float4*)&sp_s[d];
            dsum += q4.x * p4.x + q4.y * p4.y + q4.z * p4.z + q4.w * p4.w;
        }
        for (int m = l8 * 4; m < 64; m += 32) {
            float4 a4 = *(const float4*)&A_s[n * 64 + m];
            dsum += a4.x + a4.y + a4.z + a4.w;
        }
        dsum += __shfl_xor_sync(0xffffffffu, dsum, 4);
        dsum += __shfl_xor_sync(0xffffffffu, dsum, 2);
        dsum += __shfl_xor_sync(0xffffffffu, dsum, 1);
        if (l8 == 0) z_s[n] = 1.f / (dsum + EPS);
    }
    __syncthreads();

    // main: thread = (warp -> 4 n rows, lane -> e and e+32)
    int lane = t & 31, wid = t >> 5;
    int n0 = wid * 4;
    int e0 = lane, e1 = lane + 32;
    float acc[4][2];
#pragma unroll
    for (int i = 0; i < 4; i++) { acc[i][0] = 0.f; acc[i][1] = 0.f; }

    const float* S0 = &S_T[e0 * QFP];
    const float* S1 = &S_T[e1 * QFP];
    for (int d = 0; d < QFP; d += 4) {
        float4 s0 = *(const float4*)(S0 + d);
        float4 s1 = *(const float4*)(S1 + d);
#pragma unroll
        for (int nn = 0; nn < 4; nn++) {
            float4 q4 = *(const float4*)&qf_s[(n0 + nn) * QFP + d];   // broadcast
            acc[nn][0] += q4.x * s0.x + q4.y * s0.y + q4.z * s0.z + q4.w * s0.w;
            acc[nn][1] += q4.x * s1.x + q4.y * s1.y + q4.z * s1.z + q4.w * s1.w;
        }
    }
    const float* V0 = &v_T[e0 * VTP];
    const float* V1 = &v_T[e1 * VTP];
    for (int m = 0; m < 64; m += 4) {
        float4 v0 = *(const float4*)(V0 + m);
        float4 v1 = *(const float4*)(V1 + m);
#pragma unroll
        for (int nn = 0; nn < 4; nn++) {
            float4 a4 = *(const float4*)&A_s[(n0 + nn) * 64 + m];     // broadcast
            acc[nn][0] += a4.x * v0.x + a4.y * v0.y + a4.z * v0.z + a4.w * v0.w;
            acc[nn][1] += a4.x * v1.x + a4.y * v1.y + a4.z * v1.z + a4.w * v1.w;
        }
    }
#pragma unroll
    for (int nn = 0; nn < 4; nn++) {
        int n = n0 + nn;
        float z = z_s[n];
        size_t base = (size_t)(tok0 + n) * KVO + h * 64;
#pragma unroll
        for (int ee = 0; ee < 2; ee++) {
            int e = ee ? e1 : e0;
            float val = acc[nn][ee] * z;
            __half hi = __float2half_rn(val);
            __half lo = __float2half_rn(val - __half2float(hi));
            g_yh[base + e] = hi;
            g_yh[base + e + 1024] = lo;
        }
    }
}

// ---------------------------------------------------------------------------
extern "C" void kernel_launch(void* const* d_in, const int* in_sizes, int n_in,
                              void* d_out, int out_size) {
    const float* x  = (const float*)d_in[0];
    const float* Wq = (const float*)d_in[1];
    const float* Wk = (const float*)d_in[2];
    const float* Wv = (const float*)d_in[3];
    const float* Wo = (const float*)d_in[4];
    float* out = (float*)d_out;

    void *px2, *pxh, *pwqk, *pwvh, *pwoh, *pqk, *pv, *pyh;
    cudaGetSymbolAddress(&px2, g_x2);
    cudaGetSymbolAddress(&pxh, g_xh);
    cudaGetSymbolAddress(&pwqk, g_wqk);
    cudaGetSymbolAddress(&pwvh, g_wvh);
    cudaGetSymbolAddress(&pwoh, g_woh);
    cudaGetSymbolAddress(&pqk, g_qk);
    cudaGetSymbolAddress(&pv, g_v);
    cudaGetSymbolAddress(&pyh, g_yh);

    const int SM4_BYTES = (1024 + 1024 + 4096 + 64 * QFP + 64 * QFP + 64 * VTP + QFP + 64) * 4;
    cudaFuncSetAttribute(chunk_state_mma, cudaFuncAttributeMaxDynamicSharedMemorySize, CS_SMEM);
    cudaFuncSetAttribute(output_kernel, cudaFuncAttributeMaxDynamicSharedMemorySize, SM4_BYTES);
    cudaFuncSetAttribute(gemm_mma<false>, cudaFuncAttributeMaxDynamicSharedMemorySize, GEMM_SMEM);
    cudaFuncSetAttribute(gemm_mma<true>, cudaFuncAttributeMaxDynamicSharedMemorySize, GEMM_SMEM);

    // split/convert inputs
    conv_x_kernel<<<16384, 256>>>(x);
    wsplit_all<<<dim3(80, 32), dim3(32, 8)>>>(Wq, Wk, Wv, Wo);

    // projections on tensor cores
    gemm_mma<false><<<dim3(4, 32), 256, GEMM_SMEM>>>((const uint16_t*)px2, (const uint16_t*)pwqk,
                                                     (float*)pqk, 512, KQK, KQK / 64);
    gemm_mma<true><<<dim3(8, 32), 256, GEMM_SMEM>>>((const uint16_t*)pxh, (const uint16_t*)pwvh,
                                                    (float*)pv, 1024, KVO, KVO / 64);

    // chunked linear attention
    chunk_state_mma<<<NBH * NC, 256, CS_SMEM>>>();
    scan_S_kernel<<<(NBH * (64 * DFP / 2) + 255) / 256, 256>>>();
    scan_ss_kernel<<<(NBH * DF + 255) / 256, 256>>>();
    output_kernel<<<NBH * NC, 512, SM4_BYTES>>>();

    // final projection
    gemm_mma<true><<<dim3(8, 32), 256, GEMM_SMEM>>>((const uint16_t*)pyh, (const uint16_t*)pwoh,
                                                    out, 1024, KVO, KVO / 64);
}

// round 7
// speedup vs baseline: 3.3243x; 1.2057x over previous
#include <cuda_runtime.h>
#include <cuda_bf16.h>
#include <cuda_fp16.h>
#include <cstdint>

// Problem constants
#define BB 2
#define LL 2048
#define DM 1024
#define NH 16
#define FD 16
#define HD 64
#define DF 273          // 1 + 16 + 256
#define DFP 288         // DF padded to 18 n8-tiles for mma
#define CHUNK 64
#define NC 32           // LL / CHUNK
#define NBH 32          // BB * NH
#define INV_RRD 0.5f
#define INV_Q2 0.17677669529663687f   // 1/(4*sqrt(2))
#define EPS 1e-12f

#define KQK 3072        // bf16 3-term split for q/k projection
#define KVO 2048        // fp16 2-term split for v/o projections

// ---------------------------------------------------------------------------
// Scratch (device globals; no allocation)
// ---------------------------------------------------------------------------
__device__ __nv_bfloat16 g_x2[4096 * KQK];      // x: [hi | lo | hi] bf16
__device__ __half        g_xh[4096 * KVO];      // x: [hi | lo] fp16
__device__ __nv_bfloat16 g_wqk[512 * KQK];      // [Wq|Wk]^T: [hi | hi | lo] bf16
__device__ __half        g_wvh[1024 * KVO];     // Wv^T: [hi | hi] fp16
__device__ __half        g_woh[1024 * KVO];     // Wo^T: [hi | hi] fp16
__device__ float g_qk[4096 * 512];              // q (cols 0..255) | k (256..511)
__device__ float g_v[4096 * 1024];
__device__ __half g_yh[4096 * KVO];             // y: [hi | lo] fp16
__device__ __half g_Sh[(size_t)NBH * NC * 64 * DFP];  // chunk states, e-major S^T (fp16)
__device__ float g_ss[NBH * NC * DF];

// ---------------------------------------------------------------------------
// PTX helpers (baseline sm_80-compatible: ldmatrix, mma.sync, cp.async)
// ---------------------------------------------------------------------------
__device__ __forceinline__ uint32_t smem_u32(const void* p) {
    uint32_t a;
    asm("{ .reg .u64 t; cvta.to.shared.u64 t, %1; cvt.u32.u64 %0, t; }" : "=r"(a) : "l"(p));
    return a;
}
__device__ __forceinline__ void ldsm_x4(uint32_t* r, uint32_t addr) {
    asm volatile("ldmatrix.sync.aligned.m8n8.x4.shared.b16 {%0,%1,%2,%3}, [%4];"
        : "=r"(r[0]), "=r"(r[1]), "=r"(r[2]), "=r"(r[3]) : "r"(addr));
}
__device__ __forceinline__ void ldsm_x2(uint32_t* r, uint32_t addr) {
    asm volatile("ldmatrix.sync.aligned.m8n8.x2.shared.b16 {%0,%1}, [%2];"
        : "=r"(r[0]), "=r"(r[1]) : "r"(addr));
}
template<bool F16>
__device__ __forceinline__ void mma_any(float* d, const uint32_t* a, const uint32_t* b) {
    if constexpr (F16) {
        asm volatile("mma.sync.aligned.m16n8k16.row.col.f32.f16.f16.f32 "
            "{%0,%1,%2,%3}, {%4,%5,%6,%7}, {%8,%9}, {%0,%1,%2,%3};"
            : "+f"(d[0]), "+f"(d[1]), "+f"(d[2]), "+f"(d[3])
            : "r"(a[0]), "r"(a[1]), "r"(a[2]), "r"(a[3]), "r"(b[0]), "r"(b[1]));
    } else {
        asm volatile("mma.sync.aligned.m16n8k16.row.col.f32.bf16.bf16.f32 "
            "{%0,%1,%2,%3}, {%4,%5,%6,%7}, {%8,%9}, {%0,%1,%2,%3};"
            : "+f"(d[0]), "+f"(d[1]), "+f"(d[2]), "+f"(d[3])
            : "r"(a[0]), "r"(a[1]), "r"(a[2]), "r"(a[3]), "r"(b[0]), "r"(b[1]));
    }
}
#define CP_ASYNC16(dst, src) \
    asm volatile("cp.async.cg.shared.global [%0], [%1], 16;" :: "r"(dst), "l"(src))
#define CP_COMMIT() asm volatile("cp.async.commit_group;" ::: "memory")
#define CP_WAIT(n)  asm volatile("cp.async.wait_group %0;" :: "n"(n) : "memory")

// ---------------------------------------------------------------------------
// Converters
// ---------------------------------------------------------------------------
__global__ void conv_x_kernel(const float* __restrict__ x) {
    int idx = blockIdx.x * 256 + threadIdx.x;          // 4096*1024 elements
    int m = idx >> 10, k = idx & 1023;
    float v = x[idx];
    __nv_bfloat16 bh = __float2bfloat16(v);
    __nv_bfloat16 bl = __float2bfloat16(v - __bfloat162float(bh));
    size_t b2 = (size_t)m * KQK + k;
    g_x2[b2] = bh;
    g_x2[b2 + 1024] = bl;
    g_x2[b2 + 2048] = bh;
    __half fh = __float2half_rn(v);
    __half fl = __float2half_rn(v - __half2float(fh));
    size_t bh2 = (size_t)m * KVO + k;
    g_xh[bh2] = fh;
    g_xh[bh2 + 1024] = fl;
}

// All weight splits fused: blocks 0..7 Wq, 8..15 Wk (bf16 3-term),
// 16..47 Wv, 48..79 Wo (fp16 2-term).
__global__ void wsplit_all(const float* __restrict__ Wq, const float* __restrict__ Wk,
                           const float* __restrict__ Wv, const float* __restrict__ Wo) {
    __shared__ float tile[32][33];
    int bx = blockIdx.x, k0 = blockIdx.y * 32;
    const float* W;
    int Ncols, n0, mode, rowoff = 0;
    if (bx < 8)       { W = Wq; Ncols = 256;  n0 = bx * 32;        mode = 0; rowoff = 0;   }
    else if (bx < 16) { W = Wk; Ncols = 256;  n0 = (bx - 8) * 32;  mode = 0; rowoff = 256; }
    else if (bx < 48) { W = Wv; Ncols = 1024; n0 = (bx - 16) * 32; mode = 1; }
    else              { W = Wo; Ncols = 1024; n0 = (bx - 48) * 32; mode = 2; }
    int tx = threadIdx.x, ty = threadIdx.y;            // 32 x 8
    for (int i = ty; i < 32; i += 8)
        tile[i][tx] = W[(size_t)(k0 + i) * Ncols + n0 + tx];
    __syncthreads();
    for (int i = ty; i < 32; i += 8) {
        int n = n0 + i, k = k0 + tx;
        float v = tile[tx][i];
        if (mode == 0) {
            __nv_bfloat16 hi = __float2bfloat16(v);
            __nv_bfloat16 lo = __float2bfloat16(v - __bfloat162float(hi));
            size_t base = (size_t)(rowoff + n) * KQK + k;
            g_wqk[base] = hi;
            g_wqk[base + 1024] = hi;
            g_wqk[base + 2048] = lo;
        } else {
            __half hi = __float2half_rn(v);
            __half* dst = (mode == 1) ? g_wvh : g_woh;
            size_t base = (size_t)n * KVO + k;
            dst[base] = hi;
            dst[base + 1024] = hi;
        }
    }
}

// ---------------------------------------------------------------------------
// mma.sync GEMM: C (4096 x N, fp32) = A (4096 x K) @ Bt (N x K)^T
// 128x128 CTA tile, 8 warps (64x32 each), K-tile 64, 3-stage cp.async
// pipeline, paired-B ldmatrix, 2 CTAs/SM.
// ---------------------------------------------------------------------------
#define SMA(b) ((b) * 32768)
#define SMB(b) ((b) * 32768 + 16384)
#define GEMM_SMEM 98304

__device__ __forceinline__ void gemm_load_tile(const uint16_t* A, const uint16_t* B,
                                               char* sm, int m0, int n0, int kb, int buf,
                                               int t, int K) {
#pragma unroll
    for (int i = 0; i < 8; i++) {
        int idx = t + i * 256;            // 0..2047
        int row = (idx & 1023) >> 3, c = idx & 7;
        uint32_t dst;
        const uint16_t* src;
        if (idx < 1024) {
            src = A + (size_t)(m0 + row) * K + kb * 64 + c * 8;
            dst = smem_u32(sm + SMA(buf) + row * 128 + ((c ^ (row & 7)) << 4));
        } else {
            src = B + (size_t)(n0 + row) * K + kb * 64 + c * 8;
            dst = smem_u32(sm + SMB(buf) + row * 128 + ((c ^ (row & 7)) << 4));
        }
        CP_ASYNC16(dst, src);
    }
}

template<bool F16>
__global__ void __launch_bounds__(256, 2)
gemm_mma(const uint16_t* __restrict__ A, const uint16_t* __restrict__ B,
         float* __restrict__ C, int N, int K, int nkt) {
    extern __shared__ char sm[];
    int t = threadIdx.x;
    int m0 = blockIdx.y * 128, n0 = blockIdx.x * 128;
    int w = t >> 5, l = t & 31;
    int wm = (w >> 2) * 64, wn = (w & 3) * 32;

    float acc[4][4][4];
#pragma unroll
    for (int i = 0; i < 4; i++)
#pragma unroll
        for (int j = 0; j < 4; j++)
#pragma unroll
            for (int r = 0; r < 4; r++) acc[i][j][r] = 0.f;

    int ar = wm + (l & 15);
    int ac = (l >> 4);
    int brow = wn + (l & 7) + ((l >> 4) << 3);   // base row for paired-B ldsm
    int bkh = (l >> 3) & 1;

    gemm_load_tile(A, B, sm, m0, n0, 0, 0, t, K);
    CP_COMMIT();
    gemm_load_tile(A, B, sm, m0, n0, 1, 1, t, K);
    CP_COMMIT();

    int buf = 0;
    for (int kt = 0; kt < nkt; kt++) {
        if (kt + 2 < nkt) {
            int lb = buf + 2; if (lb >= 3) lb -= 3;
            gemm_load_tile(A, B, sm, m0, n0, kt + 2, lb, t, K);
        }
        CP_COMMIT();
        CP_WAIT(2);
        __syncthreads();

        uint32_t Ab = smem_u32(sm + SMA(buf));
        uint32_t Bb = smem_u32(sm + SMB(buf));
#pragma unroll
        for (int ks = 0; ks < 4; ks++) {
            uint32_t afr[4][4], bfr[4][2];
#pragma unroll
            for (int mi = 0; mi < 4; mi++) {
                int row = ar + mi * 16;
                int ch = ks * 2 + ac;
                ldsm_x4(afr[mi], Ab + row * 128 + ((ch ^ (row & 7)) << 4));
            }
#pragma unroll
            for (int p = 0; p < 2; p++) {
                uint32_t bp[4];
                int row = brow + p * 16;
                int ch = ks * 2 + bkh;
                ldsm_x4(bp, Bb + row * 128 + ((ch ^ (row & 7)) << 4));
                bfr[2 * p][0] = bp[0]; bfr[2 * p][1] = bp[1];
                bfr[2 * p + 1][0] = bp[2]; bfr[2 * p + 1][1] = bp[3];
            }
#pragma unroll
            for (int mi = 0; mi < 4; mi++)
#pragma unroll
                for (int ni = 0; ni < 4; ni++)
                    mma_any<F16>(acc[mi][ni], afr[mi], bfr[ni]);
        }
        __syncthreads();
        if (++buf == 3) buf = 0;
    }

    int r0 = l >> 2, c0 = (l & 3) * 2;
#pragma unroll
    for (int mi = 0; mi < 4; mi++) {
#pragma unroll
        for (int ni = 0; ni < 4; ni++) {
            int row = m0 + wm + mi * 16 + r0;
            int col = n0 + wn + ni * 8 + c0;
            *(float2*)(C + (size_t)row * N + col) = make_float2(acc[mi][ni][0], acc[mi][ni][1]);
            *(float2*)(C + (size_t)(row + 8) * N + col) = make_float2(acc[mi][ni][2], acc[mi][ni][3]);
        }
    }
}

// ---------------------------------------------------------------------------
// Per-chunk local state via mma.sync:
// S^T[e][d] = sum_m v[m][e] * phi(k[m])[d]  -> A = v^T (64 x 64), B = kf^T (DFP x 64)
// Output stored e-major in g_Sh (fp16). ssum via smem reduction of kf^T.
// ---------------------------------------------------------------------------
#define CS_KFT 0                       // kf^T fp16: 288 rows x 128B = 36864
#define CS_VT  36864                   // v^T  fp16: 64 rows x 128B  = 8192
#define CS_KS  45056                   // k fp32: 64 x 16 = 4096
#define CS_SMEM 49152

__global__ void __launch_bounds__(256, 2) chunk_state_mma() {
    extern __shared__ char smc[];
    float* k_s = (float*)(smc + CS_KS);

    int blk = blockIdx.x;
    int c = blk & (NC - 1);
    int bh = blk >> 5;
    int b = bh >> 4, h = bh & 15;
    int t = threadIdx.x;
    long tok0 = (long)b * LL + (long)c * CHUNK;

    for (int i = t; i < 64 * 16; i += 256) {
        int n = i >> 4, f = i & 15;
        k_s[i] = g_qk[(tok0 + n) * 512 + 256 + h * 16 + f];
    }
    // v^T fp16 (e rows, m cols), GEMM swizzle
    for (int i = t; i < 64 * 64; i += 256) {
        int m = i >> 6, e = i & 63;
        float vv = g_v[(tok0 + m) * 1024 + h * 64 + e];
        int off = e * 128 + ((((m >> 3) ^ (e & 7))) << 4) + (m & 7) * 2;
        *(__half*)(smc + CS_VT + off) = __float2half(vv);
    }
    __syncthreads();

    // kf^T fp16 (d rows, m cols), rows >= DF zeroed
    for (int i = t; i < DFP * 64; i += 256) {
        int d = i >> 6, m = i & 63;
        float val = 0.f;
        if (d == 0) val = 1.f;
        else if (d <= 16) val = k_s[m * 16 + d - 1] * INV_RRD;
        else if (d < DF) {
            int dd = d - 17;
            val = k_s[m * 16 + (dd >> 4)] * k_s[m * 16 + (dd & 15)] * INV_Q2;
        }
        int off = d * 128 + ((((m >> 3) ^ (d & 7))) << 4) + (m & 7) * 2;
        *(__half*)(smc + CS_KFT + off) = __float2half(val);
    }
    __syncthreads();

    // mma: warp w -> e-tile (w>>1), d-tiles (w&1)*18 .. +17
    int w = t >> 5, l = t & 31;
    float acc[18][4];
#pragma unroll
    for (int j = 0; j < 18; j++)
#pragma unroll
        for (int r = 0; r < 4; r++) acc[j][r] = 0.f;

    uint32_t Ab = smem_u32(smc + CS_VT);
    uint32_t Bb = smem_u32(smc + CS_KFT);
    int ar = (w >> 1) * 16 + (l & 15);
    int ac = l >> 4;
    int brow_base = (l & 7) + ((l >> 4) << 3);
    int bkh = (l >> 3) & 1;
    int ntile0 = (w & 1) * 18;

#pragma unroll
    for (int ks = 0; ks < 4; ks++) {
        uint32_t afr[4];
        int ch = ks * 2 + ac;
        ldsm_x4(afr, Ab + ar * 128 + ((ch ^ (ar & 7)) << 4));
        int chb = ks * 2 + bkh;
#pragma unroll
        for (int jp = 0; jp < 9; jp++) {
            uint32_t bp[4];
            int row = (ntile0 + jp * 2) * 8 + brow_base;
            ldsm_x4(bp, Bb + row * 128 + ((chb ^ (row & 7)) << 4));
            mma_any<true>(acc[jp * 2],     afr, bp);
            mma_any<true>(acc[jp * 2 + 1], afr, bp + 2);
        }
    }

    // store S^T e-major fp16
    int r0 = l >> 2, c0 = (l & 3) * 2;
    size_t Sbase = (size_t)blk * 64 * DFP;
    int e_lo = (w >> 1) * 16 + r0;
#pragma unroll
    for (int j = 0; j < 18; j++) {
        int d = (ntile0 + j) * 8 + c0;
        *(__half2*)&g_Sh[Sbase + (size_t)e_lo * DFP + d] =
            __floats2half2_rn(acc[j][0], acc[j][1]);
        *(__half2*)&g_Sh[Sbase + (size_t)(e_lo + 8) * DFP + d] =
            __floats2half2_rn(acc[j][2], acc[j][3]);
    }

    // ssum[d] = sum_m kf[m][d] from kf^T smem
    for (int d = t; d < DF; d += 256) {
        float s = 0.f;
#pragma unroll
        for (int c8 = 0; c8 < 8; c8++) {
            int off = d * 128 + (((c8 ^ (d & 7))) << 4);
            uint4 u = *(const uint4*)(smc + CS_KFT + off);
            const __half2* hp = (const __half2*)&u;
#pragma unroll
            for (int q = 0; q < 4; q++) {
                float2 f2 = __half22float2(hp[q]);
                s += f2.x + f2.y;
            }
        }
        g_ss[(long)blk * DF + d] = s;
    }
}

// ---------------------------------------------------------------------------
// In-place exclusive prefix scans over chunk index
// ---------------------------------------------------------------------------
__global__ void scan_S_kernel() {      // over half2 pairs, e-major layout
    long idx = (long)blockIdx.x * 256 + threadIdx.x;
    const long PER_BH = 64 * DFP / 2;  // 9216 half2 per chunk
    if (idx >= (long)NBH * PER_BH) return;
    long bh = idx / PER_BH;
    long de = idx % PER_BH;
    __half2* Sp = (__half2*)g_Sh;
    size_t base = (size_t)bh * NC * PER_BH + de;
    float2 acc = make_float2(0.f, 0.f);
#pragma unroll
    for (int c = 0; c < NC; c++) {
        size_t p = base + (size_t)c * PER_BH;
        float2 tmp = __half22float2(Sp[p]);
        Sp[p] = __floats2half2_rn(acc.x, acc.y);
        acc.x += tmp.x; acc.y += tmp.y;
    }
}

__global__ void scan_ss_kernel() {
    long idx = (long)blockIdx.x * 256 + threadIdx.x;
    if (idx >= (long)NBH * DF) return;
    long bh = idx / DF;
    long d = idx % DF;
    long base = bh * NC * DF + d;
    float acc = 0.f;
#pragma unroll
    for (int c = 0; c < NC; c++) {
        long p = base + (long)c * DF;
        float tmp = g_ss[p];
        g_ss[p] = acc;
        acc += tmp;
    }
}

// ---------------------------------------------------------------------------
// Output via one fused mma GEMM per (bh,chunk):
//   Aop = [phi(q) (64x288) | A_poly (64x64)]  (fp16, padded stride 360)
//   Bop rows (N=80): e<64: [S^T[e] | v^T[e]], row64: [0 | 1...], 65..79: 0
//   acc[n][e<64] = numerator;  acc[n][64] = rowsum(A)
//   denominator = fp32 scalar qf.sp + rowsum(A); y = num * z  (fp16 hi/lo out)
// ---------------------------------------------------------------------------
#define OTS 360                         // row stride in halves (45 x 16B, odd)
#define OT_QF 0                         // 64 x 720B  = 46080
#define OT_B  46080                     // 80 x 720B  = 57600
#define OT_Q  103680                    // 64x16 fp32 = 4096
#define OT_K  107776                    // 64x16 fp32 = 4096
#define OT_SP 111872                    // 276  fp32  = 1104
#define OT_DS 112976                    // 64 fp32
#define OT_RS 113232                    // 64 fp32
#define OT_Z  113488                    // 64 fp32
#define OT_SMEM 113792

__global__ void __launch_bounds__(256) output_mma() {
    extern __shared__ char smo[];
    float* q_s  = (float*)(smo + OT_Q);
    float* k_s  = (float*)(smo + OT_K);
    float* sp_s = (float*)(smo + OT_SP);
    float* ds_s = (float*)(smo + OT_DS);
    float* rs_s = (float*)(smo + OT_RS);
    float* z_s  = (float*)(smo + OT_Z);
    __half* qf  = (__half*)(smo + OT_QF);
    __half* Bx  = (__half*)(smo + OT_B);

    int blk = blockIdx.x;
    int c = blk & (NC - 1);
    int bh = blk >> 5;
    int b = bh >> 4, h = bh & 15;
    int t = threadIdx.x;
    long tok0 = (long)b * LL + (long)c * CHUNK;

    // ---- phase 1: loads ----
    for (int i = t; i < 64 * 16; i += 256) {
        int n = i >> 4, f = i & 15;
        long off = (tok0 + n) * 512 + h * 16 + f;
        q_s[i] = g_qk[off];
        k_s[i] = g_qk[off + 256];
    }
    for (int i = t; i < 276; i += 256) sp_s[i] = (i < DF) ? g_ss[(long)blk * DF + i] : 0.f;
    {   // S^T rows (straight uint4 copy; DFP=288 halves = 36 uint4 per row)
        const uint4* src = (const uint4*)(g_Sh + (size_t)blk * 64 * DFP);
        for (int i = t; i < 64 * 36; i += 256) {
            int e = i / 36, u = i % 36;
            *(uint4*)(smo + OT_B + e * 720 + u * 16) = src[i];
        }
    }
    for (int i = t; i < 4096; i += 256) {   // v^T into cols 288..351
        int m = i >> 6, e = i & 63;
        Bx[e * OTS + 288 + m] = __float2half(g_v[(tok0 + m) * 1024 + h * 64 + e]);
    }
    for (int i = t; i < 16 * 180; i += 256) {   // rows 64..79
        int r = 64 + i / 180, u = i % 180;      // uint (2 halves)
        uint32_t val = (r == 64 && u >= 144 && u < 176) ? 0x3C003C00u : 0u;  // ones over v-cols
        *(uint32_t*)(smo + OT_B + r * 720 + u * 4) = val;
    }
    __syncthreads();

    // ---- phase 2: build A-operand + fp32 denominator part ----
    for (int i = t; i < 64 * 288; i += 256) {   // phi(q)
        int n = i / 288, d = i % 288;
        float val = 0.f;
        if (d == 0) val = 1.f;
        else if (d <= 16) val = q_s[n * 16 + d - 1] * INV_RRD;
        else if (d < DF) {
            int dd = d - 17;
            val = q_s[n * 16 + (dd >> 4)] * q_s[n * 16 + (dd & 15)] * INV_Q2;
        }
        qf[n * OTS + d] = __float2half(val);
    }
    {   // causal polynomial scores into cols 288..351 (thread -> (n, 16 m's))
        int n = t >> 2, mq = (t & 3) << 4;
        float qr[16];
#pragma unroll
        for (int f = 0; f < 16; f++) qr[f] = q_s[n * 16 + f];
#pragma unroll
        for (int mm = 0; mm < 16; mm += 2) {
            float a2[2];
#pragma unroll
            for (int u2 = 0; u2 < 2; u2++) {
                int m = mq + mm + u2;
                float s = 0.f;
#pragma unroll
                for (int f = 0; f < 16; f++) s += qr[f] * k_s[m * 16 + f];
                a2[u2] = (m <= n) ? (1.f + 0.25f * s + s * s * 0.03125f) : 0.f;
            }
            *(__half2*)&qf[n * OTS + 288 + mq + mm] = __floats2half2_rn(a2[0], a2[1]);
        }
        if (t < 64) {                    // fp32 qf . sp
            const float* q0 = &q_s[t * 16];
            float d1 = 0.f;
#pragma unroll
            for (int f = 0; f < 16; f++) d1 += q0[f] * sp_s[1 + f];
            float d2 = 0.f;
            for (int i2 = 0; i2 < 16; i2++) {
                float inner = 0.f;
#pragma unroll
                for (int j = 0; j < 16; j++) inner += q0[j] * sp_s[17 + 16 * i2 + j];
                d2 += q0[i2] * inner;
            }
            ds_s[t] = sp_s[0] + INV_RRD * d1 + INV_Q2 * d2;
        }
    }
    __syncthreads();

    // ---- phase 3: 64x80x352 fp16 GEMM (8 warps: 4 m-tiles x 2 n-halves) ----
    int w = t >> 5, l = t & 31;
    int m0w = (w >> 1) * 16;
    int nh5 = w & 1;
    int nr0 = nh5 * 40;
    float acc[5][4];
#pragma unroll
    for (int j = 0; j < 5; j++)
#pragma unroll
        for (int r = 0; r < 4; r++) acc[j][r] = 0.f;

    uint32_t Qb = smem_u32(smo + OT_QF);
    uint32_t Bb = smem_u32(smo + OT_B);
    uint32_t aad = Qb + (m0w + (l & 15)) * 720 + (l >> 4) * 16;
    uint32_t bpd = Bb + (nr0 + (l & 7) + ((l >> 4) << 3)) * 720 + ((l >> 3) & 1) * 16;
    uint32_t bsd = Bb + (nr0 + 32 + (l & 7)) * 720 + ((l >> 3) & 1) * 16;

#pragma unroll
    for (int ks = 0; ks < 22; ks++) {
        uint32_t afr[4], bp0[4], bp1[4], bs[2];
        ldsm_x4(afr, aad + ks * 32);
        ldsm_x4(bp0, bpd + ks * 32);
        ldsm_x4(bp1, bpd + 16 * 720 + ks * 32);
        ldsm_x2(bs,  bsd + ks * 32);
        mma_any<true>(acc[0], afr, bp0);
        mma_any<true>(acc[1], afr, bp0 + 2);
        mma_any<true>(acc[2], afr, bp1);
        mma_any<true>(acc[3], afr, bp1 + 2);
        mma_any<true>(acc[4], afr, bs);
    }

    // ---- phase 4: denominator + write ----
    int r0 = l >> 2, c0 = (l & 3) * 2;
    if (nh5 == 1 && (l & 3) == 0) {     // local tile 3 = global tile 8 -> col 64
        rs_s[m0w + r0] = acc[3][0];
        rs_s[m0w + r0 + 8] = acc[3][2];
    }
    __syncthreads();
    if (t < 64) z_s[t] = 1.f / (ds_s[t] + rs_s[t] + EPS);
    __syncthreads();

    float z0 = z_s[m0w + r0], z1 = z_s[m0w + r0 + 8];
    size_t rowb0 = (size_t)(tok0 + m0w + r0) * KVO + h * 64;
    size_t rowb1 = (size_t)(tok0 + m0w + r0 + 8) * KVO + h * 64;
#pragma unroll
    for (int j = 0; j < 5; j++) {
        int col = (nh5 * 5 + j) * 8 + c0;
        if (col < 64) {
            float v00 = acc[j][0] * z0, v01 = acc[j][1] * z0;
            float v10 = acc[j][2] * z1, v11 = acc[j][3] * z1;
            __half hA = __float2half_rn(v00), hB = __float2half_rn(v01);
            __half hC = __float2half_rn(v10), hD = __float2half_rn(v11);
            *(__half2*)&g_yh[rowb0 + col] = __halves2half2(hA, hB);
            *(__half2*)&g_yh[rowb0 + col + 1024] =
                __halves2half2(__float2half_rn(v00 - __half2float(hA)),
                               __float2half_rn(v01 - __half2float(hB)));
            *(__half2*)&g_yh[rowb1 + col] = __halves2half2(hC, hD);
            *(__half2*)&g_yh[rowb1 + col + 1024] =
                __halves2half2(__float2half_rn(v10 - __half2float(hC)),
                               __float2half_rn(v11 - __half2float(hD)));
        }
    }
}

// ---------------------------------------------------------------------------
extern "C" void kernel_launch(void* const* d_in, const int* in_sizes, int n_in,
                              void* d_out, int out_size) {
    const float* x  = (const float*)d_in[0];
    const float* Wq = (const float*)d_in[1];
    const float* Wk = (const float*)d_in[2];
    const float* Wv = (const float*)d_in[3];
    const float* Wo = (const float*)d_in[4];
    float* out = (float*)d_out;

    void *px2, *pxh, *pwqk, *pwvh, *pwoh, *pqk, *pv, *pyh;
    cudaGetSymbolAddress(&px2, g_x2);
    cudaGetSymbolAddress(&pxh, g_xh);
    cudaGetSymbolAddress(&pwqk, g_wqk);
    cudaGetSymbolAddress(&pwvh, g_wvh);
    cudaGetSymbolAddress(&pwoh, g_woh);
    cudaGetSymbolAddress(&pqk, g_qk);
    cudaGetSymbolAddress(&pv, g_v);
    cudaGetSymbolAddress(&pyh, g_yh);

    cudaFuncSetAttribute(chunk_state_mma, cudaFuncAttributeMaxDynamicSharedMemorySize, CS_SMEM);
    cudaFuncSetAttribute(output_mma, cudaFuncAttributeMaxDynamicSharedMemorySize, OT_SMEM);
    cudaFuncSetAttribute(gemm_mma<false>, cudaFuncAttributeMaxDynamicSharedMemorySize, GEMM_SMEM);
    cudaFuncSetAttribute(gemm_mma<true>, cudaFuncAttributeMaxDynamicSharedMemorySize, GEMM_SMEM);

    // split/convert inputs
    conv_x_kernel<<<16384, 256>>>(x);
    wsplit_all<<<dim3(80, 32), dim3(32, 8)>>>(Wq, Wk, Wv, Wo);

    // projections on tensor cores
    gemm_mma<false><<<dim3(4, 32), 256, GEMM_SMEM>>>((const uint16_t*)px2, (const uint16_t*)pwqk,
                                                     (float*)pqk, 512, KQK, KQK / 64);
    gemm_mma<true><<<dim3(8, 32), 256, GEMM_SMEM>>>((const uint16_t*)pxh, (const uint16_t*)pwvh,
                                                    (float*)pv, 1024, KVO, KVO / 64);

    // chunked linear attention
    chunk_state_mma<<<NBH * NC, 256, CS_SMEM>>>();
    scan_S_kernel<<<(NBH * (64 * DFP / 2) + 255) / 256, 256>>>();
    scan_ss_kernel<<<(NBH * DF + 255) / 256, 256>>>();
    output_mma<<<NBH * NC, 256, OT_SMEM>>>();

    // final projection
    gemm_mma<true><<<dim3(8, 32), 256, GEMM_SMEM>>>((const uint16_t*)pyh, (const uint16_t*)pwoh,
                                                    out, 1024, KVO, KVO / 64);
}

// round 8
// speedup vs baseline: 3.4701x; 1.0439x over previous
#include <cuda_runtime.h>
#include <cuda_bf16.h>
#include <cuda_fp16.h>
#include <cstdint>

// Problem constants
#define BB 2
#define LL 2048
#define DM 1024
#define NH 16
#define FD 16
#define HD 64
#define DF 273          // 1 + 16 + 256
#define DFP 288         // DF padded to 18 n8-tiles for mma
#define CHUNK 64
#define NC 32           // LL / CHUNK
#define NBH 32          // BB * NH
#define INV_RRD 0.5f
#define INV_Q2 0.17677669529663687f   // 1/(4*sqrt(2))
#define EPS 1e-12f

#define KQK 3072        // bf16 3-term split for q/k projection
#define KVO 2048        // fp16 2-term split for v/o projections

// ---------------------------------------------------------------------------
// Scratch (device globals; no allocation)
// ---------------------------------------------------------------------------
__device__ __nv_bfloat16 g_x2[4096 * KQK];      // x: [hi | lo | hi] bf16
__device__ __half        g_xh[4096 * KVO];      // x: [hi | lo] fp16
__device__ __nv_bfloat16 g_wqk[512 * KQK];      // [Wq|Wk]^T: [hi | hi | lo] bf16
__device__ __half        g_wvh[1024 * KVO];     // Wv^T: [hi | hi] fp16
__device__ __half        g_woh[1024 * KVO];     // Wo^T: [hi | hi] fp16
__device__ float g_qk[4096 * 512];              // q (cols 0..255) | k (256..511)
__device__ float g_v[4096 * 1024];
__device__ __half g_yh[4096 * KVO];             // y: [hi | lo] fp16
__device__ __half g_Sh[(size_t)NBH * NC * 64 * DFP];  // chunk states, e-major S^T (fp16)
__device__ float g_ss[NBH * NC * DF];

// ---------------------------------------------------------------------------
// PTX helpers (baseline sm_80-compatible: ldmatrix, mma.sync, cp.async)
// ---------------------------------------------------------------------------
__device__ __forceinline__ uint32_t smem_u32(const void* p) {
    uint32_t a;
    asm("{ .reg .u64 t; cvta.to.shared.u64 t, %1; cvt.u32.u64 %0, t; }" : "=r"(a) : "l"(p));
    return a;
}
__device__ __forceinline__ void ldsm_x4(uint32_t* r, uint32_t addr) {
    asm volatile("ldmatrix.sync.aligned.m8n8.x4.shared.b16 {%0,%1,%2,%3}, [%4];"
        : "=r"(r[0]), "=r"(r[1]), "=r"(r[2]), "=r"(r[3]) : "r"(addr));
}
__device__ __forceinline__ void ldsm_x2(uint32_t* r, uint32_t addr) {
    asm volatile("ldmatrix.sync.aligned.m8n8.x2.shared.b16 {%0,%1}, [%2];"
        : "=r"(r[0]), "=r"(r[1]) : "r"(addr));
}
template<bool F16>
__device__ __forceinline__ void mma_any(float* d, const uint32_t* a, const uint32_t* b) {
    if constexpr (F16) {
        asm volatile("mma.sync.aligned.m16n8k16.row.col.f32.f16.f16.f32 "
            "{%0,%1,%2,%3}, {%4,%5,%6,%7}, {%8,%9}, {%0,%1,%2,%3};"
            : "+f"(d[0]), "+f"(d[1]), "+f"(d[2]), "+f"(d[3])
            : "r"(a[0]), "r"(a[1]), "r"(a[2]), "r"(a[3]), "r"(b[0]), "r"(b[1]));
    } else {
        asm volatile("mma.sync.aligned.m16n8k16.row.col.f32.bf16.bf16.f32 "
            "{%0,%1,%2,%3}, {%4,%5,%6,%7}, {%8,%9}, {%0,%1,%2,%3};"
            : "+f"(d[0]), "+f"(d[1]), "+f"(d[2]), "+f"(d[3])
            : "r"(a[0]), "r"(a[1]), "r"(a[2]), "r"(a[3]), "r"(b[0]), "r"(b[1]));
    }
}
#define CP_ASYNC16(dst, src) \
    asm volatile("cp.async.cg.shared.global [%0], [%1], 16;" :: "r"(dst), "l"(src))
#define CP_COMMIT() asm volatile("cp.async.commit_group;" ::: "memory")
#define CP_WAIT(n)  asm volatile("cp.async.wait_group %0;" :: "n"(n) : "memory")

// ---------------------------------------------------------------------------
// Converters
// ---------------------------------------------------------------------------
__global__ void conv_x_kernel(const float* __restrict__ x) {
    int idx = blockIdx.x * 256 + threadIdx.x;          // 4096*1024 elements
    int m = idx >> 10, k = idx & 1023;
    float v = x[idx];
    __nv_bfloat16 bh = __float2bfloat16(v);
    __nv_bfloat16 bl = __float2bfloat16(v - __bfloat162float(bh));
    size_t b2 = (size_t)m * KQK + k;
    g_x2[b2] = bh;
    g_x2[b2 + 1024] = bl;
    g_x2[b2 + 2048] = bh;
    __half fh = __float2half_rn(v);
    __half fl = __float2half_rn(v - __half2float(fh));
    size_t bh2 = (size_t)m * KVO + k;
    g_xh[bh2] = fh;
    g_xh[bh2 + 1024] = fl;
}

// All weight splits fused: blocks 0..7 Wq, 8..15 Wk (bf16 3-term),
// 16..47 Wv, 48..79 Wo (fp16 2-term).
__global__ void wsplit_all(const float* __restrict__ Wq, const float* __restrict__ Wk,
                           const float* __restrict__ Wv, const float* __restrict__ Wo) {
    __shared__ float tile[32][33];
    int bx = blockIdx.x, k0 = blockIdx.y * 32;
    const float* W;
    int Ncols, n0, mode, rowoff = 0;
    if (bx < 8)       { W = Wq; Ncols = 256;  n0 = bx * 32;        mode = 0; rowoff = 0;   }
    else if (bx < 16) { W = Wk; Ncols = 256;  n0 = (bx - 8) * 32;  mode = 0; rowoff = 256; }
    else if (bx < 48) { W = Wv; Ncols = 1024; n0 = (bx - 16) * 32; mode = 1; }
    else              { W = Wo; Ncols = 1024; n0 = (bx - 48) * 32; mode = 2; }
    int tx = threadIdx.x, ty = threadIdx.y;            // 32 x 8
    for (int i = ty; i < 32; i += 8)
        tile[i][tx] = W[(size_t)(k0 + i) * Ncols + n0 + tx];
    __syncthreads();
    for (int i = ty; i < 32; i += 8) {
        int n = n0 + i, k = k0 + tx;
        float v = tile[tx][i];
        if (mode == 0) {
            __nv_bfloat16 hi = __float2bfloat16(v);
            __nv_bfloat16 lo = __float2bfloat16(v - __bfloat162float(hi));
            size_t base = (size_t)(rowoff + n) * KQK + k;
            g_wqk[base] = hi;
            g_wqk[base + 1024] = hi;
            g_wqk[base + 2048] = lo;
        } else {
            __half hi = __float2half_rn(v);
            __half* dst = (mode == 1) ? g_wvh : g_woh;
            size_t base = (size_t)n * KVO + k;
            dst[base] = hi;
            dst[base + 1024] = hi;
        }
    }
}

// ---------------------------------------------------------------------------
// mma.sync GEMM body: C (M x N, fp32) tile (m0,n0) = A @ Bt^T
// 128x128 CTA tile, 8 warps (64x32 each), K-tile 64, 3-stage cp.async
// pipeline, paired-B ldmatrix.
// ---------------------------------------------------------------------------
#define SMA(b) ((b) * 32768)
#define SMB(b) ((b) * 32768 + 16384)
#define GEMM_SMEM 98304

__device__ __forceinline__ void gemm_load_tile(const uint16_t* A, const uint16_t* B,
                                               char* sm, int m0, int n0, int kb, int buf,
                                               int t, int K) {
#pragma unroll
    for (int i = 0; i < 8; i++) {
        int idx = t + i * 256;            // 0..2047
        int row = (idx & 1023) >> 3, c = idx & 7;
        uint32_t dst;
        const uint16_t* src;
        if (idx < 1024) {
            src = A + (size_t)(m0 + row) * K + kb * 64 + c * 8;
            dst = smem_u32(sm + SMA(buf) + row * 128 + ((c ^ (row & 7)) << 4));
        } else {
            src = B + (size_t)(n0 + row) * K + kb * 64 + c * 8;
            dst = smem_u32(sm + SMB(buf) + row * 128 + ((c ^ (row & 7)) << 4));
        }
        CP_ASYNC16(dst, src);
    }
}

template<bool F16>
__device__ __forceinline__ void gemm_body(const uint16_t* __restrict__ A,
                                          const uint16_t* __restrict__ B,
                                          float* __restrict__ C,
                                          int N, int K, int nkt,
                                          int m0, int n0, char* sm, int t) {
    int w = t >> 5, l = t & 31;
    int wm = (w >> 2) * 64, wn = (w & 3) * 32;

    float acc[4][4][4];
#pragma unroll
    for (int i = 0; i < 4; i++)
#pragma unroll
        for (int j = 0; j < 4; j++)
#pragma unroll
            for (int r = 0; r < 4; r++) acc[i][j][r] = 0.f;

    int ar = wm + (l & 15);
    int ac = (l >> 4);
    int brow = wn + (l & 7) + ((l >> 4) << 3);   // base row for paired-B ldsm
    int bkh = (l >> 3) & 1;

    gemm_load_tile(A, B, sm, m0, n0, 0, 0, t, K);
    CP_COMMIT();
    gemm_load_tile(A, B, sm, m0, n0, 1, 1, t, K);
    CP_COMMIT();

    int buf = 0;
    for (int kt = 0; kt < nkt; kt++) {
        if (kt + 2 < nkt) {
            int lb = buf + 2; if (lb >= 3) lb -= 3;
            gemm_load_tile(A, B, sm, m0, n0, kt + 2, lb, t, K);
        }
        CP_COMMIT();
        CP_WAIT(2);
        __syncthreads();

        uint32_t Ab = smem_u32(sm + SMA(buf));
        uint32_t Bb = smem_u32(sm + SMB(buf));
#pragma unroll
        for (int ks = 0; ks < 4; ks++) {
            uint32_t afr[4][4], bfr[4][2];
#pragma unroll
            for (int mi = 0; mi < 4; mi++) {
                int row = ar + mi * 16;
                int ch = ks * 2 + ac;
                ldsm_x4(afr[mi], Ab + row * 128 + ((ch ^ (row & 7)) << 4));
            }
#pragma unroll
            for (int p = 0; p < 2; p++) {
                uint32_t bp[4];
                int row = brow + p * 16;
                int ch = ks * 2 + bkh;
                ldsm_x4(bp, Bb + row * 128 + ((ch ^ (row & 7)) << 4));
                bfr[2 * p][0] = bp[0]; bfr[2 * p][1] = bp[1];
                bfr[2 * p + 1][0] = bp[2]; bfr[2 * p + 1][1] = bp[3];
            }
#pragma unroll
            for (int mi = 0; mi < 4; mi++)
#pragma unroll
                for (int ni = 0; ni < 4; ni++)
                    mma_any<F16>(acc[mi][ni], afr[mi], bfr[ni]);
        }
        __syncthreads();
        if (++buf == 3) buf = 0;
    }

    int r0 = l >> 2, c0 = (l & 3) * 2;
#pragma unroll
    for (int mi = 0; mi < 4; mi++) {
#pragma unroll
        for (int ni = 0; ni < 4; ni++) {
            int row = m0 + wm + mi * 16 + r0;
            int col = n0 + wn + ni * 8 + c0;
            *(float2*)(C + (size_t)row * N + col) = make_float2(acc[mi][ni][0], acc[mi][ni][1]);
            *(float2*)(C + (size_t)(row + 8) * N + col) = make_float2(acc[mi][ni][2], acc[mi][ni][3]);
        }
    }
}

// Fused q/k + v projections: CTAs 0..127 -> qk (bf16, K=3072, N=512),
// CTAs 128..383 -> v (fp16, K=2048, N=1024).
__global__ void __launch_bounds__(256, 2)
proj_gemm(const uint16_t* __restrict__ x2, const uint16_t* __restrict__ wqk,
          float* __restrict__ qk,
          const uint16_t* __restrict__ xh, const uint16_t* __restrict__ wvh,
          float* __restrict__ v) {
    extern __shared__ char sm[];
    int blk = blockIdx.x;
    int t = threadIdx.x;
    if (blk < 128) {
        gemm_body<false>(x2, wqk, qk, 512, KQK, KQK / 64,
                         (blk >> 2) * 128, (blk & 3) * 128, sm, t);
    } else {
        int b2 = blk - 128;
        gemm_body<true>(xh, wvh, v, 1024, KVO, KVO / 64,
                        (b2 >> 3) * 128, (b2 & 7) * 128, sm, t);
    }
}

// Standalone o-projection GEMM.
__global__ void __launch_bounds__(256, 2)
gemm_o(const uint16_t* __restrict__ A, const uint16_t* __restrict__ B,
       float* __restrict__ C) {
    extern __shared__ char sm[];
    gemm_body<true>(A, B, C, 1024, KVO, KVO / 64,
                    blockIdx.y * 128, blockIdx.x * 128, sm, threadIdx.x);
}

// ---------------------------------------------------------------------------
// Per-chunk local state via mma.sync:
// S^T[e][d] = sum_m v[m][e] * phi(k[m])[d]  -> A = v^T (64 x 64), B = kf^T (DFP x 64)
// Output stored e-major in g_Sh (fp16). ssum via smem reduction of kf^T.
// ---------------------------------------------------------------------------
#define CS_KFT 0                       // kf^T fp16: 288 rows x 128B = 36864
#define CS_VT  36864                   // v^T  fp16: 64 rows x 128B  = 8192
#define CS_KS  45056                   // k fp32: 64 x 16 = 4096
#define CS_SMEM 49152

__global__ void __launch_bounds__(256, 2) chunk_state_mma() {
    extern __shared__ char smc[];
    float* k_s = (float*)(smc + CS_KS);

    int blk = blockIdx.x;
    int c = blk & (NC - 1);
    int bh = blk >> 5;
    int b = bh >> 4, h = bh & 15;
    int t = threadIdx.x;
    long tok0 = (long)b * LL + (long)c * CHUNK;

    for (int i = t; i < 64 * 16; i += 256) {
        int n = i >> 4, f = i & 15;
        k_s[i] = g_qk[(tok0 + n) * 512 + 256 + h * 16 + f];
    }
    // v^T fp16 (e rows, m cols), GEMM swizzle
    for (int i = t; i < 64 * 64; i += 256) {
        int m = i >> 6, e = i & 63;
        float vv = g_v[(tok0 + m) * 1024 + h * 64 + e];
        int off = e * 128 + ((((m >> 3) ^ (e & 7))) << 4) + (m & 7) * 2;
        *(__half*)(smc + CS_VT + off) = __float2half(vv);
    }
    __syncthreads();

    // kf^T fp16 (d rows, m cols), rows >= DF zeroed
    for (int i = t; i < DFP * 64; i += 256) {
        int d = i >> 6, m = i & 63;
        float val = 0.f;
        if (d == 0) val = 1.f;
        else if (d <= 16) val = k_s[m * 16 + d - 1] * INV_RRD;
        else if (d < DF) {
            int dd = d - 17;
            val = k_s[m * 16 + (dd >> 4)] * k_s[m * 16 + (dd & 15)] * INV_Q2;
        }
        int off = d * 128 + ((((m >> 3) ^ (d & 7))) << 4) + (m & 7) * 2;
        *(__half*)(smc + CS_KFT + off) = __float2half(val);
    }
    __syncthreads();

    // mma: warp w -> e-tile (w>>1), d-tiles (w&1)*18 .. +17
    int w = t >> 5, l = t & 31;
    float acc[18][4];
#pragma unroll
    for (int j = 0; j < 18; j++)
#pragma unroll
        for (int r = 0; r < 4; r++) acc[j][r] = 0.f;

    uint32_t Ab = smem_u32(smc + CS_VT);
    uint32_t Bb = smem_u32(smc + CS_KFT);
    int ar = (w >> 1) * 16 + (l & 15);
    int ac = l >> 4;
    int brow_base = (l & 7) + ((l >> 4) << 3);
    int bkh = (l >> 3) & 1;
    int ntile0 = (w & 1) * 18;

#pragma unroll
    for (int ks = 0; ks < 4; ks++) {
        uint32_t afr[4];
        int ch = ks * 2 + ac;
        ldsm_x4(afr, Ab + ar * 128 + ((ch ^ (ar & 7)) << 4));
        int chb = ks * 2 + bkh;
#pragma unroll
        for (int jp = 0; jp < 9; jp++) {
            uint32_t bp[4];
            int row = (ntile0 + jp * 2) * 8 + brow_base;
            ldsm_x4(bp, Bb + row * 128 + ((chb ^ (row & 7)) << 4));
            mma_any<true>(acc[jp * 2],     afr, bp);
            mma_any<true>(acc[jp * 2 + 1], afr, bp + 2);
        }
    }

    // store S^T e-major fp16
    int r0 = l >> 2, c0 = (l & 3) * 2;
    size_t Sbase = (size_t)blk * 64 * DFP;
    int e_lo = (w >> 1) * 16 + r0;
#pragma unroll
    for (int j = 0; j < 18; j++) {
        int d = (ntile0 + j) * 8 + c0;
        *(__half2*)&g_Sh[Sbase + (size_t)e_lo * DFP + d] =
            __floats2half2_rn(acc[j][0], acc[j][1]);
        *(__half2*)&g_Sh[Sbase + (size_t)(e_lo + 8) * DFP + d] =
            __floats2half2_rn(acc[j][2], acc[j][3]);
    }

    // ssum[d] = sum_m kf[m][d] from kf^T smem
    for (int d = t; d < DF; d += 256) {
        float s = 0.f;
#pragma unroll
        for (int c8 = 0; c8 < 8; c8++) {
            int off = d * 128 + (((c8 ^ (d & 7))) << 4);
            uint4 u = *(const uint4*)(smc + CS_KFT + off);
            const __half2* hp = (const __half2*)&u;
#pragma unroll
            for (int q = 0; q < 4; q++) {
                float2 f2 = __half22float2(hp[q]);
                s += f2.x + f2.y;
            }
        }
        g_ss[(long)blk * DF + d] = s;
    }
}

// ---------------------------------------------------------------------------
// In-place exclusive prefix scans over chunk index
// ---------------------------------------------------------------------------
__global__ void scan_S_kernel() {      // over half2 pairs, e-major layout
    long idx = (long)blockIdx.x * 256 + threadIdx.x;
    const long PER_BH = 64 * DFP / 2;  // 9216 half2 per chunk
    if (idx >= (long)NBH * PER_BH) return;
    long bh = idx / PER_BH;
    long de = idx % PER_BH;
    __half2* Sp = (__half2*)g_Sh;
    size_t base = (size_t)bh * NC * PER_BH + de;
    float2 acc = make_float2(0.f, 0.f);
#pragma unroll
    for (int c = 0; c < NC; c++) {
        size_t p = base + (size_t)c * PER_BH;
        float2 tmp = __half22float2(Sp[p]);
        Sp[p] = __floats2half2_rn(acc.x, acc.y);
        acc.x += tmp.x; acc.y += tmp.y;
    }
}

__global__ void scan_ss_kernel() {
    long idx = (long)blockIdx.x * 256 + threadIdx.x;
    if (idx >= (long)NBH * DF) return;
    long bh = idx / DF;
    long d = idx % DF;
    long base = bh * NC * DF + d;
    float acc = 0.f;
#pragma unroll
    for (int c = 0; c < NC; c++) {
        long p = base + (long)c * DF;
        float tmp = g_ss[p];
        g_ss[p] = acc;
        acc += tmp;
    }
}

// ---------------------------------------------------------------------------
// Output via one fused mma GEMM per (bh,chunk):
//   Aop = [phi(q) (64x288) | A_poly (64x64)]  (fp16, padded stride 360)
//   Bop rows (N=72): e<64: [S^T[e] | v^T[e]], row64: [0 | 1...], 65..71: 0
//   acc[n][e<64] = numerator;  col 64 = rowsum(A)
//   denominator = fp32 scalar qf.sp + rowsum(A); y = num * z  (fp16 hi/lo out)
// Warp n-split: group0 -> tiles 0..4 (rows 0..39), group1 -> tiles 5..8 (rows 40..71).
// ---------------------------------------------------------------------------
#define OTS 360                         // row stride in halves (45 x 16B, odd)
#define OT_QF 0                         // 64 x 720B  = 46080
#define OT_B  46080                     // 72 x 720B  = 51840
#define OT_Q  97920                     // 64x16 fp32 = 4096
#define OT_K  102016                    // 64x16 fp32 = 4096
#define OT_SP 106112                    // 276  fp32  = 1104
#define OT_DS 107216                    // 64 fp32 (+pad)
#define OT_RS 107472                    // 64 fp32 (+pad)
#define OT_Z  107728                    // 64 fp32 (+pad)
#define OT_SMEM 107984

__global__ void __launch_bounds__(256, 2) output_mma() {
    extern __shared__ char smo[];
    float* q_s  = (float*)(smo + OT_Q);
    float* k_s  = (float*)(smo + OT_K);
    float* sp_s = (float*)(smo + OT_SP);
    float* ds_s = (float*)(smo + OT_DS);
    float* rs_s = (float*)(smo + OT_RS);
    float* z_s  = (float*)(smo + OT_Z);
    __half* qf  = (__half*)(smo + OT_QF);
    __half* Bx  = (__half*)(smo + OT_B);

    int blk = blockIdx.x;
    int c = blk & (NC - 1);
    int bh = blk >> 5;
    int b = bh >> 4, h = bh & 15;
    int t = threadIdx.x;
    long tok0 = (long)b * LL + (long)c * CHUNK;

    // ---- phase 1: loads ----
    for (int i = t; i < 64 * 16; i += 256) {
        int n = i >> 4, f = i & 15;
        long off = (tok0 + n) * 512 + h * 16 + f;
        q_s[i] = g_qk[off];
        k_s[i] = g_qk[off + 256];
    }
    for (int i = t; i < 276; i += 256) sp_s[i] = (i < DF) ? g_ss[(long)blk * DF + i] : 0.f;
    {   // S^T rows (straight uint4 copy; DFP=288 halves = 36 uint4 per row)
        const uint4* src = (const uint4*)(g_Sh + (size_t)blk * 64 * DFP);
        for (int i = t; i < 64 * 36; i += 256) {
            int e = i / 36, u = i % 36;
            *(uint4*)(smo + OT_B + e * 720 + u * 16) = src[i];
        }
    }
    for (int i = t; i < 4096; i += 256) {   // v^T into cols 288..351
        int m = i >> 6, e = i & 63;
        Bx[e * OTS + 288 + m] = __float2half(g_v[(tok0 + m) * 1024 + h * 64 + e]);
    }
    for (int i = t; i < 8 * 180; i += 256) {    // rows 64..71
        int r = 64 + i / 180, u = i % 180;      // uint (2 halves)
        uint32_t val = (r == 64 && u >= 144 && u < 176) ? 0x3C003C00u : 0u;  // ones over v-cols
        *(uint32_t*)(smo + OT_B + r * 720 + u * 4) = val;
    }
    __syncthreads();

    // ---- phase 2: build A-operand + fp32 denominator part ----
    for (int i = t; i < 64 * 288; i += 256) {   // phi(q)
        int n = i / 288, d = i % 288;
        float val = 0.f;
        if (d == 0) val = 1.f;
        else if (d <= 16) val = q_s[n * 16 + d - 1] * INV_RRD;
        else if (d < DF) {
            int dd = d - 17;
            val = q_s[n * 16 + (dd >> 4)] * q_s[n * 16 + (dd & 15)] * INV_Q2;
        }
        qf[n * OTS + d] = __float2half(val);
    }
    {   // causal polynomial scores into cols 288..351 (thread -> (n, 16 m's))
        int n = t >> 2, mq = (t & 3) << 4;
        float qr[16];
#pragma unroll
        for (int f = 0; f < 16; f++) qr[f] = q_s[n * 16 + f];
#pragma unroll
        for (int mm = 0; mm < 16; mm += 2) {
            float a2[2];
#pragma unroll
            for (int u2 = 0; u2 < 2; u2++) {
                int m = mq + mm + u2;
                float s = 0.f;
#pragma unroll
                for (int f = 0; f < 16; f++) s += qr[f] * k_s[m * 16 + f];
                a2[u2] = (m <= n) ? (1.f + 0.25f * s + s * s * 0.03125f) : 0.f;
            }
            *(__half2*)&qf[n * OTS + 288 + mq + mm] = __floats2half2_rn(a2[0], a2[1]);
        }
        if (t < 64) {                    // fp32 qf . sp
            const float* q0 = &q_s[t * 16];
            float d1 = 0.f;
#pragma unroll
            for (int f = 0; f < 16; f++) d1 += q0[f] * sp_s[1 + f];
            float d2 = 0.f;
            for (int i2 = 0; i2 < 16; i2++) {
                float inner = 0.f;
#pragma unroll
                for (int j = 0; j < 16; j++) inner += q0[j] * sp_s[17 + 16 * i2 + j];
                d2 += q0[i2] * inner;
            }
            ds_s[t] = sp_s[0] + INV_RRD * d1 + INV_Q2 * d2;
        }
    }
    __syncthreads();

    // ---- phase 3: 64x72x352 fp16 GEMM (8 warps: 4 m-tiles x 2 n-groups) ----
    int w = t >> 5, l = t & 31;
    int m0w = (w >> 1) * 16;
    int nh5 = w & 1;
    int nr0 = nh5 * 40;
    float acc[5][4];
#pragma unroll
    for (int j = 0; j < 5; j++)
#pragma unroll
        for (int r = 0; r < 4; r++) acc[j][r] = 0.f;

    uint32_t Qb = smem_u32(smo + OT_QF);
    uint32_t Bb = smem_u32(smo + OT_B);
    uint32_t aad = Qb + (m0w + (l & 15)) * 720 + (l >> 4) * 16;
    uint32_t bpd = Bb + (nr0 + (l & 7) + ((l >> 4) << 3)) * 720 + ((l >> 3) & 1) * 16;
    uint32_t bsd = Bb + (nr0 + 32 + (l & 7)) * 720 + ((l >> 3) & 1) * 16;

    if (nh5 == 0) {
#pragma unroll
        for (int ks = 0; ks < 22; ks++) {
            uint32_t afr[4], bp0[4], bp1[4], bs[2];
            ldsm_x4(afr, aad + ks * 32);
            ldsm_x4(bp0, bpd + ks * 32);
            ldsm_x4(bp1, bpd + 16 * 720 + ks * 32);
            ldsm_x2(bs,  bsd + ks * 32);
            mma_any<true>(acc[0], afr, bp0);
            mma_any<true>(acc[1], afr, bp0 + 2);
            mma_any<true>(acc[2], afr, bp1);
            mma_any<true>(acc[3], afr, bp1 + 2);
            mma_any<true>(acc[4], afr, bs);
        }
    } else {
#pragma unroll
        for (int ks = 0; ks < 22; ks++) {
            uint32_t afr[4], bp0[4], bp1[4];
            ldsm_x4(afr, aad + ks * 32);
            ldsm_x4(bp0, bpd + ks * 32);
            ldsm_x4(bp1, bpd + 16 * 720 + ks * 32);
            mma_any<true>(acc[0], afr, bp0);
            mma_any<true>(acc[1], afr, bp0 + 2);
            mma_any<true>(acc[2], afr, bp1);
            mma_any<true>(acc[3], afr, bp1 + 2);
        }
    }

    // ---- phase 4: denominator + write ----
    int r0 = l >> 2, c0 = (l & 3) * 2;
    if (nh5 == 1 && (l & 3) == 0) {     // local tile 3 = global tile 8 -> col 64
        rs_s[m0w + r0] = acc[3][0];
        rs_s[m0w + r0 + 8] = acc[3][2];
    }
    __syncthreads();
    if (t < 64) z_s[t] = 1.f / (ds_s[t] + rs_s[t] + EPS);
    __syncthreads();

    float z0 = z_s[m0w + r0], z1 = z_s[m0w + r0 + 8];
    size_t rowb0 = (size_t)(tok0 + m0w + r0) * KVO + h * 64;
    size_t rowb1 = (size_t)(tok0 + m0w + r0 + 8) * KVO + h * 64;
    int jmax = nh5 ? 4 : 5;
#pragma unroll
    for (int j = 0; j < 5; j++) {
        if (j >= jmax) break;
        int col = (nh5 * 5 + j) * 8 + c0;
        if (col < 64) {
            float v00 = acc[j][0] * z0, v01 = acc[j][1] * z0;
            float v10 = acc[j][2] * z1, v11 = acc[j][3] * z1;
            __half hA = __float2half_rn(v00), hB = __float2half_rn(v01);
            __half hC = __float2half_rn(v10), hD = __float2half_rn(v11);
            *(__half2*)&g_yh[rowb0 + col] = __halves2half2(hA, hB);
            *(__half2*)&g_yh[rowb0 + col + 1024] =
                __halves2half2(__float2half_rn(v00 - __half2float(hA)),
                               __float2half_rn(v01 - __half2float(hB)));
            *(__half2*)&g_yh[rowb1 + col] = __halves2half2(hC, hD);
            *(__half2*)&g_yh[rowb1 + col + 1024] =
                __halves2half2(__float2half_rn(v10 - __half2float(hC)),
                               __float2half_rn(v11 - __half2float(hD)));
        }
    }
}

// ---------------------------------------------------------------------------
extern "C" void kernel_launch(void* const* d_in, const int* in_sizes, int n_in,
                              void* d_out, int out_size) {
    const float* x  = (const float*)d_in[0];
    const float* Wq = (const float*)d_in[1];
    const float* Wk = (const float*)d_in[2];
    const float* Wv = (const float*)d_in[3];
    const float* Wo = (const float*)d_in[4];
    float* out = (float*)d_out;

    void *px2, *pxh, *pwqk, *pwvh, *pwoh, *pqk, *pv, *pyh;
    cudaGetSymbolAddress(&px2, g_x2);
    cudaGetSymbolAddress(&pxh, g_xh);
    cudaGetSymbolAddress(&pwqk, g_wqk);
    cudaGetSymbolAddress(&pwvh, g_wvh);
    cudaGetSymbolAddress(&pwoh, g_woh);
    cudaGetSymbolAddress(&pqk, g_qk);
    cudaGetSymbolAddress(&pv, g_v);
    cudaGetSymbolAddress(&pyh, g_yh);

    cudaFuncSetAttribute(chunk_state_mma, cudaFuncAttributeMaxDynamicSharedMemorySize, CS_SMEM);
    cudaFuncSetAttribute(output_mma, cudaFuncAttributeMaxDynamicSharedMemorySize, OT_SMEM);
    cudaFuncSetAttribute(proj_gemm, cudaFuncAttributeMaxDynamicSharedMemorySize, GEMM_SMEM);
    cudaFuncSetAttribute(gemm_o, cudaFuncAttributeMaxDynamicSharedMemorySize, GEMM_SMEM);

    // split/convert inputs
    conv_x_kernel<<<16384, 256>>>(x);
    wsplit_all<<<dim3(80, 32), dim3(32, 8)>>>(Wq, Wk, Wv, Wo);

    // fused q/k + v projections on tensor cores
    proj_gemm<<<384, 256, GEMM_SMEM>>>((const uint16_t*)px2, (const uint16_t*)pwqk, (float*)pqk,
                                       (const uint16_t*)pxh, (const uint16_t*)pwvh, (float*)pv);

    // chunked linear attention
    chunk_state_mma<<<NBH * NC, 256, CS_SMEM>>>();
    scan_S_kernel<<<(NBH * (64 * DFP / 2) + 255) / 256, 256>>>();
    scan_ss_kernel<<<(NBH * DF + 255) / 256, 256>>>();
    output_mma<<<NBH * NC, 256, OT_SMEM>>>();

    // final projection
    gemm_o<<<dim3(8, 32), 256, GEMM_SMEM>>>((const uint16_t*)pyh, (const uint16_t*)pwoh, out);
}

// round 9
// speedup vs baseline: 4.1841x; 1.2058x over previous
#include <cuda_runtime.h>
#include <cuda_bf16.h>
#include <cuda_fp16.h>
#include <cstdint>

// Problem constants
#define BB 2
#define LL 2048
#define DM 1024
#define NH 16
#define FD 16
#define HD 64
#define DF 273          // 1 + 16 + 256
#define DFP 288         // DF padded to 18 n8-tiles for mma
#define CHUNK 64
#define NC 32           // LL / CHUNK
#define NBH 32          // BB * NH
#define INV_RRD 0.5f
#define INV_Q2 0.17677669529663687f   // 1/(4*sqrt(2))
#define EPS 1e-12f

#define KQK 3072        // bf16 3-term split for q/k projection
#define KVO 2048        // fp16 2-term split for v/o projections

// ---------------------------------------------------------------------------
// Scratch (device globals; no allocation)
// ---------------------------------------------------------------------------
__device__ __nv_bfloat16 g_x2[4096 * KQK];      // x: [hi | lo | hi] bf16
__device__ __half        g_xh[4096 * KVO];      // x: [hi | lo] fp16
__device__ __nv_bfloat16 g_wqk[512 * KQK];      // [Wq|Wk]^T: [hi | hi | lo] bf16
__device__ __half        g_wvh[1024 * KVO];     // Wv^T: [hi | hi] fp16
__device__ __half        g_woh[1024 * KVO];     // Wo^T: [hi | hi] fp16
__device__ float g_qk[4096 * 512];              // q (cols 0..255) | k (256..511)
__device__ float g_v[4096 * 1024];
__device__ __half g_yh[4096 * KVO];             // y: [hi | lo] fp16
__device__ __half g_Sh[(size_t)NBH * NC * 64 * DFP];  // chunk states, e-major S^T (fp16)
__device__ float g_ss[NBH * NC * DF];

// ---------------------------------------------------------------------------
// PTX helpers (baseline sm_80-compatible: ldmatrix, mma.sync, cp.async)
// ---------------------------------------------------------------------------
__device__ __forceinline__ uint32_t smem_u32(const void* p) {
    uint32_t a;
    asm("{ .reg .u64 t; cvta.to.shared.u64 t, %1; cvt.u32.u64 %0, t; }" : "=r"(a) : "l"(p));
    return a;
}
__device__ __forceinline__ void ldsm_x4(uint32_t* r, uint32_t addr) {
    asm volatile("ldmatrix.sync.aligned.m8n8.x4.shared.b16 {%0,%1,%2,%3}, [%4];"
        : "=r"(r[0]), "=r"(r[1]), "=r"(r[2]), "=r"(r[3]) : "r"(addr));
}
__device__ __forceinline__ void ldsm_x2(uint32_t* r, uint32_t addr) {
    asm volatile("ldmatrix.sync.aligned.m8n8.x2.shared.b16 {%0,%1}, [%2];"
        : "=r"(r[0]), "=r"(r[1]) : "r"(addr));
}
template<bool F16>
__device__ __forceinline__ void mma_any(float* d, const uint32_t* a, const uint32_t* b) {
    if constexpr (F16) {
        asm volatile("mma.sync.aligned.m16n8k16.row.col.f32.f16.f16.f32 "
            "{%0,%1,%2,%3}, {%4,%5,%6,%7}, {%8,%9}, {%0,%1,%2,%3};"
            : "+f"(d[0]), "+f"(d[1]), "+f"(d[2]), "+f"(d[3])
            : "r"(a[0]), "r"(a[1]), "r"(a[2]), "r"(a[3]), "r"(b[0]), "r"(b[1]));
    } else {
        asm volatile("mma.sync.aligned.m16n8k16.row.col.f32.bf16.bf16.f32 "
            "{%0,%1,%2,%3}, {%4,%5,%6,%7}, {%8,%9}, {%0,%1,%2,%3};"
            : "+f"(d[0]), "+f"(d[1]), "+f"(d[2]), "+f"(d[3])
            : "r"(a[0]), "r"(a[1]), "r"(a[2]), "r"(a[3]), "r"(b[0]), "r"(b[1]));
    }
}
#define CP_ASYNC16(dst, src) \
    asm volatile("cp.async.cg.shared.global [%0], [%1], 16;" :: "r"(dst), "l"(src))
#define CP_COMMIT() asm volatile("cp.async.commit_group;" ::: "memory")
#define CP_WAIT(n)  asm volatile("cp.async.wait_group %0;" :: "n"(n) : "memory")

// ---------------------------------------------------------------------------
// Converters
// ---------------------------------------------------------------------------
union BF2U { __nv_bfloat162 b; uint32_t u; };
union HF2U { __half2 h; uint32_t u; };

__global__ void conv_x_kernel(const float* __restrict__ x) {
    int idx = blockIdx.x * 256 + threadIdx.x;          // 1M threads, 4 elems each
    int m = idx >> 8, k4 = (idx & 255) << 2;
    float4 v = *(const float4*)&x[(size_t)m * 1024 + k4];
    float f[4] = {v.x, v.y, v.z, v.w};
    uint32_t bh[2], bl[2], fh[2], fl[2];
#pragma unroll
    for (int p = 0; p < 2; p++) {
        float a = f[2 * p], bq = f[2 * p + 1];
        __nv_bfloat16 h0 = __float2bfloat16(a), h1 = __float2bfloat16(bq);
        BF2U uh; uh.b = __halves2bfloat162(h0, h1); bh[p] = uh.u;
        BF2U ul; ul.b = __halves2bfloat162(
            __float2bfloat16(a - __bfloat162float(h0)),
            __float2bfloat16(bq - __bfloat162float(h1))); bl[p] = ul.u;
        __half g0 = __float2half_rn(a), g1 = __float2half_rn(bq);
        HF2U vh; vh.h = __halves2half2(g0, g1); fh[p] = vh.u;
        HF2U vl; vl.h = __halves2half2(
            __float2half_rn(a - __half2float(g0)),
            __float2half_rn(bq - __half2float(g1))); fl[p] = vl.u;
    }
    size_t b2 = (size_t)m * KQK + k4;
    *(uint2*)&g_x2[b2]        = make_uint2(bh[0], bh[1]);
    *(uint2*)&g_x2[b2 + 1024] = make_uint2(bl[0], bl[1]);
    *(uint2*)&g_x2[b2 + 2048] = make_uint2(bh[0], bh[1]);
    size_t bh2 = (size_t)m * KVO + k4;
    *(uint2*)&g_xh[bh2]        = make_uint2(fh[0], fh[1]);
    *(uint2*)&g_xh[bh2 + 1024] = make_uint2(fl[0], fl[1]);
}

// All weight splits fused: blocks 0..7 Wq, 8..15 Wk (bf16 3-term),
// 16..47 Wv, 48..79 Wo (fp16 2-term).
__global__ void wsplit_all(const float* __restrict__ Wq, const float* __restrict__ Wk,
                           const float* __restrict__ Wv, const float* __restrict__ Wo) {
    __shared__ float tile[32][33];
    int bx = blockIdx.x, k0 = blockIdx.y * 32;
    const float* W;
    int Ncols, n0, mode, rowoff = 0;
    if (bx < 8)       { W = Wq; Ncols = 256;  n0 = bx * 32;        mode = 0; rowoff = 0;   }
    else if (bx < 16) { W = Wk; Ncols = 256;  n0 = (bx - 8) * 32;  mode = 0; rowoff = 256; }
    else if (bx < 48) { W = Wv; Ncols = 1024; n0 = (bx - 16) * 32; mode = 1; }
    else              { W = Wo; Ncols = 1024; n0 = (bx - 48) * 32; mode = 2; }
    int tx = threadIdx.x, ty = threadIdx.y;            // 32 x 8
    for (int i = ty; i < 32; i += 8)
        tile[i][tx] = W[(size_t)(k0 + i) * Ncols + n0 + tx];
    __syncthreads();
    for (int i = ty; i < 32; i += 8) {
        int n = n0 + i, k = k0 + tx;
        float v = tile[tx][i];
        if (mode == 0) {
            __nv_bfloat16 hi = __float2bfloat16(v);
            __nv_bfloat16 lo = __float2bfloat16(v - __bfloat162float(hi));
            size_t base = (size_t)(rowoff + n) * KQK + k;
            g_wqk[base] = hi;
            g_wqk[base + 1024] = hi;
            g_wqk[base + 2048] = lo;
        } else {
            __half hi = __float2half_rn(v);
            __half* dst = (mode == 1) ? g_wvh : g_woh;
            size_t base = (size_t)n * KVO + k;
            dst[base] = hi;
            dst[base + 1024] = hi;
        }
    }
}

// ---------------------------------------------------------------------------
// mma.sync GEMM body: C (M x N, fp32) tile (m0,n0) = A @ Bt^T
// 128x128 CTA tile, 8 warps (64x32 each), K-tile 64, 3-stage cp.async
// pipeline, paired-B ldmatrix.
// ---------------------------------------------------------------------------
#define SMA(b) ((b) * 32768)
#define SMB(b) ((b) * 32768 + 16384)
#define GEMM_SMEM 98304

__device__ __forceinline__ void gemm_load_tile(const uint16_t* A, const uint16_t* B,
                                               char* sm, int m0, int n0, int kb, int buf,
                                               int t, int K) {
#pragma unroll
    for (int i = 0; i < 8; i++) {
        int idx = t + i * 256;            // 0..2047
        int row = (idx & 1023) >> 3, c = idx & 7;
        uint32_t dst;
        const uint16_t* src;
        if (idx < 1024) {
            src = A + (size_t)(m0 + row) * K + kb * 64 + c * 8;
            dst = smem_u32(sm + SMA(buf) + row * 128 + ((c ^ (row & 7)) << 4));
        } else {
            src = B + (size_t)(n0 + row) * K + kb * 64 + c * 8;
            dst = smem_u32(sm + SMB(buf) + row * 128 + ((c ^ (row & 7)) << 4));
        }
        CP_ASYNC16(dst, src);
    }
}

template<bool F16>
__device__ __forceinline__ void gemm_body(const uint16_t* __restrict__ A,
                                          const uint16_t* __restrict__ B,
                                          float* __restrict__ C,
                                          int N, int K, int nkt,
                                          int m0, int n0, char* sm, int t) {
    int w = t >> 5, l = t & 31;
    int wm = (w >> 2) * 64, wn = (w & 3) * 32;

    float acc[4][4][4];
#pragma unroll
    for (int i = 0; i < 4; i++)
#pragma unroll
        for (int j = 0; j < 4; j++)
#pragma unroll
            for (int r = 0; r < 4; r++) acc[i][j][r] = 0.f;

    int ar = wm + (l & 15);
    int ac = (l >> 4);
    int brow = wn + (l & 7) + ((l >> 4) << 3);   // base row for paired-B ldsm
    int bkh = (l >> 3) & 1;

    gemm_load_tile(A, B, sm, m0, n0, 0, 0, t, K);
    CP_COMMIT();
    gemm_load_tile(A, B, sm, m0, n0, 1, 1, t, K);
    CP_COMMIT();

    int buf = 0;
    for (int kt = 0; kt < nkt; kt++) {
        if (kt + 2 < nkt) {
            int lb = buf + 2; if (lb >= 3) lb -= 3;
            gemm_load_tile(A, B, sm, m0, n0, kt + 2, lb, t, K);
        }
        CP_COMMIT();
        CP_WAIT(2);
        __syncthreads();

        uint32_t Ab = smem_u32(sm + SMA(buf));
        uint32_t Bb = smem_u32(sm + SMB(buf));
#pragma unroll
        for (int ks = 0; ks < 4; ks++) {
            uint32_t afr[4][4], bfr[4][2];
#pragma unroll
            for (int mi = 0; mi < 4; mi++) {
                int row = ar + mi * 16;
                int ch = ks * 2 + ac;
                ldsm_x4(afr[mi], Ab + row * 128 + ((ch ^ (row & 7)) << 4));
            }
#pragma unroll
            for (int p = 0; p < 2; p++) {
                uint32_t bp[4];
                int row = brow + p * 16;
                int ch = ks * 2 + bkh;
                ldsm_x4(bp, Bb + row * 128 + ((ch ^ (row & 7)) << 4));
                bfr[2 * p][0] = bp[0]; bfr[2 * p][1] = bp[1];
                bfr[2 * p + 1][0] = bp[2]; bfr[2 * p + 1][1] = bp[3];
            }
#pragma unroll
            for (int mi = 0; mi < 4; mi++)
#pragma unroll
                for (int ni = 0; ni < 4; ni++)
                    mma_any<F16>(acc[mi][ni], afr[mi], bfr[ni]);
        }
        __syncthreads();
        if (++buf == 3) buf = 0;
    }

    int r0 = l >> 2, c0 = (l & 3) * 2;
#pragma unroll
    for (int mi = 0; mi < 4; mi++) {
#pragma unroll
        for (int ni = 0; ni < 4; ni++) {
            int row = m0 + wm + mi * 16 + r0;
            int col = n0 + wn + ni * 8 + c0;
            *(float2*)(C + (size_t)row * N + col) = make_float2(acc[mi][ni][0], acc[mi][ni][1]);
            *(float2*)(C + (size_t)(row + 8) * N + col) = make_float2(acc[mi][ni][2], acc[mi][ni][3]);
        }
    }
}

// Fused q/k + v projections: CTAs 0..127 -> qk (bf16, K=3072, N=512),
// CTAs 128..383 -> v (fp16, K=2048, N=1024).
__global__ void __launch_bounds__(256, 2)
proj_gemm(const uint16_t* __restrict__ x2, const uint16_t* __restrict__ wqk,
          float* __restrict__ qk,
          const uint16_t* __restrict__ xh, const uint16_t* __restrict__ wvh,
          float* __restrict__ v) {
    extern __shared__ char sm[];
    int blk = blockIdx.x;
    int t = threadIdx.x;
    if (blk < 128) {
        gemm_body<false>(x2, wqk, qk, 512, KQK, KQK / 64,
                         (blk >> 2) * 128, (blk & 3) * 128, sm, t);
    } else {
        int b2 = blk - 128;
        gemm_body<true>(xh, wvh, v, 1024, KVO, KVO / 64,
                        (b2 >> 3) * 128, (b2 & 7) * 128, sm, t);
    }
}

// Standalone o-projection GEMM.
__global__ void __launch_bounds__(256, 2)
gemm_o(const uint16_t* __restrict__ A, const uint16_t* __restrict__ B,
       float* __restrict__ C) {
    extern __shared__ char sm[];
    gemm_body<true>(A, B, C, 1024, KVO, KVO / 64,
                    blockIdx.y * 128, blockIdx.x * 128, sm, threadIdx.x);
}

// ---------------------------------------------------------------------------
// Per-chunk local state via mma.sync:
// S^T[e][d] = sum_m v[m][e] * phi(k[m])[d]  -> A = v^T (64 x 64), B = kf^T (DFP x 64)
// Operand builds are fully vectorized: fp32 staging (padded stride 65) then
// one 16B swizzled store per (row, chunk). mma phase identical to validated R8.
// ---------------------------------------------------------------------------
#define CS_KFT 0                       // kf^T fp16: 288 rows x 128B = 36864
#define CS_VT  36864                   // v^T  fp16: 64 rows x 128B  = 8192
#define CS_KT  45056                   // k^T fp32 [16][65] = 4160
#define CS_VS  49216                   // v^T fp32 [64][65] = 16640
#define CS_SMEM 65856

__global__ void __launch_bounds__(256, 2) chunk_state_mma() {
    extern __shared__ char smc[];
    float* k_T = (float*)(smc + CS_KT);
    float* v_S = (float*)(smc + CS_VS);

    int blk = blockIdx.x;
    int c = blk & (NC - 1);
    int bh = blk >> 5;
    int b = bh >> 4, h = bh & 15;
    int t = threadIdx.x;
    long tok0 = (long)b * LL + (long)c * CHUNK;

    // stage k transposed [f][n] (pad 65) and v transposed [e][m] (pad 65)
    for (int i = t; i < 64 * 16; i += 256) {
        int n = i >> 4, f = i & 15;
        k_T[f * 65 + n] = g_qk[(tok0 + n) * 512 + 256 + h * 16 + f];
    }
    for (int i = t; i < 4096; i += 256) {
        int m = i >> 6, e = i & 63;
        v_S[e * 65 + m] = g_v[(tok0 + m) * 1024 + h * 64 + e];
    }
    __syncthreads();

    // v^T fp16 swizzled: one uint4 per (e, chunk)
    for (int i = t; i < 512; i += 256) {
        int e = i >> 3, c8 = i & 7;
        int mg = c8 ^ (e & 7);
        const float* vr = &v_S[e * 65 + mg * 8];
        uint4 u;
        __half2* hp = (__half2*)&u;
        hp[0] = __floats2half2_rn(vr[0], vr[1]);
        hp[1] = __floats2half2_rn(vr[2], vr[3]);
        hp[2] = __floats2half2_rn(vr[4], vr[5]);
        hp[3] = __floats2half2_rn(vr[6], vr[7]);
        *(uint4*)(smc + CS_VT + e * 128 + c8 * 16) = u;
    }

    // kf^T fp16 swizzled: one uint4 per (d, chunk)
    for (int i = t; i < DFP * 8; i += 256) {
        int d = i >> 3, c8 = i & 7;
        int mg = c8 ^ (d & 7);
        int m0 = mg * 8;
        uint4 u;
        __half2* hp = (__half2*)&u;
        if (d == 0) {
            __half2 one2 = __floats2half2_rn(1.f, 1.f);
            hp[0] = one2; hp[1] = one2; hp[2] = one2; hp[3] = one2;
        } else if (d <= 16) {
            const float* kr = &k_T[(d - 1) * 65 + m0];
            hp[0] = __floats2half2_rn(kr[0] * INV_RRD, kr[1] * INV_RRD);
            hp[1] = __floats2half2_rn(kr[2] * INV_RRD, kr[3] * INV_RRD);
            hp[2] = __floats2half2_rn(kr[4] * INV_RRD, kr[5] * INV_RRD);
            hp[3] = __floats2half2_rn(kr[6] * INV_RRD, kr[7] * INV_RRD);
        } else if (d < DF) {
            int dd = d - 17;
            const float* ka = &k_T[(dd >> 4) * 65 + m0];
            const float* kb = &k_T[(dd & 15) * 65 + m0];
            hp[0] = __floats2half2_rn(ka[0] * kb[0] * INV_Q2, ka[1] * kb[1] * INV_Q2);
            hp[1] = __floats2half2_rn(ka[2] * kb[2] * INV_Q2, ka[3] * kb[3] * INV_Q2);
            hp[2] = __floats2half2_rn(ka[4] * kb[4] * INV_Q2, ka[5] * kb[5] * INV_Q2);
            hp[3] = __floats2half2_rn(ka[6] * kb[6] * INV_Q2, ka[7] * kb[7] * INV_Q2);
        } else {
            u = make_uint4(0u, 0u, 0u, 0u);
        }
        *(uint4*)(smc + CS_KFT + d * 128 + c8 * 16) = u;
    }
    __syncthreads();

    // mma: warp w -> e-tile (w>>1), d-tiles (w&1)*18 .. +17
    int w = t >> 5, l = t & 31;
    float acc[18][4];
#pragma unroll
    for (int j = 0; j < 18; j++)
#pragma unroll
        for (int r = 0; r < 4; r++) acc[j][r] = 0.f;

    uint32_t Ab = smem_u32(smc + CS_VT);
    uint32_t Bb = smem_u32(smc + CS_KFT);
    int ar = (w >> 1) * 16 + (l & 15);
    int ac = l >> 4;
    int brow_base = (l & 7) + ((l >> 4) << 3);
    int bkh = (l >> 3) & 1;
    int ntile0 = (w & 1) * 18;

#pragma unroll
    for (int ks = 0; ks < 4; ks++) {
        uint32_t afr[4];
        int ch = ks * 2 + ac;
        ldsm_x4(afr, Ab + ar * 128 + ((ch ^ (ar & 7)) << 4));
        int chb = ks * 2 + bkh;
#pragma unroll
        for (int jp = 0; jp < 9; jp++) {
            uint32_t bp[4];
            int row = (ntile0 + jp * 2) * 8 + brow_base;
            ldsm_x4(bp, Bb + row * 128 + ((chb ^ (row & 7)) << 4));
            mma_any<true>(acc[jp * 2],     afr, bp);
            mma_any<true>(acc[jp * 2 + 1], afr, bp + 2);
        }
    }

    // store S^T e-major fp16
    int r0 = l >> 2, c0 = (l & 3) * 2;
    size_t Sbase = (size_t)blk * 64 * DFP;
    int e_lo = (w >> 1) * 16 + r0;
#pragma unroll
    for (int j = 0; j < 18; j++) {
        int d = (ntile0 + j) * 8 + c0;
        *(__half2*)&g_Sh[Sbase + (size_t)e_lo * DFP + d] =
            __floats2half2_rn(acc[j][0], acc[j][1]);
        *(__half2*)&g_Sh[Sbase + (size_t)(e_lo + 8) * DFP + d] =
            __floats2half2_rn(acc[j][2], acc[j][3]);
    }

    // ssum[d] = sum_m kf[m][d] from kf^T smem
    for (int d = t; d < DF; d += 256) {
        float s = 0.f;
#pragma unroll
        for (int c8 = 0; c8 < 8; c8++) {
            int off = d * 128 + (((c8 ^ (d & 7))) << 4);
            uint4 u = *(const uint4*)(smc + CS_KFT + off);
            const __half2* hp = (const __half2*)&u;
#pragma unroll
            for (int q = 0; q < 4; q++) {
                float2 f2 = __half22float2(hp[q]);
                s += f2.x + f2.y;
            }
        }
        g_ss[(long)blk * DF + d] = s;
    }
}

// ---------------------------------------------------------------------------
// In-place exclusive prefix scans over chunk index
// ---------------------------------------------------------------------------
__global__ void scan_S_kernel() {      // over half2 pairs, e-major layout
    long idx = (long)blockIdx.x * 256 + threadIdx.x;
    const long PER_BH = 64 * DFP / 2;  // 9216 half2 per chunk
    if (idx >= (long)NBH * PER_BH) return;
    long bh = idx / PER_BH;
    long de = idx % PER_BH;
    __half2* Sp = (__half2*)g_Sh;
    size_t base = (size_t)bh * NC * PER_BH + de;
    float2 acc = make_float2(0.f, 0.f);
#pragma unroll
    for (int c = 0; c < NC; c++) {
        size_t p = base + (size_t)c * PER_BH;
        float2 tmp = __half22float2(Sp[p]);
        Sp[p] = __floats2half2_rn(acc.x, acc.y);
        acc.x += tmp.x; acc.y += tmp.y;
    }
}

__global__ void scan_ss_kernel() {
    long idx = (long)blockIdx.x * 256 + threadIdx.x;
    if (idx >= (long)NBH * DF) return;
    long bh = idx / DF;
    long d = idx % DF;
    long base = bh * NC * DF + d;
    float acc = 0.f;
#pragma unroll
    for (int c = 0; c < NC; c++) {
        long p = base + (long)c * DF;
        float tmp = g_ss[p];
        g_ss[p] = acc;
        acc += tmp;
    }
}

// ---------------------------------------------------------------------------
// Output via one fused mma GEMM per (bh,chunk):
//   Aop = [phi(q) (64x288) | A_poly (64x64)]  (fp16, padded stride 360)
//   Bop rows (N=72): e<64: [S^T[e] | v^T[e]], row64: [0 | 1...], 65..71: 0
//   acc[n][e<64] = numerator;  col 64 = rowsum(A)
//   denominator = fp32 scalar qf.sp + rowsum(A); y = num * z  (fp16 hi/lo out)
// Warp n-split: group0 -> tiles 0..4 (rows 0..39), group1 -> tiles 5..8 (rows 40..71).
// ---------------------------------------------------------------------------
#define OTS 360                         // row stride in halves (45 x 16B, odd)
#define OT_QF 0                         // 64 x 720B  = 46080
#define OT_B  46080                     // 72 x 720B  = 51840
#define OT_Q  97920                     // 64x16 fp32 = 4096
#define OT_K  102016                    // 64x16 fp32 = 4096
#define OT_SP 106112                    // 276  fp32  = 1104
#define OT_DS 107216                    // 64 fp32 (+pad)
#define OT_RS 107472                    // 64 fp32 (+pad)
#define OT_Z  107728                    // 64 fp32 (+pad)
#define OT_SMEM 107984

__global__ void __launch_bounds__(256, 2) output_mma() {
    extern __shared__ char smo[];
    float* q_s  = (float*)(smo + OT_Q);
    float* k_s  = (float*)(smo + OT_K);
    float* sp_s = (float*)(smo + OT_SP);
    float* ds_s = (float*)(smo + OT_DS);
    float* rs_s = (float*)(smo + OT_RS);
    float* z_s  = (float*)(smo + OT_Z);
    __half* qf  = (__half*)(smo + OT_QF);
    __half* Bx  = (__half*)(smo + OT_B);

    int blk = blockIdx.x;
    int c = blk & (NC - 1);
    int bh = blk >> 5;
    int b = bh >> 4, h = bh & 15;
    int t = threadIdx.x;
    long tok0 = (long)b * LL + (long)c * CHUNK;

    // ---- phase 1: loads ----
    for (int i = t; i < 64 * 16; i += 256) {
        int n = i >> 4, f = i & 15;
        long off = (tok0 + n) * 512 + h * 16 + f;
        q_s[i] = g_qk[off];
        k_s[i] = g_qk[off + 256];
    }
    for (int i = t; i < 276; i += 256) sp_s[i] = (i < DF) ? g_ss[(long)blk * DF + i] : 0.f;
    {   // S^T rows (straight uint4 copy; DFP=288 halves = 36 uint4 per row)
        const uint4* src = (const uint4*)(g_Sh + (size_t)blk * 64 * DFP);
        for (int i = t; i < 64 * 36; i += 256) {
            int e = i / 36, u = i % 36;
            *(uint4*)(smo + OT_B + e * 720 + u * 16) = src[i];
        }
    }
    for (int i = t; i < 4096; i += 256) {   // v^T into cols 288..351
        int m = i >> 6, e = i & 63;
        Bx[e * OTS + 288 + m] = __float2half(g_v[(tok0 + m) * 1024 + h * 64 + e]);
    }
    for (int i = t; i < 8 * 180; i += 256) {    // rows 64..71
        int r = 64 + i / 180, u = i % 180;      // uint (2 halves)
        uint32_t val = (r == 64 && u >= 144 && u < 176) ? 0x3C003C00u : 0u;  // ones over v-cols
        *(uint32_t*)(smo + OT_B + r * 720 + u * 4) = val;
    }
    __syncthreads();

    // ---- phase 2: build A-operand + fp32 denominator part ----
    for (int i = t; i < 64 * 288; i += 256) {   // phi(q)
        int n = i / 288, d = i % 288;
        float val = 0.f;
        if (d == 0) val = 1.f;
        else if (d <= 16) val = q_s[n * 16 + d - 1] * INV_RRD;
        else if (d < DF) {
            int dd = d - 17;
            val = q_s[n * 16 + (dd >> 4)] * q_s[n * 16 + (dd & 15)] * INV_Q2;
        }
        qf[n * OTS + d] = __float2half(val);
    }
    {   // causal polynomial scores into cols 288..351 (thread -> (n, 16 m's))
        int n = t >> 2, mq = (t & 3) << 4;
        float qr[16];
#pragma unroll
        for (int f = 0; f < 16; f++) qr[f] = q_s[n * 16 + f];
#pragma unroll
        for (int mm = 0; mm < 16; mm += 2) {
            float a2[2];
#pragma unroll
            for (int u2 = 0; u2 < 2; u2++) {
                int m = mq + mm + u2;
                float s = 0.f;
#pragma unroll
                for (int f = 0; f < 16; f++) s += qr[f] * k_s[m * 16 + f];
                a2[u2] = (m <= n) ? (1.f + 0.25f * s + s * s * 0.03125f) : 0.f;
            }
            *(__half2*)&qf[n * OTS + 288 + mq + mm] = __floats2half2_rn(a2[0], a2[1]);
        }
        if (t < 64) {                    // fp32 qf . sp
            const float* q0 = &q_s[t * 16];
            float d1 = 0.f;
#pragma unroll
            for (int f = 0; f < 16; f++) d1 += q0[f] * sp_s[1 + f];
            float d2 = 0.f;
            for (int i2 = 0; i2 < 16; i2++) {
                float inner = 0.f;
#pragma unroll
                for (int j = 0; j < 16; j++) inner += q0[j] * sp_s[17 + 16 * i2 + j];
                d2 += q0[i2] * inner;
            }
            ds_s[t] = sp_s[0] + INV_RRD * d1 + INV_Q2 * d2;
        }
    }
    __syncthreads();

    // ---- phase 3: 64x72x352 fp16 GEMM (8 warps: 4 m-tiles x 2 n-groups) ----
    int w = t >> 5, l = t & 31;
    int m0w = (w >> 1) * 16;
    int nh5 = w & 1;
    int nr0 = nh5 * 40;
    float acc[5][4];
#pragma unroll
    for (int j = 0; j < 5; j++)
#pragma unroll
        for (int r = 0; r < 4; r++) acc[j][r] = 0.f;

    uint32_t Qb = smem_u32(smo + OT_QF);
    uint32_t Bb = smem_u32(smo + OT_B);
    uint32_t aad = Qb + (m0w + (l & 15)) * 720 + (l >> 4) * 16;
    uint32_t bpd = Bb + (nr0 + (l & 7) + ((l >> 4) << 3)) * 720 + ((l >> 3) & 1) * 16;
    uint32_t bsd = Bb + (nr0 + 32 + (l & 7)) * 720 + ((l >> 3) & 1) * 16;

    if (nh5 == 0) {
#pragma unroll
        for (int ks = 0; ks < 22; ks++) {
            uint32_t afr[4], bp0[4], bp1[4], bs[2];
            ldsm_x4(afr, aad + ks * 32);
            ldsm_x4(bp0, bpd + ks * 32);
            ldsm_x4(bp1, bpd + 16 * 720 + ks * 32);
            ldsm_x2(bs,  bsd + ks * 32);
            mma_any<true>(acc[0], afr, bp0);
            mma_any<true>(acc[1], afr, bp0 + 2);
            mma_any<true>(acc[2], afr, bp1);
            mma_any<true>(acc[3], afr, bp1 + 2);
            mma_any<true>(acc[4], afr, bs);
        }
    } else {
#pragma unroll
        for (int ks = 0; ks < 22; ks++) {
            uint32_t afr[4], bp0[4], bp1[4];
            ldsm_x4(afr, aad + ks * 32);
            ldsm_x4(bp0, bpd + ks * 32);
            ldsm_x4(bp1, bpd + 16 * 720 + ks * 32);
            mma_any<true>(acc[0], afr, bp0);
            mma_any<true>(acc[1], afr, bp0 + 2);
            mma_any<true>(acc[2], afr, bp1);
            mma_any<true>(acc[3], afr, bp1 + 2);
        }
    }

    // ---- phase 4: denominator + write ----
    int r0 = l >> 2, c0 = (l & 3) * 2;
    if (nh5 == 1 && (l & 3) == 0) {     // local tile 3 = global tile 8 -> col 64
        rs_s[m0w + r0] = acc[3][0];
        rs_s[m0w + r0 + 8] = acc[3][2];
    }
    __syncthreads();
    if (t < 64) z_s[t] = 1.f / (ds_s[t] + rs_s[t] + EPS);
    __syncthreads();

    float z0 = z_s[m0w + r0], z1 = z_s[m0w + r0 + 8];
    size_t rowb0 = (size_t)(tok0 + m0w + r0) * KVO + h * 64;
    size_t rowb1 = (size_t)(tok0 + m0w + r0 + 8) * KVO + h * 64;
    int jmax = nh5 ? 4 : 5;
#pragma unroll
    for (int j = 0; j < 5; j++) {
        if (j >= jmax) break;
        int col = (nh5 * 5 + j) * 8 + c0;
        if (col < 64) {
            float v00 = acc[j][0] * z0, v01 = acc[j][1] * z0;
            float v10 = acc[j][2] * z1, v11 = acc[j][3] * z1;
            __half hA = __float2half_rn(v00), hB = __float2half_rn(v01);
            __half hC = __float2half_rn(v10), hD = __float2half_rn(v11);
            *(__half2*)&g_yh[rowb0 + col] = __halves2half2(hA, hB);
            *(__half2*)&g_yh[rowb0 + col + 1024] =
                __halves2half2(__float2half_rn(v00 - __half2float(hA)),
                               __float2half_rn(v01 - __half2float(hB)));
            *(__half2*)&g_yh[rowb1 + col] = __halves2half2(hC, hD);
            *(__half2*)&g_yh[rowb1 + col + 1024] =
                __halves2half2(__float2half_rn(v10 - __half2float(hC)),
                               __float2half_rn(v11 - __half2float(hD)));
        }
    }
}

// ---------------------------------------------------------------------------
extern "C" void kernel_launch(void* const* d_in, const int* in_sizes, int n_in,
                              void* d_out, int out_size) {
    const float* x  = (const float*)d_in[0];
    const float* Wq = (const float*)d_in[1];
    const float* Wk = (const float*)d_in[2];
    const float* Wv = (const float*)d_in[3];
    const float* Wo = (const float*)d_in[4];
    float* out = (float*)d_out;

    void *px2, *pxh, *pwqk, *pwvh, *pwoh, *pqk, *pv, *pyh;
    cudaGetSymbolAddress(&px2, g_x2);
    cudaGetSymbolAddress(&pxh, g_xh);
    cudaGetSymbolAddress(&pwqk, g_wqk);
    cudaGetSymbolAddress(&pwvh, g_wvh);
    cudaGetSymbolAddress(&pwoh, g_woh);
    cudaGetSymbolAddress(&pqk, g_qk);
    cudaGetSymbolAddress(&pv, g_v);
    cudaGetSymbolAddress(&pyh, g_yh);

    cudaFuncSetAttribute(chunk_state_mma, cudaFuncAttributeMaxDynamicSharedMemorySize, CS_SMEM);
    cudaFuncSetAttribute(output_mma, cudaFuncAttributeMaxDynamicSharedMemorySize, OT_SMEM);
    cudaFuncSetAttribute(proj_gemm, cudaFuncAttributeMaxDynamicSharedMemorySize, GEMM_SMEM);
    cudaFuncSetAttribute(gemm_o, cudaFuncAttributeMaxDynamicSharedMemorySize, GEMM_SMEM);

    // split/convert inputs
    conv_x_kernel<<<4096, 256>>>(x);
    wsplit_all<<<dim3(80, 32), dim3(32, 8)>>>(Wq, Wk, Wv, Wo);

    // fused q/k + v projections on tensor cores
    proj_gemm<<<384, 256, GEMM_SMEM>>>((const uint16_t*)px2, (const uint16_t*)pwqk, (float*)pqk,
                                       (const uint16_t*)pxh, (const uint16_t*)pwvh, (float*)pv);

    // chunked linear attention
    chunk_state_mma<<<NBH * NC, 256, CS_SMEM>>>();
    scan_S_kernel<<<(NBH * (64 * DFP / 2) + 255) / 256, 256>>>();
    scan_ss_kernel<<<(NBH * DF + 255) / 256, 256>>>();
    output_mma<<<NBH * NC, 256, OT_SMEM>>>();

    // final projection
    gemm_o<<<dim3(8, 32), 256, GEMM_SMEM>>>((const uint16_t*)pyh, (const uint16_t*)pwoh, out);
}

// round 10
// speedup vs baseline: 4.8092x; 1.1494x over previous
#include <cuda_runtime.h>
#include <cuda_bf16.h>
#include <cuda_fp16.h>
#include <cstdint>

// Problem constants
#define BB 2
#define LL 2048
#define DM 1024
#define NH 16
#define FD 16
#define HD 64
#define DF 273          // 1 + 16 + 256
#define DFP 288         // DF padded to 18 n8-tiles for mma
#define CHUNK 64
#define NC 32           // LL / CHUNK
#define NBH 32          // BB * NH
#define INV_RRD 0.5f
#define INV_Q2 0.17677669529663687f   // 1/(4*sqrt(2))
#define EPS 1e-12f

#define KQK 3072        // bf16 3-term split for q/k projection
#define KVO 1024        // fp16 single-term for v/o projections

// ---------------------------------------------------------------------------
// Scratch (device globals; no allocation)
// ---------------------------------------------------------------------------
__device__ __nv_bfloat16 g_x2[4096 * KQK];      // x: [hi | lo | hi] bf16
__device__ __half        g_xh[4096 * KVO];      // x: hi fp16
__device__ __nv_bfloat16 g_wqk[512 * KQK];      // [Wq|Wk]^T: [hi | hi | lo] bf16
__device__ __half        g_wvh[1024 * KVO];     // Wv^T: hi fp16
__device__ __half        g_woh[1024 * KVO];     // Wo^T: hi fp16
__device__ float g_qk[4096 * 512];              // q (cols 0..255) | k (256..511)
__device__ float g_v[4096 * 1024];
__device__ __half g_yh[4096 * KVO];             // y: hi fp16
__device__ __half g_Sh[(size_t)NBH * NC * 64 * DFP];  // chunk states, e-major S^T (fp16)
__device__ float g_ss[NBH * NC * DF];

// ---------------------------------------------------------------------------
// PTX helpers (baseline sm_80-compatible: ldmatrix, mma.sync, cp.async)
// ---------------------------------------------------------------------------
__device__ __forceinline__ uint32_t smem_u32(const void* p) {
    uint32_t a;
    asm("{ .reg .u64 t; cvta.to.shared.u64 t, %1; cvt.u32.u64 %0, t; }" : "=r"(a) : "l"(p));
    return a;
}
__device__ __forceinline__ void ldsm_x4(uint32_t* r, uint32_t addr) {
    asm volatile("ldmatrix.sync.aligned.m8n8.x4.shared.b16 {%0,%1,%2,%3}, [%4];"
        : "=r"(r[0]), "=r"(r[1]), "=r"(r[2]), "=r"(r[3]) : "r"(addr));
}
__device__ __forceinline__ void ldsm_x2(uint32_t* r, uint32_t addr) {
    asm volatile("ldmatrix.sync.aligned.m8n8.x2.shared.b16 {%0,%1}, [%2];"
        : "=r"(r[0]), "=r"(r[1]) : "r"(addr));
}
template<bool F16>
__device__ __forceinline__ void mma_any(float* d, const uint32_t* a, const uint32_t* b) {
    if constexpr (F16) {
        asm volatile("mma.sync.aligned.m16n8k16.row.col.f32.f16.f16.f32 "
            "{%0,%1,%2,%3}, {%4,%5,%6,%7}, {%8,%9}, {%0,%1,%2,%3};"
            : "+f"(d[0]), "+f"(d[1]), "+f"(d[2]), "+f"(d[3])
            : "r"(a[0]), "r"(a[1]), "r"(a[2]), "r"(a[3]), "r"(b[0]), "r"(b[1]));
    } else {
        asm volatile("mma.sync.aligned.m16n8k16.row.col.f32.bf16.bf16.f32 "
            "{%0,%1,%2,%3}, {%4,%5,%6,%7}, {%8,%9}, {%0,%1,%2,%3};"
            : "+f"(d[0]), "+f"(d[1]), "+f"(d[2]), "+f"(d[3])
            : "r"(a[0]), "r"(a[1]), "r"(a[2]), "r"(a[3]), "r"(b[0]), "r"(b[1]));
    }
}
#define CP_ASYNC16(dst, src) \
    asm volatile("cp.async.cg.shared.global [%0], [%1], 16;" :: "r"(dst), "l"(src))
#define CP_COMMIT() asm volatile("cp.async.commit_group;" ::: "memory")
#define CP_WAIT(n)  asm volatile("cp.async.wait_group %0;" :: "n"(n) : "memory")

// ---------------------------------------------------------------------------
// Converters
// ---------------------------------------------------------------------------
union BF2U { __nv_bfloat162 b; uint32_t u; };
union HF2U { __half2 h; uint32_t u; };

__global__ void conv_x_kernel(const float* __restrict__ x) {
    int idx = blockIdx.x * 256 + threadIdx.x;          // 1M threads, 4 elems each
    int m = idx >> 8, k4 = (idx & 255) << 2;
    float4 v = *(const float4*)&x[(size_t)m * 1024 + k4];
    float f[4] = {v.x, v.y, v.z, v.w};
    uint32_t bh[2], bl[2], fh[2];
#pragma unroll
    for (int p = 0; p < 2; p++) {
        float a = f[2 * p], bq = f[2 * p + 1];
        __nv_bfloat16 h0 = __float2bfloat16(a), h1 = __float2bfloat16(bq);
        BF2U uh; uh.b = __halves2bfloat162(h0, h1); bh[p] = uh.u;
        BF2U ul; ul.b = __halves2bfloat162(
            __float2bfloat16(a - __bfloat162float(h0)),
            __float2bfloat16(bq - __bfloat162float(h1))); bl[p] = ul.u;
        HF2U vh; vh.h = __floats2half2_rn(a, bq); fh[p] = vh.u;
    }
    size_t b2 = (size_t)m * KQK + k4;
    *(uint2*)&g_x2[b2]        = make_uint2(bh[0], bh[1]);
    *(uint2*)&g_x2[b2 + 1024] = make_uint2(bl[0], bl[1]);
    *(uint2*)&g_x2[b2 + 2048] = make_uint2(bh[0], bh[1]);
    *(uint2*)&g_xh[(size_t)m * KVO + k4] = make_uint2(fh[0], fh[1]);
}

// All weight splits fused: blocks 0..7 Wq, 8..15 Wk (bf16 3-term),
// 16..47 Wv, 48..79 Wo (fp16 single-term).
__global__ void wsplit_all(const float* __restrict__ Wq, const float* __restrict__ Wk,
                           const float* __restrict__ Wv, const float* __restrict__ Wo) {
    __shared__ float tile[32][33];
    int bx = blockIdx.x, k0 = blockIdx.y * 32;
    const float* W;
    int Ncols, n0, mode, rowoff = 0;
    if (bx < 8)       { W = Wq; Ncols = 256;  n0 = bx * 32;        mode = 0; rowoff = 0;   }
    else if (bx < 16) { W = Wk; Ncols = 256;  n0 = (bx - 8) * 32;  mode = 0; rowoff = 256; }
    else if (bx < 48) { W = Wv; Ncols = 1024; n0 = (bx - 16) * 32; mode = 1; }
    else              { W = Wo; Ncols = 1024; n0 = (bx - 48) * 32; mode = 2; }
    int tx = threadIdx.x, ty = threadIdx.y;            // 32 x 8
    for (int i = ty; i < 32; i += 8)
        tile[i][tx] = W[(size_t)(k0 + i) * Ncols + n0 + tx];
    __syncthreads();
    for (int i = ty; i < 32; i += 8) {
        int n = n0 + i, k = k0 + tx;
        float v = tile[tx][i];
        if (mode == 0) {
            __nv_bfloat16 hi = __float2bfloat16(v);
            __nv_bfloat16 lo = __float2bfloat16(v - __bfloat162float(hi));
            size_t base = (size_t)(rowoff + n) * KQK + k;
            g_wqk[base] = hi;
            g_wqk[base + 1024] = hi;
            g_wqk[base + 2048] = lo;
        } else {
            __half* dst = (mode == 1) ? g_wvh : g_woh;
            dst[(size_t)n * KVO + k] = __float2half_rn(v);
        }
    }
}

// ---------------------------------------------------------------------------
// mma.sync GEMM body: C (M x N, fp32) tile (m0,n0) = A @ Bt^T
// 128x128 CTA tile, 8 warps (64x32 each), K-tile 64, 3-stage cp.async
// pipeline, paired-B ldmatrix.
// ---------------------------------------------------------------------------
#define SMA(b) ((b) * 32768)
#define SMB(b) ((b) * 32768 + 16384)
#define GEMM_SMEM 98304

__device__ __forceinline__ void gemm_load_tile(const uint16_t* A, const uint16_t* B,
                                               char* sm, int m0, int n0, int kb, int buf,
                                               int t, int K) {
#pragma unroll
    for (int i = 0; i < 8; i++) {
        int idx = t + i * 256;            // 0..2047
        int row = (idx & 1023) >> 3, c = idx & 7;
        uint32_t dst;
        const uint16_t* src;
        if (idx < 1024) {
            src = A + (size_t)(m0 + row) * K + kb * 64 + c * 8;
            dst = smem_u32(sm + SMA(buf) + row * 128 + ((c ^ (row & 7)) << 4));
        } else {
            src = B + (size_t)(n0 + row) * K + kb * 64 + c * 8;
            dst = smem_u32(sm + SMB(buf) + row * 128 + ((c ^ (row & 7)) << 4));
        }
        CP_ASYNC16(dst, src);
    }
}

template<bool F16>
__device__ __forceinline__ void gemm_body(const uint16_t* __restrict__ A,
                                          const uint16_t* __restrict__ B,
                                          float* __restrict__ C,
                                          int N, int K, int nkt,
                                          int m0, int n0, char* sm, int t) {
    int w = t >> 5, l = t & 31;
    int wm = (w >> 2) * 64, wn = (w & 3) * 32;

    float acc[4][4][4];
#pragma unroll
    for (int i = 0; i < 4; i++)
#pragma unroll
        for (int j = 0; j < 4; j++)
#pragma unroll
            for (int r = 0; r < 4; r++) acc[i][j][r] = 0.f;

    int ar = wm + (l & 15);
    int ac = (l >> 4);
    int brow = wn + (l & 7) + ((l >> 4) << 3);   // base row for paired-B ldsm
    int bkh = (l >> 3) & 1;

    gemm_load_tile(A, B, sm, m0, n0, 0, 0, t, K);
    CP_COMMIT();
    gemm_load_tile(A, B, sm, m0, n0, 1, 1, t, K);
    CP_COMMIT();

    int buf = 0;
    for (int kt = 0; kt < nkt; kt++) {
        if (kt + 2 < nkt) {
            int lb = buf + 2; if (lb >= 3) lb -= 3;
            gemm_load_tile(A, B, sm, m0, n0, kt + 2, lb, t, K);
        }
        CP_COMMIT();
        CP_WAIT(2);
        __syncthreads();

        uint32_t Ab = smem_u32(sm + SMA(buf));
        uint32_t Bb = smem_u32(sm + SMB(buf));
#pragma unroll
        for (int ks = 0; ks < 4; ks++) {
            uint32_t afr[4][4], bfr[4][2];
#pragma unroll
            for (int mi = 0; mi < 4; mi++) {
                int row = ar + mi * 16;
                int ch = ks * 2 + ac;
                ldsm_x4(afr[mi], Ab + row * 128 + ((ch ^ (row & 7)) << 4));
            }
#pragma unroll
            for (int p = 0; p < 2; p++) {
                uint32_t bp[4];
                int row = brow + p * 16;
                int ch = ks * 2 + bkh;
                ldsm_x4(bp, Bb + row * 128 + ((ch ^ (row & 7)) << 4));
                bfr[2 * p][0] = bp[0]; bfr[2 * p][1] = bp[1];
                bfr[2 * p + 1][0] = bp[2]; bfr[2 * p + 1][1] = bp[3];
            }
#pragma unroll
            for (int mi = 0; mi < 4; mi++)
#pragma unroll
                for (int ni = 0; ni < 4; ni++)
                    mma_any<F16>(acc[mi][ni], afr[mi], bfr[ni]);
        }
        __syncthreads();
        if (++buf == 3) buf = 0;
    }

    int r0 = l >> 2, c0 = (l & 3) * 2;
#pragma unroll
    for (int mi = 0; mi < 4; mi++) {
#pragma unroll
        for (int ni = 0; ni < 4; ni++) {
            int row = m0 + wm + mi * 16 + r0;
            int col = n0 + wn + ni * 8 + c0;
            *(float2*)(C + (size_t)row * N + col) = make_float2(acc[mi][ni][0], acc[mi][ni][1]);
            *(float2*)(C + (size_t)(row + 8) * N + col) = make_float2(acc[mi][ni][2], acc[mi][ni][3]);
        }
    }
}

// Fused q/k + v projections: CTAs 0..127 -> qk (bf16, K=3072, N=512),
// CTAs 128..383 -> v (fp16, K=1024, N=1024).
__global__ void __launch_bounds__(256, 2)
proj_gemm(const uint16_t* __restrict__ x2, const uint16_t* __restrict__ wqk,
          float* __restrict__ qk,
          const uint16_t* __restrict__ xh, const uint16_t* __restrict__ wvh,
          float* __restrict__ v) {
    extern __shared__ char sm[];
    int blk = blockIdx.x;
    int t = threadIdx.x;
    if (blk < 128) {
        gemm_body<false>(x2, wqk, qk, 512, KQK, KQK / 64,
                         (blk >> 2) * 128, (blk & 3) * 128, sm, t);
    } else {
        int b2 = blk - 128;
        gemm_body<true>(xh, wvh, v, 1024, KVO, KVO / 64,
                        (b2 >> 3) * 128, (b2 & 7) * 128, sm, t);
    }
}

// Standalone o-projection GEMM.
__global__ void __launch_bounds__(256, 2)
gemm_o(const uint16_t* __restrict__ A, const uint16_t* __restrict__ B,
       float* __restrict__ C) {
    extern __shared__ char sm[];
    gemm_body<true>(A, B, C, 1024, KVO, KVO / 64,
                    blockIdx.y * 128, blockIdx.x * 128, sm, threadIdx.x);
}

// ---------------------------------------------------------------------------
// Per-chunk local state via mma.sync:
// S^T[e][d] = sum_m v[m][e] * phi(k[m])[d]  -> A = v^T (64 x 64), B = kf^T (DFP x 64)
// Vectorized operand builds; mma in two 9-tile passes (fewer regs, 3 CTAs/SM).
// ---------------------------------------------------------------------------
#define CS_KFT 0                       // kf^T fp16: 288 rows x 128B = 36864
#define CS_VT  36864                   // v^T  fp16: 64 rows x 128B  = 8192
#define CS_KT  45056                   // k^T fp32 [16][65] = 4160
#define CS_VS  49216                   // v^T fp32 [64][65] = 16640
#define CS_SMEM 65856

__global__ void __launch_bounds__(256, 3) chunk_state_mma() {
    extern __shared__ char smc[];
    float* k_T = (float*)(smc + CS_KT);
    float* v_S = (float*)(smc + CS_VS);

    int blk = blockIdx.x;
    int c = blk & (NC - 1);
    int bh = blk >> 5;
    int b = bh >> 4, h = bh & 15;
    int t = threadIdx.x;
    long tok0 = (long)b * LL + (long)c * CHUNK;

    // stage k transposed [f][n] (pad 65) and v transposed [e][m] (pad 65)
    for (int i = t; i < 64 * 16; i += 256) {
        int n = i >> 4, f = i & 15;
        k_T[f * 65 + n] = g_qk[(tok0 + n) * 512 + 256 + h * 16 + f];
    }
    for (int i = t; i < 4096; i += 256) {
        int m = i >> 6, e = i & 63;
        v_S[e * 65 + m] = g_v[(tok0 + m) * 1024 + h * 64 + e];
    }
    __syncthreads();

    // v^T fp16 swizzled: one uint4 per (e, chunk)
    for (int i = t; i < 512; i += 256) {
        int e = i >> 3, c8 = i & 7;
        int mg = c8 ^ (e & 7);
        const float* vr = &v_S[e * 65 + mg * 8];
        uint4 u;
        __half2* hp = (__half2*)&u;
        hp[0] = __floats2half2_rn(vr[0], vr[1]);
        hp[1] = __floats2half2_rn(vr[2], vr[3]);
        hp[2] = __floats2half2_rn(vr[4], vr[5]);
        hp[3] = __floats2half2_rn(vr[6], vr[7]);
        *(uint4*)(smc + CS_VT + e * 128 + c8 * 16) = u;
    }

    // kf^T fp16 swizzled: one uint4 per (d, chunk)
    for (int i = t; i < DFP * 8; i += 256) {
        int d = i >> 3, c8 = i & 7;
        int mg = c8 ^ (d & 7);
        int m0 = mg * 8;
        uint4 u;
        __half2* hp = (__half2*)&u;
        if (d == 0) {
            __half2 one2 = __floats2half2_rn(1.f, 1.f);
            hp[0] = one2; hp[1] = one2; hp[2] = one2; hp[3] = one2;
        } else if (d <= 16) {
            const float* kr = &k_T[(d - 1) * 65 + m0];
            hp[0] = __floats2half2_rn(kr[0] * INV_RRD, kr[1] * INV_RRD);
            hp[1] = __floats2half2_rn(kr[2] * INV_RRD, kr[3] * INV_RRD);
            hp[2] = __floats2half2_rn(kr[4] * INV_RRD, kr[5] * INV_RRD);
            hp[3] = __floats2half2_rn(kr[6] * INV_RRD, kr[7] * INV_RRD);
        } else if (d < DF) {
            int dd = d - 17;
            const float* ka = &k_T[(dd >> 4) * 65 + m0];
            const float* kb = &k_T[(dd & 15) * 65 + m0];
            hp[0] = __floats2half2_rn(ka[0] * kb[0] * INV_Q2, ka[1] * kb[1] * INV_Q2);
            hp[1] = __floats2half2_rn(ka[2] * kb[2] * INV_Q2, ka[3] * kb[3] * INV_Q2);
            hp[2] = __floats2half2_rn(ka[4] * kb[4] * INV_Q2, ka[5] * kb[5] * INV_Q2);
            hp[3] = __floats2half2_rn(ka[6] * kb[6] * INV_Q2, ka[7] * kb[7] * INV_Q2);
        } else {
            u = make_uint4(0u, 0u, 0u, 0u);
        }
        *(uint4*)(smc + CS_KFT + d * 128 + c8 * 16) = u;
    }
    __syncthreads();

    // mma: warp w -> e-tile (w>>1); d-tiles (w&1)*18 .. +17 in two 9-tile passes
    int w = t >> 5, l = t & 31;
    uint32_t Ab = smem_u32(smc + CS_VT);
    uint32_t Bb = smem_u32(smc + CS_KFT);
    int ar = (w >> 1) * 16 + (l & 15);
    int ac = l >> 4;
    int brow_base = (l & 7) + ((l >> 4) << 3);
    int bkh = (l >> 3) & 1;
    int ntile0 = (w & 1) * 18;
    int r0 = l >> 2, c0 = (l & 3) * 2;
    size_t Sbase = (size_t)blk * 64 * DFP;
    int e_lo = (w >> 1) * 16 + r0;

#pragma unroll
    for (int half = 0; half < 2; half++) {
        int tb = ntile0 + half * 9;
        float acc[9][4];
#pragma unroll
        for (int j = 0; j < 9; j++)
#pragma unroll
            for (int r = 0; r < 4; r++) acc[j][r] = 0.f;

#pragma unroll
        for (int ks = 0; ks < 4; ks++) {
            uint32_t afr[4];
            int ch = ks * 2 + ac;
            ldsm_x4(afr, Ab + ar * 128 + ((ch ^ (ar & 7)) << 4));
            int chb = ks * 2 + bkh;
#pragma unroll
            for (int jp = 0; jp < 4; jp++) {
                uint32_t bp[4];
                int row = (tb + jp * 2) * 8 + brow_base;
                ldsm_x4(bp, Bb + row * 128 + ((chb ^ (row & 7)) << 4));
                mma_any<true>(acc[jp * 2],     afr, bp);
                mma_any<true>(acc[jp * 2 + 1], afr, bp + 2);
            }
            {   // last single tile
                uint32_t bs[2];
                int row = (tb + 8) * 8 + (l & 7);
                int chs = ks * 2 + ((l >> 3) & 1);
                ldsm_x2(bs, Bb + row * 128 + ((chs ^ (row & 7)) << 4));
                mma_any<true>(acc[8], afr, bs);
            }
        }

        // store this half's 9 d-tiles, e-major fp16
#pragma unroll
        for (int j = 0; j < 9; j++) {
            int d = (tb + j) * 8 + c0;
            *(__half2*)&g_Sh[Sbase + (size_t)e_lo * DFP + d] =
                __floats2half2_rn(acc[j][0], acc[j][1]);
            *(__half2*)&g_Sh[Sbase + (size_t)(e_lo + 8) * DFP + d] =
                __floats2half2_rn(acc[j][2], acc[j][3]);
        }
    }

    // ssum[d] = sum_m kf[m][d] from kf^T smem
    for (int d = t; d < DF; d += 256) {
        float s = 0.f;
#pragma unroll
        for (int c8 = 0; c8 < 8; c8++) {
            int off = d * 128 + (((c8 ^ (d & 7))) << 4);
            uint4 u = *(const uint4*)(smc + CS_KFT + off);
            const __half2* hp = (const __half2*)&u;
#pragma unroll
            for (int q = 0; q < 4; q++) {
                float2 f2 = __half22float2(hp[q]);
                s += f2.x + f2.y;
            }
        }
        g_ss[(long)blk * DF + d] = s;
    }
}

// ---------------------------------------------------------------------------
// In-place exclusive prefix scans over chunk index
// ---------------------------------------------------------------------------
__global__ void scan_S_kernel() {      // over half2 pairs, e-major layout
    long idx = (long)blockIdx.x * 256 + threadIdx.x;
    const long PER_BH = 64 * DFP / 2;  // 9216 half2 per chunk
    if (idx >= (long)NBH * PER_BH) return;
    long bh = idx / PER_BH;
    long de = idx % PER_BH;
    __half2* Sp = (__half2*)g_Sh;
    size_t base = (size_t)bh * NC * PER_BH + de;
    float2 acc = make_float2(0.f, 0.f);
#pragma unroll
    for (int c = 0; c < NC; c++) {
        size_t p = base + (size_t)c * PER_BH;
        float2 tmp = __half22float2(Sp[p]);
        Sp[p] = __floats2half2_rn(acc.x, acc.y);
        acc.x += tmp.x; acc.y += tmp.y;
    }
}

__global__ void scan_ss_kernel() {
    long idx = (long)blockIdx.x * 256 + threadIdx.x;
    if (idx >= (long)NBH * DF) return;
    long bh = idx / DF;
    long d = idx % DF;
    long base = bh * NC * DF + d;
    float acc = 0.f;
#pragma unroll
    for (int c = 0; c < NC; c++) {
        long p = base + (long)c * DF;
        float tmp = g_ss[p];
        g_ss[p] = acc;
        acc += tmp;
    }
}

// ---------------------------------------------------------------------------
// Output via one fused mma GEMM per (bh,chunk):
//   Aop = [phi(q) (64x288) | A_poly (64x64)]  (fp16, padded stride 360)
//   Bop rows (N=72): e<64: [S^T[e] | v^T[e]], row64: [0 | 1...], 65..71: 0
//   acc[n][e<64] = numerator;  col 64 = rowsum(A)
//   denominator = fp32 scalar qf.sp + rowsum(A); y = num * z  (fp16 hi out)
// Warp n-split: group0 -> tiles 0..4, group1 -> tiles 5..8 (incl. rowsum).
// ---------------------------------------------------------------------------
#define OTS 360                         // row stride in halves (45 x 16B, odd)
#define OT_QF 0                         // 64 x 720B  = 46080
#define OT_B  46080                     // 72 x 720B  = 51840
#define OT_Q  97920                     // 64x16 fp32 = 4096
#define OT_K  102016                    // 64x16 fp32 = 4096
#define OT_SP 106112                    // 276  fp32  = 1104
#define OT_DS 107216                    // 64 fp32 (+pad)
#define OT_RS 107472                    // 64 fp32 (+pad)
#define OT_Z  107728                    // 64 fp32 (+pad)
#define OT_SMEM 107984

__global__ void __launch_bounds__(256, 2) output_mma() {
    extern __shared__ char smo[];
    float* q_s  = (float*)(smo + OT_Q);
    float* k_s  = (float*)(smo + OT_K);
    float* sp_s = (float*)(smo + OT_SP);
    float* ds_s = (float*)(smo + OT_DS);
    float* rs_s = (float*)(smo + OT_RS);
    float* z_s  = (float*)(smo + OT_Z);
    __half* qf  = (__half*)(smo + OT_QF);
    __half* Bx  = (__half*)(smo + OT_B);

    int blk = blockIdx.x;
    int c = blk & (NC - 1);
    int bh = blk >> 5;
    int b = bh >> 4, h = bh & 15;
    int t = threadIdx.x;
    long tok0 = (long)b * LL + (long)c * CHUNK;

    // ---- phase 1: loads ----
    for (int i = t; i < 64 * 16; i += 256) {
        int n = i >> 4, f = i & 15;
        long off = (tok0 + n) * 512 + h * 16 + f;
        q_s[i] = g_qk[off];
        k_s[i] = g_qk[off + 256];
    }
    for (int i = t; i < 276; i += 256) sp_s[i] = (i < DF) ? g_ss[(long)blk * DF + i] : 0.f;
    {   // S^T rows (straight uint4 copy; DFP=288 halves = 36 uint4 per row)
        const uint4* src = (const uint4*)(g_Sh + (size_t)blk * 64 * DFP);
        for (int i = t; i < 64 * 36; i += 256) {
            int e = i / 36, u = i % 36;
            *(uint4*)(smo + OT_B + e * 720 + u * 16) = src[i];
        }
    }
    for (int i = t; i < 4096; i += 256) {   // v^T into cols 288..351
        int m = i >> 6, e = i & 63;
        Bx[e * OTS + 288 + m] = __float2half(g_v[(tok0 + m) * 1024 + h * 64 + e]);
    }
    for (int i = t; i < 8 * 180; i += 256) {    // rows 64..71
        int r = 64 + i / 180, u = i % 180;      // uint (2 halves)
        uint32_t val = (r == 64 && u >= 144 && u < 176) ? 0x3C003C00u : 0u;  // ones over v-cols
        *(uint32_t*)(smo + OT_B + r * 720 + u * 4) = val;
    }
    __syncthreads();

    // ---- phase 2: build A-operand + fp32 denominator part ----
    for (int i = t; i < 64 * 288; i += 256) {   // phi(q)
        int n = i / 288, d = i % 288;
        float val = 0.f;
        if (d == 0) val = 1.f;
        else if (d <= 16) val = q_s[n * 16 + d - 1] * INV_RRD;
        else if (d < DF) {
            int dd = d - 17;
            val = q_s[n * 16 + (dd >> 4)] * q_s[n * 16 + (dd & 15)] * INV_Q2;
        }
        qf[n * OTS + d] = __float2half(val);
    }
    {   // causal polynomial scores into cols 288..351 (thread -> (n, 16 m's))
        int n = t >> 2, mq = (t & 3) << 4;
        float qr[16];
#pragma unroll
        for (int f = 0; f < 16; f++) qr[f] = q_s[n * 16 + f];
#pragma unroll
        for (int mm = 0; mm < 16; mm += 2) {
            float a2[2];
#pragma unroll
            for (int u2 = 0; u2 < 2; u2++) {
                int m = mq + mm + u2;
                float s = 0.f;
#pragma unroll
                for (int f = 0; f < 16; f++) s += qr[f] * k_s[m * 16 + f];
                a2[u2] = (m <= n) ? (1.f + 0.25f * s + s * s * 0.03125f) : 0.f;
            }
            *(__half2*)&qf[n * OTS + 288 + mq + mm] = __floats2half2_rn(a2[0], a2[1]);
        }
        if (t < 64) {                    // fp32 qf . sp
            const float* q0 = &q_s[t * 16];
            float d1 = 0.f;
#pragma unroll
            for (int f = 0; f < 16; f++) d1 += q0[f] * sp_s[1 + f];
            float d2 = 0.f;
            for (int i2 = 0; i2 < 16; i2++) {
                float inner = 0.f;
#pragma unroll
                for (int j = 0; j < 16; j++) inner += q0[j] * sp_s[17 + 16 * i2 + j];
                d2 += q0[i2] * inner;
            }
            ds_s[t] = sp_s[0] + INV_RRD * d1 + INV_Q2 * d2;
        }
    }
    __syncthreads();

    // ---- phase 3: 64x72x352 fp16 GEMM (8 warps: 4 m-tiles x 2 n-groups) ----
    int w = t >> 5, l = t & 31;
    int m0w = (w >> 1) * 16;
    int nh5 = w & 1;
    int nr0 = nh5 * 40;
    float acc[5][4];
#pragma unroll
    for (int j = 0; j < 5; j++)
#pragma unroll
        for (int r = 0; r < 4; r++) acc[j][r] = 0.f;

    uint32_t Qb = smem_u32(smo + OT_QF);
    uint32_t Bb = smem_u32(smo + OT_B);
    uint32_t aad = Qb + (m0w + (l & 15)) * 720 + (l >> 4) * 16;
    uint32_t bpd = Bb + (nr0 + (l & 7) + ((l >> 4) << 3)) * 720 + ((l >> 3) & 1) * 16;
    uint32_t bsd = Bb + (nr0 + 32 + (l & 7)) * 720 + ((l >> 3) & 1) * 16;

    if (nh5 == 0) {
#pragma unroll
        for (int ks = 0; ks < 22; ks++) {
            uint32_t afr[4], bp0[4], bp1[4], bs[2];
            ldsm_x4(afr, aad + ks * 32);
            ldsm_x4(bp0, bpd + ks * 32);
            ldsm_x4(bp1, bpd + 16 * 720 + ks * 32);
            ldsm_x2(bs,  bsd + ks * 32);
            mma_any<true>(acc[0], afr, bp0);
            mma_any<true>(acc[1], afr, bp0 + 2);
            mma_any<true>(acc[2], afr, bp1);
            mma_any<true>(acc[3], afr, bp1 + 2);
            mma_any<true>(acc[4], afr, bs);
        }
    } else {
#pragma unroll
        for (int ks = 0; ks < 22; ks++) {
            uint32_t afr[4], bp0[4], bp1[4];
            ldsm_x4(afr, aad + ks * 32);
            ldsm_x4(bp0, bpd + ks * 32);
            ldsm_x4(bp1, bpd + 16 * 720 + ks * 32);
            mma_any<true>(acc[0], afr, bp0);
            mma_any<true>(acc[1], afr, bp0 + 2);
            mma_any<true>(acc[2], afr, bp1);
            mma_any<true>(acc[3], afr, bp1 + 2);
        }
    }

    // ---- phase 4: denominator + write ----
    int r0 = l >> 2, c0 = (l & 3) * 2;
    if (nh5 == 1 && (l & 3) == 0) {     // local tile 3 = global tile 8 -> col 64
        rs_s[m0w + r0] = acc[3][0];
        rs_s[m0w + r0 + 8] = acc[3][2];
    }
    __syncthreads();
    if (t < 64) z_s[t] = 1.f / (ds_s[t] + rs_s[t] + EPS);
    __syncthreads();

    float z0 = z_s[m0w + r0], z1 = z_s[m0w + r0 + 8];
    size_t rowb0 = (size_t)(tok0 + m0w + r0) * KVO + h * 64;
    size_t rowb1 = (size_t)(tok0 + m0w + r0 + 8) * KVO + h * 64;
    int jmax = nh5 ? 4 : 5;
#pragma unroll
    for (int j = 0; j < 5; j++) {
        if (j >= jmax) break;
        int col = (nh5 * 5 + j) * 8 + c0;
        if (col < 64) {
            *(__half2*)&g_yh[rowb0 + col] =
                __floats2half2_rn(acc[j][0] * z0, acc[j][1] * z0);
            *(__half2*)&g_yh[rowb1 + col] =
                __floats2half2_rn(acc[j][2] * z1, acc[j][3] * z1);
        }
    }
}

// ---------------------------------------------------------------------------
extern "C" void kernel_launch(void* const* d_in, const int* in_sizes, int n_in,
                              void* d_out, int out_size) {
    const float* x  = (const float*)d_in[0];
    const float* Wq = (const float*)d_in[1];
    const float* Wk = (const float*)d_in[2];
    const float* Wv = (const float*)d_in[3];
    const float* Wo = (const float*)d_in[4];
    float* out = (float*)d_out;

    void *px2, *pxh, *pwqk, *pwvh, *pwoh, *pqk, *pv, *pyh;
    cudaGetSymbolAddress(&px2, g_x2);
    cudaGetSymbolAddress(&pxh, g_xh);
    cudaGetSymbolAddress(&pwqk, g_wqk);
    cudaGetSymbolAddress(&pwvh, g_wvh);
    cudaGetSymbolAddress(&pwoh, g_woh);
    cudaGetSymbolAddress(&pqk, g_qk);
    cudaGetSymbolAddress(&pv, g_v);
    cudaGetSymbolAddress(&pyh, g_yh);

    cudaFuncSetAttribute(chunk_state_mma, cudaFuncAttributeMaxDynamicSharedMemorySize, CS_SMEM);
    cudaFuncSetAttribute(output_mma, cudaFuncAttributeMaxDynamicSharedMemorySize, OT_SMEM);
    cudaFuncSetAttribute(proj_gemm, cudaFuncAttributeMaxDynamicSharedMemorySize, GEMM_SMEM);
    cudaFuncSetAttribute(gemm_o, cudaFuncAttributeMaxDynamicSharedMemorySize, GEMM_SMEM);

    // split/convert inputs
    conv_x_kernel<<<4096, 256>>>(x);
    wsplit_all<<<dim3(80, 32), dim3(32, 8)>>>(Wq, Wk, Wv, Wo);

    // fused q/k + v projections on tensor cores
    proj_gemm<<<384, 256, GEMM_SMEM>>>((const uint16_t*)px2, (const uint16_t*)pwqk, (float*)pqk,
                                       (const uint16_t*)pxh, (const uint16_t*)pwvh, (float*)pv);

    // chunked linear attention
    chunk_state_mma<<<NBH * NC, 256, CS_SMEM>>>();
    scan_S_kernel<<<(NBH * (64 * DFP / 2) + 255) / 256, 256>>>();
    scan_ss_kernel<<<(NBH * DF + 255) / 256, 256>>>();
    output_mma<<<NBH * NC, 256, OT_SMEM>>>();

    // final projection
    gemm_o<<<dim3(8, 32), 256, GEMM_SMEM>>>((const uint16_t*)pyh, (const uint16_t*)pwoh, out);
}

// round 11
// speedup vs baseline: 5.0336x; 1.0467x over previous
#include <cuda_runtime.h>
#include <cuda_bf16.h>
#include <cuda_fp16.h>
#include <cstdint>

// Problem constants
#define BB 2
#define LL 2048
#define DM 1024
#define NH 16
#define FD 16
#define HD 64
#define DF 273          // 1 + 16 + 256
#define DFP 288         // DF padded to 18 n8-tiles for mma
#define CHUNK 64
#define NC 32           // LL / CHUNK
#define NBH 32          // BB * NH
#define INV_RRD 0.5f
#define INV_Q2 0.17677669529663687f   // 1/(4*sqrt(2))
#define EPS 1e-12f

#define KQK 3072        // bf16 3-term split for q/k projection
#define KVO 1024        // fp16 single-term for v/o projections

// ---------------------------------------------------------------------------
// Scratch (device globals; no allocation)
// ---------------------------------------------------------------------------
__device__ __nv_bfloat16 g_x2[4096 * KQK];      // x: [hi | lo | hi] bf16
__device__ __half        g_xh[4096 * KVO];      // x: hi fp16
__device__ __nv_bfloat16 g_wqk[512 * KQK];      // [Wq|Wk]^T: [hi | hi | lo] bf16
__device__ __half        g_wvh[1024 * KVO];     // Wv^T: hi fp16
__device__ __half        g_woh[1024 * KVO];     // Wo^T: hi fp16
__device__ float g_qk[4096 * 512];              // q (cols 0..255) | k (256..511)
__device__ __half g_vh[4096 * 1024];            // v fp16
__device__ __half g_yh[4096 * KVO];             // y: hi fp16
__device__ __half g_Sh[(size_t)NBH * NC * 64 * DFP];  // chunk states, e-major S^T (fp16)
__device__ float g_ss[NBH * NC * DF];

// ---------------------------------------------------------------------------
// PTX helpers (baseline sm_80-compatible: ldmatrix, mma.sync, cp.async)
// ---------------------------------------------------------------------------
__device__ __forceinline__ uint32_t smem_u32(const void* p) {
    uint32_t a;
    asm("{ .reg .u64 t; cvta.to.shared.u64 t, %1; cvt.u32.u64 %0, t; }" : "=r"(a) : "l"(p));
    return a;
}
__device__ __forceinline__ void ldsm_x4(uint32_t* r, uint32_t addr) {
    asm volatile("ldmatrix.sync.aligned.m8n8.x4.shared.b16 {%0,%1,%2,%3}, [%4];"
        : "=r"(r[0]), "=r"(r[1]), "=r"(r[2]), "=r"(r[3]) : "r"(addr));
}
__device__ __forceinline__ void ldsm_x2(uint32_t* r, uint32_t addr) {
    asm volatile("ldmatrix.sync.aligned.m8n8.x2.shared.b16 {%0,%1}, [%2];"
        : "=r"(r[0]), "=r"(r[1]) : "r"(addr));
}
template<bool F16>
__device__ __forceinline__ void mma_any(float* d, const uint32_t* a, const uint32_t* b) {
    if constexpr (F16) {
        asm volatile("mma.sync.aligned.m16n8k16.row.col.f32.f16.f16.f32 "
            "{%0,%1,%2,%3}, {%4,%5,%6,%7}, {%8,%9}, {%0,%1,%2,%3};"
            : "+f"(d[0]), "+f"(d[1]), "+f"(d[2]), "+f"(d[3])
            : "r"(a[0]), "r"(a[1]), "r"(a[2]), "r"(a[3]), "r"(b[0]), "r"(b[1]));
    } else {
        asm volatile("mma.sync.aligned.m16n8k16.row.col.f32.bf16.bf16.f32 "
            "{%0,%1,%2,%3}, {%4,%5,%6,%7}, {%8,%9}, {%0,%1,%2,%3};"
            : "+f"(d[0]), "+f"(d[1]), "+f"(d[2]), "+f"(d[3])
            : "r"(a[0]), "r"(a[1]), "r"(a[2]), "r"(a[3]), "r"(b[0]), "r"(b[1]));
    }
}
#define CP_ASYNC16(dst, src) \
    asm volatile("cp.async.cg.shared.global [%0], [%1], 16;" :: "r"(dst), "l"(src))
#define CP_COMMIT() asm volatile("cp.async.commit_group;" ::: "memory")
#define CP_WAIT(n)  asm volatile("cp.async.wait_group %0;" :: "n"(n) : "memory")

// ---------------------------------------------------------------------------
// Fused prep: blocks 0..4095 convert x; blocks 4096.. split weights.
// ---------------------------------------------------------------------------
union BF2U { __nv_bfloat162 b; uint32_t u; };
union HF2U { __half2 h; uint32_t u; };

__global__ void prep_kernel(const float* __restrict__ x,
                            const float* __restrict__ Wq, const float* __restrict__ Wk,
                            const float* __restrict__ Wv, const float* __restrict__ Wo) {
    __shared__ float tile[32][33];
    int blk = blockIdx.x;
    if (blk < 4096) {
        int idx = blk * 256 + threadIdx.x;
        int m = idx >> 8, k4 = (idx & 255) << 2;
        float4 v = *(const float4*)&x[(size_t)m * 1024 + k4];
        float f[4] = {v.x, v.y, v.z, v.w};
        uint32_t bh[2], bl[2], fh[2];
#pragma unroll
        for (int p = 0; p < 2; p++) {
            float a = f[2 * p], bq = f[2 * p + 1];
            __nv_bfloat16 h0 = __float2bfloat16(a), h1 = __float2bfloat16(bq);
            BF2U uh; uh.b = __halves2bfloat162(h0, h1); bh[p] = uh.u;
            BF2U ul; ul.b = __halves2bfloat162(
                __float2bfloat16(a - __bfloat162float(h0)),
                __float2bfloat16(bq - __bfloat162float(h1))); bl[p] = ul.u;
            HF2U vh; vh.h = __floats2half2_rn(a, bq); fh[p] = vh.u;
        }
        size_t b2 = (size_t)m * KQK + k4;
        *(uint2*)&g_x2[b2]        = make_uint2(bh[0], bh[1]);
        *(uint2*)&g_x2[b2 + 1024] = make_uint2(bl[0], bl[1]);
        *(uint2*)&g_x2[b2 + 2048] = make_uint2(bh[0], bh[1]);
        *(uint2*)&g_xh[(size_t)m * KVO + k4] = make_uint2(fh[0], fh[1]);
        return;
    }
    // weight split part: 80 x 32 virtual grid
    int b2i = blk - 4096;
    int bx = b2i % 80, k0 = (b2i / 80) * 32;
    const float* W;
    int Ncols, n0, mode, rowoff = 0;
    if (bx < 8)       { W = Wq; Ncols = 256;  n0 = bx * 32;        mode = 0; rowoff = 0;   }
    else if (bx < 16) { W = Wk; Ncols = 256;  n0 = (bx - 8) * 32;  mode = 0; rowoff = 256; }
    else if (bx < 48) { W = Wv; Ncols = 1024; n0 = (bx - 16) * 32; mode = 1; }
    else              { W = Wo; Ncols = 1024; n0 = (bx - 48) * 32; mode = 2; }
    int tx = threadIdx.x & 31, ty = threadIdx.x >> 5;  // 32 x 8
    for (int i = ty; i < 32; i += 8)
        tile[i][tx] = W[(size_t)(k0 + i) * Ncols + n0 + tx];
    __syncthreads();
    for (int i = ty; i < 32; i += 8) {
        int n = n0 + i, k = k0 + tx;
        float v = tile[tx][i];
        if (mode == 0) {
            __nv_bfloat16 hi = __float2bfloat16(v);
            __nv_bfloat16 lo = __float2bfloat16(v - __bfloat162float(hi));
            size_t base = (size_t)(rowoff + n) * KQK + k;
            g_wqk[base] = hi;
            g_wqk[base + 1024] = hi;
            g_wqk[base + 2048] = lo;
        } else {
            __half* dst = (mode == 1) ? g_wvh : g_woh;
            dst[(size_t)n * KVO + k] = __float2half_rn(v);
        }
    }
}

// ---------------------------------------------------------------------------
// mma.sync GEMM body: C (M x N) tile (m0,n0) = A @ Bt^T; fp32 or fp16 output.
// ---------------------------------------------------------------------------
#define SMA(b) ((b) * 32768)
#define SMB(b) ((b) * 32768 + 16384)
#define GEMM_SMEM 98304

__device__ __forceinline__ void gemm_load_tile(const uint16_t* A, const uint16_t* B,
                                               char* sm, int m0, int n0, int kb, int buf,
                                               int t, int K) {
#pragma unroll
    for (int i = 0; i < 8; i++) {
        int idx = t + i * 256;            // 0..2047
        int row = (idx & 1023) >> 3, c = idx & 7;
        uint32_t dst;
        const uint16_t* src;
        if (idx < 1024) {
            src = A + (size_t)(m0 + row) * K + kb * 64 + c * 8;
            dst = smem_u32(sm + SMA(buf) + row * 128 + ((c ^ (row & 7)) << 4));
        } else {
            src = B + (size_t)(n0 + row) * K + kb * 64 + c * 8;
            dst = smem_u32(sm + SMB(buf) + row * 128 + ((c ^ (row & 7)) << 4));
        }
        CP_ASYNC16(dst, src);
    }
}

template<bool F16, bool HOUT>
__device__ __forceinline__ void gemm_body(const uint16_t* __restrict__ A,
                                          const uint16_t* __restrict__ B,
                                          void* __restrict__ Cv,
                                          int N, int K, int nkt,
                                          int m0, int n0, char* sm, int t) {
    int w = t >> 5, l = t & 31;
    int wm = (w >> 2) * 64, wn = (w & 3) * 32;

    float acc[4][4][4];
#pragma unroll
    for (int i = 0; i < 4; i++)
#pragma unroll
        for (int j = 0; j < 4; j++)
#pragma unroll
            for (int r = 0; r < 4; r++) acc[i][j][r] = 0.f;

    int ar = wm + (l & 15);
    int ac = (l >> 4);
    int brow = wn + (l & 7) + ((l >> 4) << 3);   // base row for paired-B ldsm
    int bkh = (l >> 3) & 1;

    gemm_load_tile(A, B, sm, m0, n0, 0, 0, t, K);
    CP_COMMIT();
    gemm_load_tile(A, B, sm, m0, n0, 1, 1, t, K);
    CP_COMMIT();

    int buf = 0;
    for (int kt = 0; kt < nkt; kt++) {
        if (kt + 2 < nkt) {
            int lb = buf + 2; if (lb >= 3) lb -= 3;
            gemm_load_tile(A, B, sm, m0, n0, kt + 2, lb, t, K);
        }
        CP_COMMIT();
        CP_WAIT(2);
        __syncthreads();

        uint32_t Ab = smem_u32(sm + SMA(buf));
        uint32_t Bb = smem_u32(sm + SMB(buf));
#pragma unroll
        for (int ks = 0; ks < 4; ks++) {
            uint32_t afr[4][4], bfr[4][2];
#pragma unroll
            for (int mi = 0; mi < 4; mi++) {
                int row = ar + mi * 16;
                int ch = ks * 2 + ac;
                ldsm_x4(afr[mi], Ab + row * 128 + ((ch ^ (row & 7)) << 4));
            }
#pragma unroll
            for (int p = 0; p < 2; p++) {
                uint32_t bp[4];
                int row = brow + p * 16;
                int ch = ks * 2 + bkh;
                ldsm_x4(bp, Bb + row * 128 + ((ch ^ (row & 7)) << 4));
                bfr[2 * p][0] = bp[0]; bfr[2 * p][1] = bp[1];
                bfr[2 * p + 1][0] = bp[2]; bfr[2 * p + 1][1] = bp[3];
            }
#pragma unroll
            for (int mi = 0; mi < 4; mi++)
#pragma unroll
                for (int ni = 0; ni < 4; ni++)
                    mma_any<F16>(acc[mi][ni], afr[mi], bfr[ni]);
        }
        __syncthreads();
        if (++buf == 3) buf = 0;
    }

    int r0 = l >> 2, c0 = (l & 3) * 2;
#pragma unroll
    for (int mi = 0; mi < 4; mi++) {
#pragma unroll
        for (int ni = 0; ni < 4; ni++) {
            int row = m0 + wm + mi * 16 + r0;
            int col = n0 + wn + ni * 8 + c0;
            if constexpr (HOUT) {
                __half* C = (__half*)Cv;
                *(__half2*)&C[(size_t)row * N + col] =
                    __floats2half2_rn(acc[mi][ni][0], acc[mi][ni][1]);
                *(__half2*)&C[(size_t)(row + 8) * N + col] =
                    __floats2half2_rn(acc[mi][ni][2], acc[mi][ni][3]);
            } else {
                float* C = (float*)Cv;
                *(float2*)(C + (size_t)row * N + col) = make_float2(acc[mi][ni][0], acc[mi][ni][1]);
                *(float2*)(C + (size_t)(row + 8) * N + col) = make_float2(acc[mi][ni][2], acc[mi][ni][3]);
            }
        }
    }
}

// Fused q/k + v projections: CTAs 0..127 -> qk (bf16, K=3072, N=512, fp32 out),
// CTAs 128..383 -> v (fp16, K=1024, N=1024, fp16 out).
__global__ void __launch_bounds__(256, 2)
proj_gemm(const uint16_t* __restrict__ x2, const uint16_t* __restrict__ wqk,
          float* __restrict__ qk,
          const uint16_t* __restrict__ xh, const uint16_t* __restrict__ wvh,
          __half* __restrict__ v) {
    extern __shared__ char sm[];
    int blk = blockIdx.x;
    int t = threadIdx.x;
    if (blk < 128) {
        gemm_body<false, false>(x2, wqk, qk, 512, KQK, KQK / 64,
                                (blk >> 2) * 128, (blk & 3) * 128, sm, t);
    } else {
        int b2 = blk - 128;
        gemm_body<true, true>(xh, wvh, v, 1024, KVO, KVO / 64,
                              (b2 >> 3) * 128, (b2 & 7) * 128, sm, t);
    }
}

// Standalone o-projection GEMM (fp32 out -> harness buffer).
__global__ void __launch_bounds__(256, 2)
gemm_o(const uint16_t* __restrict__ A, const uint16_t* __restrict__ B,
       float* __restrict__ C) {
    extern __shared__ char sm[];
    gemm_body<true, false>(A, B, C, 1024, KVO, KVO / 64,
                           blockIdx.y * 128, blockIdx.x * 128, sm, threadIdx.x);
}

// ---------------------------------------------------------------------------
// Per-chunk local state via mma.sync:
// S^T[e][d] = sum_m v[m][e] * phi(k[m])[d]  -> A = v^T (64 x 64), B = kf^T (DFP x 64)
// Vectorized operand builds; mma in two 9-tile passes (3 CTAs/SM).
// ---------------------------------------------------------------------------
#define CS_KFT 0                       // kf^T fp16: 288 rows x 128B = 36864
#define CS_VT  36864                   // v^T  fp16: 64 rows x 128B  = 8192
#define CS_KT  45056                   // k^T fp32 [16][65] = 4160
#define CS_VS  49216                   // v^T fp32 [64][65] = 16640
#define CS_SMEM 65856

__global__ void __launch_bounds__(256, 3) chunk_state_mma() {
    extern __shared__ char smc[];
    float* k_T = (float*)(smc + CS_KT);
    float* v_S = (float*)(smc + CS_VS);

    int blk = blockIdx.x;
    int c = blk & (NC - 1);
    int bh = blk >> 5;
    int b = bh >> 4, h = bh & 15;
    int t = threadIdx.x;
    long tok0 = (long)b * LL + (long)c * CHUNK;

    // stage k transposed [f][n] (pad 65) and v transposed [e][m] (pad 65)
    for (int i = t; i < 64 * 16; i += 256) {
        int n = i >> 4, f = i & 15;
        k_T[f * 65 + n] = g_qk[(tok0 + n) * 512 + 256 + h * 16 + f];
    }
    for (int i = t; i < 4096; i += 256) {
        int m = i >> 6, e = i & 63;
        v_S[e * 65 + m] = __half2float(g_vh[(tok0 + m) * 1024 + h * 64 + e]);
    }
    __syncthreads();

    // v^T fp16 swizzled: one uint4 per (e, chunk)
    for (int i = t; i < 512; i += 256) {
        int e = i >> 3, c8 = i & 7;
        int mg = c8 ^ (e & 7);
        const float* vr = &v_S[e * 65 + mg * 8];
        uint4 u;
        __half2* hp = (__half2*)&u;
        hp[0] = __floats2half2_rn(vr[0], vr[1]);
        hp[1] = __floats2half2_rn(vr[2], vr[3]);
        hp[2] = __floats2half2_rn(vr[4], vr[5]);
        hp[3] = __floats2half2_rn(vr[6], vr[7]);
        *(uint4*)(smc + CS_VT + e * 128 + c8 * 16) = u;
    }

    // kf^T fp16 swizzled: one uint4 per (d, chunk)
    for (int i = t; i < DFP * 8; i += 256) {
        int d = i >> 3, c8 = i & 7;
        int mg = c8 ^ (d & 7);
        int m0 = mg * 8;
        uint4 u;
        __half2* hp = (__half2*)&u;
        if (d == 0) {
            __half2 one2 = __floats2half2_rn(1.f, 1.f);
            hp[0] = one2; hp[1] = one2; hp[2] = one2; hp[3] = one2;
        } else if (d <= 16) {
            const float* kr = &k_T[(d - 1) * 65 + m0];
            hp[0] = __floats2half2_rn(kr[0] * INV_RRD, kr[1] * INV_RRD);
            hp[1] = __floats2half2_rn(kr[2] * INV_RRD, kr[3] * INV_RRD);
            hp[2] = __floats2half2_rn(kr[4] * INV_RRD, kr[5] * INV_RRD);
            hp[3] = __floats2half2_rn(kr[6] * INV_RRD, kr[7] * INV_RRD);
        } else if (d < DF) {
            int dd = d - 17;
            const float* ka = &k_T[(dd >> 4) * 65 + m0];
            const float* kb = &k_T[(dd & 15) * 65 + m0];
            hp[0] = __floats2half2_rn(ka[0] * kb[0] * INV_Q2, ka[1] * kb[1] * INV_Q2);
            hp[1] = __floats2half2_rn(ka[2] * kb[2] * INV_Q2, ka[3] * kb[3] * INV_Q2);
            hp[2] = __floats2half2_rn(ka[4] * kb[4] * INV_Q2, ka[5] * kb[5] * INV_Q2);
            hp[3] = __floats2half2_rn(ka[6] * kb[6] * INV_Q2, ka[7] * kb[7] * INV_Q2);
        } else {
            u = make_uint4(0u, 0u, 0u, 0u);
        }
        *(uint4*)(smc + CS_KFT + d * 128 + c8 * 16) = u;
    }
    __syncthreads();

    // mma: warp w -> e-tile (w>>1); d-tiles (w&1)*18 .. +17 in two 9-tile passes
    int w = t >> 5, l = t & 31;
    uint32_t Ab = smem_u32(smc + CS_VT);
    uint32_t Bb = smem_u32(smc + CS_KFT);
    int ar = (w >> 1) * 16 + (l & 15);
    int ac = l >> 4;
    int brow_base = (l & 7) + ((l >> 4) << 3);
    int bkh = (l >> 3) & 1;
    int ntile0 = (w & 1) * 18;
    int r0 = l >> 2, c0 = (l & 3) * 2;
    size_t Sbase = (size_t)blk * 64 * DFP;
    int e_lo = (w >> 1) * 16 + r0;

#pragma unroll
    for (int half = 0; half < 2; half++) {
        int tb = ntile0 + half * 9;
        float acc[9][4];
#pragma unroll
        for (int j = 0; j < 9; j++)
#pragma unroll
            for (int r = 0; r < 4; r++) acc[j][r] = 0.f;

#pragma unroll
        for (int ks = 0; ks < 4; ks++) {
            uint32_t afr[4];
            int ch = ks * 2 + ac;
            ldsm_x4(afr, Ab + ar * 128 + ((ch ^ (ar & 7)) << 4));
            int chb = ks * 2 + bkh;
#pragma unroll
            for (int jp = 0; jp < 4; jp++) {
                uint32_t bp[4];
                int row = (tb + jp * 2) * 8 + brow_base;
                ldsm_x4(bp, Bb + row * 128 + ((chb ^ (row & 7)) << 4));
                mma_any<true>(acc[jp * 2],     afr, bp);
                mma_any<true>(acc[jp * 2 + 1], afr, bp + 2);
            }
            {   // last single tile
                uint32_t bs[2];
                int row = (tb + 8) * 8 + (l & 7);
                int chs = ks * 2 + ((l >> 3) & 1);
                ldsm_x2(bs, Bb + row * 128 + ((chs ^ (row & 7)) << 4));
                mma_any<true>(acc[8], afr, bs);
            }
        }

        // store this half's 9 d-tiles, e-major fp16
#pragma unroll
        for (int j = 0; j < 9; j++) {
            int d = (tb + j) * 8 + c0;
            *(__half2*)&g_Sh[Sbase + (size_t)e_lo * DFP + d] =
                __floats2half2_rn(acc[j][0], acc[j][1]);
            *(__half2*)&g_Sh[Sbase + (size_t)(e_lo + 8) * DFP + d] =
                __floats2half2_rn(acc[j][2], acc[j][3]);
        }
    }

    // ssum[d] = sum_m kf[m][d] from kf^T smem
    for (int d = t; d < DF; d += 256) {
        float s = 0.f;
#pragma unroll
        for (int c8 = 0; c8 < 8; c8++) {
            int off = d * 128 + (((c8 ^ (d & 7))) << 4);
            uint4 u = *(const uint4*)(smc + CS_KFT + off);
            const __half2* hp = (const __half2*)&u;
#pragma unroll
            for (int q = 0; q < 4; q++) {
                float2 f2 = __half22float2(hp[q]);
                s += f2.x + f2.y;
            }
        }
        g_ss[(long)blk * DF + d] = s;
    }
}

// ---------------------------------------------------------------------------
// Fused in-place exclusive prefix scans (S blocks first, then ss blocks)
// ---------------------------------------------------------------------------
#define SCAN_S_BLOCKS 1152   // NBH * (64*DFP/2) / 256
#define SCAN_SS_BLOCKS 35    // ceil(NBH*DF / 256)

__global__ void scan_all() {
    int blk = blockIdx.x;
    if (blk < SCAN_S_BLOCKS) {
        long idx = (long)blk * 256 + threadIdx.x;
        const long PER_BH = 64 * DFP / 2;  // 9216 half2 per chunk
        long bh = idx / PER_BH;
        long de = idx % PER_BH;
        __half2* Sp = (__half2*)g_Sh;
        size_t base = (size_t)bh * NC * PER_BH + de;
        float2 acc = make_float2(0.f, 0.f);
#pragma unroll
        for (int c = 0; c < NC; c++) {
            size_t p = base + (size_t)c * PER_BH;
            float2 tmp = __half22float2(Sp[p]);
            Sp[p] = __floats2half2_rn(acc.x, acc.y);
            acc.x += tmp.x; acc.y += tmp.y;
        }
    } else {
        long idx = (long)(blk - SCAN_S_BLOCKS) * 256 + threadIdx.x;
        if (idx >= (long)NBH * DF) return;
        long bh = idx / DF;
        long d = idx % DF;
        long base = bh * NC * DF + d;
        float acc = 0.f;
#pragma unroll
        for (int c = 0; c < NC; c++) {
            long p = base + (long)c * DF;
            float tmp = g_ss[p];
            g_ss[p] = acc;
            acc += tmp;
        }
    }
}

// ---------------------------------------------------------------------------
// Output via one fused mma GEMM per (bh,chunk):
//   Aop = [phi(q) (64x288) | A_poly (64x64)]  (fp16, padded stride 360)
//   Bop rows (N=72): e<64: [S^T[e] | v^T[e]], row64: [0 | 1...], 65..71: 0
//   denominator = fp32 scalar qf.sp + rowsum(A); y = num * z  (fp16 hi out)
// ---------------------------------------------------------------------------
#define OTS 360                         // row stride in halves (45 x 16B, odd)
#define OT_QF 0                         // 64 x 720B  = 46080
#define OT_B  46080                     // 72 x 720B  = 51840
#define OT_Q  97920                     // 64x16 fp32 = 4096
#define OT_K  102016                    // 64x16 fp32 = 4096
#define OT_SP 106112                    // 276  fp32  = 1104
#define OT_DS 107216                    // 64 fp32 (+pad)
#define OT_RS 107472                    // 64 fp32 (+pad)
#define OT_Z  107728                    // 64 fp32 (+pad)
#define OT_SMEM 107984

__global__ void __launch_bounds__(256, 2) output_mma() {
    extern __shared__ char smo[];
    float* q_s  = (float*)(smo + OT_Q);
    float* k_s  = (float*)(smo + OT_K);
    float* sp_s = (float*)(smo + OT_SP);
    float* ds_s = (float*)(smo + OT_DS);
    float* rs_s = (float*)(smo + OT_RS);
    float* z_s  = (float*)(smo + OT_Z);
    __half* qf  = (__half*)(smo + OT_QF);
    __half* Bx  = (__half*)(smo + OT_B);

    int blk = blockIdx.x;
    int c = blk & (NC - 1);
    int bh = blk >> 5;
    int b = bh >> 4, h = bh & 15;
    int t = threadIdx.x;
    long tok0 = (long)b * LL + (long)c * CHUNK;

    // ---- phase 1: loads ----
    {   // S^T rows via cp.async (36 uint4 per row)
        const uint4* src = (const uint4*)(g_Sh + (size_t)blk * 64 * DFP);
        for (int i = t; i < 64 * 36; i += 256) {
            int e = i / 36, u = i % 36;
            CP_ASYNC16(smem_u32(smo + OT_B + e * 720 + u * 16), src + i);
        }
        CP_COMMIT();
    }
    for (int i = t; i < 64 * 16; i += 256) {
        int n = i >> 4, f = i & 15;
        long off = (tok0 + n) * 512 + h * 16 + f;
        q_s[i] = g_qk[off];
        k_s[i] = g_qk[off + 256];
    }
    for (int i = t; i < 276; i += 256) sp_s[i] = (i < DF) ? g_ss[(long)blk * DF + i] : 0.f;
    for (int i = t; i < 4096; i += 256) {   // v^T into cols 288..351 (fp16 direct)
        int m = i >> 6, e = i & 63;
        Bx[e * OTS + 288 + m] = g_vh[(tok0 + m) * 1024 + h * 64 + e];
    }
    for (int i = t; i < 8 * 180; i += 256) {    // rows 64..71
        int r = 64 + i / 180, u = i % 180;      // uint (2 halves)
        uint32_t val = (r == 64 && u >= 144 && u < 176) ? 0x3C003C00u : 0u;  // ones over v-cols
        *(uint32_t*)(smo + OT_B + r * 720 + u * 4) = val;
    }
    CP_WAIT(0);
    __syncthreads();

    // ---- phase 2: build A-operand (vectorized) + fp32 denominator part ----
    for (int i = t; i < 64 * 36; i += 256) {    // phi(q): one uint4 per 8 features
        int n = i / 36, d0 = (i % 36) * 8;
        const float* q0 = &q_s[n * 16];
        uint4 u;
        __half2* hp = (__half2*)&u;
#pragma unroll
        for (int p = 0; p < 4; p++) {
            float vv[2];
#pragma unroll
            for (int s2 = 0; s2 < 2; s2++) {
                int d = d0 + p * 2 + s2;
                float val = 0.f;
                if (d == 0) val = 1.f;
                else if (d <= 16) val = q0[d - 1] * INV_RRD;
                else if (d < DF) {
                    int dd = d - 17;
                    val = q0[dd >> 4] * q0[dd & 15] * INV_Q2;
                }
                vv[s2] = val;
            }
            hp[p] = __floats2half2_rn(vv[0], vv[1]);
        }
        *(uint4*)&qf[n * OTS + d0] = u;
    }
    {   // causal polynomial scores into cols 288..351 (thread -> (n, 16 m's))
        int n = t >> 2, mq = (t & 3) << 4;
        float qr[16];
#pragma unroll
        for (int f = 0; f < 16; f++) qr[f] = q_s[n * 16 + f];
#pragma unroll
        for (int mm = 0; mm < 16; mm += 2) {
            float a2[2];
#pragma unroll
            for (int u2 = 0; u2 < 2; u2++) {
                int m = mq + mm + u2;
                float s = 0.f;
#pragma unroll
                for (int f = 0; f < 16; f++) s += qr[f] * k_s[m * 16 + f];
                a2[u2] = (m <= n) ? (1.f + 0.25f * s + s * s * 0.03125f) : 0.f;
            }
            *(__half2*)&qf[n * OTS + 288 + mq + mm] = __floats2half2_rn(a2[0], a2[1]);
        }
        if (t < 64) {                    // fp32 qf . sp
            const float* q0 = &q_s[t * 16];
            float d1 = 0.f;
#pragma unroll
            for (int f = 0; f < 16; f++) d1 += q0[f] * sp_s[1 + f];
            float d2 = 0.f;
            for (int i2 = 0; i2 < 16; i2++) {
                float inner = 0.f;
#pragma unroll
                for (int j = 0; j < 16; j++) inner += q0[j] * sp_s[17 + 16 * i2 + j];
                d2 += q0[i2] * inner;
            }
            ds_s[t] = sp_s[0] + INV_RRD * d1 + INV_Q2 * d2;
        }
    }
    __syncthreads();

    // ---- phase 3: 64x72x352 fp16 GEMM (8 warps: 4 m-tiles x 2 n-groups) ----
    int w = t >> 5, l = t & 31;
    int m0w = (w >> 1) * 16;
    int nh5 = w & 1;
    int nr0 = nh5 * 40;
    float acc[5][4];
#pragma unroll
    for (int j = 0; j < 5; j++)
#pragma unroll
        for (int r = 0; r < 4; r++) acc[j][r] = 0.f;

    uint32_t Qb = smem_u32(smo + OT_QF);
    uint32_t Bb = smem_u32(smo + OT_B);
    uint32_t aad = Qb + (m0w + (l & 15)) * 720 + (l >> 4) * 16;
    uint32_t bpd = Bb + (nr0 + (l & 7) + ((l >> 4) << 3)) * 720 + ((l >> 3) & 1) * 16;
    uint32_t bsd = Bb + (nr0 + 32 + (l & 7)) * 720 + ((l >> 3) & 1) * 16;

    if (nh5 == 0) {
#pragma unroll
        for (int ks = 0; ks < 22; ks++) {
            uint32_t afr[4], bp0[4], bp1[4], bs[2];
            ldsm_x4(afr, aad + ks * 32);
            ldsm_x4(bp0, bpd + ks * 32);
            ldsm_x4(bp1, bpd + 16 * 720 + ks * 32);
            ldsm_x2(bs,  bsd + ks * 32);
            mma_any<true>(acc[0], afr, bp0);
            mma_any<true>(acc[1], afr, bp0 + 2);
            mma_any<true>(acc[2], afr, bp1);
            mma_any<true>(acc[3], afr, bp1 + 2);
            mma_any<true>(acc[4], afr, bs);
        }
    } else {
#pragma unroll
        for (int ks = 0; ks < 22; ks++) {
            uint32_t afr[4], bp0[4], bp1[4];
            ldsm_x4(afr, aad + ks * 32);
            ldsm_x4(bp0, bpd + ks * 32);
            ldsm_x4(bp1, bpd + 16 * 720 + ks * 32);
            mma_any<true>(acc[0], afr, bp0);
            mma_any<true>(acc[1], afr, bp0 + 2);
            mma_any<true>(acc[2], afr, bp1);
            mma_any<true>(acc[3], afr, bp1 + 2);
        }
    }

    // ---- phase 4: denominator + write ----
    int r0 = l >> 2, c0 = (l & 3) * 2;
    if (nh5 == 1 && (l & 3) == 0) {     // local tile 3 = global tile 8 -> col 64
        rs_s[m0w + r0] = acc[3][0];
        rs_s[m0w + r0 + 8] = acc[3][2];
    }
    __syncthreads();
    if (t < 64) z_s[t] = 1.f / (ds_s[t] + rs_s[t] + EPS);
    __syncthreads();

    float z0 = z_s[m0w + r0], z1 = z_s[m0w + r0 + 8];
    size_t rowb0 = (size_t)(tok0 + m0w + r0) * KVO + h * 64;
    size_t rowb1 = (size_t)(tok0 + m0w + r0 + 8) * KVO + h * 64;
    int jmax = nh5 ? 4 : 5;
#pragma unroll
    for (int j = 0; j < 5; j++) {
        if (j >= jmax) break;
        int col = (nh5 * 5 + j) * 8 + c0;
        if (col < 64) {
            *(__half2*)&g_yh[rowb0 + col] =
                __floats2half2_rn(acc[j][0] * z0, acc[j][1] * z0);
            *(__half2*)&g_yh[rowb1 + col] =
                __floats2half2_rn(acc[j][2] * z1, acc[j][3] * z1);
        }
    }
}

// ---------------------------------------------------------------------------
extern "C" void kernel_launch(void* const* d_in, const int* in_sizes, int n_in,
                              void* d_out, int out_size) {
    const float* x  = (const float*)d_in[0];
    const float* Wq = (const float*)d_in[1];
    const float* Wk = (const float*)d_in[2];
    const float* Wv = (const float*)d_in[3];
    const float* Wo = (const float*)d_in[4];
    float* out = (float*)d_out;

    void *px2, *pxh, *pwqk, *pwvh, *pwoh, *pqk, *pvh, *pyh;
    cudaGetSymbolAddress(&px2, g_x2);
    cudaGetSymbolAddress(&pxh, g_xh);
    cudaGetSymbolAddress(&pwqk, g_wqk);
    cudaGetSymbolAddress(&pwvh, g_wvh);
    cudaGetSymbolAddress(&pwoh, g_woh);
    cudaGetSymbolAddress(&pqk, g_qk);
    cudaGetSymbolAddress(&pvh, g_vh);
    cudaGetSymbolAddress(&pyh, g_yh);

    cudaFuncSetAttribute(chunk_state_mma, cudaFuncAttributeMaxDynamicSharedMemorySize, CS_SMEM);
    cudaFuncSetAttribute(output_mma, cudaFuncAttributeMaxDynamicSharedMemorySize, OT_SMEM);
    cudaFuncSetAttribute(proj_gemm, cudaFuncAttributeMaxDynamicSharedMemorySize, GEMM_SMEM);
    cudaFuncSetAttribute(gemm_o, cudaFuncAttributeMaxDynamicSharedMemorySize, GEMM_SMEM);

    // split/convert inputs (fused)
    prep_kernel<<<4096 + 80 * 32, 256>>>(x, Wq, Wk, Wv, Wo);

    // fused q/k + v projections on tensor cores
    proj_gemm<<<384, 256, GEMM_SMEM>>>((const uint16_t*)px2, (const uint16_t*)pwqk, (float*)pqk,
                                       (const uint16_t*)pxh, (const uint16_t*)pwvh, (__half*)pvh);

    // chunked linear attention
    chunk_state_mma<<<NBH * NC, 256, CS_SMEM>>>();
    scan_all<<<SCAN_S_BLOCKS + SCAN_SS_BLOCKS, 256>>>();
    output_mma<<<NBH * NC, 256, OT_SMEM>>>();

    // final projection
    gemm_o<<<dim3(8, 32), 256, GEMM_SMEM>>>((const uint16_t*)pyh, (const uint16_t*)pwoh, out);
}

// round 12
// speedup vs baseline: 5.4958x; 1.0918x over previous
#include <cuda_runtime.h>
#include <cuda_bf16.h>
#include <cuda_fp16.h>
#include <cstdint>

// Problem constants
#define BB 2
#define LL 2048
#define DM 1024
#define NH 16
#define FD 16
#define HD 64
#define DF 273          // 1 + 16 + 256
#define DFP 288         // DF padded to 18 n8-tiles for mma
#define CHUNK 64
#define NC 32           // LL / CHUNK
#define NBH 32          // BB * NH
#define INV_RRD 0.5f
#define INV_Q2 0.17677669529663687f   // 1/(4*sqrt(2))
#define EPS 1e-12f

#define KQK 2048        // fp16 2-term split for q/k projection
#define KVO 1024        // fp16 single-term for v/o projections

// ---------------------------------------------------------------------------
// Scratch (device globals; no allocation)
// ---------------------------------------------------------------------------
__device__ __half g_xh2[4096 * KQK];            // x: [hi | lo] fp16 (hi half also feeds v GEMM)
__device__ __half g_wqk[512 * KQK];             // [Wq|Wk]^T: [W' | W'] fp16 duplicated
__device__ __half g_wvh[1024 * KVO];            // Wv^T fp16
__device__ __half g_woh[1024 * KVO];            // Wo^T fp16
__device__ float g_qk[4096 * 512];              // q (cols 0..255) | k (256..511)
__device__ __half g_vh[4096 * 1024];            // v fp16
__device__ __half g_yh[4096 * KVO];             // y fp16
__device__ __half g_Sh[(size_t)NBH * NC * 64 * DFP];  // chunk states, e-major S^T (fp16)
__device__ float g_ss[NBH * NC * DF];

// ---------------------------------------------------------------------------
// PTX helpers (baseline sm_80-compatible: ldmatrix, mma.sync, cp.async)
// ---------------------------------------------------------------------------
__device__ __forceinline__ uint32_t smem_u32(const void* p) {
    uint32_t a;
    asm("{ .reg .u64 t; cvta.to.shared.u64 t, %1; cvt.u32.u64 %0, t; }" : "=r"(a) : "l"(p));
    return a;
}
__device__ __forceinline__ void ldsm_x4(uint32_t* r, uint32_t addr) {
    asm volatile("ldmatrix.sync.aligned.m8n8.x4.shared.b16 {%0,%1,%2,%3}, [%4];"
        : "=r"(r[0]), "=r"(r[1]), "=r"(r[2]), "=r"(r[3]) : "r"(addr));
}
__device__ __forceinline__ void ldsm_x2(uint32_t* r, uint32_t addr) {
    asm volatile("ldmatrix.sync.aligned.m8n8.x2.shared.b16 {%0,%1}, [%2];"
        : "=r"(r[0]), "=r"(r[1]) : "r"(addr));
}
__device__ __forceinline__ void mma_f16(float* d, const uint32_t* a, const uint32_t* b) {
    asm volatile("mma.sync.aligned.m16n8k16.row.col.f32.f16.f16.f32 "
        "{%0,%1,%2,%3}, {%4,%5,%6,%7}, {%8,%9}, {%0,%1,%2,%3};"
        : "+f"(d[0]), "+f"(d[1]), "+f"(d[2]), "+f"(d[3])
        : "r"(a[0]), "r"(a[1]), "r"(a[2]), "r"(a[3]), "r"(b[0]), "r"(b[1]));
}
#define CP_ASYNC16(dst, src) \
    asm volatile("cp.async.cg.shared.global [%0], [%1], 16;" :: "r"(dst), "l"(src))
#define CP_COMMIT() asm volatile("cp.async.commit_group;" ::: "memory")
#define CP_WAIT(n)  asm volatile("cp.async.wait_group %0;" :: "n"(n) : "memory")

// ---------------------------------------------------------------------------
// Fused prep: blocks 0..4095 convert x (fp16 hi/lo); blocks 4096.. split weights.
// ---------------------------------------------------------------------------
union HF2U { __half2 h; uint32_t u; };

__global__ void prep_kernel(const float* __restrict__ x,
                            const float* __restrict__ Wq, const float* __restrict__ Wk,
                            const float* __restrict__ Wv, const float* __restrict__ Wo) {
    __shared__ float tile[32][33];
    int blk = blockIdx.x;
    if (blk < 4096) {
        int idx = blk * 256 + threadIdx.x;
        int m = idx >> 8, k4 = (idx & 255) << 2;
        float4 v = *(const float4*)&x[(size_t)m * 1024 + k4];
        float f[4] = {v.x, v.y, v.z, v.w};
        uint32_t fh[2], fl[2];
#pragma unroll
        for (int p = 0; p < 2; p++) {
            float a = f[2 * p], bq = f[2 * p + 1];
            __half h0 = __float2half_rn(a), h1 = __float2half_rn(bq);
            HF2U uh; uh.h = __halves2half2(h0, h1); fh[p] = uh.u;
            HF2U ul; ul.h = __halves2half2(
                __float2half_rn(a - __half2float(h0)),
                __float2half_rn(bq - __half2float(h1))); fl[p] = ul.u;
        }
        size_t b2 = (size_t)m * KQK + k4;
        *(uint2*)&g_xh2[b2]        = make_uint2(fh[0], fh[1]);
        *(uint2*)&g_xh2[b2 + 1024] = make_uint2(fl[0], fl[1]);
        return;
    }
    // weight split part: 80 x 32 virtual grid
    int b2i = blk - 4096;
    int bx = b2i % 80, k0 = (b2i / 80) * 32;
    const float* W;
    int Ncols, n0, mode, rowoff = 0;
    if (bx < 8)       { W = Wq; Ncols = 256;  n0 = bx * 32;        mode = 0; rowoff = 0;   }
    else if (bx < 16) { W = Wk; Ncols = 256;  n0 = (bx - 8) * 32;  mode = 0; rowoff = 256; }
    else if (bx < 48) { W = Wv; Ncols = 1024; n0 = (bx - 16) * 32; mode = 1; }
    else              { W = Wo; Ncols = 1024; n0 = (bx - 48) * 32; mode = 2; }
    int tx = threadIdx.x & 31, ty = threadIdx.x >> 5;  // 32 x 8
    for (int i = ty; i < 32; i += 8)
        tile[i][tx] = W[(size_t)(k0 + i) * Ncols + n0 + tx];
    __syncthreads();
    for (int i = ty; i < 32; i += 8) {
        int n = n0 + i, k = k0 + tx;
        __half hv = __float2half_rn(tile[tx][i]);
        if (mode == 0) {
            size_t base = (size_t)(rowoff + n) * KQK + k;
            g_wqk[base] = hv;
            g_wqk[base + 1024] = hv;
        } else {
            __half* dst = (mode == 1) ? g_wvh : g_woh;
            dst[(size_t)n * KVO + k] = hv;
        }
    }
}

// ---------------------------------------------------------------------------
// mma.sync fp16 GEMM body: C (M x N) tile (m0,n0) = A @ Bt^T
// lda/ldb row strides decoupled from k-loop count (nkt).
// ---------------------------------------------------------------------------
#define SMA(b) ((b) * 32768)
#define SMB(b) ((b) * 32768 + 16384)
#define GEMM_SMEM 98304

__device__ __forceinline__ void gemm_load_tile(const __half* A, const __half* B,
                                               char* sm, int m0, int n0, int kb, int buf,
                                               int t, int lda, int ldb) {
#pragma unroll
    for (int i = 0; i < 8; i++) {
        int idx = t + i * 256;            // 0..2047
        int row = (idx & 1023) >> 3, c = idx & 7;
        uint32_t dst;
        const __half* src;
        if (idx < 1024) {
            src = A + (size_t)(m0 + row) * lda + kb * 64 + c * 8;
            dst = smem_u32(sm + SMA(buf) + row * 128 + ((c ^ (row & 7)) << 4));
        } else {
            src = B + (size_t)(n0 + row) * ldb + kb * 64 + c * 8;
            dst = smem_u32(sm + SMB(buf) + row * 128 + ((c ^ (row & 7)) << 4));
        }
        CP_ASYNC16(dst, src);
    }
}

template<bool HOUT>
__device__ __forceinline__ void gemm_body(const __half* __restrict__ A,
                                          const __half* __restrict__ B,
                                          void* __restrict__ Cv,
                                          int N, int lda, int ldb, int nkt,
                                          int m0, int n0, char* sm, int t) {
    int w = t >> 5, l = t & 31;
    int wm = (w >> 2) * 64, wn = (w & 3) * 32;

    float acc[4][4][4];
#pragma unroll
    for (int i = 0; i < 4; i++)
#pragma unroll
        for (int j = 0; j < 4; j++)
#pragma unroll
            for (int r = 0; r < 4; r++) acc[i][j][r] = 0.f;

    int ar = wm + (l & 15);
    int ac = (l >> 4);
    int brow = wn + (l & 7) + ((l >> 4) << 3);   // base row for paired-B ldsm
    int bkh = (l >> 3) & 1;

    gemm_load_tile(A, B, sm, m0, n0, 0, 0, t, lda, ldb);
    CP_COMMIT();
    gemm_load_tile(A, B, sm, m0, n0, 1, 1, t, lda, ldb);
    CP_COMMIT();

    int buf = 0;
    for (int kt = 0; kt < nkt; kt++) {
        if (kt + 2 < nkt) {
            int lb = buf + 2; if (lb >= 3) lb -= 3;
            gemm_load_tile(A, B, sm, m0, n0, kt + 2, lb, t, lda, ldb);
        }
        CP_COMMIT();
        CP_WAIT(2);
        __syncthreads();

        uint32_t Ab = smem_u32(sm + SMA(buf));
        uint32_t Bb = smem_u32(sm + SMB(buf));
#pragma unroll
        for (int ks = 0; ks < 4; ks++) {
            uint32_t afr[4][4], bfr[4][2];
#pragma unroll
            for (int mi = 0; mi < 4; mi++) {
                int row = ar + mi * 16;
                int ch = ks * 2 + ac;
                ldsm_x4(afr[mi], Ab + row * 128 + ((ch ^ (row & 7)) << 4));
            }
#pragma unroll
            for (int p = 0; p < 2; p++) {
                uint32_t bp[4];
                int row = brow + p * 16;
                int ch = ks * 2 + bkh;
                ldsm_x4(bp, Bb + row * 128 + ((ch ^ (row & 7)) << 4));
                bfr[2 * p][0] = bp[0]; bfr[2 * p][1] = bp[1];
                bfr[2 * p + 1][0] = bp[2]; bfr[2 * p + 1][1] = bp[3];
            }
#pragma unroll
            for (int mi = 0; mi < 4; mi++)
#pragma unroll
                for (int ni = 0; ni < 4; ni++)
                    mma_f16(acc[mi][ni], afr[mi], bfr[ni]);
        }
        __syncthreads();
        if (++buf == 3) buf = 0;
    }

    int r0 = l >> 2, c0 = (l & 3) * 2;
#pragma unroll
    for (int mi = 0; mi < 4; mi++) {
#pragma unroll
        for (int ni = 0; ni < 4; ni++) {
            int row = m0 + wm + mi * 16 + r0;
            int col = n0 + wn + ni * 8 + c0;
            if constexpr (HOUT) {
                __half* C = (__half*)Cv;
                *(__half2*)&C[(size_t)row * N + col] =
                    __floats2half2_rn(acc[mi][ni][0], acc[mi][ni][1]);
                *(__half2*)&C[(size_t)(row + 8) * N + col] =
                    __floats2half2_rn(acc[mi][ni][2], acc[mi][ni][3]);
            } else {
                float* C = (float*)Cv;
                *(float2*)(C + (size_t)row * N + col) = make_float2(acc[mi][ni][0], acc[mi][ni][1]);
                *(float2*)(C + (size_t)(row + 8) * N + col) = make_float2(acc[mi][ni][2], acc[mi][ni][3]);
            }
        }
    }
}

// Fused q/k + v projections: CTAs 0..127 -> qk (K=2048 2-term, fp32 out),
// CTAs 128..383 -> v (K=1024 over the hi half of g_xh2, fp16 out).
__global__ void __launch_bounds__(256, 2)
proj_gemm(const __half* __restrict__ xh2, const __half* __restrict__ wqk,
          float* __restrict__ qk,
          const __half* __restrict__ wvh, __half* __restrict__ v) {
    extern __shared__ char sm[];
    int blk = blockIdx.x;
    int t = threadIdx.x;
    if (blk < 128) {
        gemm_body<false>(xh2, wqk, qk, 512, KQK, KQK, KQK / 64,
                         (blk >> 2) * 128, (blk & 3) * 128, sm, t);
    } else {
        int b2 = blk - 128;
        gemm_body<true>(xh2, wvh, v, 1024, KQK, KVO, KVO / 64,
                        (b2 >> 3) * 128, (b2 & 7) * 128, sm, t);
    }
}

// Standalone o-projection GEMM (fp32 out -> harness buffer).
__global__ void __launch_bounds__(256, 2)
gemm_o(const __half* __restrict__ A, const __half* __restrict__ B,
       float* __restrict__ C) {
    extern __shared__ char sm[];
    gemm_body<false>(A, B, C, 1024, KVO, KVO, KVO / 64,
                     blockIdx.y * 128, blockIdx.x * 128, sm, threadIdx.x);
}

// ---------------------------------------------------------------------------
// Per-chunk local state via mma.sync:
// S^T[e][d] = sum_m v[m][e] * phi(k[m])[d]  -> A = v^T (64 x 64), B = kf^T (DFP x 64)
// Vectorized operand builds; mma in two 9-tile passes (3 CTAs/SM).
// ---------------------------------------------------------------------------
#define CS_KFT 0                       // kf^T fp16: 288 rows x 128B = 36864
#define CS_VT  36864                   // v^T  fp16: 64 rows x 128B  = 8192
#define CS_KT  45056                   // k^T fp32 [16][65] = 4160
#define CS_VS  49216                   // v^T fp32 [64][65] = 16640
#define CS_SMEM 65856

__global__ void __launch_bounds__(256, 3) chunk_state_mma() {
    extern __shared__ char smc[];
    float* k_T = (float*)(smc + CS_KT);
    float* v_S = (float*)(smc + CS_VS);

    int blk = blockIdx.x;
    int c = blk & (NC - 1);
    int bh = blk >> 5;
    int b = bh >> 4, h = bh & 15;
    int t = threadIdx.x;
    long tok0 = (long)b * LL + (long)c * CHUNK;

    // stage k transposed [f][n] (pad 65) and v transposed [e][m] (pad 65)
    for (int i = t; i < 64 * 16; i += 256) {
        int n = i >> 4, f = i & 15;
        k_T[f * 65 + n] = g_qk[(tok0 + n) * 512 + 256 + h * 16 + f];
    }
    for (int i = t; i < 4096; i += 256) {
        int m = i >> 6, e = i & 63;
        v_S[e * 65 + m] = __half2float(g_vh[(tok0 + m) * 1024 + h * 64 + e]);
    }
    __syncthreads();

    // v^T fp16 swizzled: one uint4 per (e, chunk)
    for (int i = t; i < 512; i += 256) {
        int e = i >> 3, c8 = i & 7;
        int mg = c8 ^ (e & 7);
        const float* vr = &v_S[e * 65 + mg * 8];
        uint4 u;
        __half2* hp = (__half2*)&u;
        hp[0] = __floats2half2_rn(vr[0], vr[1]);
        hp[1] = __floats2half2_rn(vr[2], vr[3]);
        hp[2] = __floats2half2_rn(vr[4], vr[5]);
        hp[3] = __floats2half2_rn(vr[6], vr[7]);
        *(uint4*)(smc + CS_VT + e * 128 + c8 * 16) = u;
    }

    // kf^T fp16 swizzled: one uint4 per (d, chunk)
    for (int i = t; i < DFP * 8; i += 256) {
        int d = i >> 3, c8 = i & 7;
        int mg = c8 ^ (d & 7);
        int m0 = mg * 8;
        uint4 u;
        __half2* hp = (__half2*)&u;
        if (d == 0) {
            __half2 one2 = __floats2half2_rn(1.f, 1.f);
            hp[0] = one2; hp[1] = one2; hp[2] = one2; hp[3] = one2;
        } else if (d <= 16) {
            const float* kr = &k_T[(d - 1) * 65 + m0];
            hp[0] = __floats2half2_rn(kr[0] * INV_RRD, kr[1] * INV_RRD);
            hp[1] = __floats2half2_rn(kr[2] * INV_RRD, kr[3] * INV_RRD);
            hp[2] = __floats2half2_rn(kr[4] * INV_RRD, kr[5] * INV_RRD);
            hp[3] = __floats2half2_rn(kr[6] * INV_RRD, kr[7] * INV_RRD);
        } else if (d < DF) {
            int dd = d - 17;
            const float* ka = &k_T[(dd >> 4) * 65 + m0];
            const float* kb = &k_T[(dd & 15) * 65 + m0];
            hp[0] = __floats2half2_rn(ka[0] * kb[0] * INV_Q2, ka[1] * kb[1] * INV_Q2);
            hp[1] = __floats2half2_rn(ka[2] * kb[2] * INV_Q2, ka[3] * kb[3] * INV_Q2);
            hp[2] = __floats2half2_rn(ka[4] * kb[4] * INV_Q2, ka[5] * kb[5] * INV_Q2);
            hp[3] = __floats2half2_rn(ka[6] * kb[6] * INV_Q2, ka[7] * kb[7] * INV_Q2);
        } else {
            u = make_uint4(0u, 0u, 0u, 0u);
        }
        *(uint4*)(smc + CS_KFT + d * 128 + c8 * 16) = u;
    }
    __syncthreads();

    // mma: warp w -> e-tile (w>>1); d-tiles (w&1)*18 .. +17 in two 9-tile passes
    int w = t >> 5, l = t & 31;
    uint32_t Ab = smem_u32(smc + CS_VT);
    uint32_t Bb = smem_u32(smc + CS_KFT);
    int ar = (w >> 1) * 16 + (l & 15);
    int ac = l >> 4;
    int brow_base = (l & 7) + ((l >> 4) << 3);
    int bkh = (l >> 3) & 1;
    int ntile0 = (w & 1) * 18;
    int r0 = l >> 2, c0 = (l & 3) * 2;
    size_t Sbase = (size_t)blk * 64 * DFP;
    int e_lo = (w >> 1) * 16 + r0;

#pragma unroll
    for (int half = 0; half < 2; half++) {
        int tb = ntile0 + half * 9;
        float acc[9][4];
#pragma unroll
        for (int j = 0; j < 9; j++)
#pragma unroll
            for (int r = 0; r < 4; r++) acc[j][r] = 0.f;

#pragma unroll
        for (int ks = 0; ks < 4; ks++) {
            uint32_t afr[4];
            int ch = ks * 2 + ac;
            ldsm_x4(afr, Ab + ar * 128 + ((ch ^ (ar & 7)) << 4));
            int chb = ks * 2 + bkh;
#pragma unroll
            for (int jp = 0; jp < 4; jp++) {
                uint32_t bp[4];
                int row = (tb + jp * 2) * 8 + brow_base;
                ldsm_x4(bp, Bb + row * 128 + ((chb ^ (row & 7)) << 4));
                mma_f16(acc[jp * 2],     afr, bp);
                mma_f16(acc[jp * 2 + 1], afr, bp + 2);
            }
            {   // last single tile
                uint32_t bs[2];
                int row = (tb + 8) * 8 + (l & 7);
                int chs = ks * 2 + ((l >> 3) & 1);
                ldsm_x2(bs, Bb + row * 128 + ((chs ^ (row & 7)) << 4));
                mma_f16(acc[8], afr, bs);
            }
        }

        // store this half's 9 d-tiles, e-major fp16
#pragma unroll
        for (int j = 0; j < 9; j++) {
            int d = (tb + j) * 8 + c0;
            *(__half2*)&g_Sh[Sbase + (size_t)e_lo * DFP + d] =
                __floats2half2_rn(acc[j][0], acc[j][1]);
            *(__half2*)&g_Sh[Sbase + (size_t)(e_lo + 8) * DFP + d] =
                __floats2half2_rn(acc[j][2], acc[j][3]);
        }
    }

    // ssum[d] = sum_m kf[m][d] from kf^T smem
    for (int d = t; d < DF; d += 256) {
        float s = 0.f;
#pragma unroll
        for (int c8 = 0; c8 < 8; c8++) {
            int off = d * 128 + (((c8 ^ (d & 7))) << 4);
            uint4 u = *(const uint4*)(smc + CS_KFT + off);
            const __half2* hp = (const __half2*)&u;
#pragma unroll
            for (int q = 0; q < 4; q++) {
                float2 f2 = __half22float2(hp[q]);
                s += f2.x + f2.y;
            }
        }
        g_ss[(long)blk * DF + d] = s;
    }
}

// ---------------------------------------------------------------------------
// Fused in-place exclusive prefix scans (S blocks first, then ss blocks)
// ---------------------------------------------------------------------------
#define SCAN_S_BLOCKS 1152   // NBH * (64*DFP/2) / 256
#define SCAN_SS_BLOCKS 35    // ceil(NBH*DF / 256)

__global__ void scan_all() {
    int blk = blockIdx.x;
    if (blk < SCAN_S_BLOCKS) {
        long idx = (long)blk * 256 + threadIdx.x;
        const long PER_BH = 64 * DFP / 2;  // 9216 half2 per chunk
        long bh = idx / PER_BH;
        long de = idx % PER_BH;
        __half2* Sp = (__half2*)g_Sh;
        size_t base = (size_t)bh * NC * PER_BH + de;
        float2 acc = make_float2(0.f, 0.f);
#pragma unroll
        for (int c = 0; c < NC; c++) {
            size_t p = base + (size_t)c * PER_BH;
            float2 tmp = __half22float2(Sp[p]);
            Sp[p] = __floats2half2_rn(acc.x, acc.y);
            acc.x += tmp.x; acc.y += tmp.y;
        }
    } else {
        long idx = (long)(blk - SCAN_S_BLOCKS) * 256 + threadIdx.x;
        if (idx >= (long)NBH * DF) return;
        long bh = idx / DF;
        long d = idx % DF;
        long base = bh * NC * DF + d;
        float acc = 0.f;
#pragma unroll
        for (int c = 0; c < NC; c++) {
            long p = base + (long)c * DF;
            float tmp = g_ss[p];
            g_ss[p] = acc;
            acc += tmp;
        }
    }
}

// ---------------------------------------------------------------------------
// Output via one fused mma GEMM per (bh,chunk):
//   Aop = [phi(q) (64x288) | A_poly (64x64)]  (fp16, padded stride 360)
//   Bop rows (N=72): e<64: [S^T[e] | v^T[e]], row64: [0 | 1...], 65..71: 0
//   denominator = fp32 scalar qf.sp + rowsum(A); y = num * z  (fp16 out)
// ---------------------------------------------------------------------------
#define OTS 360                         // row stride in halves (45 x 16B, odd)
#define OT_QF 0                         // 64 x 720B  = 46080
#define OT_B  46080                     // 72 x 720B  = 51840
#define OT_Q  97920                     // 64x16 fp32 = 4096
#define OT_K  102016                    // 64x16 fp32 = 4096
#define OT_SP 106112                    // 276  fp32  = 1104
#define OT_DS 107216                    // 64 fp32 (+pad)
#define OT_RS 107472                    // 64 fp32 (+pad)
#define OT_Z  107728                    // 64 fp32 (+pad)
#define OT_SMEM 107984

__global__ void __launch_bounds__(256, 2) output_mma() {
    extern __shared__ char smo[];
    float* q_s  = (float*)(smo + OT_Q);
    float* k_s  = (float*)(smo + OT_K);
    float* sp_s = (float*)(smo + OT_SP);
    float* ds_s = (float*)(smo + OT_DS);
    float* rs_s = (float*)(smo + OT_RS);
    float* z_s  = (float*)(smo + OT_Z);
    __half* qf  = (__half*)(smo + OT_QF);
    __half* Bx  = (__half*)(smo + OT_B);

    int blk = blockIdx.x;
    int c = blk & (NC - 1);
    int bh = blk >> 5;
    int b = bh >> 4, h = bh & 15;
    int t = threadIdx.x;
    long tok0 = (long)b * LL + (long)c * CHUNK;

    // ---- phase 1: loads ----
    {   // S^T rows via cp.async (36 uint4 per row)
        const uint4* src = (const uint4*)(g_Sh + (size_t)blk * 64 * DFP);
        for (int i = t; i < 64 * 36; i += 256) {
            int e = i / 36, u = i % 36;
            CP_ASYNC16(smem_u32(smo + OT_B + e * 720 + u * 16), src + i);
        }
        CP_COMMIT();
    }
    for (int i = t; i < 64 * 16; i += 256) {
        int n = i >> 4, f = i & 15;
        long off = (tok0 + n) * 512 + h * 16 + f;
        q_s[i] = g_qk[off];
        k_s[i] = g_qk[off + 256];
    }
    for (int i = t; i < 276; i += 256) sp_s[i] = (i < DF) ? g_ss[(long)blk * DF + i] : 0.f;
    for (int i = t; i < 4096; i += 256) {   // v^T into cols 288..351 (fp16 direct)
        int m = i >> 6, e = i & 63;
        Bx[e * OTS + 288 + m] = g_vh[(tok0 + m) * 1024 + h * 64 + e];
    }
    for (int i = t; i < 8 * 180; i += 256) {    // rows 64..71
        int r = 64 + i / 180, u = i % 180;      // uint (2 halves)
        uint32_t val = (r == 64 && u >= 144 && u < 176) ? 0x3C003C00u : 0u;  // ones over v-cols
        *(uint32_t*)(smo + OT_B + r * 720 + u * 4) = val;
    }
    CP_WAIT(0);
    __syncthreads();

    // ---- phase 2: build A-operand (vectorized) + fp32 denominator part ----
    for (int i = t; i < 64 * 36; i += 256) {    // phi(q): one uint4 per 8 features
        int n = i / 36, d0 = (i % 36) * 8;
        const float* q0 = &q_s[n * 16];
        uint4 u;
        __half2* hp = (__half2*)&u;
#pragma unroll
        for (int p = 0; p < 4; p++) {
            float vv[2];
#pragma unroll
            for (int s2 = 0; s2 < 2; s2++) {
                int d = d0 + p * 2 + s2;
                float val = 0.f;
                if (d == 0) val = 1.f;
                else if (d <= 16) val = q0[d - 1] * INV_RRD;
                else if (d < DF) {
                    int dd = d - 17;
                    val = q0[dd >> 4] * q0[dd & 15] * INV_Q2;
                }
                vv[s2] = val;
            }
            hp[p] = __floats2half2_rn(vv[0], vv[1]);
        }
        *(uint4*)&qf[n * OTS + d0] = u;
    }
    {   // causal polynomial scores into cols 288..351 (thread -> (n, 16 m's))
        int n = t >> 2, mq = (t & 3) << 4;
        float qr[16];
#pragma unroll
        for (int f = 0; f < 16; f++) qr[f] = q_s[n * 16 + f];
#pragma unroll
        for (int mm = 0; mm < 16; mm += 2) {
            float a2[2];
#pragma unroll
            for (int u2 = 0; u2 < 2; u2++) {
                int m = mq + mm + u2;
                float s = 0.f;
#pragma unroll
                for (int f = 0; f < 16; f++) s += qr[f] * k_s[m * 16 + f];
                a2[u2] = (m <= n) ? (1.f + 0.25f * s + s * s * 0.03125f) : 0.f;
            }
            *(__half2*)&qf[n * OTS + 288 + mq + mm] = __floats2half2_rn(a2[0], a2[1]);
        }
        if (t < 64) {                    // fp32 qf . sp
            const float* q0 = &q_s[t * 16];
            float d1 = 0.f;
#pragma unroll
            for (int f = 0; f < 16; f++) d1 += q0[f] * sp_s[1 + f];
            float d2 = 0.f;
            for (int i2 = 0; i2 < 16; i2++) {
                float inner = 0.f;
#pragma unroll
                for (int j = 0; j < 16; j++) inner += q0[j] * sp_s[17 + 16 * i2 + j];
                d2 += q0[i2] * inner;
            }
            ds_s[t] = sp_s[0] + INV_RRD * d1 + INV_Q2 * d2;
        }
    }
    __syncthreads();

    // ---- phase 3: 64x72x352 fp16 GEMM (8 warps: 4 m-tiles x 2 n-groups) ----
    int w = t >> 5, l = t & 31;
    int m0w = (w >> 1) * 16;
    int nh5 = w & 1;
    int nr0 = nh5 * 40;
    float acc[5][4];
#pragma unroll
    for (int j = 0; j < 5; j++)
#pragma unroll
        for (int r = 0; r < 4; r++) acc[j][r] = 0.f;

    uint32_t Qb = smem_u32(smo + OT_QF);
    uint32_t Bb = smem_u32(smo + OT_B);
    uint32_t aad = Qb + (m0w + (l & 15)) * 720 + (l >> 4) * 16;
    uint32_t bpd = Bb + (nr0 + (l & 7) + ((l >> 4) << 3)) * 720 + ((l >> 3) & 1) * 16;
    uint32_t bsd = Bb + (nr0 + 32 + (l & 7)) * 720 + ((l >> 3) & 1) * 16;

    if (nh5 == 0) {
#pragma unroll
        for (int ks = 0; ks < 22; ks++) {
            uint32_t afr[4], bp0[4], bp1[4], bs[2];
            ldsm_x4(afr, aad + ks * 32);
            ldsm_x4(bp0, bpd + ks * 32);
            ldsm_x4(bp1, bpd + 16 * 720 + ks * 32);
            ldsm_x2(bs,  bsd + ks * 32);
            mma_f16(acc[0], afr, bp0);
            mma_f16(acc[1], afr, bp0 + 2);
            mma_f16(acc[2], afr, bp1);
            mma_f16(acc[3], afr, bp1 + 2);
            mma_f16(acc[4], afr, bs);
        }
    } else {
#pragma unroll
        for (int ks = 0; ks < 22; ks++) {
            uint32_t afr[4], bp0[4], bp1[4];
            ldsm_x4(afr, aad + ks * 32);
            ldsm_x4(bp0, bpd + ks * 32);
            ldsm_x4(bp1, bpd + 16 * 720 + ks * 32);
            mma_f16(acc[0], afr, bp0);
            mma_f16(acc[1], afr, bp0 + 2);
            mma_f16(acc[2], afr, bp1);
            mma_f16(acc[3], afr, bp1 + 2);
        }
    }

    // ---- phase 4: denominator + write ----
    int r0 = l >> 2, c0 = (l & 3) * 2;
    if (nh5 == 1 && (l & 3) == 0) {     // local tile 3 = global tile 8 -> col 64
        rs_s[m0w + r0] = acc[3][0];
        rs_s[m0w + r0 + 8] = acc[3][2];
    }
    __syncthreads();
    if (t < 64) z_s[t] = 1.f / (ds_s[t] + rs_s[t] + EPS);
    __syncthreads();

    float z0 = z_s[m0w + r0], z1 = z_s[m0w + r0 + 8];
    size_t rowb0 = (size_t)(tok0 + m0w + r0) * KVO + h * 64;
    size_t rowb1 = (size_t)(tok0 + m0w + r0 + 8) * KVO + h * 64;
    int jmax = nh5 ? 4 : 5;
#pragma unroll
    for (int j = 0; j < 5; j++) {
        if (j >= jmax) break;
        int col = (nh5 * 5 + j) * 8 + c0;
        if (col < 64) {
            *(__half2*)&g_yh[rowb0 + col] =
                __floats2half2_rn(acc[j][0] * z0, acc[j][1] * z0);
            *(__half2*)&g_yh[rowb1 + col] =
                __floats2half2_rn(acc[j][2] * z1, acc[j][3] * z1);
        }
    }
}

// ---------------------------------------------------------------------------
extern "C" void kernel_launch(void* const* d_in, const int* in_sizes, int n_in,
                              void* d_out, int out_size) {
    const float* x  = (const float*)d_in[0];
    const float* Wq = (const float*)d_in[1];
    const float* Wk = (const float*)d_in[2];
    const float* Wv = (const float*)d_in[3];
    const float* Wo = (const float*)d_in[4];
    float* out = (float*)d_out;

    void *pxh2, *pwqk, *pwvh, *pwoh, *pqk, *pvh, *pyh;
    cudaGetSymbolAddress(&pxh2, g_xh2);
    cudaGetSymbolAddress(&pwqk, g_wqk);
    cudaGetSymbolAddress(&pwvh, g_wvh);
    cudaGetSymbolAddress(&pwoh, g_woh);
    cudaGetSymbolAddress(&pqk, g_qk);
    cudaGetSymbolAddress(&pvh, g_vh);
    cudaGetSymbolAddress(&pyh, g_yh);

    cudaFuncSetAttribute(chunk_state_mma, cudaFuncAttributeMaxDynamicSharedMemorySize, CS_SMEM);
    cudaFuncSetAttribute(output_mma, cudaFuncAttributeMaxDynamicSharedMemorySize, OT_SMEM);
    cudaFuncSetAttribute(proj_gemm, cudaFuncAttributeMaxDynamicSharedMemorySize, GEMM_SMEM);
    cudaFuncSetAttribute(gemm_o, cudaFuncAttributeMaxDynamicSharedMemorySize, GEMM_SMEM);

    // split/convert inputs (fused)
    prep_kernel<<<4096 + 80 * 32, 256>>>(x, Wq, Wk, Wv, Wo);

    // fused q/k + v projections on tensor cores
    proj_gemm<<<384, 256, GEMM_SMEM>>>((const __half*)pxh2, (const __half*)pwqk, (float*)pqk,
                                       (const __half*)pwvh, (__half*)pvh);

    // chunked linear attention
    chunk_state_mma<<<NBH * NC, 256, CS_SMEM>>>();
    scan_all<<<SCAN_S_BLOCKS + SCAN_SS_BLOCKS, 256>>>();
    output_mma<<<NBH * NC, 256, OT_SMEM>>>();

    // final projection
    gemm_o<<<dim3(8, 32), 256, GEMM_SMEM>>>((const __half*)pyh, (const __half*)pwoh, out);
}

// round 13
// speedup vs baseline: 5.8080x; 1.0568x over previous
#include <cuda_runtime.h>
#include <cuda_bf16.h>
#include <cuda_fp16.h>
#include <cstdint>

// Problem constants
#define BB 2
#define LL 2048
#define DM 1024
#define NH 16
#define FD 16
#define HD 64
#define DF 273          // 1 + 16 + 256
#define DFP 288         // DF padded to 18 n8-tiles for mma
#define CHUNK 64
#define NC 32           // LL / CHUNK
#define NBH 32          // BB * NH
#define INV_RRD 0.5f
#define INV_Q2 0.17677669529663687f   // 1/(4*sqrt(2))
#define EPS 1e-12f

#define KP 1024         // unified K for all projections (single-term fp16)

// ---------------------------------------------------------------------------
// Scratch (device globals; no allocation)
// ---------------------------------------------------------------------------
__device__ __half g_xh[4096 * KP];              // x fp16
__device__ __half g_wqk[512 * KP];              // [Wq|Wk]^T fp16
__device__ __half g_wvh[1024 * KP];             // Wv^T fp16
__device__ __half g_woh[1024 * KP];             // Wo^T fp16
__device__ float g_qk[4096 * 512];              // q (cols 0..255) | k (256..511)
__device__ __half g_vh[4096 * 1024];            // v fp16
__device__ __half g_yh[4096 * KP];              // y fp16
__device__ __half g_Sh[(size_t)NBH * NC * 64 * DFP];  // chunk states, e-major S^T (fp16)
__device__ float g_ss[NBH * NC * DF];

// ---------------------------------------------------------------------------
// PTX helpers (baseline sm_80-compatible: ldmatrix, mma.sync, cp.async)
// ---------------------------------------------------------------------------
__device__ __forceinline__ uint32_t smem_u32(const void* p) {
    uint32_t a;
    asm("{ .reg .u64 t; cvta.to.shared.u64 t, %1; cvt.u32.u64 %0, t; }" : "=r"(a) : "l"(p));
    return a;
}
__device__ __forceinline__ void ldsm_x4(uint32_t* r, uint32_t addr) {
    asm volatile("ldmatrix.sync.aligned.m8n8.x4.shared.b16 {%0,%1,%2,%3}, [%4];"
        : "=r"(r[0]), "=r"(r[1]), "=r"(r[2]), "=r"(r[3]) : "r"(addr));
}
__device__ __forceinline__ void ldsm_x2(uint32_t* r, uint32_t addr) {
    asm volatile("ldmatrix.sync.aligned.m8n8.x2.shared.b16 {%0,%1}, [%2];"
        : "=r"(r[0]), "=r"(r[1]) : "r"(addr));
}
__device__ __forceinline__ void mma_f16(float* d, const uint32_t* a, const uint32_t* b) {
    asm volatile("mma.sync.aligned.m16n8k16.row.col.f32.f16.f16.f32 "
        "{%0,%1,%2,%3}, {%4,%5,%6,%7}, {%8,%9}, {%0,%1,%2,%3};"
        : "+f"(d[0]), "+f"(d[1]), "+f"(d[2]), "+f"(d[3])
        : "r"(a[0]), "r"(a[1]), "r"(a[2]), "r"(a[3]), "r"(b[0]), "r"(b[1]));
}
#define CP_ASYNC16(dst, src) \
    asm volatile("cp.async.cg.shared.global [%0], [%1], 16;" :: "r"(dst), "l"(src))
#define CP_COMMIT() asm volatile("cp.async.commit_group;" ::: "memory")
#define CP_WAIT(n)  asm volatile("cp.async.wait_group %0;" :: "n"(n) : "memory")

// ---------------------------------------------------------------------------
// Fused prep: blocks 0..4095 convert x (fp16); blocks 4096.. split weights.
// ---------------------------------------------------------------------------
union HF2U { __half2 h; uint32_t u; };

__global__ void prep_kernel(const float* __restrict__ x,
                            const float* __restrict__ Wq, const float* __restrict__ Wk,
                            const float* __restrict__ Wv, const float* __restrict__ Wo) {
    __shared__ float tile[32][33];
    int blk = blockIdx.x;
    if (blk < 4096) {
        int idx = blk * 256 + threadIdx.x;
        int m = idx >> 8, k4 = (idx & 255) << 2;
        float4 v = *(const float4*)&x[(size_t)m * 1024 + k4];
        HF2U u0; u0.h = __floats2half2_rn(v.x, v.y);
        HF2U u1; u1.h = __floats2half2_rn(v.z, v.w);
        *(uint2*)&g_xh[(size_t)m * KP + k4] = make_uint2(u0.u, u1.u);
        return;
    }
    // weight split part: 80 x 32 virtual grid
    int b2i = blk - 4096;
    int bx = b2i % 80, k0 = (b2i / 80) * 32;
    const float* W;
    int Ncols, n0, mode, rowoff = 0;
    if (bx < 8)       { W = Wq; Ncols = 256;  n0 = bx * 32;        mode = 0; rowoff = 0;   }
    else if (bx < 16) { W = Wk; Ncols = 256;  n0 = (bx - 8) * 32;  mode = 0; rowoff = 256; }
    else if (bx < 48) { W = Wv; Ncols = 1024; n0 = (bx - 16) * 32; mode = 1; }
    else              { W = Wo; Ncols = 1024; n0 = (bx - 48) * 32; mode = 2; }
    int tx = threadIdx.x & 31, ty = threadIdx.x >> 5;  // 32 x 8
    for (int i = ty; i < 32; i += 8)
        tile[i][tx] = W[(size_t)(k0 + i) * Ncols + n0 + tx];
    __syncthreads();
    for (int i = ty; i < 32; i += 8) {
        int n = n0 + i, k = k0 + tx;
        __half hv = __float2half_rn(tile[tx][i]);
        if (mode == 0)      g_wqk[(size_t)(rowoff + n) * KP + k] = hv;
        else if (mode == 1) g_wvh[(size_t)n * KP + k] = hv;
        else                g_woh[(size_t)n * KP + k] = hv;
    }
}

// ---------------------------------------------------------------------------
// mma.sync fp16 GEMM body: C (M x N) tile (m0,n0) = A @ Bt^T
// ---------------------------------------------------------------------------
#define SMA(b) ((b) * 32768)
#define SMB(b) ((b) * 32768 + 16384)
#define GEMM_SMEM 98304

__device__ __forceinline__ void gemm_load_tile(const __half* A, const __half* B,
                                               char* sm, int m0, int n0, int kb, int buf,
                                               int t, int lda, int ldb) {
#pragma unroll
    for (int i = 0; i < 8; i++) {
        int idx = t + i * 256;            // 0..2047
        int row = (idx & 1023) >> 3, c = idx & 7;
        uint32_t dst;
        const __half* src;
        if (idx < 1024) {
            src = A + (size_t)(m0 + row) * lda + kb * 64 + c * 8;
            dst = smem_u32(sm + SMA(buf) + row * 128 + ((c ^ (row & 7)) << 4));
        } else {
            src = B + (size_t)(n0 + row) * ldb + kb * 64 + c * 8;
            dst = smem_u32(sm + SMB(buf) + row * 128 + ((c ^ (row & 7)) << 4));
        }
        CP_ASYNC16(dst, src);
    }
}

template<bool HOUT>
__device__ __forceinline__ void gemm_body(const __half* __restrict__ A,
                                          const __half* __restrict__ B,
                                          void* __restrict__ Cv,
                                          int N, int lda, int ldb, int nkt,
                                          int m0, int n0, char* sm, int t) {
    int w = t >> 5, l = t & 31;
    int wm = (w >> 2) * 64, wn = (w & 3) * 32;

    float acc[4][4][4];
#pragma unroll
    for (int i = 0; i < 4; i++)
#pragma unroll
        for (int j = 0; j < 4; j++)
#pragma unroll
            for (int r = 0; r < 4; r++) acc[i][j][r] = 0.f;

    int ar = wm + (l & 15);
    int ac = (l >> 4);
    int brow = wn + (l & 7) + ((l >> 4) << 3);   // base row for paired-B ldsm
    int bkh = (l >> 3) & 1;

    gemm_load_tile(A, B, sm, m0, n0, 0, 0, t, lda, ldb);
    CP_COMMIT();
    gemm_load_tile(A, B, sm, m0, n0, 1, 1, t, lda, ldb);
    CP_COMMIT();

    int buf = 0;
    for (int kt = 0; kt < nkt; kt++) {
        if (kt + 2 < nkt) {
            int lb = buf + 2; if (lb >= 3) lb -= 3;
            gemm_load_tile(A, B, sm, m0, n0, kt + 2, lb, t, lda, ldb);
        }
        CP_COMMIT();
        CP_WAIT(2);
        __syncthreads();

        uint32_t Ab = smem_u32(sm + SMA(buf));
        uint32_t Bb = smem_u32(sm + SMB(buf));
#pragma unroll
        for (int ks = 0; ks < 4; ks++) {
            uint32_t afr[4][4], bfr[4][2];
#pragma unroll
            for (int mi = 0; mi < 4; mi++) {
                int row = ar + mi * 16;
                int ch = ks * 2 + ac;
                ldsm_x4(afr[mi], Ab + row * 128 + ((ch ^ (row & 7)) << 4));
            }
#pragma unroll
            for (int p = 0; p < 2; p++) {
                uint32_t bp[4];
                int row = brow + p * 16;
                int ch = ks * 2 + bkh;
                ldsm_x4(bp, Bb + row * 128 + ((ch ^ (row & 7)) << 4));
                bfr[2 * p][0] = bp[0]; bfr[2 * p][1] = bp[1];
                bfr[2 * p + 1][0] = bp[2]; bfr[2 * p + 1][1] = bp[3];
            }
#pragma unroll
            for (int mi = 0; mi < 4; mi++)
#pragma unroll
                for (int ni = 0; ni < 4; ni++)
                    mma_f16(acc[mi][ni], afr[mi], bfr[ni]);
        }
        __syncthreads();
        if (++buf == 3) buf = 0;
    }

    int r0 = l >> 2, c0 = (l & 3) * 2;
#pragma unroll
    for (int mi = 0; mi < 4; mi++) {
#pragma unroll
        for (int ni = 0; ni < 4; ni++) {
            int row = m0 + wm + mi * 16 + r0;
            int col = n0 + wn + ni * 8 + c0;
            if constexpr (HOUT) {
                __half* C = (__half*)Cv;
                *(__half2*)&C[(size_t)row * N + col] =
                    __floats2half2_rn(acc[mi][ni][0], acc[mi][ni][1]);
                *(__half2*)&C[(size_t)(row + 8) * N + col] =
                    __floats2half2_rn(acc[mi][ni][2], acc[mi][ni][3]);
            } else {
                float* C = (float*)Cv;
                *(float2*)(C + (size_t)row * N + col) = make_float2(acc[mi][ni][0], acc[mi][ni][1]);
                *(float2*)(C + (size_t)(row + 8) * N + col) = make_float2(acc[mi][ni][2], acc[mi][ni][3]);
            }
        }
    }
}

// Fused q/k + v projections: CTAs 0..127 -> qk (N=512, fp32 out),
// CTAs 128..383 -> v (N=1024, fp16 out). All K=1024 over g_xh.
__global__ void __launch_bounds__(256, 2)
proj_gemm(const __half* __restrict__ xh, const __half* __restrict__ wqk,
          float* __restrict__ qk,
          const __half* __restrict__ wvh, __half* __restrict__ v) {
    extern __shared__ char sm[];
    int blk = blockIdx.x;
    int t = threadIdx.x;
    if (blk < 128) {
        gemm_body<false>(xh, wqk, qk, 512, KP, KP, KP / 64,
                         (blk >> 2) * 128, (blk & 3) * 128, sm, t);
    } else {
        int b2 = blk - 128;
        gemm_body<true>(xh, wvh, v, 1024, KP, KP, KP / 64,
                        (b2 >> 3) * 128, (b2 & 7) * 128, sm, t);
    }
}

// Standalone o-projection GEMM (fp32 out -> harness buffer).
__global__ void __launch_bounds__(256, 2)
gemm_o(const __half* __restrict__ A, const __half* __restrict__ B,
       float* __restrict__ C) {
    extern __shared__ char sm[];
    gemm_body<false>(A, B, C, 1024, KP, KP, KP / 64,
                     blockIdx.y * 128, blockIdx.x * 128, sm, threadIdx.x);
}

// ---------------------------------------------------------------------------
// Per-chunk local state via mma.sync:
// S^T[e][d] = sum_m v[m][e] * phi(k[m])[d]  -> A = v^T (64 x 64), B = kf^T (DFP x 64)
// fp16 v staging; vectorized operand builds; two 9-tile mma passes (3 CTAs/SM).
// ---------------------------------------------------------------------------
#define CS_KFT 0                       // kf^T fp16: 288 rows x 128B = 36864
#define CS_VT  36864                   // v^T  fp16 swizzled: 64 x 128B = 8192
#define CS_KT  45056                   // k^T fp32 [16][65] = 4160
#define CS_VS  49216                   // v stage fp16 [64][65] = 8320
#define CS_SMEM 57536

__global__ void __launch_bounds__(256, 3) chunk_state_mma() {
    extern __shared__ char smc[];
    float* k_T = (float*)(smc + CS_KT);
    __half* v_S = (__half*)(smc + CS_VS);

    int blk = blockIdx.x;
    int c = blk & (NC - 1);
    int bh = blk >> 5;
    int b = bh >> 4, h = bh & 15;
    int t = threadIdx.x;
    long tok0 = (long)b * LL + (long)c * CHUNK;

    // stage k transposed [f][n] (fp32 pad 65) and v as-is [m][e] (fp16 pad 65)
    for (int i = t; i < 64 * 16; i += 256) {
        int n = i >> 4, f = i & 15;
        k_T[f * 65 + n] = g_qk[(tok0 + n) * 512 + 256 + h * 16 + f];
    }
    for (int i = t; i < 4096; i += 256) {
        int m = i >> 6, e = i & 63;
        v_S[m * 65 + e] = g_vh[(tok0 + m) * 1024 + h * 64 + e];
    }
    __syncthreads();

    // v^T fp16 swizzled: one uint4 per (e, chunk); transpose from v_S
    for (int i = t; i < 512; i += 256) {
        int e = i >> 3, c8 = i & 7;
        int m0 = (c8 ^ (e & 7)) * 8;
        uint4 u;
        __half* hp = (__half*)&u;
#pragma unroll
        for (int j = 0; j < 8; j++) hp[j] = v_S[(m0 + j) * 65 + e];
        *(uint4*)(smc + CS_VT + e * 128 + c8 * 16) = u;
    }

    // kf^T fp16 swizzled: one uint4 per (d, chunk)
    for (int i = t; i < DFP * 8; i += 256) {
        int d = i >> 3, c8 = i & 7;
        int mg = c8 ^ (d & 7);
        int m0 = mg * 8;
        uint4 u;
        __half2* hp = (__half2*)&u;
        if (d == 0) {
            __half2 one2 = __floats2half2_rn(1.f, 1.f);
            hp[0] = one2; hp[1] = one2; hp[2] = one2; hp[3] = one2;
        } else if (d <= 16) {
            const float* kr = &k_T[(d - 1) * 65 + m0];
            hp[0] = __floats2half2_rn(kr[0] * INV_RRD, kr[1] * INV_RRD);
            hp[1] = __floats2half2_rn(kr[2] * INV_RRD, kr[3] * INV_RRD);
            hp[2] = __floats2half2_rn(kr[4] * INV_RRD, kr[5] * INV_RRD);
            hp[3] = __floats2half2_rn(kr[6] * INV_RRD, kr[7] * INV_RRD);
        } else if (d < DF) {
            int dd = d - 17;
            const float* ka = &k_T[(dd >> 4) * 65 + m0];
            const float* kb = &k_T[(dd & 15) * 65 + m0];
            hp[0] = __floats2half2_rn(ka[0] * kb[0] * INV_Q2, ka[1] * kb[1] * INV_Q2);
            hp[1] = __floats2half2_rn(ka[2] * kb[2] * INV_Q2, ka[3] * kb[3] * INV_Q2);
            hp[2] = __floats2half2_rn(ka[4] * kb[4] * INV_Q2, ka[5] * kb[5] * INV_Q2);
            hp[3] = __floats2half2_rn(ka[6] * kb[6] * INV_Q2, ka[7] * kb[7] * INV_Q2);
        } else {
            u = make_uint4(0u, 0u, 0u, 0u);
        }
        *(uint4*)(smc + CS_KFT + d * 128 + c8 * 16) = u;
    }
    __syncthreads();

    // mma: warp w -> e-tile (w>>1); d-tiles (w&1)*18 .. +17 in two 9-tile passes
    int w = t >> 5, l = t & 31;
    uint32_t Ab = smem_u32(smc + CS_VT);
    uint32_t Bb = smem_u32(smc + CS_KFT);
    int ar = (w >> 1) * 16 + (l & 15);
    int ac = l >> 4;
    int brow_base = (l & 7) + ((l >> 4) << 3);
    int bkh = (l >> 3) & 1;
    int ntile0 = (w & 1) * 18;
    int r0 = l >> 2, c0 = (l & 3) * 2;
    size_t Sbase = (size_t)blk * 64 * DFP;
    int e_lo = (w >> 1) * 16 + r0;

#pragma unroll
    for (int half = 0; half < 2; half++) {
        int tb = ntile0 + half * 9;
        float acc[9][4];
#pragma unroll
        for (int j = 0; j < 9; j++)
#pragma unroll
            for (int r = 0; r < 4; r++) acc[j][r] = 0.f;

#pragma unroll
        for (int ks = 0; ks < 4; ks++) {
            uint32_t afr[4];
            int ch = ks * 2 + ac;
            ldsm_x4(afr, Ab + ar * 128 + ((ch ^ (ar & 7)) << 4));
            int chb = ks * 2 + bkh;
#pragma unroll
            for (int jp = 0; jp < 4; jp++) {
                uint32_t bp[4];
                int row = (tb + jp * 2) * 8 + brow_base;
                ldsm_x4(bp, Bb + row * 128 + ((chb ^ (row & 7)) << 4));
                mma_f16(acc[jp * 2],     afr, bp);
                mma_f16(acc[jp * 2 + 1], afr, bp + 2);
            }
            {   // last single tile
                uint32_t bs[2];
                int row = (tb + 8) * 8 + (l & 7);
                int chs = ks * 2 + ((l >> 3) & 1);
                ldsm_x2(bs, Bb + row * 128 + ((chs ^ (row & 7)) << 4));
                mma_f16(acc[8], afr, bs);
            }
        }

        // store this half's 9 d-tiles, e-major fp16
#pragma unroll
        for (int j = 0; j < 9; j++) {
            int d = (tb + j) * 8 + c0;
            *(__half2*)&g_Sh[Sbase + (size_t)e_lo * DFP + d] =
                __floats2half2_rn(acc[j][0], acc[j][1]);
            *(__half2*)&g_Sh[Sbase + (size_t)(e_lo + 8) * DFP + d] =
                __floats2half2_rn(acc[j][2], acc[j][3]);
        }
    }

    // ssum[d] = sum_m kf[m][d] from kf^T smem
    for (int d = t; d < DF; d += 256) {
        float s = 0.f;
#pragma unroll
        for (int c8 = 0; c8 < 8; c8++) {
            int off = d * 128 + (((c8 ^ (d & 7))) << 4);
            uint4 u = *(const uint4*)(smc + CS_KFT + off);
            const __half2* hp = (const __half2*)&u;
#pragma unroll
            for (int q = 0; q < 4; q++) {
                float2 f2 = __half22float2(hp[q]);
                s += f2.x + f2.y;
            }
        }
        g_ss[(long)blk * DF + d] = s;
    }
}

// ---------------------------------------------------------------------------
// Fused in-place exclusive prefix scans (S blocks first, then ss blocks)
// ---------------------------------------------------------------------------
#define SCAN_S_BLOCKS 1152   // NBH * (64*DFP/2) / 256
#define SCAN_SS_BLOCKS 35    // ceil(NBH*DF / 256)

__global__ void scan_all() {
    int blk = blockIdx.x;
    if (blk < SCAN_S_BLOCKS) {
        long idx = (long)blk * 256 + threadIdx.x;
        const long PER_BH = 64 * DFP / 2;  // 9216 half2 per chunk
        long bh = idx / PER_BH;
        long de = idx % PER_BH;
        __half2* Sp = (__half2*)g_Sh;
        size_t base = (size_t)bh * NC * PER_BH + de;
        float2 acc = make_float2(0.f, 0.f);
#pragma unroll
        for (int c = 0; c < NC; c++) {
            size_t p = base + (size_t)c * PER_BH;
            float2 tmp = __half22float2(Sp[p]);
            Sp[p] = __floats2half2_rn(acc.x, acc.y);
            acc.x += tmp.x; acc.y += tmp.y;
        }
    } else {
        long idx = (long)(blk - SCAN_S_BLOCKS) * 256 + threadIdx.x;
        if (idx >= (long)NBH * DF) return;
        long bh = idx / DF;
        long d = idx % DF;
        long base = bh * NC * DF + d;
        float acc = 0.f;
#pragma unroll
        for (int c = 0; c < NC; c++) {
            long p = base + (long)c * DF;
            float tmp = g_ss[p];
            g_ss[p] = acc;
            acc += tmp;
        }
    }
}

// ---------------------------------------------------------------------------
// Output via one fused mma GEMM per (bh,chunk):
//   Aop = [phi(q) (64x288) | A_poly (64x64)]  (fp16, padded stride 360)
//   Bop rows (N=72): e<64: [S^T[e] | v^T[e]], row64: [0 | 1...], 65..71: 0
//   denominator = fp32 scalar qf.sp + rowsum(A); y = num * z  (fp16 out)
// ---------------------------------------------------------------------------
#define OTS 360                         // row stride in halves (45 x 16B, odd)
#define OT_QF 0                         // 64 x 720B  = 46080
#define OT_B  46080                     // 72 x 720B  = 51840
#define OT_Q  97920                     // 64x16 fp32 = 4096
#define OT_K  102016                    // 64x16 fp32 = 4096
#define OT_SP 106112                    // 276  fp32  = 1104
#define OT_DS 107216                    // 64 fp32 (+pad)
#define OT_RS 107472                    // 64 fp32 (+pad)
#define OT_Z  107728                    // 64 fp32 (+pad)
#define OT_SMEM 107984

__global__ void __launch_bounds__(256, 2) output_mma() {
    extern __shared__ char smo[];
    float* q_s  = (float*)(smo + OT_Q);
    float* k_s  = (float*)(smo + OT_K);
    float* sp_s = (float*)(smo + OT_SP);
    float* ds_s = (float*)(smo + OT_DS);
    float* rs_s = (float*)(smo + OT_RS);
    float* z_s  = (float*)(smo + OT_Z);
    __half* qf  = (__half*)(smo + OT_QF);
    __half* Bx  = (__half*)(smo + OT_B);

    int blk = blockIdx.x;
    int c = blk & (NC - 1);
    int bh = blk >> 5;
    int b = bh >> 4, h = bh & 15;
    int t = threadIdx.x;
    long tok0 = (long)b * LL + (long)c * CHUNK;

    // ---- phase 1: loads ----
    {   // S^T rows via cp.async (36 uint4 per row)
        const uint4* src = (const uint4*)(g_Sh + (size_t)blk * 64 * DFP);
        for (int i = t; i < 64 * 36; i += 256) {
            int e = i / 36, u = i % 36;
            CP_ASYNC16(smem_u32(smo + OT_B + e * 720 + u * 16), src + i);
        }
        CP_COMMIT();
    }
    for (int i = t; i < 64 * 16; i += 256) {
        int n = i >> 4, f = i & 15;
        long off = (tok0 + n) * 512 + h * 16 + f;
        q_s[i] = g_qk[off];
        k_s[i] = g_qk[off + 256];
    }
    for (int i = t; i < 276; i += 256) sp_s[i] = (i < DF) ? g_ss[(long)blk * DF + i] : 0.f;
    for (int i = t; i < 4096; i += 256) {   // v^T into cols 288..351 (fp16 direct)
        int m = i >> 6, e = i & 63;
        Bx[e * OTS + 288 + m] = g_vh[(tok0 + m) * 1024 + h * 64 + e];
    }
    for (int i = t; i < 8 * 180; i += 256) {    // rows 64..71
        int r = 64 + i / 180, u = i % 180;      // uint (2 halves)
        uint32_t val = (r == 64 && u >= 144 && u < 176) ? 0x3C003C00u : 0u;  // ones over v-cols
        *(uint32_t*)(smo + OT_B + r * 720 + u * 4) = val;
    }
    CP_WAIT(0);
    __syncthreads();

    // ---- phase 2: build A-operand (vectorized) + fp32 denominator part ----
    for (int i = t; i < 64 * 36; i += 256) {    // phi(q): one uint4 per 8 features
        int n = i / 36, d0 = (i % 36) * 8;
        const float* q0 = &q_s[n * 16];
        uint4 u;
        __half2* hp = (__half2*)&u;
#pragma unroll
        for (int p = 0; p < 4; p++) {
            float vv[2];
#pragma unroll
            for (int s2 = 0; s2 < 2; s2++) {
                int d = d0 + p * 2 + s2;
                float val = 0.f;
                if (d == 0) val = 1.f;
                else if (d <= 16) val = q0[d - 1] * INV_RRD;
                else if (d < DF) {
                    int dd = d - 17;
                    val = q0[dd >> 4] * q0[dd & 15] * INV_Q2;
                }
                vv[s2] = val;
            }
            hp[p] = __floats2half2_rn(vv[0], vv[1]);
        }
        *(uint4*)&qf[n * OTS + d0] = u;
    }
    {   // causal polynomial scores into cols 288..351 (thread -> (n, 16 m's))
        int n = t >> 2, mq = (t & 3) << 4;
        float qr[16];
#pragma unroll
        for (int f = 0; f < 16; f++) qr[f] = q_s[n * 16 + f];
#pragma unroll
        for (int mm = 0; mm < 16; mm += 2) {
            float a2[2];
#pragma unroll
            for (int u2 = 0; u2 < 2; u2++) {
                int m = mq + mm + u2;
                float s = 0.f;
#pragma unroll
                for (int f = 0; f < 16; f++) s += qr[f] * k_s[m * 16 + f];
                a2[u2] = (m <= n) ? (1.f + 0.25f * s + s * s * 0.03125f) : 0.f;
            }
            *(__half2*)&qf[n * OTS + 288 + mq + mm] = __floats2half2_rn(a2[0], a2[1]);
        }
        if (t < 64) {                    // fp32 qf . sp
            const float* q0 = &q_s[t * 16];
            float d1 = 0.f;
#pragma unroll
            for (int f = 0; f < 16; f++) d1 += q0[f] * sp_s[1 + f];
            float d2 = 0.f;
            for (int i2 = 0; i2 < 16; i2++) {
                float inner = 0.f;
#pragma unroll
                for (int j = 0; j < 16; j++) inner += q0[j] * sp_s[17 + 16 * i2 + j];
                d2 += q0[i2] * inner;
            }
            ds_s[t] = sp_s[0] + INV_RRD * d1 + INV_Q2 * d2;
        }
    }
    __syncthreads();

    // ---- phase 3: 64x72x352 fp16 GEMM (8 warps: 4 m-tiles x 2 n-groups) ----
    int w = t >> 5, l = t & 31;
    int m0w = (w >> 1) * 16;
    int nh5 = w & 1;
    int nr0 = nh5 * 40;
    float acc[5][4];
#pragma unroll
    for (int j = 0; j < 5; j++)
#pragma unroll
        for (int r = 0; r < 4; r++) acc[j][r] = 0.f;

    uint32_t Qb = smem_u32(smo + OT_QF);
    uint32_t Bb = smem_u32(smo + OT_B);
    uint32_t aad = Qb + (m0w + (l & 15)) * 720 + (l >> 4) * 16;
    uint32_t bpd = Bb + (nr0 + (l & 7) + ((l >> 4) << 3)) * 720 + ((l >> 3) & 1) * 16;
    uint32_t bsd = Bb + (nr0 + 32 + (l & 7)) * 720 + ((l >> 3) & 1) * 16;

    if (nh5 == 0) {
#pragma unroll
        for (int ks = 0; ks < 22; ks++) {
            uint32_t afr[4], bp0[4], bp1[4], bs[2];
            ldsm_x4(afr, aad + ks * 32);
            ldsm_x4(bp0, bpd + ks * 32);
            ldsm_x4(bp1, bpd + 16 * 720 + ks * 32);
            ldsm_x2(bs,  bsd + ks * 32);
            mma_f16(acc[0], afr, bp0);
            mma_f16(acc[1], afr, bp0 + 2);
            mma_f16(acc[2], afr, bp1);
            mma_f16(acc[3], afr, bp1 + 2);
            mma_f16(acc[4], afr, bs);
        }
    } else {
#pragma unroll
        for (int ks = 0; ks < 22; ks++) {
            uint32_t afr[4], bp0[4], bp1[4];
            ldsm_x4(afr, aad + ks * 32);
            ldsm_x4(bp0, bpd + ks * 32);
            ldsm_x4(bp1, bpd + 16 * 720 + ks * 32);
            mma_f16(acc[0], afr, bp0);
            mma_f16(acc[1], afr, bp0 + 2);
            mma_f16(acc[2], afr, bp1);
            mma_f16(acc[3], afr, bp1 + 2);
        }
    }

    // ---- phase 4: denominator + write ----
    int r0 = l >> 2, c0 = (l & 3) * 2;
    if (nh5 == 1 && (l & 3) == 0) {     // local tile 3 = global tile 8 -> col 64
        rs_s[m0w + r0] = acc[3][0];
        rs_s[m0w + r0 + 8] = acc[3][2];
    }
    __syncthreads();
    if (t < 64) z_s[t] = 1.f / (ds_s[t] + rs_s[t] + EPS);
    __syncthreads();

    float z0 = z_s[m0w + r0], z1 = z_s[m0w + r0 + 8];
    size_t rowb0 = (size_t)(tok0 + m0w + r0) * KP + h * 64;
    size_t rowb1 = (size_t)(tok0 + m0w + r0 + 8) * KP + h * 64;
    int jmax = nh5 ? 4 : 5;
#pragma unroll
    for (int j = 0; j < 5; j++) {
        if (j >= jmax) break;
        int col = (nh5 * 5 + j) * 8 + c0;
        if (col < 64) {
            *(__half2*)&g_yh[rowb0 + col] =
                __floats2half2_rn(acc[j][0] * z0, acc[j][1] * z0);
            *(__half2*)&g_yh[rowb1 + col] =
                __floats2half2_rn(acc[j][2] * z1, acc[j][3] * z1);
        }
    }
}

// ---------------------------------------------------------------------------
extern "C" void kernel_launch(void* const* d_in, const int* in_sizes, int n_in,
                              void* d_out, int out_size) {
    const float* x  = (const float*)d_in[0];
    const float* Wq = (const float*)d_in[1];
    const float* Wk = (const float*)d_in[2];
    const float* Wv = (const float*)d_in[3];
    const float* Wo = (const float*)d_in[4];
    float* out = (float*)d_out;

    void *pxh, *pwqk, *pwvh, *pwoh, *pqk, *pvh, *pyh;
    cudaGetSymbolAddress(&pxh, g_xh);
    cudaGetSymbolAddress(&pwqk, g_wqk);
    cudaGetSymbolAddress(&pwvh, g_wvh);
    cudaGetSymbolAddress(&pwoh, g_woh);
    cudaGetSymbolAddress(&pqk, g_qk);
    cudaGetSymbolAddress(&pvh, g_vh);
    cudaGetSymbolAddress(&pyh, g_yh);

    cudaFuncSetAttribute(chunk_state_mma, cudaFuncAttributeMaxDynamicSharedMemorySize, CS_SMEM);
    cudaFuncSetAttribute(output_mma, cudaFuncAttributeMaxDynamicSharedMemorySize, OT_SMEM);
    cudaFuncSetAttribute(proj_gemm, cudaFuncAttributeMaxDynamicSharedMemorySize, GEMM_SMEM);
    cudaFuncSetAttribute(gemm_o, cudaFuncAttributeMaxDynamicSharedMemorySize, GEMM_SMEM);

    // split/convert inputs (fused)
    prep_kernel<<<4096 + 80 * 32, 256>>>(x, Wq, Wk, Wv, Wo);

    // fused q/k + v projections on tensor cores
    proj_gemm<<<384, 256, GEMM_SMEM>>>((const __half*)pxh, (const __half*)pwqk, (float*)pqk,
                                       (const __half*)pwvh, (__half*)pvh);

    // chunked linear attention
    chunk_state_mma<<<NBH * NC, 256, CS_SMEM>>>();
    scan_all<<<SCAN_S_BLOCKS + SCAN_SS_BLOCKS, 256>>>();
    output_mma<<<NBH * NC, 256, OT_SMEM>>>();

    // final projection
    gemm_o<<<dim3(8, 32), 256, GEMM_SMEM>>>((const __half*)pyh, (const __half*)pwoh, out);
}

// round 14
// speedup vs baseline: 6.1241x; 1.0544x over previous
#include <cuda_runtime.h>
#include <cuda_bf16.h>
#include <cuda_fp16.h>
#include <cstdint>

// Problem constants
#define BB 2
#define LL 2048
#define DM 1024
#define NH 16
#define FD 16
#define HD 64
#define DF 273          // 1 + 16 + 256
#define DFP 288         // DF padded to 18 n8-tiles for mma
#define CHUNK 64
#define NC 32           // LL / CHUNK
#define NBH 32          // BB * NH
#define INV_RRD 0.5f
#define INV_Q2 0.17677669529663687f   // 1/(4*sqrt(2))
#define EPS 1e-12f

#define KP 1024         // unified K for all projections (single-term fp16)

// ---------------------------------------------------------------------------
// Scratch (device globals; no allocation)
// ---------------------------------------------------------------------------
__device__ __half g_xh[4096 * KP];              // x fp16
__device__ __half g_wqk[512 * KP];              // [Wq|Wk]^T fp16
__device__ __half g_wvh[1024 * KP];             // Wv^T fp16
__device__ __half g_woh[1024 * KP];             // Wo^T fp16
__device__ float g_qk[4096 * 512];              // q (cols 0..255) | k (256..511)
__device__ __half g_vh[4096 * 1024];            // v fp16
__device__ __half g_yh[4096 * KP];              // y fp16
__device__ __half g_Sh[(size_t)NBH * NC * 64 * DFP];  // chunk states, e-major S^T (fp16)
__device__ float g_ss[NBH * NC * DF];

// ---------------------------------------------------------------------------
// PTX helpers (baseline sm_80-compatible: ldmatrix, mma.sync, cp.async)
// ---------------------------------------------------------------------------
__device__ __forceinline__ uint32_t smem_u32(const void* p) {
    uint32_t a;
    asm("{ .reg .u64 t; cvta.to.shared.u64 t, %1; cvt.u32.u64 %0, t; }" : "=r"(a) : "l"(p));
    return a;
}
__device__ __forceinline__ void ldsm_x4(uint32_t* r, uint32_t addr) {
    asm volatile("ldmatrix.sync.aligned.m8n8.x4.shared.b16 {%0,%1,%2,%3}, [%4];"
        : "=r"(r[0]), "=r"(r[1]), "=r"(r[2]), "=r"(r[3]) : "r"(addr));
}
__device__ __forceinline__ void ldsm_x4_trans(uint32_t* r, uint32_t addr) {
    asm volatile("ldmatrix.sync.aligned.m8n8.x4.trans.shared.b16 {%0,%1,%2,%3}, [%4];"
        : "=r"(r[0]), "=r"(r[1]), "=r"(r[2]), "=r"(r[3]) : "r"(addr));
}
__device__ __forceinline__ void ldsm_x2(uint32_t* r, uint32_t addr) {
    asm volatile("ldmatrix.sync.aligned.m8n8.x2.shared.b16 {%0,%1}, [%2];"
        : "=r"(r[0]), "=r"(r[1]) : "r"(addr));
}
__device__ __forceinline__ void mma_f16(float* d, const uint32_t* a, const uint32_t* b) {
    asm volatile("mma.sync.aligned.m16n8k16.row.col.f32.f16.f16.f32 "
        "{%0,%1,%2,%3}, {%4,%5,%6,%7}, {%8,%9}, {%0,%1,%2,%3};"
        : "+f"(d[0]), "+f"(d[1]), "+f"(d[2]), "+f"(d[3])
        : "r"(a[0]), "r"(a[1]), "r"(a[2]), "r"(a[3]), "r"(b[0]), "r"(b[1]));
}
#define CP_ASYNC16(dst, src) \
    asm volatile("cp.async.cg.shared.global [%0], [%1], 16;" :: "r"(dst), "l"(src))
#define CP_COMMIT() asm volatile("cp.async.commit_group;" ::: "memory")
#define CP_WAIT(n)  asm volatile("cp.async.wait_group %0;" :: "n"(n) : "memory")

// ---------------------------------------------------------------------------
// Fused prep: blocks 0..4095 convert x (fp16); blocks 4096.. split weights.
// ---------------------------------------------------------------------------
union HF2U { __half2 h; uint32_t u; };

__global__ void prep_kernel(const float* __restrict__ x,
                            const float* __restrict__ Wq, const float* __restrict__ Wk,
                            const float* __restrict__ Wv, const float* __restrict__ Wo) {
    __shared__ float tile[32][33];
    int blk = blockIdx.x;
    if (blk < 4096) {
        int idx = blk * 256 + threadIdx.x;
        int m = idx >> 8, k4 = (idx & 255) << 2;
        float4 v = *(const float4*)&x[(size_t)m * 1024 + k4];
        HF2U u0; u0.h = __floats2half2_rn(v.x, v.y);
        HF2U u1; u1.h = __floats2half2_rn(v.z, v.w);
        *(uint2*)&g_xh[(size_t)m * KP + k4] = make_uint2(u0.u, u1.u);
        return;
    }
    // weight split part: 80 x 32 virtual grid
    int b2i = blk - 4096;
    int bx = b2i % 80, k0 = (b2i / 80) * 32;
    const float* W;
    int Ncols, n0, mode, rowoff = 0;
    if (bx < 8)       { W = Wq; Ncols = 256;  n0 = bx * 32;        mode = 0; rowoff = 0;   }
    else if (bx < 16) { W = Wk; Ncols = 256;  n0 = (bx - 8) * 32;  mode = 0; rowoff = 256; }
    else if (bx < 48) { W = Wv; Ncols = 1024; n0 = (bx - 16) * 32; mode = 1; }
    else              { W = Wo; Ncols = 1024; n0 = (bx - 48) * 32; mode = 2; }
    int tx = threadIdx.x & 31, ty = threadIdx.x >> 5;  // 32 x 8
    for (int i = ty; i < 32; i += 8)
        tile[i][tx] = W[(size_t)(k0 + i) * Ncols + n0 + tx];
    __syncthreads();
    for (int i = ty; i < 32; i += 8) {
        int n = n0 + i, k = k0 + tx;
        __half hv = __float2half_rn(tile[tx][i]);
        if (mode == 0)      g_wqk[(size_t)(rowoff + n) * KP + k] = hv;
        else if (mode == 1) g_wvh[(size_t)n * KP + k] = hv;
        else                g_woh[(size_t)n * KP + k] = hv;
    }
}

// ---------------------------------------------------------------------------
// mma.sync fp16 GEMM body: C (M x N) tile (m0,n0) = A @ Bt^T
// ---------------------------------------------------------------------------
#define SMA(b) ((b) * 32768)
#define SMB(b) ((b) * 32768 + 16384)
#define GEMM_SMEM 98304

__device__ __forceinline__ void gemm_load_tile(const __half* A, const __half* B,
                                               char* sm, int m0, int n0, int kb, int buf,
                                               int t, int lda, int ldb) {
#pragma unroll
    for (int i = 0; i < 8; i++) {
        int idx = t + i * 256;            // 0..2047
        int row = (idx & 1023) >> 3, c = idx & 7;
        uint32_t dst;
        const __half* src;
        if (idx < 1024) {
            src = A + (size_t)(m0 + row) * lda + kb * 64 + c * 8;
            dst = smem_u32(sm + SMA(buf) + row * 128 + ((c ^ (row & 7)) << 4));
        } else {
            src = B + (size_t)(n0 + row) * ldb + kb * 64 + c * 8;
            dst = smem_u32(sm + SMB(buf) + row * 128 + ((c ^ (row & 7)) << 4));
        }
        CP_ASYNC16(dst, src);
    }
}

template<bool HOUT>
__device__ __forceinline__ void gemm_body(const __half* __restrict__ A,
                                          const __half* __restrict__ B,
                                          void* __restrict__ Cv,
                                          int N, int lda, int ldb, int nkt,
                                          int m0, int n0, char* sm, int t) {
    int w = t >> 5, l = t & 31;
    int wm = (w >> 2) * 64, wn = (w & 3) * 32;

    float acc[4][4][4];
#pragma unroll
    for (int i = 0; i < 4; i++)
#pragma unroll
        for (int j = 0; j < 4; j++)
#pragma unroll
            for (int r = 0; r < 4; r++) acc[i][j][r] = 0.f;

    int ar = wm + (l & 15);
    int ac = (l >> 4);
    int brow = wn + (l & 7) + ((l >> 4) << 3);   // base row for paired-B ldsm
    int bkh = (l >> 3) & 1;

    gemm_load_tile(A, B, sm, m0, n0, 0, 0, t, lda, ldb);
    CP_COMMIT();
    gemm_load_tile(A, B, sm, m0, n0, 1, 1, t, lda, ldb);
    CP_COMMIT();

    int buf = 0;
    for (int kt = 0; kt < nkt; kt++) {
        if (kt + 2 < nkt) {
            int lb = buf + 2; if (lb >= 3) lb -= 3;
            gemm_load_tile(A, B, sm, m0, n0, kt + 2, lb, t, lda, ldb);
        }
        CP_COMMIT();
        CP_WAIT(2);
        __syncthreads();

        uint32_t Ab = smem_u32(sm + SMA(buf));
        uint32_t Bb = smem_u32(sm + SMB(buf));
#pragma unroll
        for (int ks = 0; ks < 4; ks++) {
            uint32_t afr[4][4], bfr[4][2];
#pragma unroll
            for (int mi = 0; mi < 4; mi++) {
                int row = ar + mi * 16;
                int ch = ks * 2 + ac;
                ldsm_x4(afr[mi], Ab + row * 128 + ((ch ^ (row & 7)) << 4));
            }
#pragma unroll
            for (int p = 0; p < 2; p++) {
                uint32_t bp[4];
                int row = brow + p * 16;
                int ch = ks * 2 + bkh;
                ldsm_x4(bp, Bb + row * 128 + ((ch ^ (row & 7)) << 4));
                bfr[2 * p][0] = bp[0]; bfr[2 * p][1] = bp[1];
                bfr[2 * p + 1][0] = bp[2]; bfr[2 * p + 1][1] = bp[3];
            }
#pragma unroll
            for (int mi = 0; mi < 4; mi++)
#pragma unroll
                for (int ni = 0; ni < 4; ni++)
                    mma_f16(acc[mi][ni], afr[mi], bfr[ni]);
        }
        __syncthreads();
        if (++buf == 3) buf = 0;
    }

    int r0 = l >> 2, c0 = (l & 3) * 2;
#pragma unroll
    for (int mi = 0; mi < 4; mi++) {
#pragma unroll
        for (int ni = 0; ni < 4; ni++) {
            int row = m0 + wm + mi * 16 + r0;
            int col = n0 + wn + ni * 8 + c0;
            if constexpr (HOUT) {
                __half* C = (__half*)Cv;
                *(__half2*)&C[(size_t)row * N + col] =
                    __floats2half2_rn(acc[mi][ni][0], acc[mi][ni][1]);
                *(__half2*)&C[(size_t)(row + 8) * N + col] =
                    __floats2half2_rn(acc[mi][ni][2], acc[mi][ni][3]);
            } else {
                float* C = (float*)Cv;
                *(float2*)(C + (size_t)row * N + col) = make_float2(acc[mi][ni][0], acc[mi][ni][1]);
                *(float2*)(C + (size_t)(row + 8) * N + col) = make_float2(acc[mi][ni][2], acc[mi][ni][3]);
            }
        }
    }
}

// Fused q/k + v projections: CTAs 0..127 -> qk (N=512, fp32 out),
// CTAs 128..383 -> v (N=1024, fp16 out). All K=1024 over g_xh.
__global__ void __launch_bounds__(256, 2)
proj_gemm(const __half* __restrict__ xh, const __half* __restrict__ wqk,
          float* __restrict__ qk,
          const __half* __restrict__ wvh, __half* __restrict__ v) {
    extern __shared__ char sm[];
    int blk = blockIdx.x;
    int t = threadIdx.x;
    if (blk < 128) {
        gemm_body<false>(xh, wqk, qk, 512, KP, KP, KP / 64,
                         (blk >> 2) * 128, (blk & 3) * 128, sm, t);
    } else {
        int b2 = blk - 128;
        gemm_body<true>(xh, wvh, v, 1024, KP, KP, KP / 64,
                        (b2 >> 3) * 128, (b2 & 7) * 128, sm, t);
    }
}

// Standalone o-projection GEMM (fp32 out -> harness buffer).
__global__ void __launch_bounds__(256, 2)
gemm_o(const __half* __restrict__ A, const __half* __restrict__ B,
       float* __restrict__ C) {
    extern __shared__ char sm[];
    gemm_body<false>(A, B, C, 1024, KP, KP, KP / 64,
                     blockIdx.y * 128, blockIdx.x * 128, sm, threadIdx.x);
}

// ---------------------------------------------------------------------------
// Per-chunk local state via mma.sync:
// S^T[e][d] = sum_m v[m][e] * phi(k[m])[d]
// A-operand = v^T via ldmatrix.trans on the raw [m][e] tile (no transpose pass).
// kf^T built with float4 loads (k_T stride 68, 16B-aligned rows).
// Two 9-tile mma passes; 4 CTAs/SM.
// ---------------------------------------------------------------------------
#define CS_KFT 0                       // kf^T fp16 swizzled: 288 x 128B = 36864
#define CS_KT  36864                   // k^T fp32 [16][68] = 4352
#define CS_VS  41216                   // v fp16 [m][e] stride 72 halves = 9216
#define CS_SMEM 50432
#define VS_STRIDE_B 144                // 72 halves per row

__global__ void __launch_bounds__(256, 4) chunk_state_mma() {
    extern __shared__ char smc[];
    float* k_T = (float*)(smc + CS_KT);

    int blk = blockIdx.x;
    int c = blk & (NC - 1);
    int bh = blk >> 5;
    int b = bh >> 4, h = bh & 15;
    int t = threadIdx.x;
    long tok0 = (long)b * LL + (long)c * CHUNK;

    // v tile [m][e] fp16 via cp.async (coalesced, 512 x 16B)
    for (int i = t; i < 512; i += 256) {
        int m = i >> 3, e8 = i & 7;
        CP_ASYNC16(smem_u32(smc + CS_VS + m * VS_STRIDE_B + e8 * 16),
                   g_vh + (tok0 + m) * 1024 + h * 64 + e8 * 8);
    }
    CP_COMMIT();

    // k transposed [f][n] fp32 (stride 68 -> rows 16B-aligned)
    for (int i = t; i < 64 * 16; i += 256) {
        int n = i >> 4, f = i & 15;
        k_T[f * 68 + n] = g_qk[(tok0 + n) * 512 + 256 + h * 16 + f];
    }
    __syncthreads();

    // kf^T fp16 swizzled: one uint4 per (d, chunk); float4 source loads
    for (int i = t; i < DFP * 8; i += 256) {
        int d = i >> 3, c8 = i & 7;
        int m0 = (c8 ^ (d & 7)) * 8;
        uint4 u;
        __half2* hp = (__half2*)&u;
        if (d == 0) {
            __half2 one2 = __floats2half2_rn(1.f, 1.f);
            hp[0] = one2; hp[1] = one2; hp[2] = one2; hp[3] = one2;
        } else if (d <= 16) {
            const float4* kr = (const float4*)&k_T[(d - 1) * 68 + m0];
            float4 a0 = kr[0], a1 = kr[1];
            hp[0] = __floats2half2_rn(a0.x * INV_RRD, a0.y * INV_RRD);
            hp[1] = __floats2half2_rn(a0.z * INV_RRD, a0.w * INV_RRD);
            hp[2] = __floats2half2_rn(a1.x * INV_RRD, a1.y * INV_RRD);
            hp[3] = __floats2half2_rn(a1.z * INV_RRD, a1.w * INV_RRD);
        } else if (d < DF) {
            int dd = d - 17;
            const float4* ka = (const float4*)&k_T[(dd >> 4) * 68 + m0];
            const float4* kb = (const float4*)&k_T[(dd & 15) * 68 + m0];
            float4 a0 = ka[0], a1 = ka[1], b0 = kb[0], b1 = kb[1];
            hp[0] = __floats2half2_rn(a0.x * b0.x * INV_Q2, a0.y * b0.y * INV_Q2);
            hp[1] = __floats2half2_rn(a0.z * b0.z * INV_Q2, a0.w * b0.w * INV_Q2);
            hp[2] = __floats2half2_rn(a1.x * b1.x * INV_Q2, a1.y * b1.y * INV_Q2);
            hp[3] = __floats2half2_rn(a1.z * b1.z * INV_Q2, a1.w * b1.w * INV_Q2);
        } else {
            u = make_uint4(0u, 0u, 0u, 0u);
        }
        *(uint4*)(smc + CS_KFT + d * 128 + c8 * 16) = u;
    }
    CP_WAIT(0);
    __syncthreads();

    // mma: warp w -> e-tile (w>>1); d-tiles (w&1)*18 .. +17 in two 9-tile passes
    int w = t >> 5, l = t & 31;
    uint32_t VSb = smem_u32(smc + CS_VS);
    uint32_t Bb = smem_u32(smc + CS_KFT);
    // A (v^T) fragment via ldmatrix.trans: lane -> v row / e-col
    int e0 = (w >> 1) * 16;
    int vrow_off = ((l >> 4) << 3) + (l & 7);            // + ks*16
    int veoff = e0 + (((l >> 3) & 1) << 3);
    uint32_t vaddr = VSb + vrow_off * VS_STRIDE_B + veoff * 2;
    int brow_base = (l & 7) + ((l >> 4) << 3);
    int bkh = (l >> 3) & 1;
    int ntile0 = (w & 1) * 18;
    int r0 = l >> 2, c0 = (l & 3) * 2;
    size_t Sbase = (size_t)blk * 64 * DFP;
    int e_lo = e0 + r0;

#pragma unroll
    for (int half = 0; half < 2; half++) {
        int tb = ntile0 + half * 9;
        float acc[9][4];
#pragma unroll
        for (int j = 0; j < 9; j++)
#pragma unroll
            for (int r = 0; r < 4; r++) acc[j][r] = 0.f;

#pragma unroll
        for (int ks = 0; ks < 4; ks++) {
            uint32_t afr[4];
            ldsm_x4_trans(afr, vaddr + ks * 16 * VS_STRIDE_B);
            int chb = ks * 2 + bkh;
#pragma unroll
            for (int jp = 0; jp < 4; jp++) {
                uint32_t bp[4];
                int row = (tb + jp * 2) * 8 + brow_base;
                ldsm_x4(bp, Bb + row * 128 + ((chb ^ (row & 7)) << 4));
                mma_f16(acc[jp * 2],     afr, bp);
                mma_f16(acc[jp * 2 + 1], afr, bp + 2);
            }
            {   // last single tile
                uint32_t bs[2];
                int row = (tb + 8) * 8 + (l & 7);
                int chs = ks * 2 + ((l >> 3) & 1);
                ldsm_x2(bs, Bb + row * 128 + ((chs ^ (row & 7)) << 4));
                mma_f16(acc[8], afr, bs);
            }
        }

        // store this half's 9 d-tiles, e-major fp16
#pragma unroll
        for (int j = 0; j < 9; j++) {
            int d = (tb + j) * 8 + c0;
            *(__half2*)&g_Sh[Sbase + (size_t)e_lo * DFP + d] =
                __floats2half2_rn(acc[j][0], acc[j][1]);
            *(__half2*)&g_Sh[Sbase + (size_t)(e_lo + 8) * DFP + d] =
                __floats2half2_rn(acc[j][2], acc[j][3]);
        }
    }

    // ssum[d] = sum_m kf[m][d] from kf^T smem
    for (int d = t; d < DF; d += 256) {
        float s = 0.f;
#pragma unroll
        for (int c8 = 0; c8 < 8; c8++) {
            int off = d * 128 + (((c8 ^ (d & 7))) << 4);
            uint4 u = *(const uint4*)(smc + CS_KFT + off);
            const __half2* hp = (const __half2*)&u;
#pragma unroll
            for (int q = 0; q < 4; q++) {
                float2 f2 = __half22float2(hp[q]);
                s += f2.x + f2.y;
            }
        }
        g_ss[(long)blk * DF + d] = s;
    }
}

// ---------------------------------------------------------------------------
// Fused in-place exclusive prefix scans (S blocks first, then ss blocks)
// ---------------------------------------------------------------------------
#define SCAN_S_BLOCKS 1152   // NBH * (64*DFP/2) / 256
#define SCAN_SS_BLOCKS 35    // ceil(NBH*DF / 256)

__global__ void scan_all() {
    int blk = blockIdx.x;
    if (blk < SCAN_S_BLOCKS) {
        long idx = (long)blk * 256 + threadIdx.x;
        const long PER_BH = 64 * DFP / 2;  // 9216 half2 per chunk
        long bh = idx / PER_BH;
        long de = idx % PER_BH;
        __half2* Sp = (__half2*)g_Sh;
        size_t base = (size_t)bh * NC * PER_BH + de;
        float2 acc = make_float2(0.f, 0.f);
#pragma unroll
        for (int c = 0; c < NC; c++) {
            size_t p = base + (size_t)c * PER_BH;
            float2 tmp = __half22float2(Sp[p]);
            Sp[p] = __floats2half2_rn(acc.x, acc.y);
            acc.x += tmp.x; acc.y += tmp.y;
        }
    } else {
        long idx = (long)(blk - SCAN_S_BLOCKS) * 256 + threadIdx.x;
        if (idx >= (long)NBH * DF) return;
        long bh = idx / DF;
        long d = idx % DF;
        long base = bh * NC * DF + d;
        float acc = 0.f;
#pragma unroll
        for (int c = 0; c < NC; c++) {
            long p = base + (long)c * DF;
            float tmp = g_ss[p];
            g_ss[p] = acc;
            acc += tmp;
        }
    }
}

// ---------------------------------------------------------------------------
// Output via one fused mma GEMM per (bh,chunk):
//   Aop = [phi(q) (64x288) | A_poly (64x64)]  (fp16, padded stride 360)
//   Bop rows (N=72): e<64: [S^T[e] | v^T[e]], row64: [0 | 1...], 65..71: 0
//   denominator = fp32 scalar qf.sp + rowsum(A); y = num * z  (fp16 out)
// ---------------------------------------------------------------------------
#define OTS 360                         // row stride in halves (45 x 16B, odd)
#define OT_QF 0                         // 64 x 720B  = 46080
#define OT_B  46080                     // 72 x 720B  = 51840
#define OT_Q  97920                     // 64x16 fp32 = 4096
#define OT_K  102016                    // 64x16 fp32 = 4096
#define OT_SP 106112                    // 276  fp32  = 1104
#define OT_DS 107216                    // 64 fp32 (+pad)
#define OT_RS 107472                    // 64 fp32 (+pad)
#define OT_Z  107728                    // 64 fp32 (+pad)
#define OT_SMEM 107984

__global__ void __launch_bounds__(256, 2) output_mma() {
    extern __shared__ char smo[];
    float* q_s  = (float*)(smo + OT_Q);
    float* k_s  = (float*)(smo + OT_K);
    float* sp_s = (float*)(smo + OT_SP);
    float* ds_s = (float*)(smo + OT_DS);
    float* rs_s = (float*)(smo + OT_RS);
    float* z_s  = (float*)(smo + OT_Z);
    __half* qf  = (__half*)(smo + OT_QF);
    __half* Bx  = (__half*)(smo + OT_B);

    int blk = blockIdx.x;
    int c = blk & (NC - 1);
    int bh = blk >> 5;
    int b = bh >> 4, h = bh & 15;
    int t = threadIdx.x;
    long tok0 = (long)b * LL + (long)c * CHUNK;

    // ---- phase 1: loads ----
    {   // S^T rows via cp.async (36 uint4 per row)
        const uint4* src = (const uint4*)(g_Sh + (size_t)blk * 64 * DFP);
        for (int i = t; i < 64 * 36; i += 256) {
            int e = i / 36, u = i % 36;
            CP_ASYNC16(smem_u32(smo + OT_B + e * 720 + u * 16), src + i);
        }
        CP_COMMIT();
    }
    for (int i = t; i < 64 * 16; i += 256) {
        int n = i >> 4, f = i & 15;
        long off = (tok0 + n) * 512 + h * 16 + f;
        q_s[i] = g_qk[off];
        k_s[i] = g_qk[off + 256];
    }
    for (int i = t; i < 276; i += 256) sp_s[i] = (i < DF) ? g_ss[(long)blk * DF + i] : 0.f;
    for (int i = t; i < 4096; i += 256) {   // v^T into cols 288..351 (fp16 direct)
        int m = i >> 6, e = i & 63;
        Bx[e * OTS + 288 + m] = g_vh[(tok0 + m) * 1024 + h * 64 + e];
    }
    for (int i = t; i < 8 * 180; i += 256) {    // rows 64..71
        int r = 64 + i / 180, u = i % 180;      // uint (2 halves)
        uint32_t val = (r == 64 && u >= 144 && u < 176) ? 0x3C003C00u : 0u;  // ones over v-cols
        *(uint32_t*)(smo + OT_B + r * 720 + u * 4) = val;
    }
    CP_WAIT(0);
    __syncthreads();

    // ---- phase 2: build A-operand (vectorized) + fp32 denominator part ----
    for (int i = t; i < 64 * 36; i += 256) {    // phi(q): one uint4 per 8 features
        int n = i / 36, d0 = (i % 36) * 8;
        const float* q0 = &q_s[n * 16];
        uint4 u;
        __half2* hp = (__half2*)&u;
#pragma unroll
        for (int p = 0; p < 4; p++) {
            float vv[2];
#pragma unroll
            for (int s2 = 0; s2 < 2; s2++) {
                int d = d0 + p * 2 + s2;
                float val = 0.f;
                if (d == 0) val = 1.f;
                else if (d <= 16) val = q0[d - 1] * INV_RRD;
                else if (d < DF) {
                    int dd = d - 17;
                    val = q0[dd >> 4] * q0[dd & 15] * INV_Q2;
                }
                vv[s2] = val;
            }
            hp[p] = __floats2half2_rn(vv[0], vv[1]);
        }
        *(uint4*)&qf[n * OTS + d0] = u;
    }
    {   // causal polynomial scores into cols 288..351 (thread -> (n, 16 m's))
        int n = t >> 2, mq = (t & 3) << 4;
        float qr[16];
#pragma unroll
        for (int f = 0; f < 16; f++) qr[f] = q_s[n * 16 + f];
#pragma unroll
        for (int mm = 0; mm < 16; mm += 2) {
            float a2[2];
#pragma unroll
            for (int u2 = 0; u2 < 2; u2++) {
                int m = mq + mm + u2;
                float s = 0.f;
#pragma unroll
                for (int f = 0; f < 16; f++) s += qr[f] * k_s[m * 16 + f];
                a2[u2] = (m <= n) ? (1.f + 0.25f * s + s * s * 0.03125f) : 0.f;
            }
            *(__half2*)&qf[n * OTS + 288 + mq + mm] = __floats2half2_rn(a2[0], a2[1]);
        }
        if (t < 64) {                    // fp32 qf . sp
            const float* q0 = &q_s[t * 16];
            float d1 = 0.f;
#pragma unroll
            for (int f = 0; f < 16; f++) d1 += q0[f] * sp_s[1 + f];
            float d2 = 0.f;
            for (int i2 = 0; i2 < 16; i2++) {
                float inner = 0.f;
#pragma unroll
                for (int j = 0; j < 16; j++) inner += q0[j] * sp_s[17 + 16 * i2 + j];
                d2 += q0[i2] * inner;
            }
            ds_s[t] = sp_s[0] + INV_RRD * d1 + INV_Q2 * d2;
        }
    }
    __syncthreads();

    // ---- phase 3: 64x72x352 fp16 GEMM (8 warps: 4 m-tiles x 2 n-groups) ----
    int w = t >> 5, l = t & 31;
    int m0w = (w >> 1) * 16;
    int nh5 = w & 1;
    int nr0 = nh5 * 40;
    float acc[5][4];
#pragma unroll
    for (int j = 0; j < 5; j++)
#pragma unroll
        for (int r = 0; r < 4; r++) acc[j][r] = 0.f;

    uint32_t Qb = smem_u32(smo + OT_QF);
    uint32_t Bb = smem_u32(smo + OT_B);
    uint32_t aad = Qb + (m0w + (l & 15)) * 720 + (l >> 4) * 16;
    uint32_t bpd = Bb + (nr0 + (l & 7) + ((l >> 4) << 3)) * 720 + ((l >> 3) & 1) * 16;
    uint32_t bsd = Bb + (nr0 + 32 + (l & 7)) * 720 + ((l >> 3) & 1) * 16;

    if (nh5 == 0) {
#pragma unroll
        for (int ks = 0; ks < 22; ks++) {
            uint32_t afr[4], bp0[4], bp1[4], bs[2];
            ldsm_x4(afr, aad + ks * 32);
            ldsm_x4(bp0, bpd + ks * 32);
            ldsm_x4(bp1, bpd + 16 * 720 + ks * 32);
            ldsm_x2(bs,  bsd + ks * 32);
            mma_f16(acc[0], afr, bp0);
            mma_f16(acc[1], afr, bp0 + 2);
            mma_f16(acc[2], afr, bp1);
            mma_f16(acc[3], afr, bp1 + 2);
            mma_f16(acc[4], afr, bs);
        }
    } else {
#pragma unroll
        for (int ks = 0; ks < 22; ks++) {
            uint32_t afr[4], bp0[4], bp1[4];
            ldsm_x4(afr, aad + ks * 32);
            ldsm_x4(bp0, bpd + ks * 32);
            ldsm_x4(bp1, bpd + 16 * 720 + ks * 32);
            mma_f16(acc[0], afr, bp0);
            mma_f16(acc[1], afr, bp0 + 2);
            mma_f16(acc[2], afr, bp1);
            mma_f16(acc[3], afr, bp1 + 2);
        }
    }

    // ---- phase 4: denominator + write ----
    int r0 = l >> 2, c0 = (l & 3) * 2;
    if (nh5 == 1 && (l & 3) == 0) {     // local tile 3 = global tile 8 -> col 64
        rs_s[m0w + r0] = acc[3][0];
        rs_s[m0w + r0 + 8] = acc[3][2];
    }
    __syncthreads();
    if (t < 64) z_s[t] = 1.f / (ds_s[t] + rs_s[t] + EPS);
    __syncthreads();

    float z0 = z_s[m0w + r0], z1 = z_s[m0w + r0 + 8];
    size_t rowb0 = (size_t)(tok0 + m0w + r0) * KP + h * 64;
    size_t rowb1 = (size_t)(tok0 + m0w + r0 + 8) * KP + h * 64;
    int jmax = nh5 ? 4 : 5;
#pragma unroll
    for (int j = 0; j < 5; j++) {
        if (j >= jmax) break;
        int col = (nh5 * 5 + j) * 8 + c0;
        if (col < 64) {
            *(__half2*)&g_yh[rowb0 + col] =
                __floats2half2_rn(acc[j][0] * z0, acc[j][1] * z0);
            *(__half2*)&g_yh[rowb1 + col] =
                __floats2half2_rn(acc[j][2] * z1, acc[j][3] * z1);
        }
    }
}

// ---------------------------------------------------------------------------
extern "C" void kernel_launch(void* const* d_in, const int* in_sizes, int n_in,
                              void* d_out, int out_size) {
    const float* x  = (const float*)d_in[0];
    const float* Wq = (const float*)d_in[1];
    const float* Wk = (const float*)d_in[2];
    const float* Wv = (const float*)d_in[3];
    const float* Wo = (const float*)d_in[4];
    float* out = (float*)d_out;

    void *pxh, *pwqk, *pwvh, *pwoh, *pqk, *pvh, *pyh;
    cudaGetSymbolAddress(&pxh, g_xh);
    cudaGetSymbolAddress(&pwqk, g_wqk);
    cudaGetSymbolAddress(&pwvh, g_wvh);
    cudaGetSymbolAddress(&pwoh, g_woh);
    cudaGetSymbolAddress(&pqk, g_qk);
    cudaGetSymbolAddress(&pvh, g_vh);
    cudaGetSymbolAddress(&pyh, g_yh);

    cudaFuncSetAttribute(chunk_state_mma, cudaFuncAttributeMaxDynamicSharedMemorySize, CS_SMEM);
    cudaFuncSetAttribute(output_mma, cudaFuncAttributeMaxDynamicSharedMemorySize, OT_SMEM);
    cudaFuncSetAttribute(proj_gemm, cudaFuncAttributeMaxDynamicSharedMemorySize, GEMM_SMEM);
    cudaFuncSetAttribute(gemm_o, cudaFuncAttributeMaxDynamicSharedMemorySize, GEMM_SMEM);

    // split/convert inputs (fused)
    prep_kernel<<<4096 + 80 * 32, 256>>>(x, Wq, Wk, Wv, Wo);

    // fused q/k + v projections on tensor cores
    proj_gemm<<<384, 256, GEMM_SMEM>>>((const __half*)pxh, (const __half*)pwqk, (float*)pqk,
                                       (const __half*)pwvh, (__half*)pvh);

    // chunked linear attention
    chunk_state_mma<<<NBH * NC, 256, CS_SMEM>>>();
    scan_all<<<SCAN_S_BLOCKS + SCAN_SS_BLOCKS, 256>>>();
    output_mma<<<NBH * NC, 256, OT_SMEM>>>();

    // final projection
    gemm_o<<<dim3(8, 32), 256, GEMM_SMEM>>>((const __half*)pyh, (const __half*)pwoh, out);
}

// round 15
// speedup vs baseline: 6.2520x; 1.0209x over previous
#include <cuda_runtime.h>
#include <cuda_bf16.h>
#include <cuda_fp16.h>
#include <cstdint>

// Problem constants
#define BB 2
#define LL 2048
#define DM 1024
#define NH 16
#define FD 16
#define HD 64
#define DF 273          // 1 + 16 + 256
#define DFP 288         // DF padded to 18 n8-tiles for mma
#define CHUNK 64
#define NC 32           // LL / CHUNK
#define NBH 32          // BB * NH
#define INV_RRD 0.5f
#define INV_Q2 0.17677669529663687f   // 1/(4*sqrt(2))
#define EPS 1e-12f

#define KP 1024         // unified K for all projections (single-term fp16)

// ---------------------------------------------------------------------------
// Scratch (device globals; no allocation)
// ---------------------------------------------------------------------------
__device__ __half g_xh[4096 * KP];              // x fp16
__device__ __half g_wqk[512 * KP];              // [Wq|Wk]^T fp16
__device__ __half g_wvh[1024 * KP];             // Wv^T fp16
__device__ __half g_woh[1024 * KP];             // Wo^T fp16
__device__ float g_qk[4096 * 512];              // q (cols 0..255) | k (256..511)
__device__ __half g_vh[4096 * 1024];            // v fp16
__device__ __half g_yh[4096 * KP];              // y fp16
__device__ __half g_Sh[(size_t)NBH * NC * 64 * DFP];  // chunk states, e-major S^T (fp16)
__device__ float g_ss[NBH * NC * DF];

// ---------------------------------------------------------------------------
// PTX helpers (baseline sm_80-compatible: ldmatrix, mma.sync, cp.async)
// ---------------------------------------------------------------------------
__device__ __forceinline__ uint32_t smem_u32(const void* p) {
    uint32_t a;
    asm("{ .reg .u64 t; cvta.to.shared.u64 t, %1; cvt.u32.u64 %0, t; }" : "=r"(a) : "l"(p));
    return a;
}
__device__ __forceinline__ void ldsm_x4(uint32_t* r, uint32_t addr) {
    asm volatile("ldmatrix.sync.aligned.m8n8.x4.shared.b16 {%0,%1,%2,%3}, [%4];"
        : "=r"(r[0]), "=r"(r[1]), "=r"(r[2]), "=r"(r[3]) : "r"(addr));
}
__device__ __forceinline__ void ldsm_x4_trans(uint32_t* r, uint32_t addr) {
    asm volatile("ldmatrix.sync.aligned.m8n8.x4.trans.shared.b16 {%0,%1,%2,%3}, [%4];"
        : "=r"(r[0]), "=r"(r[1]), "=r"(r[2]), "=r"(r[3]) : "r"(addr));
}
__device__ __forceinline__ void ldsm_x2(uint32_t* r, uint32_t addr) {
    asm volatile("ldmatrix.sync.aligned.m8n8.x2.shared.b16 {%0,%1}, [%2];"
        : "=r"(r[0]), "=r"(r[1]) : "r"(addr));
}
__device__ __forceinline__ void mma_f16(float* d, const uint32_t* a, const uint32_t* b) {
    asm volatile("mma.sync.aligned.m16n8k16.row.col.f32.f16.f16.f32 "
        "{%0,%1,%2,%3}, {%4,%5,%6,%7}, {%8,%9}, {%0,%1,%2,%3};"
        : "+f"(d[0]), "+f"(d[1]), "+f"(d[2]), "+f"(d[3])
        : "r"(a[0]), "r"(a[1]), "r"(a[2]), "r"(a[3]), "r"(b[0]), "r"(b[1]));
}
#define CP_ASYNC16(dst, src) \
    asm volatile("cp.async.cg.shared.global [%0], [%1], 16;" :: "r"(dst), "l"(src))
#define CP_COMMIT() asm volatile("cp.async.commit_group;" ::: "memory")
#define CP_WAIT(n)  asm volatile("cp.async.wait_group %0;" :: "n"(n) : "memory")

// ---------------------------------------------------------------------------
// Fused prep: blocks 0..4095 convert x (fp16); blocks 4096.. split weights.
// ---------------------------------------------------------------------------
union HF2U { __half2 h; uint32_t u; };

__global__ void prep_kernel(const float* __restrict__ x,
                            const float* __restrict__ Wq, const float* __restrict__ Wk,
                            const float* __restrict__ Wv, const float* __restrict__ Wo) {
    __shared__ float tile[32][33];
    int blk = blockIdx.x;
    if (blk < 4096) {
        int idx = blk * 256 + threadIdx.x;
        int m = idx >> 8, k4 = (idx & 255) << 2;
        float4 v = *(const float4*)&x[(size_t)m * 1024 + k4];
        HF2U u0; u0.h = __floats2half2_rn(v.x, v.y);
        HF2U u1; u1.h = __floats2half2_rn(v.z, v.w);
        *(uint2*)&g_xh[(size_t)m * KP + k4] = make_uint2(u0.u, u1.u);
        return;
    }
    // weight split part: 80 x 32 virtual grid
    int b2i = blk - 4096;
    int bx = b2i % 80, k0 = (b2i / 80) * 32;
    const float* W;
    int Ncols, n0, mode, rowoff = 0;
    if (bx < 8)       { W = Wq; Ncols = 256;  n0 = bx * 32;        mode = 0; rowoff = 0;   }
    else if (bx < 16) { W = Wk; Ncols = 256;  n0 = (bx - 8) * 32;  mode = 0; rowoff = 256; }
    else if (bx < 48) { W = Wv; Ncols = 1024; n0 = (bx - 16) * 32; mode = 1; }
    else              { W = Wo; Ncols = 1024; n0 = (bx - 48) * 32; mode = 2; }
    int tx = threadIdx.x & 31, ty = threadIdx.x >> 5;  // 32 x 8
    for (int i = ty; i < 32; i += 8)
        tile[i][tx] = W[(size_t)(k0 + i) * Ncols + n0 + tx];
    __syncthreads();
    for (int i = ty; i < 32; i += 8) {
        int n = n0 + i, k = k0 + tx;
        __half hv = __float2half_rn(tile[tx][i]);
        if (mode == 0)      g_wqk[(size_t)(rowoff + n) * KP + k] = hv;
        else if (mode == 1) g_wvh[(size_t)n * KP + k] = hv;
        else                g_woh[(size_t)n * KP + k] = hv;
    }
}

// ---------------------------------------------------------------------------
// mma.sync fp16 GEMM body: C (M x N) tile (m0,n0) = A @ Bt^T
// ---------------------------------------------------------------------------
#define SMA(b) ((b) * 32768)
#define SMB(b) ((b) * 32768 + 16384)
#define GEMM_SMEM 98304

__device__ __forceinline__ void gemm_load_tile(const __half* A, const __half* B,
                                               char* sm, int m0, int n0, int kb, int buf,
                                               int t, int lda, int ldb) {
#pragma unroll
    for (int i = 0; i < 8; i++) {
        int idx = t + i * 256;            // 0..2047
        int row = (idx & 1023) >> 3, c = idx & 7;
        uint32_t dst;
        const __half* src;
        if (idx < 1024) {
            src = A + (size_t)(m0 + row) * lda + kb * 64 + c * 8;
            dst = smem_u32(sm + SMA(buf) + row * 128 + ((c ^ (row & 7)) << 4));
        } else {
            src = B + (size_t)(n0 + row) * ldb + kb * 64 + c * 8;
            dst = smem_u32(sm + SMB(buf) + row * 128 + ((c ^ (row & 7)) << 4));
        }
        CP_ASYNC16(dst, src);
    }
}

template<bool HOUT>
__device__ __forceinline__ void gemm_body(const __half* __restrict__ A,
                                          const __half* __restrict__ B,
                                          void* __restrict__ Cv,
                                          int N, int lda, int ldb, int nkt,
                                          int m0, int n0, char* sm, int t) {
    int w = t >> 5, l = t & 31;
    int wm = (w >> 2) * 64, wn = (w & 3) * 32;

    float acc[4][4][4];
#pragma unroll
    for (int i = 0; i < 4; i++)
#pragma unroll
        for (int j = 0; j < 4; j++)
#pragma unroll
            for (int r = 0; r < 4; r++) acc[i][j][r] = 0.f;

    int ar = wm + (l & 15);
    int ac = (l >> 4);
    int brow = wn + (l & 7) + ((l >> 4) << 3);   // base row for paired-B ldsm
    int bkh = (l >> 3) & 1;

    gemm_load_tile(A, B, sm, m0, n0, 0, 0, t, lda, ldb);
    CP_COMMIT();
    gemm_load_tile(A, B, sm, m0, n0, 1, 1, t, lda, ldb);
    CP_COMMIT();

    int buf = 0;
    for (int kt = 0; kt < nkt; kt++) {
        if (kt + 2 < nkt) {
            int lb = buf + 2; if (lb >= 3) lb -= 3;
            gemm_load_tile(A, B, sm, m0, n0, kt + 2, lb, t, lda, ldb);
        }
        CP_COMMIT();
        CP_WAIT(2);
        __syncthreads();

        uint32_t Ab = smem_u32(sm + SMA(buf));
        uint32_t Bb = smem_u32(sm + SMB(buf));
#pragma unroll
        for (int ks = 0; ks < 4; ks++) {
            uint32_t afr[4][4], bfr[4][2];
#pragma unroll
            for (int mi = 0; mi < 4; mi++) {
                int row = ar + mi * 16;
                int ch = ks * 2 + ac;
                ldsm_x4(afr[mi], Ab + row * 128 + ((ch ^ (row & 7)) << 4));
            }
#pragma unroll
            for (int p = 0; p < 2; p++) {
                uint32_t bp[4];
                int row = brow + p * 16;
                int ch = ks * 2 + bkh;
                ldsm_x4(bp, Bb + row * 128 + ((ch ^ (row & 7)) << 4));
                bfr[2 * p][0] = bp[0]; bfr[2 * p][1] = bp[1];
                bfr[2 * p + 1][0] = bp[2]; bfr[2 * p + 1][1] = bp[3];
            }
#pragma unroll
            for (int mi = 0; mi < 4; mi++)
#pragma unroll
                for (int ni = 0; ni < 4; ni++)
                    mma_f16(acc[mi][ni], afr[mi], bfr[ni]);
        }
        __syncthreads();
        if (++buf == 3) buf = 0;
    }

    int r0 = l >> 2, c0 = (l & 3) * 2;
#pragma unroll
    for (int mi = 0; mi < 4; mi++) {
#pragma unroll
        for (int ni = 0; ni < 4; ni++) {
            int row = m0 + wm + mi * 16 + r0;
            int col = n0 + wn + ni * 8 + c0;
            if constexpr (HOUT) {
                __half* C = (__half*)Cv;
                *(__half2*)&C[(size_t)row * N + col] =
                    __floats2half2_rn(acc[mi][ni][0], acc[mi][ni][1]);
                *(__half2*)&C[(size_t)(row + 8) * N + col] =
                    __floats2half2_rn(acc[mi][ni][2], acc[mi][ni][3]);
            } else {
                float* C = (float*)Cv;
                *(float2*)(C + (size_t)row * N + col) = make_float2(acc[mi][ni][0], acc[mi][ni][1]);
                *(float2*)(C + (size_t)(row + 8) * N + col) = make_float2(acc[mi][ni][2], acc[mi][ni][3]);
            }
        }
    }
}

// Fused q/k + v projections: CTAs 0..127 -> qk (N=512, fp32 out),
// CTAs 128..383 -> v (N=1024, fp16 out). All K=1024 over g_xh.
__global__ void __launch_bounds__(256, 2)
proj_gemm(const __half* __restrict__ xh, const __half* __restrict__ wqk,
          float* __restrict__ qk,
          const __half* __restrict__ wvh, __half* __restrict__ v) {
    extern __shared__ char sm[];
    int blk = blockIdx.x;
    int t = threadIdx.x;
    if (blk < 128) {
        gemm_body<false>(xh, wqk, qk, 512, KP, KP, KP / 64,
                         (blk >> 2) * 128, (blk & 3) * 128, sm, t);
    } else {
        int b2 = blk - 128;
        gemm_body<true>(xh, wvh, v, 1024, KP, KP, KP / 64,
                        (b2 >> 3) * 128, (b2 & 7) * 128, sm, t);
    }
}

// Standalone o-projection GEMM (fp32 out -> harness buffer).
__global__ void __launch_bounds__(256, 2)
gemm_o(const __half* __restrict__ A, const __half* __restrict__ B,
       float* __restrict__ C) {
    extern __shared__ char sm[];
    gemm_body<false>(A, B, C, 1024, KP, KP, KP / 64,
                     blockIdx.y * 128, blockIdx.x * 128, sm, threadIdx.x);
}

// ---------------------------------------------------------------------------
// Per-chunk local state via mma.sync:
// S^T[e][d] = sum_m v[m][e] * phi(k[m])[d]
// A-operand = v^T via ldmatrix.trans on the raw [m][e] tile (no transpose pass).
// kf^T built with float4 loads (k_T stride 68, 16B-aligned rows).
// Two 9-tile mma passes; 4 CTAs/SM.
// ---------------------------------------------------------------------------
#define CS_KFT 0                       // kf^T fp16 swizzled: 288 x 128B = 36864
#define CS_KT  36864                   // k^T fp32 [16][68] = 4352
#define CS_VS  41216                   // v fp16 [m][e] stride 72 halves = 9216
#define CS_SMEM 50432
#define VS_STRIDE_B 144                // 72 halves per row

__global__ void __launch_bounds__(256, 4) chunk_state_mma() {
    extern __shared__ char smc[];
    float* k_T = (float*)(smc + CS_KT);

    int blk = blockIdx.x;
    int c = blk & (NC - 1);
    int bh = blk >> 5;
    int b = bh >> 4, h = bh & 15;
    int t = threadIdx.x;
    long tok0 = (long)b * LL + (long)c * CHUNK;

    // v tile [m][e] fp16 via cp.async (coalesced, 512 x 16B)
    for (int i = t; i < 512; i += 256) {
        int m = i >> 3, e8 = i & 7;
        CP_ASYNC16(smem_u32(smc + CS_VS + m * VS_STRIDE_B + e8 * 16),
                   g_vh + (tok0 + m) * 1024 + h * 64 + e8 * 8);
    }
    CP_COMMIT();

    // k transposed [f][n] fp32 (stride 68 -> rows 16B-aligned)
    for (int i = t; i < 64 * 16; i += 256) {
        int n = i >> 4, f = i & 15;
        k_T[f * 68 + n] = g_qk[(tok0 + n) * 512 + 256 + h * 16 + f];
    }
    __syncthreads();

    // kf^T fp16 swizzled: one uint4 per (d, chunk); float4 source loads
    for (int i = t; i < DFP * 8; i += 256) {
        int d = i >> 3, c8 = i & 7;
        int m0 = (c8 ^ (d & 7)) * 8;
        uint4 u;
        __half2* hp = (__half2*)&u;
        if (d == 0) {
            __half2 one2 = __floats2half2_rn(1.f, 1.f);
            hp[0] = one2; hp[1] = one2; hp[2] = one2; hp[3] = one2;
        } else if (d <= 16) {
            const float4* kr = (const float4*)&k_T[(d - 1) * 68 + m0];
            float4 a0 = kr[0], a1 = kr[1];
            hp[0] = __floats2half2_rn(a0.x * INV_RRD, a0.y * INV_RRD);
            hp[1] = __floats2half2_rn(a0.z * INV_RRD, a0.w * INV_RRD);
            hp[2] = __floats2half2_rn(a1.x * INV_RRD, a1.y * INV_RRD);
            hp[3] = __floats2half2_rn(a1.z * INV_RRD, a1.w * INV_RRD);
        } else if (d < DF) {
            int dd = d - 17;
            const float4* ka = (const float4*)&k_T[(dd >> 4) * 68 + m0];
            const float4* kb = (const float4*)&k_T[(dd & 15) * 68 + m0];
            float4 a0 = ka[0], a1 = ka[1], b0 = kb[0], b1 = kb[1];
            hp[0] = __floats2half2_rn(a0.x * b0.x * INV_Q2, a0.y * b0.y * INV_Q2);
            hp[1] = __floats2half2_rn(a0.z * b0.z * INV_Q2, a0.w * b0.w * INV_Q2);
            hp[2] = __floats2half2_rn(a1.x * b1.x * INV_Q2, a1.y * b1.y * INV_Q2);
            hp[3] = __floats2half2_rn(a1.z * b1.z * INV_Q2, a1.w * b1.w * INV_Q2);
        } else {
            u = make_uint4(0u, 0u, 0u, 0u);
        }
        *(uint4*)(smc + CS_KFT + d * 128 + c8 * 16) = u;
    }
    CP_WAIT(0);
    __syncthreads();

    // mma: warp w -> e-tile (w>>1); d-tiles (w&1)*18 .. +17 in two 9-tile passes
    int w = t >> 5, l = t & 31;
    uint32_t VSb = smem_u32(smc + CS_VS);
    uint32_t Bb = smem_u32(smc + CS_KFT);
    // A (v^T) fragment via ldmatrix.trans: lane -> v row / e-col
    int e0 = (w >> 1) * 16;
    int vrow_off = ((l >> 4) << 3) + (l & 7);            // + ks*16
    int veoff = e0 + (((l >> 3) & 1) << 3);
    uint32_t vaddr = VSb + vrow_off * VS_STRIDE_B + veoff * 2;
    int brow_base = (l & 7) + ((l >> 4) << 3);
    int bkh = (l >> 3) & 1;
    int ntile0 = (w & 1) * 18;
    int r0 = l >> 2, c0 = (l & 3) * 2;
    size_t Sbase = (size_t)blk * 64 * DFP;
    int e_lo = e0 + r0;

#pragma unroll
    for (int half = 0; half < 2; half++) {
        int tb = ntile0 + half * 9;
        float acc[9][4];
#pragma unroll
        for (int j = 0; j < 9; j++)
#pragma unroll
            for (int r = 0; r < 4; r++) acc[j][r] = 0.f;

#pragma unroll
        for (int ks = 0; ks < 4; ks++) {
            uint32_t afr[4];
            ldsm_x4_trans(afr, vaddr + ks * 16 * VS_STRIDE_B);
            int chb = ks * 2 + bkh;
#pragma unroll
            for (int jp = 0; jp < 4; jp++) {
                uint32_t bp[4];
                int row = (tb + jp * 2) * 8 + brow_base;
                ldsm_x4(bp, Bb + row * 128 + ((chb ^ (row & 7)) << 4));
                mma_f16(acc[jp * 2],     afr, bp);
                mma_f16(acc[jp * 2 + 1], afr, bp + 2);
            }
            {   // last single tile
                uint32_t bs[2];
                int row = (tb + 8) * 8 + (l & 7);
                int chs = ks * 2 + ((l >> 3) & 1);
                ldsm_x2(bs, Bb + row * 128 + ((chs ^ (row & 7)) << 4));
                mma_f16(acc[8], afr, bs);
            }
        }

        // store this half's 9 d-tiles, e-major fp16
#pragma unroll
        for (int j = 0; j < 9; j++) {
            int d = (tb + j) * 8 + c0;
            *(__half2*)&g_Sh[Sbase + (size_t)e_lo * DFP + d] =
                __floats2half2_rn(acc[j][0], acc[j][1]);
            *(__half2*)&g_Sh[Sbase + (size_t)(e_lo + 8) * DFP + d] =
                __floats2half2_rn(acc[j][2], acc[j][3]);
        }
    }

    // ssum[d] = sum_m kf[m][d] from kf^T smem
    for (int d = t; d < DF; d += 256) {
        float s = 0.f;
#pragma unroll
        for (int c8 = 0; c8 < 8; c8++) {
            int off = d * 128 + (((c8 ^ (d & 7))) << 4);
            uint4 u = *(const uint4*)(smc + CS_KFT + off);
            const __half2* hp = (const __half2*)&u;
#pragma unroll
            for (int q = 0; q < 4; q++) {
                float2 f2 = __half22float2(hp[q]);
                s += f2.x + f2.y;
            }
        }
        g_ss[(long)blk * DF + d] = s;
    }
}

// ---------------------------------------------------------------------------
// Fused in-place exclusive prefix scans. S part at uint4 (8 halves) per
// thread for 4x fewer instructions and higher MLP; ss part unchanged.
// ---------------------------------------------------------------------------
#define PER_U4 (64 * DFP / 8)          // 2304 uint4 per chunk-state
#define SCAN_S_BLOCKS 288              // NBH * PER_U4 / 256
#define SCAN_SS_BLOCKS 35              // ceil(NBH*DF / 256)

__global__ void scan_all() {
    int blk = blockIdx.x;
    if (blk < SCAN_S_BLOCKS) {
        long idx = (long)blk * 256 + threadIdx.x;   // 0 .. NBH*PER_U4-1
        long bh = idx / PER_U4;
        long de = idx % PER_U4;
        uint4* Sp = (uint4*)g_Sh;
        size_t base = (size_t)bh * NC * PER_U4 + de;
        float acc[8];
#pragma unroll
        for (int j = 0; j < 8; j++) acc[j] = 0.f;
#pragma unroll
        for (int c = 0; c < NC; c++) {
            size_t p = base + (size_t)c * PER_U4;
            uint4 u = Sp[p];
            const __half2* hp = (const __half2*)&u;
            uint4 o;
            __half2* op = (__half2*)&o;
#pragma unroll
            for (int q = 0; q < 4; q++) {
                float2 f2 = __half22float2(hp[q]);
                op[q] = __floats2half2_rn(acc[2 * q], acc[2 * q + 1]);
                acc[2 * q] += f2.x;
                acc[2 * q + 1] += f2.y;
            }
            Sp[p] = o;
        }
    } else {
        long idx = (long)(blk - SCAN_S_BLOCKS) * 256 + threadIdx.x;
        if (idx >= (long)NBH * DF) return;
        long bh = idx / DF;
        long d = idx % DF;
        long base = bh * NC * DF + d;
        float acc = 0.f;
#pragma unroll
        for (int c = 0; c < NC; c++) {
            long p = base + (long)c * DF;
            float tmp = g_ss[p];
            g_ss[p] = acc;
            acc += tmp;
        }
    }
}

// ---------------------------------------------------------------------------
// Output via one fused mma GEMM per (bh,chunk):
//   Aop = [phi(q) (64x288) | A_poly (64x64)]  (fp16, padded stride 360)
//   Bop rows (N=72): e<64: [S^T[e] | v^T[e]], row64: [0 | 1...], 65..71: 0
//   denominator = fp32 scalar qf.sp + rowsum(A); y = num * z  (fp16 out)
// ---------------------------------------------------------------------------
#define OTS 360                         // row stride in halves (45 x 16B, odd)
#define OT_QF 0                         // 64 x 720B  = 46080
#define OT_B  46080                     // 72 x 720B  = 51840
#define OT_Q  97920                     // 64x16 fp32 = 4096
#define OT_K  102016                    // 64x16 fp32 = 4096
#define OT_SP 106112                    // 276  fp32  = 1104
#define OT_DS 107216                    // 64 fp32 (+pad)
#define OT_RS 107472                    // 64 fp32 (+pad)
#define OT_Z  107728                    // 64 fp32 (+pad)
#define OT_SMEM 107984

__global__ void __launch_bounds__(256, 2) output_mma() {
    extern __shared__ char smo[];
    float* q_s  = (float*)(smo + OT_Q);
    float* k_s  = (float*)(smo + OT_K);
    float* sp_s = (float*)(smo + OT_SP);
    float* ds_s = (float*)(smo + OT_DS);
    float* rs_s = (float*)(smo + OT_RS);
    float* z_s  = (float*)(smo + OT_Z);
    __half* qf  = (__half*)(smo + OT_QF);
    __half* Bx  = (__half*)(smo + OT_B);

    int blk = blockIdx.x;
    int c = blk & (NC - 1);
    int bh = blk >> 5;
    int b = bh >> 4, h = bh & 15;
    int t = threadIdx.x;
    long tok0 = (long)b * LL + (long)c * CHUNK;

    // ---- phase 1: loads ----
    {   // S^T rows via cp.async (36 uint4 per row)
        const uint4* src = (const uint4*)(g_Sh + (size_t)blk * 64 * DFP);
        for (int i = t; i < 64 * 36; i += 256) {
            int e = i / 36, u = i % 36;
            CP_ASYNC16(smem_u32(smo + OT_B + e * 720 + u * 16), src + i);
        }
        CP_COMMIT();
    }
    for (int i = t; i < 64 * 16; i += 256) {
        int n = i >> 4, f = i & 15;
        long off = (tok0 + n) * 512 + h * 16 + f;
        q_s[i] = g_qk[off];
        k_s[i] = g_qk[off + 256];
    }
    for (int i = t; i < 276; i += 256) sp_s[i] = (i < DF) ? g_ss[(long)blk * DF + i] : 0.f;
    for (int i = t; i < 2048; i += 256) {   // v^T into cols 288..351 (half2 stores)
        int m2 = (i >> 6) << 1, e = i & 63;
        __half va = g_vh[(tok0 + m2) * 1024 + h * 64 + e];
        __half vb = g_vh[(tok0 + m2 + 1) * 1024 + h * 64 + e];
        *(__half2*)&Bx[e * OTS + 288 + m2] = __halves2half2(va, vb);
    }
    for (int i = t; i < 8 * 180; i += 256) {    // rows 64..71
        int r = 64 + i / 180, u = i % 180;      // uint (2 halves)
        uint32_t val = (r == 64 && u >= 144 && u < 176) ? 0x3C003C00u : 0u;  // ones over v-cols
        *(uint32_t*)(smo + OT_B + r * 720 + u * 4) = val;
    }
    CP_WAIT(0);
    __syncthreads();

    // ---- phase 2: build A-operand (vectorized) + fp32 denominator part ----
    for (int i = t; i < 64 * 36; i += 256) {    // phi(q): one uint4 per 8 features
        int n = i / 36, d0 = (i % 36) * 8;
        const float* q0 = &q_s[n * 16];
        uint4 u;
        __half2* hp = (__half2*)&u;
#pragma unroll
        for (int p = 0; p < 4; p++) {
            float vv[2];
#pragma unroll
            for (int s2 = 0; s2 < 2; s2++) {
                int d = d0 + p * 2 + s2;
                float val = 0.f;
                if (d == 0) val = 1.f;
                else if (d <= 16) val = q0[d - 1] * INV_RRD;
                else if (d < DF) {
                    int dd = d - 17;
                    val = q0[dd >> 4] * q0[dd & 15] * INV_Q2;
                }
                vv[s2] = val;
            }
            hp[p] = __floats2half2_rn(vv[0], vv[1]);
        }
        *(uint4*)&qf[n * OTS + d0] = u;
    }
    {   // causal polynomial scores into cols 288..351 (thread -> (n, 16 m's))
        int n = t >> 2, mq = (t & 3) << 4;
        float qr[16];
#pragma unroll
        for (int f = 0; f < 16; f++) qr[f] = q_s[n * 16 + f];
#pragma unroll
        for (int mm = 0; mm < 16; mm += 2) {
            float a2[2];
#pragma unroll
            for (int u2 = 0; u2 < 2; u2++) {
                int m = mq + mm + u2;
                float s = 0.f;
#pragma unroll
                for (int f = 0; f < 16; f++) s += qr[f] * k_s[m * 16 + f];
                a2[u2] = (m <= n) ? (1.f + 0.25f * s + s * s * 0.03125f) : 0.f;
            }
            *(__half2*)&qf[n * OTS + 288 + mq + mm] = __floats2half2_rn(a2[0], a2[1]);
        }
        if (t < 64) {                    // fp32 qf . sp
            const float* q0 = &q_s[t * 16];
            float d1 = 0.f;
#pragma unroll
            for (int f = 0; f < 16; f++) d1 += q0[f] * sp_s[1 + f];
            float d2 = 0.f;
            for (int i2 = 0; i2 < 16; i2++) {
                float inner = 0.f;
#pragma unroll
                for (int j = 0; j < 16; j++) inner += q0[j] * sp_s[17 + 16 * i2 + j];
                d2 += q0[i2] * inner;
            }
            ds_s[t] = sp_s[0] + INV_RRD * d1 + INV_Q2 * d2;
        }
    }
    __syncthreads();

    // ---- phase 3: 64x72x352 fp16 GEMM (8 warps: 4 m-tiles x 2 n-groups) ----
    int w = t >> 5, l = t & 31;
    int m0w = (w >> 1) * 16;
    int nh5 = w & 1;
    int nr0 = nh5 * 40;
    float acc[5][4];
#pragma unroll
    for (int j = 0; j < 5; j++)
#pragma unroll
        for (int r = 0; r < 4; r++) acc[j][r] = 0.f;

    uint32_t Qb = smem_u32(smo + OT_QF);
    uint32_t Bb = smem_u32(smo + OT_B);
    uint32_t aad = Qb + (m0w + (l & 15)) * 720 + (l >> 4) * 16;
    uint32_t bpd = Bb + (nr0 + (l & 7) + ((l >> 4) << 3)) * 720 + ((l >> 3) & 1) * 16;
    uint32_t bsd = Bb + (nr0 + 32 + (l & 7)) * 720 + ((l >> 3) & 1) * 16;

    if (nh5 == 0) {
#pragma unroll
        for (int ks = 0; ks < 22; ks++) {
            uint32_t afr[4], bp0[4], bp1[4], bs[2];
            ldsm_x4(afr, aad + ks * 32);
            ldsm_x4(bp0, bpd + ks * 32);
            ldsm_x4(bp1, bpd + 16 * 720 + ks * 32);
            ldsm_x2(bs,  bsd + ks * 32);
            mma_f16(acc[0], afr, bp0);
            mma_f16(acc[1], afr, bp0 + 2);
            mma_f16(acc[2], afr, bp1);
            mma_f16(acc[3], afr, bp1 + 2);
            mma_f16(acc[4], afr, bs);
        }
    } else {
#pragma unroll
        for (int ks = 0; ks < 22; ks++) {
            uint32_t afr[4], bp0[4], bp1[4];
            ldsm_x4(afr, aad + ks * 32);
            ldsm_x4(bp0, bpd + ks * 32);
            ldsm_x4(bp1, bpd + 16 * 720 + ks * 32);
            mma_f16(acc[0], afr, bp0);
            mma_f16(acc[1], afr, bp0 + 2);
            mma_f16(acc[2], afr, bp1);
            mma_f16(acc[3], afr, bp1 + 2);
        }
    }

    // ---- phase 4: denominator + write ----
    int r0 = l >> 2, c0 = (l & 3) * 2;
    if (nh5 == 1 && (l & 3) == 0) {     // local tile 3 = global tile 8 -> col 64
        rs_s[m0w + r0] = acc[3][0];
        rs_s[m0w + r0 + 8] = acc[3][2];
    }
    __syncthreads();
    if (t < 64) z_s[t] = 1.f / (ds_s[t] + rs_s[t] + EPS);
    __syncthreads();

    float z0 = z_s[m0w + r0], z1 = z_s[m0w + r0 + 8];
    size_t rowb0 = (size_t)(tok0 + m0w + r0) * KP + h * 64;
    size_t rowb1 = (size_t)(tok0 + m0w + r0 + 8) * KP + h * 64;
    int jmax = nh5 ? 4 : 5;
#pragma unroll
    for (int j = 0; j < 5; j++) {
        if (j >= jmax) break;
        int col = (nh5 * 5 + j) * 8 + c0;
        if (col < 64) {
            *(__half2*)&g_yh[rowb0 + col] =
                __floats2half2_rn(acc[j][0] * z0, acc[j][1] * z0);
            *(__half2*)&g_yh[rowb1 + col] =
                __floats2half2_rn(acc[j][2] * z1, acc[j][3] * z1);
        }
    }
}

// ---------------------------------------------------------------------------
extern "C" void kernel_launch(void* const* d_in, const int* in_sizes, int n_in,
                              void* d_out, int out_size) {
    const float* x  = (const float*)d_in[0];
    const float* Wq = (const float*)d_in[1];
    const float* Wk = (const float*)d_in[2];
    const float* Wv = (const float*)d_in[3];
    const float* Wo = (const float*)d_in[4];
    float* out = (float*)d_out;

    void *pxh, *pwqk, *pwvh, *pwoh, *pqk, *pvh, *pyh;
    cudaGetSymbolAddress(&pxh, g_xh);
    cudaGetSymbolAddress(&pwqk, g_wqk);
    cudaGetSymbolAddress(&pwvh, g_wvh);
    cudaGetSymbolAddress(&pwoh, g_woh);
    cudaGetSymbolAddress(&pqk, g_qk);
    cudaGetSymbolAddress(&pvh, g_vh);
    cudaGetSymbolAddress(&pyh, g_yh);

    cudaFuncSetAttribute(chunk_state_mma, cudaFuncAttributeMaxDynamicSharedMemorySize, CS_SMEM);
    cudaFuncSetAttribute(output_mma, cudaFuncAttributeMaxDynamicSharedMemorySize, OT_SMEM);
    cudaFuncSetAttribute(proj_gemm, cudaFuncAttributeMaxDynamicSharedMemorySize, GEMM_SMEM);
    cudaFuncSetAttribute(gemm_o, cudaFuncAttributeMaxDynamicSharedMemorySize, GEMM_SMEM);

    // split/convert inputs (fused)
    prep_kernel<<<4096 + 80 * 32, 256>>>(x, Wq, Wk, Wv, Wo);

    // fused q/k + v projections on tensor cores
    proj_gemm<<<384, 256, GEMM_SMEM>>>((const __half*)pxh, (const __half*)pwqk, (float*)pqk,
                                       (const __half*)pwvh, (__half*)pvh);

    // chunked linear attention
    chunk_state_mma<<<NBH * NC, 256, CS_SMEM>>>();
    scan_all<<<SCAN_S_BLOCKS + SCAN_SS_BLOCKS, 256>>>();
    output_mma<<<NBH * NC, 256, OT_SMEM>>>();

    // final projection
    gemm_o<<<dim3(8, 32), 256, GEMM_SMEM>>>((const __half*)pyh, (const __half*)pwoh, out);
}

// round 16
// speedup vs baseline: 6.3055x; 1.0085x over previous
#include <cuda_runtime.h>
#include <cuda_bf16.h>
#include <cuda_fp16.h>
#include <cstdint>

// Problem constants
#define BB 2
#define LL 2048
#define DM 1024
#define NH 16
#define FD 16
#define HD 64
#define DF 273          // 1 + 16 + 256
#define DFP 288         // DF padded to 18 n8-tiles for mma
#define CHUNK 64
#define NC 32           // LL / CHUNK
#define NBH 32          // BB * NH
#define INV_RRD 0.5f
#define INV_Q2 0.17677669529663687f   // 1/(4*sqrt(2))
#define EPS 1e-12f

#define KP 1024         // unified K for all projections (single-term fp16)

// ---------------------------------------------------------------------------
// Scratch (device globals; no allocation)
// ---------------------------------------------------------------------------
__device__ __half g_xh[4096 * KP];              // x fp16
__device__ __half g_wqk[512 * KP];              // [Wq|Wk]^T fp16
__device__ __half g_wvh[1024 * KP];             // Wv^T fp16
__device__ __half g_woh[1024 * KP];             // Wo^T fp16
__device__ float g_qk[4096 * 512];              // q (cols 0..255) | k (256..511)
__device__ __half g_vh[4096 * 1024];            // v fp16
__device__ __half g_yh[4096 * KP];              // y fp16
__device__ __half g_Sh[(size_t)NBH * NC * 64 * DFP];  // chunk states, e-major S^T (fp16)
__device__ float g_ss[NBH * NC * DF];

// ---------------------------------------------------------------------------
// PTX helpers (baseline sm_80-compatible: ldmatrix, mma.sync, cp.async)
// ---------------------------------------------------------------------------
__device__ __forceinline__ uint32_t smem_u32(const void* p) {
    uint32_t a;
    asm("{ .reg .u64 t; cvta.to.shared.u64 t, %1; cvt.u32.u64 %0, t; }" : "=r"(a) : "l"(p));
    return a;
}
__device__ __forceinline__ void ldsm_x4(uint32_t* r, uint32_t addr) {
    asm volatile("ldmatrix.sync.aligned.m8n8.x4.shared.b16 {%0,%1,%2,%3}, [%4];"
        : "=r"(r[0]), "=r"(r[1]), "=r"(r[2]), "=r"(r[3]) : "r"(addr));
}
__device__ __forceinline__ void ldsm_x4_trans(uint32_t* r, uint32_t addr) {
    asm volatile("ldmatrix.sync.aligned.m8n8.x4.trans.shared.b16 {%0,%1,%2,%3}, [%4];"
        : "=r"(r[0]), "=r"(r[1]), "=r"(r[2]), "=r"(r[3]) : "r"(addr));
}
__device__ __forceinline__ void ldsm_x2(uint32_t* r, uint32_t addr) {
    asm volatile("ldmatrix.sync.aligned.m8n8.x2.shared.b16 {%0,%1}, [%2];"
        : "=r"(r[0]), "=r"(r[1]) : "r"(addr));
}
__device__ __forceinline__ void mma_f16(float* d, const uint32_t* a, const uint32_t* b) {
    asm volatile("mma.sync.aligned.m16n8k16.row.col.f32.f16.f16.f32 "
        "{%0,%1,%2,%3}, {%4,%5,%6,%7}, {%8,%9}, {%0,%1,%2,%3};"
        : "+f"(d[0]), "+f"(d[1]), "+f"(d[2]), "+f"(d[3])
        : "r"(a[0]), "r"(a[1]), "r"(a[2]), "r"(a[3]), "r"(b[0]), "r"(b[1]));
}
#define CP_ASYNC16(dst, src) \
    asm volatile("cp.async.cg.shared.global [%0], [%1], 16;" :: "r"(dst), "l"(src))
#define CP_COMMIT() asm volatile("cp.async.commit_group;" ::: "memory")
#define CP_WAIT(n)  asm volatile("cp.async.wait_group %0;" :: "n"(n) : "memory")

// ---------------------------------------------------------------------------
// Fused prep: blocks 0..4095 convert x (fp16); blocks 4096.. split weights.
// ---------------------------------------------------------------------------
union HF2U { __half2 h; uint32_t u; };

__global__ void prep_kernel(const float* __restrict__ x,
                            const float* __restrict__ Wq, const float* __restrict__ Wk,
                            const float* __restrict__ Wv, const float* __restrict__ Wo) {
    __shared__ float tile[32][33];
    int blk = blockIdx.x;
    if (blk < 4096) {
        int idx = blk * 256 + threadIdx.x;
        int m = idx >> 8, k4 = (idx & 255) << 2;
        float4 v = *(const float4*)&x[(size_t)m * 1024 + k4];
        HF2U u0; u0.h = __floats2half2_rn(v.x, v.y);
        HF2U u1; u1.h = __floats2half2_rn(v.z, v.w);
        *(uint2*)&g_xh[(size_t)m * KP + k4] = make_uint2(u0.u, u1.u);
        return;
    }
    // weight split part: 80 x 32 virtual grid
    int b2i = blk - 4096;
    int bx = b2i % 80, k0 = (b2i / 80) * 32;
    const float* W;
    int Ncols, n0, mode, rowoff = 0;
    if (bx < 8)       { W = Wq; Ncols = 256;  n0 = bx * 32;        mode = 0; rowoff = 0;   }
    else if (bx < 16) { W = Wk; Ncols = 256;  n0 = (bx - 8) * 32;  mode = 0; rowoff = 256; }
    else if (bx < 48) { W = Wv; Ncols = 1024; n0 = (bx - 16) * 32; mode = 1; }
    else              { W = Wo; Ncols = 1024; n0 = (bx - 48) * 32; mode = 2; }
    int tx = threadIdx.x & 31, ty = threadIdx.x >> 5;  // 32 x 8
    for (int i = ty; i < 32; i += 8)
        tile[i][tx] = W[(size_t)(k0 + i) * Ncols + n0 + tx];
    __syncthreads();
    for (int i = ty; i < 32; i += 8) {
        int n = n0 + i, k = k0 + tx;
        __half hv = __float2half_rn(tile[tx][i]);
        if (mode == 0)      g_wqk[(size_t)(rowoff + n) * KP + k] = hv;
        else if (mode == 1) g_wvh[(size_t)n * KP + k] = hv;
        else                g_woh[(size_t)n * KP + k] = hv;
    }
}

// ---------------------------------------------------------------------------
// mma.sync fp16 GEMM body: C (M x N) tile (m0,n0) = A @ Bt^T
// ---------------------------------------------------------------------------
#define SMA(b) ((b) * 32768)
#define SMB(b) ((b) * 32768 + 16384)
#define GEMM_SMEM 98304

__device__ __forceinline__ void gemm_load_tile(const __half* A, const __half* B,
                                               char* sm, int m0, int n0, int kb, int buf,
                                               int t, int lda, int ldb) {
#pragma unroll
    for (int i = 0; i < 8; i++) {
        int idx = t + i * 256;            // 0..2047
        int row = (idx & 1023) >> 3, c = idx & 7;
        uint32_t dst;
        const __half* src;
        if (idx < 1024) {
            src = A + (size_t)(m0 + row) * lda + kb * 64 + c * 8;
            dst = smem_u32(sm + SMA(buf) + row * 128 + ((c ^ (row & 7)) << 4));
        } else {
            src = B + (size_t)(n0 + row) * ldb + kb * 64 + c * 8;
            dst = smem_u32(sm + SMB(buf) + row * 128 + ((c ^ (row & 7)) << 4));
        }
        CP_ASYNC16(dst, src);
    }
}

template<bool HOUT>
__device__ __forceinline__ void gemm_body(const __half* __restrict__ A,
                                          const __half* __restrict__ B,
                                          void* __restrict__ Cv,
                                          int N, int lda, int ldb, int nkt,
                                          int m0, int n0, char* sm, int t) {
    int w = t >> 5, l = t & 31;
    int wm = (w >> 2) * 64, wn = (w & 3) * 32;

    float acc[4][4][4];
#pragma unroll
    for (int i = 0; i < 4; i++)
#pragma unroll
        for (int j = 0; j < 4; j++)
#pragma unroll
            for (int r = 0; r < 4; r++) acc[i][j][r] = 0.f;

    int ar = wm + (l & 15);
    int ac = (l >> 4);
    int brow = wn + (l & 7) + ((l >> 4) << 3);   // base row for paired-B ldsm
    int bkh = (l >> 3) & 1;

    gemm_load_tile(A, B, sm, m0, n0, 0, 0, t, lda, ldb);
    CP_COMMIT();
    gemm_load_tile(A, B, sm, m0, n0, 1, 1, t, lda, ldb);
    CP_COMMIT();

    int buf = 0;
    for (int kt = 0; kt < nkt; kt++) {
        if (kt + 2 < nkt) {
            int lb = buf + 2; if (lb >= 3) lb -= 3;
            gemm_load_tile(A, B, sm, m0, n0, kt + 2, lb, t, lda, ldb);
        }
        CP_COMMIT();
        CP_WAIT(2);
        __syncthreads();

        uint32_t Ab = smem_u32(sm + SMA(buf));
        uint32_t Bb = smem_u32(sm + SMB(buf));
#pragma unroll
        for (int ks = 0; ks < 4; ks++) {
            uint32_t afr[4][4], bfr[4][2];
#pragma unroll
            for (int mi = 0; mi < 4; mi++) {
                int row = ar + mi * 16;
                int ch = ks * 2 + ac;
                ldsm_x4(afr[mi], Ab + row * 128 + ((ch ^ (row & 7)) << 4));
            }
#pragma unroll
            for (int p = 0; p < 2; p++) {
                uint32_t bp[4];
                int row = brow + p * 16;
                int ch = ks * 2 + bkh;
                ldsm_x4(bp, Bb + row * 128 + ((ch ^ (row & 7)) << 4));
                bfr[2 * p][0] = bp[0]; bfr[2 * p][1] = bp[1];
                bfr[2 * p + 1][0] = bp[2]; bfr[2 * p + 1][1] = bp[3];
            }
#pragma unroll
            for (int mi = 0; mi < 4; mi++)
#pragma unroll
                for (int ni = 0; ni < 4; ni++)
                    mma_f16(acc[mi][ni], afr[mi], bfr[ni]);
        }
        __syncthreads();
        if (++buf == 3) buf = 0;
    }

    int r0 = l >> 2, c0 = (l & 3) * 2;
#pragma unroll
    for (int mi = 0; mi < 4; mi++) {
#pragma unroll
        for (int ni = 0; ni < 4; ni++) {
            int row = m0 + wm + mi * 16 + r0;
            int col = n0 + wn + ni * 8 + c0;
            if constexpr (HOUT) {
                __half* C = (__half*)Cv;
                *(__half2*)&C[(size_t)row * N + col] =
                    __floats2half2_rn(acc[mi][ni][0], acc[mi][ni][1]);
                *(__half2*)&C[(size_t)(row + 8) * N + col] =
                    __floats2half2_rn(acc[mi][ni][2], acc[mi][ni][3]);
            } else {
                float* C = (float*)Cv;
                *(float2*)(C + (size_t)row * N + col) = make_float2(acc[mi][ni][0], acc[mi][ni][1]);
                *(float2*)(C + (size_t)(row + 8) * N + col) = make_float2(acc[mi][ni][2], acc[mi][ni][3]);
            }
        }
    }
}

// Fused q/k + v projections: CTAs 0..127 -> qk (N=512, fp32 out),
// CTAs 128..383 -> v (N=1024, fp16 out). All K=1024 over g_xh.
__global__ void __launch_bounds__(256, 2)
proj_gemm(const __half* __restrict__ xh, const __half* __restrict__ wqk,
          float* __restrict__ qk,
          const __half* __restrict__ wvh, __half* __restrict__ v) {
    extern __shared__ char sm[];
    int blk = blockIdx.x;
    int t = threadIdx.x;
    if (blk < 128) {
        gemm_body<false>(xh, wqk, qk, 512, KP, KP, KP / 64,
                         (blk >> 2) * 128, (blk & 3) * 128, sm, t);
    } else {
        int b2 = blk - 128;
        gemm_body<true>(xh, wvh, v, 1024, KP, KP, KP / 64,
                        (b2 >> 3) * 128, (b2 & 7) * 128, sm, t);
    }
}

// Standalone o-projection GEMM (fp32 out -> harness buffer).
__global__ void __launch_bounds__(256, 2)
gemm_o(const __half* __restrict__ A, const __half* __restrict__ B,
       float* __restrict__ C) {
    extern __shared__ char sm[];
    gemm_body<false>(A, B, C, 1024, KP, KP, KP / 64,
                     blockIdx.y * 128, blockIdx.x * 128, sm, threadIdx.x);
}

// ---------------------------------------------------------------------------
// Per-chunk local state via mma.sync:
// S^T[e][d] = sum_m v[m][e] * phi(k[m])[d]
// A-operand = v^T via ldmatrix.trans on the raw [m][e] tile (no transpose pass).
// kf^T built with float4 loads (k_T stride 68, 16B-aligned rows).
// Two 9-tile mma passes; 4 CTAs/SM.
// ---------------------------------------------------------------------------
#define CS_KFT 0                       // kf^T fp16 swizzled: 288 x 128B = 36864
#define CS_KT  36864                   // k^T fp32 [16][68] = 4352
#define CS_VS  41216                   // v fp16 [m][e] stride 72 halves = 9216
#define CS_SMEM 50432
#define VS_STRIDE_B 144                // 72 halves per row

__global__ void __launch_bounds__(256, 4) chunk_state_mma() {
    extern __shared__ char smc[];
    float* k_T = (float*)(smc + CS_KT);

    int blk = blockIdx.x;
    int c = blk & (NC - 1);
    int bh = blk >> 5;
    int b = bh >> 4, h = bh & 15;
    int t = threadIdx.x;
    long tok0 = (long)b * LL + (long)c * CHUNK;

    // v tile [m][e] fp16 via cp.async (coalesced, 512 x 16B)
    for (int i = t; i < 512; i += 256) {
        int m = i >> 3, e8 = i & 7;
        CP_ASYNC16(smem_u32(smc + CS_VS + m * VS_STRIDE_B + e8 * 16),
                   g_vh + (tok0 + m) * 1024 + h * 64 + e8 * 8);
    }
    CP_COMMIT();

    // k transposed [f][n] fp32 (stride 68 -> rows 16B-aligned)
    for (int i = t; i < 64 * 16; i += 256) {
        int n = i >> 4, f = i & 15;
        k_T[f * 68 + n] = g_qk[(tok0 + n) * 512 + 256 + h * 16 + f];
    }
    __syncthreads();

    // kf^T fp16 swizzled: one uint4 per (d, chunk); float4 source loads
    for (int i = t; i < DFP * 8; i += 256) {
        int d = i >> 3, c8 = i & 7;
        int m0 = (c8 ^ (d & 7)) * 8;
        uint4 u;
        __half2* hp = (__half2*)&u;
        if (d == 0) {
            __half2 one2 = __floats2half2_rn(1.f, 1.f);
            hp[0] = one2; hp[1] = one2; hp[2] = one2; hp[3] = one2;
        } else if (d <= 16) {
            const float4* kr = (const float4*)&k_T[(d - 1) * 68 + m0];
            float4 a0 = kr[0], a1 = kr[1];
            hp[0] = __floats2half2_rn(a0.x * INV_RRD, a0.y * INV_RRD);
            hp[1] = __floats2half2_rn(a0.z * INV_RRD, a0.w * INV_RRD);
            hp[2] = __floats2half2_rn(a1.x * INV_RRD, a1.y * INV_RRD);
            hp[3] = __floats2half2_rn(a1.z * INV_RRD, a1.w * INV_RRD);
        } else if (d < DF) {
            int dd = d - 17;
            const float4* ka = (const float4*)&k_T[(dd >> 4) * 68 + m0];
            const float4* kb = (const float4*)&k_T[(dd & 15) * 68 + m0];
            float4 a0 = ka[0], a1 = ka[1], b0 = kb[0], b1 = kb[1];
            hp[0] = __floats2half2_rn(a0.x * b0.x * INV_Q2, a0.y * b0.y * INV_Q2);
            hp[1] = __floats2half2_rn(a0.z * b0.z * INV_Q2, a0.w * b0.w * INV_Q2);
            hp[2] = __floats2half2_rn(a1.x * b1.x * INV_Q2, a1.y * b1.y * INV_Q2);
            hp[3] = __floats2half2_rn(a1.z * b1.z * INV_Q2, a1.w * b1.w * INV_Q2);
        } else {
            u = make_uint4(0u, 0u, 0u, 0u);
        }
        *(uint4*)(smc + CS_KFT + d * 128 + c8 * 16) = u;
    }
    CP_WAIT(0);
    __syncthreads();

    // mma: warp w -> e-tile (w>>1); d-tiles (w&1)*18 .. +17 in two 9-tile passes
    int w = t >> 5, l = t & 31;
    uint32_t VSb = smem_u32(smc + CS_VS);
    uint32_t Bb = smem_u32(smc + CS_KFT);
    // A (v^T) fragment via ldmatrix.trans: lane -> v row / e-col
    int e0 = (w >> 1) * 16;
    int vrow_off = ((l >> 4) << 3) + (l & 7);            // + ks*16
    int veoff = e0 + (((l >> 3) & 1) << 3);
    uint32_t vaddr = VSb + vrow_off * VS_STRIDE_B + veoff * 2;
    int brow_base = (l & 7) + ((l >> 4) << 3);
    int bkh = (l >> 3) & 1;
    int ntile0 = (w & 1) * 18;
    int r0 = l >> 2, c0 = (l & 3) * 2;
    size_t Sbase = (size_t)blk * 64 * DFP;
    int e_lo = e0 + r0;

#pragma unroll
    for (int half = 0; half < 2; half++) {
        int tb = ntile0 + half * 9;
        float acc[9][4];
#pragma unroll
        for (int j = 0; j < 9; j++)
#pragma unroll
            for (int r = 0; r < 4; r++) acc[j][r] = 0.f;

#pragma unroll
        for (int ks = 0; ks < 4; ks++) {
            uint32_t afr[4];
            ldsm_x4_trans(afr, vaddr + ks * 16 * VS_STRIDE_B);
            int chb = ks * 2 + bkh;
#pragma unroll
            for (int jp = 0; jp < 4; jp++) {
                uint32_t bp[4];
                int row = (tb + jp * 2) * 8 + brow_base;
                ldsm_x4(bp, Bb + row * 128 + ((chb ^ (row & 7)) << 4));
                mma_f16(acc[jp * 2],     afr, bp);
                mma_f16(acc[jp * 2 + 1], afr, bp + 2);
            }
            {   // last single tile
                uint32_t bs[2];
                int row = (tb + 8) * 8 + (l & 7);
                int chs = ks * 2 + ((l >> 3) & 1);
                ldsm_x2(bs, Bb + row * 128 + ((chs ^ (row & 7)) << 4));
                mma_f16(acc[8], afr, bs);
            }
        }

        // store this half's 9 d-tiles, e-major fp16
#pragma unroll
        for (int j = 0; j < 9; j++) {
            int d = (tb + j) * 8 + c0;
            *(__half2*)&g_Sh[Sbase + (size_t)e_lo * DFP + d] =
                __floats2half2_rn(acc[j][0], acc[j][1]);
            *(__half2*)&g_Sh[Sbase + (size_t)(e_lo + 8) * DFP + d] =
                __floats2half2_rn(acc[j][2], acc[j][3]);
        }
    }

    // ssum[d] = sum_m kf[m][d] from kf^T smem
    for (int d = t; d < DF; d += 256) {
        float s = 0.f;
#pragma unroll
        for (int c8 = 0; c8 < 8; c8++) {
            int off = d * 128 + (((c8 ^ (d & 7))) << 4);
            uint4 u = *(const uint4*)(smc + CS_KFT + off);
            const __half2* hp = (const __half2*)&u;
#pragma unroll
            for (int q = 0; q < 4; q++) {
                float2 f2 = __half22float2(hp[q]);
                s += f2.x + f2.y;
            }
        }
        g_ss[(long)blk * DF + d] = s;
    }
}

// ---------------------------------------------------------------------------
// Fused in-place exclusive prefix scans (half2 granularity — max parallelism;
// the uint4 variant regressed: latency-bound, needs the warps).
// ---------------------------------------------------------------------------
#define SCAN_S_BLOCKS 1152   // NBH * (64*DFP/2) / 256
#define SCAN_SS_BLOCKS 35    // ceil(NBH*DF / 256)

__global__ void scan_all() {
    int blk = blockIdx.x;
    if (blk < SCAN_S_BLOCKS) {
        long idx = (long)blk * 256 + threadIdx.x;
        const long PER_BH = 64 * DFP / 2;  // 9216 half2 per chunk
        long bh = idx / PER_BH;
        long de = idx % PER_BH;
        __half2* Sp = (__half2*)g_Sh;
        size_t base = (size_t)bh * NC * PER_BH + de;
        float2 acc = make_float2(0.f, 0.f);
#pragma unroll
        for (int c = 0; c < NC; c++) {
            size_t p = base + (size_t)c * PER_BH;
            float2 tmp = __half22float2(Sp[p]);
            Sp[p] = __floats2half2_rn(acc.x, acc.y);
            acc.x += tmp.x; acc.y += tmp.y;
        }
    } else {
        long idx = (long)(blk - SCAN_S_BLOCKS) * 256 + threadIdx.x;
        if (idx >= (long)NBH * DF) return;
        long bh = idx / DF;
        long d = idx % DF;
        long base = bh * NC * DF + d;
        float acc = 0.f;
#pragma unroll
        for (int c = 0; c < NC; c++) {
            long p = base + (long)c * DF;
            float tmp = g_ss[p];
            g_ss[p] = acc;
            acc += tmp;
        }
    }
}

// ---------------------------------------------------------------------------
// Output via one fused mma GEMM per (bh,chunk):
//   Aop = [phi(q) (64x288) | A_poly (64x64)]  (fp16, padded stride 360)
//   Bop rows (N=72): e<64: [S^T[e] | v^T[e]], row64: [0 | 1...], 65..71: 0
//   denominator = fp32 scalar qf.sp + rowsum(A); y = num * z  (fp16 out)
// ---------------------------------------------------------------------------
#define OTS 360                         // row stride in halves (45 x 16B, odd)
#define OT_QF 0                         // 64 x 720B  = 46080
#define OT_B  46080                     // 72 x 720B  = 51840
#define OT_Q  97920                     // 64x16 fp32 = 4096
#define OT_K  102016                    // 64x16 fp32 = 4096
#define OT_SP 106112                    // 276  fp32  = 1104
#define OT_DS 107216                    // 64 fp32 (+pad)
#define OT_RS 107472                    // 64 fp32 (+pad)
#define OT_Z  107728                    // 64 fp32 (+pad)
#define OT_SMEM 107984

__global__ void __launch_bounds__(256, 2) output_mma() {
    extern __shared__ char smo[];
    float* q_s  = (float*)(smo + OT_Q);
    float* k_s  = (float*)(smo + OT_K);
    float* sp_s = (float*)(smo + OT_SP);
    float* ds_s = (float*)(smo + OT_DS);
    float* rs_s = (float*)(smo + OT_RS);
    float* z_s  = (float*)(smo + OT_Z);
    __half* qf  = (__half*)(smo + OT_QF);
    __half* Bx  = (__half*)(smo + OT_B);

    int blk = blockIdx.x;
    int c = blk & (NC - 1);
    int bh = blk >> 5;
    int b = bh >> 4, h = bh & 15;
    int t = threadIdx.x;
    long tok0 = (long)b * LL + (long)c * CHUNK;

    // ---- phase 1: loads ----
    {   // S^T rows via cp.async (36 uint4 per row)
        const uint4* src = (const uint4*)(g_Sh + (size_t)blk * 64 * DFP);
        for (int i = t; i < 64 * 36; i += 256) {
            int e = i / 36, u = i % 36;
            CP_ASYNC16(smem_u32(smo + OT_B + e * 720 + u * 16), src + i);
        }
        CP_COMMIT();
    }
    for (int i = t; i < 64 * 16; i += 256) {
        int n = i >> 4, f = i & 15;
        long off = (tok0 + n) * 512 + h * 16 + f;
        q_s[i] = g_qk[off];
        k_s[i] = g_qk[off + 256];
    }
    for (int i = t; i < 276; i += 256) sp_s[i] = (i < DF) ? g_ss[(long)blk * DF + i] : 0.f;
    for (int i = t; i < 2048; i += 256) {   // v^T into cols 288..351 (half2 stores)
        int m2 = (i >> 6) << 1, e = i & 63;
        __half va = g_vh[(tok0 + m2) * 1024 + h * 64 + e];
        __half vb = g_vh[(tok0 + m2 + 1) * 1024 + h * 64 + e];
        *(__half2*)&Bx[e * OTS + 288 + m2] = __halves2half2(va, vb);
    }
    for (int i = t; i < 8 * 180; i += 256) {    // rows 64..71
        int r = 64 + i / 180, u = i % 180;      // uint (2 halves)
        uint32_t val = (r == 64 && u >= 144 && u < 176) ? 0x3C003C00u : 0u;  // ones over v-cols
        *(uint32_t*)(smo + OT_B + r * 720 + u * 4) = val;
    }
    CP_WAIT(0);
    __syncthreads();

    // ---- phase 2: build A-operand (vectorized) + fp32 denominator part ----
    for (int i = t; i < 64 * 36; i += 256) {    // phi(q): one uint4 per 8 features
        int n = i / 36, d0 = (i % 36) * 8;
        const float* q0 = &q_s[n * 16];
        uint4 u;
        __half2* hp = (__half2*)&u;
#pragma unroll
        for (int p = 0; p < 4; p++) {
            float vv[2];
#pragma unroll
            for (int s2 = 0; s2 < 2; s2++) {
                int d = d0 + p * 2 + s2;
                float val = 0.f;
                if (d == 0) val = 1.f;
                else if (d <= 16) val = q0[d - 1] * INV_RRD;
                else if (d < DF) {
                    int dd = d - 17;
                    val = q0[dd >> 4] * q0[dd & 15] * INV_Q2;
                }
                vv[s2] = val;
            }
            hp[p] = __floats2half2_rn(vv[0], vv[1]);
        }
        *(uint4*)&qf[n * OTS + d0] = u;
    }
    {   // causal polynomial scores into cols 288..351 (thread -> (n, 16 m's))
        int n = t >> 2, mq = (t & 3) << 4;
        float qr[16];
#pragma unroll
        for (int f = 0; f < 16; f++) qr[f] = q_s[n * 16 + f];
#pragma unroll
        for (int mm = 0; mm < 16; mm += 2) {
            float a2[2];
#pragma unroll
            for (int u2 = 0; u2 < 2; u2++) {
                int m = mq + mm + u2;
                float s = 0.f;
#pragma unroll
                for (int f = 0; f < 16; f++) s += qr[f] * k_s[m * 16 + f];
                a2[u2] = (m <= n) ? (1.f + 0.25f * s + s * s * 0.03125f) : 0.f;
            }
            *(__half2*)&qf[n * OTS + 288 + mq + mm] = __floats2half2_rn(a2[0], a2[1]);
        }
        if (t < 64) {                    // fp32 qf . sp
            const float* q0 = &q_s[t * 16];
            float d1 = 0.f;
#pragma unroll
            for (int f = 0; f < 16; f++) d1 += q0[f] * sp_s[1 + f];
            float d2 = 0.f;
            for (int i2 = 0; i2 < 16; i2++) {
                float inner = 0.f;
#pragma unroll
                for (int j = 0; j < 16; j++) inner += q0[j] * sp_s[17 + 16 * i2 + j];
                d2 += q0[i2] * inner;
            }
            ds_s[t] = sp_s[0] + INV_RRD * d1 + INV_Q2 * d2;
        }
    }
    __syncthreads();

    // ---- phase 3: 64x72x352 fp16 GEMM (8 warps: 4 m-tiles x 2 n-groups) ----
    int w = t >> 5, l = t & 31;
    int m0w = (w >> 1) * 16;
    int nh5 = w & 1;
    int nr0 = nh5 * 40;
    float acc[5][4];
#pragma unroll
    for (int j = 0; j < 5; j++)
#pragma unroll
        for (int r = 0; r < 4; r++) acc[j][r] = 0.f;

    uint32_t Qb = smem_u32(smo + OT_QF);
    uint32_t Bb = smem_u32(smo + OT_B);
    uint32_t aad = Qb + (m0w + (l & 15)) * 720 + (l >> 4) * 16;
    uint32_t bpd = Bb + (nr0 + (l & 7) + ((l >> 4) << 3)) * 720 + ((l >> 3) & 1) * 16;
    uint32_t bsd = Bb + (nr0 + 32 + (l & 7)) * 720 + ((l >> 3) & 1) * 16;

    if (nh5 == 0) {
#pragma unroll
        for (int ks = 0; ks < 22; ks++) {
            uint32_t afr[4], bp0[4], bp1[4], bs[2];
            ldsm_x4(afr, aad + ks * 32);
            ldsm_x4(bp0, bpd + ks * 32);
            ldsm_x4(bp1, bpd + 16 * 720 + ks * 32);
            ldsm_x2(bs,  bsd + ks * 32);
            mma_f16(acc[0], afr, bp0);
            mma_f16(acc[1], afr, bp0 + 2);
            mma_f16(acc[2], afr, bp1);
            mma_f16(acc[3], afr, bp1 + 2);
            mma_f16(acc[4], afr, bs);
        }
    } else {
#pragma unroll
        for (int ks = 0; ks < 22; ks++) {
            uint32_t afr[4], bp0[4], bp1[4];
            ldsm_x4(afr, aad + ks * 32);
            ldsm_x4(bp0, bpd + ks * 32);
            ldsm_x4(bp1, bpd + 16 * 720 + ks * 32);
            mma_f16(acc[0], afr, bp0);
            mma_f16(acc[1], afr, bp0 + 2);
            mma_f16(acc[2], afr, bp1);
            mma_f16(acc[3], afr, bp1 + 2);
        }
    }

    // ---- phase 4: denominator + write ----
    int r0 = l >> 2, c0 = (l & 3) * 2;
    if (nh5 == 1 && (l & 3) == 0) {     // local tile 3 = global tile 8 -> col 64
        rs_s[m0w + r0] = acc[3][0];
        rs_s[m0w + r0 + 8] = acc[3][2];
    }
    __syncthreads();
    if (t < 64) z_s[t] = 1.f / (ds_s[t] + rs_s[t] + EPS);
    __syncthreads();

    float z0 = z_s[m0w + r0], z1 = z_s[m0w + r0 + 8];
    size_t rowb0 = (size_t)(tok0 + m0w + r0) * KP + h * 64;
    size_t rowb1 = (size_t)(tok0 + m0w + r0 + 8) * KP + h * 64;
    int jmax = nh5 ? 4 : 5;
#pragma unroll
    for (int j = 0; j < 5; j++) {
        if (j >= jmax) break;
        int col = (nh5 * 5 + j) * 8 + c0;
        if (col < 64) {
            *(__half2*)&g_yh[rowb0 + col] =
                __floats2half2_rn(acc[j][0] * z0, acc[j][1] * z0);
            *(__half2*)&g_yh[rowb1 + col] =
                __floats2half2_rn(acc[j][2] * z1, acc[j][3] * z1);
        }
    }
}

// ---------------------------------------------------------------------------
extern "C" void kernel_launch(void* const* d_in, const int* in_sizes, int n_in,
                              void* d_out, int out_size) {
    const float* x  = (const float*)d_in[0];
    const float* Wq = (const float*)d_in[1];
    const float* Wk = (const float*)d_in[2];
    const float* Wv = (const float*)d_in[3];
    const float* Wo = (const float*)d_in[4];
    float* out = (float*)d_out;

    void *pxh, *pwqk, *pwvh, *pwoh, *pqk, *pvh, *pyh;
    cudaGetSymbolAddress(&pxh, g_xh);
    cudaGetSymbolAddress(&pwqk, g_wqk);
    cudaGetSymbolAddress(&pwvh, g_wvh);
    cudaGetSymbolAddress(&pwoh, g_woh);
    cudaGetSymbolAddress(&pqk, g_qk);
    cudaGetSymbolAddress(&pvh, g_vh);
    cudaGetSymbolAddress(&pyh, g_yh);

    cudaFuncSetAttribute(chunk_state_mma, cudaFuncAttributeMaxDynamicSharedMemorySize, CS_SMEM);
    cudaFuncSetAttribute(output_mma, cudaFuncAttributeMaxDynamicSharedMemorySize, OT_SMEM);
    cudaFuncSetAttribute(proj_gemm, cudaFuncAttributeMaxDynamicSharedMemorySize, GEMM_SMEM);
    cudaFuncSetAttribute(gemm_o, cudaFuncAttributeMaxDynamicSharedMemorySize, GEMM_SMEM);

    // split/convert inputs (fused)
    prep_kernel<<<4096 + 80 * 32, 256>>>(x, Wq, Wk, Wv, Wo);

    // fused q/k + v projections on tensor cores
    proj_gemm<<<384, 256, GEMM_SMEM>>>((const __half*)pxh, (const __half*)pwqk, (float*)pqk,
                                       (const __half*)pwvh, (__half*)pvh);

    // chunked linear attention
    chunk_state_mma<<<NBH * NC, 256, CS_SMEM>>>();
    scan_all<<<SCAN_S_BLOCKS + SCAN_SS_BLOCKS, 256>>>();
    output_mma<<<NBH * NC, 256, OT_SMEM>>>();

    // final projection
    gemm_o<<<dim3(8, 32), 256, GEMM_SMEM>>>((const __half*)pyh, (const __half*)pwoh, out);
}